// round 1
// baseline (speedup 1.0000x reference)
#include <cuda_runtime.h>
#include <math.h>

#define BB   2
#define LSEQ 2048
#define DM   1024
#define DI   2048
#define DSTT 16
#define NH   8
#define DH   128
#define NEXP 4
#define DFF  4096
#define NTOK (BB*LSEQ)   // 4096

// ---------------- static scratch (allowed: __device__ globals) ----------------
__device__ float g_rms1[NTOK*DM];
__device__ float g_xz[NTOK*2*DI];
__device__ float g_xc[NTOK*DI];
__device__ float g_dtBC[NTOK*48];
__device__ float g_scanp[NTOK*48];
__device__ float g_ymul[NTOK*DI];
__device__ float g_tmp[NTOK*DM];
__device__ float g_x1[NTOK*DM];
__device__ float g_rms2[NTOK*DM];
__device__ float g_qkv[NTOK*3*DM];
__device__ float g_scores[BB*NH*LSEQ*LSEQ];   // 268 MB
__device__ float g_att[NTOK*DM];
__device__ float g_x2[NTOK*DM];
__device__ float g_xf[NTOK*DM];
__device__ float g_g1[NTOK*512];
__device__ float g_gs[NTOK*NEXP];
__device__ int   g_topi[NTOK*2];
__device__ float g_topw[NTOK*2];
__device__ float g_h1[NTOK*DFF];
__device__ float g_h2[NTOK*DFF];
__device__ float g_eo[NEXP*NTOK*DM];

__device__ __forceinline__ float siluf(float x){ return x / (1.f + expf(-x)); }

// ---------------- RMSNorm ----------------
__global__ void rmsnorm_k(const float* __restrict__ x, const float* __restrict__ w,
                          float* __restrict__ o){
    int row = blockIdx.x;
    const float* xr = x + (long)row*DM;
    __shared__ float red[256];
    float s = 0.f;
    for (int i = threadIdx.x; i < DM; i += 256){ float v = xr[i]; s += v*v; }
    red[threadIdx.x] = s; __syncthreads();
    for (int st = 128; st > 0; st >>= 1){
        if (threadIdx.x < st) red[threadIdx.x] += red[threadIdx.x+st];
        __syncthreads();
    }
    float r = rsqrtf(red[0]/(float)DM + 1e-6f);
    for (int i = threadIdx.x; i < DM; i += 256) o[(long)row*DM+i] = w[i]*xr[i]*r;
}

// ---------------- SGEMM: C[M,N] = A[M,K] * op(B), 128x128x8 tile, 8x8/thread ----------------
// TRANSB==0: B is [K,N] row-major (ldb).  TRANSB==1: B is [N,K] row-major (A*B^T).
// EPI==1: C = relu(acc + bias[n]).
template<int TRANSB, int EPI>
__global__ void __launch_bounds__(256) gemm_k(
    const float* __restrict__ A, const float* __restrict__ B, float* __restrict__ C,
    int M, int N, int K, int lda, int ldb, int ldc,
    long sA, long sB, long sC, const float* __restrict__ bias)
{
    __shared__ float As[8][132];
    __shared__ float Bs[8][132];
    const float* Ab = A + (long)blockIdx.z * sA;
    const float* Bb = B + (long)blockIdx.z * sB;
    float* Cb = C + (long)blockIdx.z * sC;
    const int bm = blockIdx.y * 128;
    const int bn = blockIdx.x * 128;
    const int tid = threadIdx.x;
    const int tx = tid & 15, ty = tid >> 4;
    const int lm = tid >> 1;           // 0..127
    const int lk = (tid & 1) * 4;      // 0 or 4
    const int bkk = tid >> 5;          // 0..7
    const int bnn = (tid & 31) * 4;    // 0..124

    float acc[8][8];
    #pragma unroll
    for (int i = 0; i < 8; i++)
        #pragma unroll
        for (int j = 0; j < 8; j++) acc[i][j] = 0.f;

    for (int k0 = 0; k0 < K; k0 += 8){
        float4 a4 = *reinterpret_cast<const float4*>(&Ab[(long)(bm+lm)*lda + k0 + lk]);
        As[lk+0][lm] = a4.x; As[lk+1][lm] = a4.y; As[lk+2][lm] = a4.z; As[lk+3][lm] = a4.w;
        if (TRANSB == 0){
            float4 b4 = *reinterpret_cast<const float4*>(&Bb[(long)(k0+bkk)*ldb + bn + bnn]);
            *reinterpret_cast<float4*>(&Bs[bkk][bnn]) = b4;
        } else {
            float4 b4 = *reinterpret_cast<const float4*>(&Bb[(long)(bn+lm)*ldb + k0 + lk]);
            Bs[lk+0][lm] = b4.x; Bs[lk+1][lm] = b4.y; Bs[lk+2][lm] = b4.z; Bs[lk+3][lm] = b4.w;
        }
        __syncthreads();
        #pragma unroll
        for (int kk = 0; kk < 8; kk++){
            float av[8], bv[8];
            *reinterpret_cast<float4*>(&av[0]) = *reinterpret_cast<const float4*>(&As[kk][ty*8]);
            *reinterpret_cast<float4*>(&av[4]) = *reinterpret_cast<const float4*>(&As[kk][ty*8+4]);
            *reinterpret_cast<float4*>(&bv[0]) = *reinterpret_cast<const float4*>(&Bs[kk][tx*8]);
            *reinterpret_cast<float4*>(&bv[4]) = *reinterpret_cast<const float4*>(&Bs[kk][tx*8+4]);
            #pragma unroll
            for (int i = 0; i < 8; i++)
                #pragma unroll
                for (int j = 0; j < 8; j++)
                    acc[i][j] = fmaf(av[i], bv[j], acc[i][j]);
        }
        __syncthreads();
    }
    #pragma unroll
    for (int i = 0; i < 8; i++){
        long row = bm + ty*8 + i;
        float* cp = Cb + row*(long)ldc + bn + tx*8;
        float v[8];
        #pragma unroll
        for (int j = 0; j < 8; j++){
            float t = acc[i][j];
            if (EPI == 1){ t += bias[bn + tx*8 + j]; t = fmaxf(t, 0.f); }
            v[j] = t;
        }
        *reinterpret_cast<float4*>(&cp[0]) = *reinterpret_cast<float4*>(&v[0]);
        *reinterpret_cast<float4*>(&cp[4]) = *reinterpret_cast<float4*>(&v[4]);
    }
}

// ---------------- depthwise conv (K=4, pad (2,1)) + bias + SiLU ----------------
__global__ void conv_k(const float* __restrict__ xz, const float* __restrict__ cw,
                       const float* __restrict__ cb, float* __restrict__ xc){
    long idx = (long)blockIdx.x*blockDim.x + threadIdx.x;
    if (idx >= (long)NTOK*DI) return;
    int d = (int)(idx % DI);
    int row = (int)(idx / DI);
    int t = row % LSEQ, b = row / LSEQ;
    float s = cb[d];
    #pragma unroll
    for (int k = 0; k < 4; k++){
        int tt = t + k - 2;
        if (tt >= 0 && tt < LSEQ)
            s = fmaf(cw[d*4+k], xz[(long)(b*LSEQ+tt)*(2*DI) + d], s);
    }
    xc[idx] = siluf(s);
}

// ---------------- dt/B/C small projections: per-row, 48 outputs ----------------
__global__ void projsmall_k(const float* __restrict__ xc, const float* __restrict__ Wdt,
                            const float* __restrict__ WB, const float* __restrict__ WC,
                            float* __restrict__ out){
    int row = blockIdx.x;
    __shared__ float sx[DI];
    for (int i = threadIdx.x; i < DI; i += blockDim.x) sx[i] = xc[(long)row*DI + i];
    __syncthreads();
    int warp = threadIdx.x / 32, lane = threadIdx.x % 32;
    for (int o = warp; o < 48; o += 8){
        const float* W = (o < 16) ? Wdt : (o < 32 ? WB : WC);
        int n = o & 15;
        float s = 0.f;
        for (int j = lane; j < DI; j += 32) s = fmaf(sx[j], W[j*16+n], s);
        #pragma unroll
        for (int off = 16; off > 0; off >>= 1) s += __shfl_down_sync(0xffffffffu, s, off);
        if (lane == 0) out[(long)row*48 + o] = s;
    }
}

// ---------------- scan preprocessing: softplus(dt)+decay+dB ----------------
__global__ void scanprep_k(const float* __restrict__ dtBC, const float* __restrict__ bdt,
                           const float* __restrict__ A, float* __restrict__ sp){
    int idx = blockIdx.x*blockDim.x + threadIdx.x;
    if (idx >= NTOK*16) return;
    int n = idx & 15, row = idx >> 4;
    float dtp = dtBC[(long)row*48 + n] + bdt[n];
    float dt  = fmaxf(dtp, 0.f) + log1pf(expf(-fabsf(dtp)));   // softplus
    sp[(long)row*48 + n]      = expf(dt * A[n]);               // decay
    sp[(long)row*48 + 16 + n] = dt * dtBC[(long)row*48 + 16 + n]; // dB
    sp[(long)row*48 + 32 + n] = dtBC[(long)row*48 + 32 + n];   // C
}

// ---------------- selective scan: one thread per (b, d), 16 states ----------------
__global__ void scan_k(const float* __restrict__ sp, const float* __restrict__ xc,
                       const float* __restrict__ xz, const float* __restrict__ Dp,
                       float* __restrict__ ymul){
    int gid = blockIdx.x*blockDim.x + threadIdx.x;   // 0..BB*DI
    if (gid >= BB*DI) return;
    int b = gid / DI, d = gid % DI;
    float h[16];
    #pragma unroll
    for (int n = 0; n < 16; n++) h[n] = 0.f;
    const float dpv = Dp[d];
    for (int t = 0; t < LSEQ; t++){
        int row = b*LSEQ + t;
        const float4* p = reinterpret_cast<const float4*>(sp + (long)row*48);
        float4 de0 = p[0], de1 = p[1], de2 = p[2], de3 = p[3];
        float4 db0 = p[4], db1 = p[5], db2 = p[6], db3 = p[7];
        float4 c0  = p[8], c1  = p[9], c2  = p[10], c3 = p[11];
        float xv = xc[(long)row*DI + d];
        float y = 0.f;
        h[0]=fmaf(de0.x,h[0],db0.x*xv); y=fmaf(h[0],c0.x,y);
        h[1]=fmaf(de0.y,h[1],db0.y*xv); y=fmaf(h[1],c0.y,y);
        h[2]=fmaf(de0.z,h[2],db0.z*xv); y=fmaf(h[2],c0.z,y);
        h[3]=fmaf(de0.w,h[3],db0.w*xv); y=fmaf(h[3],c0.w,y);
        h[4]=fmaf(de1.x,h[4],db1.x*xv); y=fmaf(h[4],c1.x,y);
        h[5]=fmaf(de1.y,h[5],db1.y*xv); y=fmaf(h[5],c1.y,y);
        h[6]=fmaf(de1.z,h[6],db1.z*xv); y=fmaf(h[6],c1.z,y);
        h[7]=fmaf(de1.w,h[7],db1.w*xv); y=fmaf(h[7],c1.w,y);
        h[8]=fmaf(de2.x,h[8],db2.x*xv); y=fmaf(h[8],c2.x,y);
        h[9]=fmaf(de2.y,h[9],db2.y*xv); y=fmaf(h[9],c2.y,y);
        h[10]=fmaf(de2.z,h[10],db2.z*xv); y=fmaf(h[10],c2.z,y);
        h[11]=fmaf(de2.w,h[11],db2.w*xv); y=fmaf(h[11],c2.w,y);
        h[12]=fmaf(de3.x,h[12],db3.x*xv); y=fmaf(h[12],c3.x,y);
        h[13]=fmaf(de3.y,h[13],db3.y*xv); y=fmaf(h[13],c3.y,y);
        h[14]=fmaf(de3.z,h[14],db3.z*xv); y=fmaf(h[14],c3.z,y);
        h[15]=fmaf(de3.w,h[15],db3.w*xv); y=fmaf(h[15],c3.w,y);
        float z = xz[(long)row*(2*DI) + DI + d];
        ymul[(long)row*DI + d] = (y + dpv*xv) * siluf(z);
    }
}

// ---------------- residual: o = x + ls * delta ----------------
__global__ void resid_k(const float* __restrict__ x, const float* __restrict__ ls,
                        const float* __restrict__ dlt, float* __restrict__ o, long n){
    long idx = (long)blockIdx.x*blockDim.x + threadIdx.x;
    if (idx >= n) return;
    int d = (int)(idx % DM);
    o[idx] = fmaf(ls[d], dlt[idx], x[idx]);
}

// ---------------- RoPE on q,k (in place), q *= sqrt(DH) ----------------
__global__ void rope_k(float* __restrict__ qkv){
    int row = blockIdx.x;
    int t = row % LSEQ;
    __shared__ float q[DM], kk[DM];
    float* base = qkv + (long)row*3*DM;
    for (int i = threadIdx.x; i < DM; i += 256){ q[i] = base[i]; kk[i] = base[DM+i]; }
    __syncthreads();
    const float sq = sqrtf((float)DH);
    const float lg = logf(10000.f) / 64.f;
    for (int idx = threadIdx.x; idx < DM; idx += 256){
        int h = idx / DH, i = idx % DH;
        int j = i & 63;
        float inv = expf(-(float)j * lg);
        float ang = (float)t * inv;
        float c = cosf(ang), s = sinf(ang);
        int off = h * DH;
        float rq, rk;
        if (i < 64){ rq = -q[off + 2*i + 1]; rk = -kk[off + 2*i + 1]; }
        else       { rq =  q[off + 2*(i-64)]; rk =  kk[off + 2*(i-64)]; }
        base[idx]      = (q[idx]*c + rq*s) * sq;
        base[DM + idx] =  kk[idx]*c + rk*s;
    }
}

// ---------------- row softmax over L with per-head scale ----------------
__global__ void softmax_k(float* __restrict__ sc, const float* __restrict__ ascale){
    long row = blockIdx.x;
    int h = (int)((row / LSEQ) % NH);
    float a = ascale[h];
    float* p = sc + row*(long)LSEQ;
    int tid = threadIdx.x;
    float v[8]; float mx = -1e30f;
    #pragma unroll
    for (int j = 0; j < 8; j++){ v[j] = p[tid + j*256]*a; mx = fmaxf(mx, v[j]); }
    __shared__ float red[256];
    red[tid] = mx; __syncthreads();
    for (int st = 128; st > 0; st >>= 1){ if (tid < st) red[tid] = fmaxf(red[tid], red[tid+st]); __syncthreads(); }
    mx = red[0]; __syncthreads();
    float s = 0.f;
    #pragma unroll
    for (int j = 0; j < 8; j++){ v[j] = expf(v[j]-mx); s += v[j]; }
    red[tid] = s; __syncthreads();
    for (int st = 128; st > 0; st >>= 1){ if (tid < st) red[tid] += red[tid+st]; __syncthreads(); }
    float inv = 1.f / red[0];
    #pragma unroll
    for (int j = 0; j < 8; j++) p[tid + j*256] = v[j]*inv;
}

// ---------------- gate stage 2: logits(4), softmax, top-2 ----------------
__global__ void gate2_k(const float* __restrict__ g1, const float* __restrict__ Wg2,
                        float* __restrict__ gs, int* __restrict__ topi, float* __restrict__ topw){
    int row = blockIdx.x;
    int tid = threadIdx.x; // 64 threads
    __shared__ float red[64*4];
    float a[4] = {0.f,0.f,0.f,0.f};
    for (int j = tid; j < 512; j += 64){
        float v = g1[(long)row*512 + j];
        #pragma unroll
        for (int e = 0; e < 4; e++) a[e] = fmaf(v, Wg2[j*4+e], a[e]);
    }
    #pragma unroll
    for (int e = 0; e < 4; e++) red[e*64 + tid] = a[e];
    __syncthreads();
    for (int st = 32; st > 0; st >>= 1){
        if (tid < st){
            #pragma unroll
            for (int e = 0; e < 4; e++) red[e*64+tid] += red[e*64+tid+st];
        }
        __syncthreads();
    }
    if (tid == 0){
        float l[4]; for (int e = 0; e < 4; e++) l[e] = red[e*64];
        float m = fmaxf(fmaxf(l[0],l[1]), fmaxf(l[2],l[3]));
        float ex[4]; float s = 0.f;
        for (int e = 0; e < 4; e++){ ex[e] = expf(l[e]-m); s += ex[e]; }
        float gsv[4];
        for (int e = 0; e < 4; e++){ gsv[e] = ex[e]/s; gs[(long)row*4+e] = gsv[e]; }
        int i0 = 0;
        for (int e = 1; e < 4; e++) if (gsv[e] > gsv[i0]) i0 = e;
        int i1 = -1;
        for (int e = 0; e < 4; e++) if (e != i0 && (i1 < 0 || gsv[e] > gsv[i1])) i1 = e;
        float v0 = gsv[i0], v1 = gsv[i1];
        float mm = fmaxf(v0, v1);
        float w0 = expf(v0-mm), w1 = expf(v1-mm);
        float ws = w0 + w1;
        topi[row*2] = i0; topi[row*2+1] = i1;
        topw[row*2] = w0/ws; topw[row*2+1] = w1/ws;
    }
}

// ---------------- balance loss (deterministic single-block reduce) ----------------
__global__ void bal_k(const float* __restrict__ gs, float* __restrict__ out){
    int tid = threadIdx.x;
    __shared__ float red[256*4];
    float a[4] = {0.f,0.f,0.f,0.f};
    for (int r = tid; r < NTOK; r += 256){
        #pragma unroll
        for (int e = 0; e < 4; e++) a[e] += gs[(long)r*4+e];
    }
    #pragma unroll
    for (int e = 0; e < 4; e++) red[e*256+tid] = a[e];
    __syncthreads();
    for (int st = 128; st > 0; st >>= 1){
        if (tid < st){
            #pragma unroll
            for (int e = 0; e < 4; e++) red[e*256+tid] += red[e*256+tid+st];
        }
        __syncthreads();
    }
    if (tid == 0){
        float bal = 0.f;
        for (int e = 0; e < 4; e++){
            float gm = red[e*256] / (float)NTOK;
            bal += gm * logf(gm + 1e-8f);
        }
        out[0] = (float)NEXP * bal;
    }
}

// ---------------- MoE: h = silu(h1)*h2 ----------------
__global__ void silumul_k(float* __restrict__ h1, const float* __restrict__ h2, long n){
    long idx = (long)blockIdx.x*blockDim.x + threadIdx.x;
    if (idx >= n) return;
    h1[idx] = siluf(h1[idx]) * h2[idx];
}

// ---------------- MoE combine + final residual -> d_out ----------------
__global__ void combine_k(const float* __restrict__ x2, const float* __restrict__ ls3,
                          const float* __restrict__ eo, const int* __restrict__ topi,
                          const float* __restrict__ topw, float* __restrict__ out){
    long idx = (long)blockIdx.x*blockDim.x + threadIdx.x;
    if (idx >= (long)NTOK*DM) return;
    int row = (int)(idx / DM), d = (int)(idx % DM);
    int i0 = topi[row*2], i1 = topi[row*2+1];
    float m = topw[row*2]   * eo[((long)i0*NTOK + row)*DM + d]
            + topw[row*2+1] * eo[((long)i1*NTOK + row)*DM + d];
    out[idx] = fmaf(ls3[d], m, x2[idx]);
}

// ============================== host ==============================
#define SYMP(p, s) do { void* _t; cudaGetSymbolAddress(&_t, s); p = (float*)_t; } while(0)

extern "C" void kernel_launch(void* const* d_in, const int* in_sizes, int n_in,
                              void* d_out, int out_size){
    const float* x      = (const float*)d_in[0];
    const float* rms1_w = (const float*)d_in[1];
    const float* rms2_w = (const float*)d_in[2];
    const float* rms3_w = (const float*)d_in[3];
    const float* ls1    = (const float*)d_in[4];
    const float* ls2    = (const float*)d_in[5];
    const float* ls3    = (const float*)d_in[6];
    const float* W_in   = (const float*)d_in[7];
    const float* conv_w = (const float*)d_in[8];
    const float* conv_b = (const float*)d_in[9];
    const float* W_B    = (const float*)d_in[10];
    const float* W_C    = (const float*)d_in[11];
    const float* W_dt   = (const float*)d_in[12];
    const float* b_dt   = (const float*)d_in[13];
    const float* W_out_m= (const float*)d_in[14];
    const float* Avec   = (const float*)d_in[15];
    const float* Dp     = (const float*)d_in[16];
    const float* W_qkv  = (const float*)d_in[17];
    const float* W_o    = (const float*)d_in[18];
    const float* ascale = (const float*)d_in[19];
    const float* Wg1    = (const float*)d_in[20];
    const float* bg1    = (const float*)d_in[21];
    const float* Wg2    = (const float*)d_in[22];
    const float* w1     = (const float*)d_in[23];
    const float* w2     = (const float*)d_in[24];
    const float* w3     = (const float*)d_in[25];
    float* out = (float*)d_out;

    float *p_rms1, *p_xz, *p_xc, *p_dtBC, *p_scanp, *p_ymul, *p_tmp, *p_x1, *p_rms2;
    float *p_qkv, *p_scores, *p_att, *p_x2, *p_xf, *p_g1, *p_gs, *p_topw, *p_h1, *p_h2, *p_eo;
    int* p_topi;
    SYMP(p_rms1, g_rms1); SYMP(p_xz, g_xz); SYMP(p_xc, g_xc); SYMP(p_dtBC, g_dtBC);
    SYMP(p_scanp, g_scanp); SYMP(p_ymul, g_ymul); SYMP(p_tmp, g_tmp); SYMP(p_x1, g_x1);
    SYMP(p_rms2, g_rms2); SYMP(p_qkv, g_qkv); SYMP(p_scores, g_scores); SYMP(p_att, g_att);
    SYMP(p_x2, g_x2); SYMP(p_xf, g_xf); SYMP(p_g1, g_g1); SYMP(p_gs, g_gs); SYMP(p_topw, g_topw);
    SYMP(p_h1, g_h1); SYMP(p_h2, g_h2); SYMP(p_eo, g_eo);
    { void* _t; cudaGetSymbolAddress(&_t, g_topi); p_topi = (int*)_t; }

    // ---- 1. Mamba sub-block ----
    rmsnorm_k<<<NTOK, 256>>>(x, rms1_w, p_rms1);
    {   dim3 g(2*DI/128, NTOK/128, 1);
        gemm_k<0,0><<<g, 256>>>(p_rms1, W_in, p_xz, NTOK, 2*DI, DM, DM, 2*DI, 2*DI, 0,0,0, nullptr); }
    conv_k<<<(NTOK*DI+255)/256, 256>>>(p_xz, conv_w, conv_b, p_xc);
    projsmall_k<<<NTOK, 256>>>(p_xc, W_dt, W_B, W_C, p_dtBC);
    scanprep_k<<<(NTOK*16+255)/256, 256>>>(p_dtBC, b_dt, Avec, p_scanp);
    scan_k<<<(BB*DI+255)/256, 256>>>(p_scanp, p_xc, p_xz, Dp, p_ymul);
    {   dim3 g(DM/128, NTOK/128, 1);
        gemm_k<0,0><<<g, 256>>>(p_ymul, W_out_m, p_tmp, NTOK, DM, DI, DI, DM, DM, 0,0,0, nullptr); }
    resid_k<<<(NTOK*DM+255)/256, 256>>>(x, ls1, p_tmp, p_x1, (long)NTOK*DM);

    // ---- 2. Attention sub-block ----
    rmsnorm_k<<<NTOK, 256>>>(p_x1, rms2_w, p_rms2);
    {   dim3 g(3*DM/128, NTOK/128, 1);
        gemm_k<0,0><<<g, 256>>>(p_rms2, W_qkv, p_qkv, NTOK, 3*DM, DM, DM, 3*DM, 3*DM, 0,0,0, nullptr); }
    rope_k<<<NTOK, 256>>>(p_qkv);
    for (int b = 0; b < BB; b++){
        dim3 g(LSEQ/128, LSEQ/128, NH);
        gemm_k<1,0><<<g, 256>>>(p_qkv + (long)b*LSEQ*3*DM,
                                p_qkv + (long)b*LSEQ*3*DM + DM,
                                p_scores + (long)b*NH*LSEQ*LSEQ,
                                LSEQ, LSEQ, DH, 3*DM, 3*DM, LSEQ,
                                128, 128, (long)LSEQ*LSEQ, nullptr);
    }
    softmax_k<<<BB*NH*LSEQ, 256>>>(p_scores, ascale);
    for (int b = 0; b < BB; b++){
        dim3 g(DH/128, LSEQ/128, NH);
        gemm_k<0,0><<<g, 256>>>(p_scores + (long)b*NH*LSEQ*LSEQ,
                                p_qkv + (long)b*LSEQ*3*DM + 2*DM,
                                p_att + (long)b*LSEQ*DM,
                                LSEQ, DH, LSEQ, LSEQ, 3*DM, DM,
                                (long)LSEQ*LSEQ, 128, 128, nullptr);
    }
    {   dim3 g(DM/128, NTOK/128, 1);
        gemm_k<0,0><<<g, 256>>>(p_att, W_o, p_tmp, NTOK, DM, DM, DM, DM, DM, 0,0,0, nullptr); }
    resid_k<<<(NTOK*DM+255)/256, 256>>>(p_x1, ls2, p_tmp, p_x2, (long)NTOK*DM);

    // ---- 3. MoE sub-block ----
    rmsnorm_k<<<NTOK, 256>>>(p_x2, rms3_w, p_xf);
    {   dim3 g(512/128, NTOK/128, 1);
        gemm_k<0,1><<<g, 256>>>(p_xf, Wg1, p_g1, NTOK, 512, DM, DM, 512, 512, 0,0,0, bg1); }
    gate2_k<<<NTOK, 64>>>(p_g1, Wg2, p_gs, p_topi, p_topw);
    if (out_size > NTOK*DM)
        bal_k<<<1, 256>>>(p_gs, out + (long)NTOK*DM);
    for (int e = 0; e < NEXP; e++){
        dim3 g1d(DFF/128, NTOK/128, 1);
        gemm_k<0,0><<<g1d, 256>>>(p_xf, w1 + (long)e*DM*DFF, p_h1, NTOK, DFF, DM, DM, DFF, DFF, 0,0,0, nullptr);
        gemm_k<0,0><<<g1d, 256>>>(p_xf, w2 + (long)e*DM*DFF, p_h2, NTOK, DFF, DM, DM, DFF, DFF, 0,0,0, nullptr);
        silumul_k<<<(int)(((long)NTOK*DFF+255)/256), 256>>>(p_h1, p_h2, (long)NTOK*DFF);
        dim3 g3(DM/128, NTOK/128, 1);
        gemm_k<0,0><<<g3, 256>>>(p_h1, w3 + (long)e*DFF*DM, p_eo + (long)e*NTOK*DM,
                                 NTOK, DM, DFF, DFF, DM, DM, 0,0,0, nullptr);
    }
    combine_k<<<(NTOK*DM+255)/256, 256>>>(p_x2, ls3, p_eo, p_topi, p_topw, out);
}

// round 3
// speedup vs baseline: 3.2634x; 3.2634x over previous
#include <cuda_runtime.h>
#include <cuda_bf16.h>
#include <math.h>

#define BB   2
#define LSEQ 2048
#define DM   1024
#define DI   2048
#define NH   8
#define DH   128
#define NEXP 4
#define DFF  4096
#define NTOK (BB*LSEQ)   // 4096

typedef __nv_bfloat16 bf16;

// ---------------- static scratch ----------------
__device__ float g_xz[NTOK*2*DI];
__device__ float g_xc[NTOK*DI];
__device__ float g_dtBC[NTOK*64];
__device__ float g_scanp[NTOK*48];
__device__ float g_tmp[NTOK*DM];
__device__ float g_x1[NTOK*DM];
__device__ float g_qkv[NTOK*3*DM];
__device__ float g_scores[BB*NH*LSEQ*LSEQ];   // 268 MB
__device__ float g_x2[NTOK*DM];
__device__ float g_g1[NTOK*512];
__device__ float g_gs[NTOK*NEXP];
__device__ int   g_topi[NTOK*2];
__device__ float g_topw[NTOK*2];
__device__ float g_h1[NTOK*DFF];
__device__ float g_h2[NTOK*DFF];
__device__ float g_eo[NEXP*NTOK*DM];

// bf16 activations
__device__ bf16 g_rms1b[NTOK*DM];
__device__ bf16 g_xcb[NTOK*DI];
__device__ bf16 g_ymulb[NTOK*DI];
__device__ bf16 g_rms2b[NTOK*DM];
__device__ bf16 g_qb[NTOK*DM];
__device__ bf16 g_kb[NTOK*DM];
__device__ bf16 g_vb[NTOK*DM];
__device__ bf16 g_probsb[BB*NH*LSEQ*LSEQ];    // 134 MB
__device__ bf16 g_attb[NTOK*DM];
__device__ bf16 g_xfb[NTOK*DM];
__device__ bf16 g_hb[NTOK*DFF];

// bf16 weights
__device__ bf16 g_Winb[DM*2*DI];
__device__ bf16 g_Woutb[DI*DM];
__device__ bf16 g_Wqkvb[DM*3*DM];
__device__ bf16 g_Wob[DM*DM];
__device__ bf16 g_Wg1b[DM*512];
__device__ bf16 g_w1b[NEXP*DM*DFF];
__device__ bf16 g_w2b[NEXP*DM*DFF];
__device__ bf16 g_w3b[NEXP*DFF*DM];
__device__ bf16 g_Wcatb[DI*64];

__device__ __forceinline__ float siluf(float x){ return x / (1.f + expf(-x)); }

// ---------------- fp32 -> bf16 convert ----------------
__global__ void f2bf_k(const float* __restrict__ s, bf16* __restrict__ d, long n){
    long i = ((long)blockIdx.x*blockDim.x + threadIdx.x)*4;
    if (i >= n) return;
    float4 v = *reinterpret_cast<const float4*>(s+i);
    *reinterpret_cast<__nv_bfloat162*>(d+i)   = __floats2bfloat162_rn(v.x, v.y);
    *reinterpret_cast<__nv_bfloat162*>(d+i+2) = __floats2bfloat162_rn(v.z, v.w);
}

// pack [W_dt | W_B | W_C | 0] -> [2048][64] bf16
__global__ void packw_k(const float* __restrict__ Wdt, const float* __restrict__ WB,
                        const float* __restrict__ WC, bf16* __restrict__ o){
    int idx = blockIdx.x*256 + threadIdx.x;
    if (idx >= DI*64) return;
    int j = idx >> 6, n = idx & 63;
    float v = 0.f;
    if (n < 16) v = Wdt[j*16+n];
    else if (n < 32) v = WB[j*16+n-16];
    else if (n < 48) v = WC[j*16+n-32];
    o[idx] = __float2bfloat16(v);
}

// ---------------- RMSNorm -> bf16 ----------------
__global__ void rmsnorm_bf_k(const float* __restrict__ x, const float* __restrict__ w,
                             bf16* __restrict__ o){
    int row = blockIdx.x;
    const float* xr = x + (long)row*DM;
    __shared__ float red[256];
    float s = 0.f;
    for (int i = threadIdx.x; i < DM; i += 256){ float v = xr[i]; s += v*v; }
    red[threadIdx.x] = s; __syncthreads();
    for (int st = 128; st > 0; st >>= 1){
        if (threadIdx.x < st) red[threadIdx.x] += red[threadIdx.x+st];
        __syncthreads();
    }
    float r = rsqrtf(red[0]/(float)DM + 1e-6f);
    for (int i = threadIdx.x; i < DM; i += 256)
        o[(long)row*DM+i] = __float2bfloat16(w[i]*xr[i]*r);
}

// ---------------- bf16 tensor-core GEMM ----------------
__device__ __forceinline__ void ldsm_x4(unsigned saddr, unsigned &o0, unsigned &o1,
                                        unsigned &o2, unsigned &o3){
    asm volatile("ldmatrix.sync.aligned.m8n8.x4.shared.b16 {%0,%1,%2,%3},[%4];"
        : "=r"(o0),"=r"(o1),"=r"(o2),"=r"(o3) : "r"(saddr));
}
__device__ __forceinline__ void ldsm_x4_t(unsigned saddr, unsigned &o0, unsigned &o1,
                                          unsigned &o2, unsigned &o3){
    asm volatile("ldmatrix.sync.aligned.m8n8.x4.trans.shared.b16 {%0,%1,%2,%3},[%4];"
        : "=r"(o0),"=r"(o1),"=r"(o2),"=r"(o3) : "r"(saddr));
}
__device__ __forceinline__ void mma16816(float* d, const unsigned* am, const unsigned* bm){
    asm volatile("mma.sync.aligned.m16n8k16.row.col.f32.bf16.bf16.f32 "
        "{%0,%1,%2,%3},{%4,%5,%6,%7},{%8,%9},{%0,%1,%2,%3};"
        : "+f"(d[0]),"+f"(d[1]),"+f"(d[2]),"+f"(d[3])
        : "r"(am[0]),"r"(am[1]),"r"(am[2]),"r"(am[3]), "r"(bm[0]),"r"(bm[1]));
}

// C[M,N] = A[M,K] * op(B).  A bf16 row-major.
// TRANSB==0: B bf16 [K][N].  TRANSB==1: B bf16 [N][K] (A*B^T).
// EPI==1: relu(acc + bias[n]).  OUTBF==1: bf16 C, else fp32 C.
template<int TRANSB, int EPI, int OUTBF>
__global__ void __launch_bounds__(256) bgemm_k(
    const bf16* __restrict__ Aptr, const bf16* __restrict__ Bptr, void* __restrict__ Cv,
    int M, int N, int K, int lda, int ldb, int ldc,
    long sA, long sB, long sC, const float* __restrict__ bias)
{
    __shared__ bf16 As[128*40];     // [128][32+8]
    __shared__ bf16 Bs[5120];       // TRANSB0: [32][136]; TRANSB1: [128][40]
    const bf16* Ab = Aptr + (long)blockIdx.z * sA;
    const bf16* Bb = Bptr + (long)blockIdx.z * sB;
    const int bm = blockIdx.y * 128;
    const int bn = blockIdx.x * 128;
    const int tid  = threadIdx.x;
    const int lane = tid & 31;
    const int warp = tid >> 5;
    const int wm = warp >> 1;       // 0..3
    const int wn = warp & 1;        // 0..1

    float acc[2][8][4];
    #pragma unroll
    for (int i = 0; i < 2; i++)
        #pragma unroll
        for (int j = 0; j < 8; j++)
            #pragma unroll
            for (int q = 0; q < 4; q++) acc[i][j][q] = 0.f;

    unsigned Afrag[2][4];
    unsigned Bfrag[8][2];

    const unsigned As_base = (unsigned)__cvta_generic_to_shared(As);
    const unsigned Bs_base = (unsigned)__cvta_generic_to_shared(Bs);

    // lane-invariant ldmatrix base offsets (bytes), ks-dependent part added in-loop
    const int rowA = wm*32 + (lane & 15);
    const int colA = (lane >> 4) * 8;
    unsigned aoff0 = As_base + 2u*(unsigned)( rowA       *40 + colA);
    unsigned aoff1 = As_base + 2u*(unsigned)((rowA + 16) *40 + colA);

    unsigned boff[4];
    #pragma unroll
    for (int p = 0; p < 4; p++){
        if (TRANSB == 0){
            int brow = lane & 15;          // k index within 16
            int bcol = (lane >> 4) * 8;    // +0 / +8 within n group
            boff[p] = Bs_base + 2u*(unsigned)(brow*136 + wn*64 + p*16 + bcol);
        } else {
            int brow = (lane & 7) + (((lane >> 4) & 1) << 3);  // n row within 16
            int bcol = ((lane >> 3) & 1) << 3;                 // k col +0 / +8
            boff[p] = Bs_base + 2u*(unsigned)((wn*64 + p*16 + brow)*40 + bcol);
        }
    }

    for (int k0 = 0; k0 < K; k0 += 32){
        // stage A tile 128x32
        #pragma unroll
        for (int c = tid; c < 512; c += 256){
            int r = c >> 2;
            int ko = (c & 3) << 3;
            uint4 v = *reinterpret_cast<const uint4*>(Ab + (long)(bm + r)*lda + k0 + ko);
            *reinterpret_cast<uint4*>(&As[r*40 + ko]) = v;
        }
        // stage B tile
        if (TRANSB == 0){
            #pragma unroll
            for (int c = tid; c < 512; c += 256){
                int r = c >> 4;
                int no = (c & 15) << 3;
                uint4 v = make_uint4(0u,0u,0u,0u);
                if (bn + no < N)
                    v = *reinterpret_cast<const uint4*>(Bb + (long)(k0 + r)*ldb + bn + no);
                *reinterpret_cast<uint4*>(&Bs[r*136 + no]) = v;
            }
        } else {
            #pragma unroll
            for (int c = tid; c < 512; c += 256){
                int r = c >> 2;
                int ko = (c & 3) << 3;
                uint4 v = *reinterpret_cast<const uint4*>(Bb + (long)(bn + r)*ldb + k0 + ko);
                *reinterpret_cast<uint4*>(&Bs[r*40 + ko]) = v;
            }
        }
        __syncthreads();

        #pragma unroll
        for (int ks = 0; ks < 32; ks += 16){
            ldsm_x4(aoff0 + 2u*ks, Afrag[0][0], Afrag[0][1], Afrag[0][2], Afrag[0][3]);
            ldsm_x4(aoff1 + 2u*ks, Afrag[1][0], Afrag[1][1], Afrag[1][2], Afrag[1][3]);
            #pragma unroll
            for (int p = 0; p < 4; p++){
                if (TRANSB == 0){
                    unsigned ba = boff[p] + 2u*(unsigned)(ks*136);
                    ldsm_x4_t(ba, Bfrag[2*p][0], Bfrag[2*p][1],
                                  Bfrag[2*p+1][0], Bfrag[2*p+1][1]);
                } else {
                    unsigned ba = boff[p] + 2u*(unsigned)ks;
                    ldsm_x4(ba, Bfrag[2*p][0], Bfrag[2*p][1],
                                Bfrag[2*p+1][0], Bfrag[2*p+1][1]);
                }
            }
            #pragma unroll
            for (int mt = 0; mt < 2; mt++)
                #pragma unroll
                for (int nt = 0; nt < 8; nt++)
                    mma16816(acc[mt][nt], Afrag[mt], Bfrag[nt]);
        }
        __syncthreads();
    }

    // epilogue
    #pragma unroll
    for (int mt = 0; mt < 2; mt++){
        int r0 = bm + wm*32 + mt*16 + (lane >> 2);
        #pragma unroll
        for (int nt = 0; nt < 8; nt++){
            int col = bn + wn*64 + nt*8 + ((lane & 3) << 1);
            if (col < N){
                float v0 = acc[mt][nt][0];
                float v1 = acc[mt][nt][1];
                float v2 = acc[mt][nt][2];
                float v3 = acc[mt][nt][3];
                if (EPI == 1){
                    float b0 = bias[col];
                    float b1 = bias[col+1];
                    v0 = fmaxf(v0+b0, 0.f); v1 = fmaxf(v1+b1, 0.f);
                    v2 = fmaxf(v2+b0, 0.f); v3 = fmaxf(v3+b1, 0.f);
                }
                if (OUTBF){
                    bf16* Cb = (bf16*)Cv + (long)blockIdx.z * sC;
                    *reinterpret_cast<__nv_bfloat162*>(&Cb[(long)r0*ldc + col]) =
                        __floats2bfloat162_rn(v0, v1);
                    *reinterpret_cast<__nv_bfloat162*>(&Cb[(long)(r0+8)*ldc + col]) =
                        __floats2bfloat162_rn(v2, v3);
                } else {
                    float* Cb = (float*)Cv + (long)blockIdx.z * sC;
                    *reinterpret_cast<float2*>(&Cb[(long)r0*ldc + col]) = make_float2(v0, v1);
                    *reinterpret_cast<float2*>(&Cb[(long)(r0+8)*ldc + col]) = make_float2(v2, v3);
                }
            }
        }
    }
}

// ---------------- depthwise conv + bias + SiLU (fp32 + bf16 out) ----------------
__global__ void conv_k(const float* __restrict__ xz, const float* __restrict__ cw,
                       const float* __restrict__ cb, float* __restrict__ xc,
                       bf16* __restrict__ xcb){
    long idx = (long)blockIdx.x*blockDim.x + threadIdx.x;
    if (idx >= (long)NTOK*DI) return;
    int d = (int)(idx % DI);
    int row = (int)(idx / DI);
    int t = row % LSEQ, b = row / LSEQ;
    float s = cb[d];
    #pragma unroll
    for (int k = 0; k < 4; k++){
        int tt = t + k - 2;
        if (tt >= 0 && tt < LSEQ)
            s = fmaf(cw[d*4+k], xz[(long)(b*LSEQ+tt)*(2*DI) + d], s);
    }
    float v = siluf(s);
    xc[idx] = v;
    xcb[idx] = __float2bfloat16(v);
}

// ---------------- scan preprocessing (dtBC has ld 64) ----------------
__global__ void scanprep_k(const float* __restrict__ dtBC, const float* __restrict__ bdt,
                           const float* __restrict__ A, float* __restrict__ sp){
    int idx = blockIdx.x*blockDim.x + threadIdx.x;
    if (idx >= NTOK*16) return;
    int n = idx & 15, row = idx >> 4;
    float dtp = dtBC[(long)row*64 + n] + bdt[n];
    float dt  = fmaxf(dtp, 0.f) + log1pf(expf(-fabsf(dtp)));
    sp[(long)row*48 + n]      = expf(dt * A[n]);
    sp[(long)row*48 + 16 + n] = dt * dtBC[(long)row*64 + 16 + n];
    sp[(long)row*48 + 32 + n] = dtBC[(long)row*64 + 32 + n];
}

// ---------------- selective scan: smem-staged chunks, bf16 ymul out ----------------
__global__ void scan2_k(const float* __restrict__ sp, const float* __restrict__ xc,
                        const float* __restrict__ xz, const float* __restrict__ Dp,
                        bf16* __restrict__ ymulb){
    int b = blockIdx.x >> 4;
    int d = (blockIdx.x & 15)*128 + threadIdx.x;
    __shared__ float s[64*48];
    float h[16];
    #pragma unroll
    for (int n = 0; n < 16; n++) h[n] = 0.f;
    const float dpv = Dp[d];
    for (int t0 = 0; t0 < LSEQ; t0 += 64){
        __syncthreads();
        const float* src = sp + ((long)b*LSEQ + t0)*48;
        for (int i = threadIdx.x; i < 64*48; i += 128) s[i] = src[i];
        __syncthreads();
        for (int tt = 0; tt < 64; tt++){
            long row = (long)b*LSEQ + t0 + tt;
            float xv = xc[row*DI + d];
            const float* e = s + tt*48;
            float y = 0.f;
            #pragma unroll
            for (int n = 0; n < 16; n++){
                h[n] = fmaf(e[n], h[n], e[16+n]*xv);
                y = fmaf(h[n], e[32+n], y);
            }
            float z = xz[row*(2*DI) + DI + d];
            ymulb[row*DI + d] = __float2bfloat16((y + dpv*xv) * siluf(z));
        }
    }
}

// ---------------- residual ----------------
__global__ void resid_k(const float* __restrict__ x, const float* __restrict__ ls,
                        const float* __restrict__ dlt, float* __restrict__ o, long n){
    long idx = (long)blockIdx.x*blockDim.x + threadIdx.x;
    if (idx >= n) return;
    int d = (int)(idx % DM);
    o[idx] = fmaf(ls[d], dlt[idx], x[idx]);
}

// ---------------- RoPE -> qb,kb,vb bf16 in [b*NH+h][L][DH] layout ----------------
__global__ void rope2_k(const float* __restrict__ qkv, bf16* __restrict__ qb,
                        bf16* __restrict__ kb, bf16* __restrict__ vb){
    int row = blockIdx.x;
    int t = row % LSEQ, b = row / LSEQ;
    __shared__ float q[DM], kk[DM];
    const float* base = qkv + (long)row*3*DM;
    for (int i = threadIdx.x; i < DM; i += 256){ q[i] = base[i]; kk[i] = base[DM+i]; }
    __syncthreads();
    const float sq = sqrtf((float)DH);
    const float lg = logf(10000.f) / 64.f;
    for (int idx = threadIdx.x; idx < DM; idx += 256){
        int h = idx / DH, i = idx % DH;
        int j = i & 63;
        float inv = expf(-(float)j * lg);
        float ang = (float)t * inv;
        float c = cosf(ang), s = sinf(ang);
        int off = h * DH;
        float rq, rk;
        if (i < 64){ rq = -q[off + 2*i + 1]; rk = -kk[off + 2*i + 1]; }
        else       { rq =  q[off + 2*(i-64)]; rk =  kk[off + 2*(i-64)]; }
        long o = ((long)(b*NH + h)*LSEQ + t)*DH + i;
        qb[o] = __float2bfloat16((q[idx]*c + rq*s) * sq);
        kb[o] = __float2bfloat16(kk[idx]*c + rk*s);
        vb[o] = __float2bfloat16(base[2*DM + idx]);
    }
}

// ---------------- row softmax -> bf16 probs ----------------
__global__ void softmax_k(const float* __restrict__ sc, const float* __restrict__ ascale,
                          bf16* __restrict__ pb){
    long row = blockIdx.x;
    int h = (int)((row / LSEQ) % NH);
    float a = ascale[h];
    const float* p = sc + row*(long)LSEQ;
    bf16* po = pb + row*(long)LSEQ;
    int tid = threadIdx.x;
    float v[8]; float mx = -1e30f;
    #pragma unroll
    for (int j = 0; j < 8; j++){ v[j] = p[tid + j*256]*a; mx = fmaxf(mx, v[j]); }
    __shared__ float red[256];
    red[tid] = mx; __syncthreads();
    for (int st = 128; st > 0; st >>= 1){ if (tid < st) red[tid] = fmaxf(red[tid], red[tid+st]); __syncthreads(); }
    mx = red[0]; __syncthreads();
    float s = 0.f;
    #pragma unroll
    for (int j = 0; j < 8; j++){ v[j] = expf(v[j]-mx); s += v[j]; }
    red[tid] = s; __syncthreads();
    for (int st = 128; st > 0; st >>= 1){ if (tid < st) red[tid] += red[tid+st]; __syncthreads(); }
    float inv = 1.f / red[0];
    #pragma unroll
    for (int j = 0; j < 8; j++) po[tid + j*256] = __float2bfloat16(v[j]*inv);
}

// ---------------- gate stage 2 ----------------
__global__ void gate2_k(const float* __restrict__ g1, const float* __restrict__ Wg2,
                        float* __restrict__ gs, int* __restrict__ topi, float* __restrict__ topw){
    int row = blockIdx.x;
    int tid = threadIdx.x; // 64 threads
    __shared__ float red[64*4];
    float a[4] = {0.f,0.f,0.f,0.f};
    for (int j = tid; j < 512; j += 64){
        float v = g1[(long)row*512 + j];
        #pragma unroll
        for (int e = 0; e < 4; e++) a[e] = fmaf(v, Wg2[j*4+e], a[e]);
    }
    #pragma unroll
    for (int e = 0; e < 4; e++) red[e*64 + tid] = a[e];
    __syncthreads();
    for (int st = 32; st > 0; st >>= 1){
        if (tid < st){
            #pragma unroll
            for (int e = 0; e < 4; e++) red[e*64+tid] += red[e*64+tid+st];
        }
        __syncthreads();
    }
    if (tid == 0){
        float l[4]; for (int e = 0; e < 4; e++) l[e] = red[e*64];
        float m = fmaxf(fmaxf(l[0],l[1]), fmaxf(l[2],l[3]));
        float ex[4]; float s = 0.f;
        for (int e = 0; e < 4; e++){ ex[e] = expf(l[e]-m); s += ex[e]; }
        float gsv[4];
        for (int e = 0; e < 4; e++){ gsv[e] = ex[e]/s; gs[(long)row*4+e] = gsv[e]; }
        int i0 = 0;
        for (int e = 1; e < 4; e++) if (gsv[e] > gsv[i0]) i0 = e;
        int i1 = -1;
        for (int e = 0; e < 4; e++) if (e != i0 && (i1 < 0 || gsv[e] > gsv[i1])) i1 = e;
        float v0 = gsv[i0], v1 = gsv[i1];
        float mm = fmaxf(v0, v1);
        float w0 = expf(v0-mm), w1 = expf(v1-mm);
        float ws = w0 + w1;
        topi[row*2] = i0; topi[row*2+1] = i1;
        topw[row*2] = w0/ws; topw[row*2+1] = w1/ws;
    }
}

// ---------------- balance loss ----------------
__global__ void bal_k(const float* __restrict__ gs, float* __restrict__ out){
    int tid = threadIdx.x;
    __shared__ float red[256*4];
    float a[4] = {0.f,0.f,0.f,0.f};
    for (int r = tid; r < NTOK; r += 256){
        #pragma unroll
        for (int e = 0; e < 4; e++) a[e] += gs[(long)r*4+e];
    }
    #pragma unroll
    for (int e = 0; e < 4; e++) red[e*256+tid] = a[e];
    __syncthreads();
    for (int st = 128; st > 0; st >>= 1){
        if (tid < st){
            #pragma unroll
            for (int e = 0; e < 4; e++) red[e*256+tid] += red[e*256+tid+st];
        }
        __syncthreads();
    }
    if (tid == 0){
        float bal = 0.f;
        for (int e = 0; e < 4; e++){
            float gm = red[e*256] / (float)NTOK;
            bal += gm * logf(gm + 1e-8f);
        }
        out[0] = (float)NEXP * bal;
    }
}

// ---------------- h = silu(h1)*h2 -> bf16 ----------------
__global__ void silumul_bf_k(const float* __restrict__ h1, const float* __restrict__ h2,
                             bf16* __restrict__ hb, long n){
    long idx = (long)blockIdx.x*blockDim.x + threadIdx.x;
    if (idx >= n) return;
    hb[idx] = __float2bfloat16(siluf(h1[idx]) * h2[idx]);
}

// ---------------- MoE combine + final residual ----------------
__global__ void combine_k(const float* __restrict__ x2, const float* __restrict__ ls3,
                          const float* __restrict__ eo, const int* __restrict__ topi,
                          const float* __restrict__ topw, float* __restrict__ out){
    long idx = (long)blockIdx.x*blockDim.x + threadIdx.x;
    if (idx >= (long)NTOK*DM) return;
    int row = (int)(idx / DM), d = (int)(idx % DM);
    int i0 = topi[row*2], i1 = topi[row*2+1];
    float m = topw[row*2]   * eo[((long)i0*NTOK + row)*DM + d]
            + topw[row*2+1] * eo[((long)i1*NTOK + row)*DM + d];
    out[idx] = fmaf(ls3[d], m, x2[idx]);
}

// ============================== host ==============================
#define SYMPF(p, s) do { void* _t; cudaGetSymbolAddress(&_t, s); p = (float*)_t; } while(0)
#define SYMPB(p, s) do { void* _t; cudaGetSymbolAddress(&_t, s); p = (bf16*)_t; } while(0)

extern "C" void kernel_launch(void* const* d_in, const int* in_sizes, int n_in,
                              void* d_out, int out_size){
    const float* x      = (const float*)d_in[0];
    const float* rms1_w = (const float*)d_in[1];
    const float* rms2_w = (const float*)d_in[2];
    const float* rms3_w = (const float*)d_in[3];
    const float* ls1    = (const float*)d_in[4];
    const float* ls2    = (const float*)d_in[5];
    const float* ls3    = (const float*)d_in[6];
    const float* W_in   = (const float*)d_in[7];
    const float* conv_w = (const float*)d_in[8];
    const float* conv_b = (const float*)d_in[9];
    const float* W_B    = (const float*)d_in[10];
    const float* W_C    = (const float*)d_in[11];
    const float* W_dt   = (const float*)d_in[12];
    const float* b_dt   = (const float*)d_in[13];
    const float* W_out_m= (const float*)d_in[14];
    const float* Avec   = (const float*)d_in[15];
    const float* Dp     = (const float*)d_in[16];
    const float* W_qkv  = (const float*)d_in[17];
    const float* W_o    = (const float*)d_in[18];
    const float* ascale = (const float*)d_in[19];
    const float* Wg1    = (const float*)d_in[20];
    const float* bg1    = (const float*)d_in[21];
    const float* Wg2    = (const float*)d_in[22];
    const float* w1     = (const float*)d_in[23];
    const float* w2     = (const float*)d_in[24];
    const float* w3     = (const float*)d_in[25];
    float* out = (float*)d_out;

    float *p_xz, *p_xc, *p_dtBC, *p_scanp, *p_tmp, *p_x1, *p_qkv, *p_scores,
          *p_x2, *p_g1, *p_gs, *p_topw, *p_h1, *p_h2, *p_eo;
    int* p_topi;
    bf16 *b_rms1, *b_xc, *b_ymul, *b_rms2, *b_q, *b_k, *b_v, *b_probs, *b_att, *b_xf, *b_h;
    bf16 *b_Win, *b_Wout, *b_Wqkv, *b_Wo, *b_Wg1, *b_w1, *b_w2, *b_w3, *b_Wcat;

    SYMPF(p_xz, g_xz); SYMPF(p_xc, g_xc); SYMPF(p_dtBC, g_dtBC); SYMPF(p_scanp, g_scanp);
    SYMPF(p_tmp, g_tmp); SYMPF(p_x1, g_x1); SYMPF(p_qkv, g_qkv); SYMPF(p_scores, g_scores);
    SYMPF(p_x2, g_x2); SYMPF(p_g1, g_g1); SYMPF(p_gs, g_gs); SYMPF(p_topw, g_topw);
    SYMPF(p_h1, g_h1); SYMPF(p_h2, g_h2); SYMPF(p_eo, g_eo);
    { void* _t; cudaGetSymbolAddress(&_t, g_topi); p_topi = (int*)_t; }
    SYMPB(b_rms1, g_rms1b); SYMPB(b_xc, g_xcb); SYMPB(b_ymul, g_ymulb); SYMPB(b_rms2, g_rms2b);
    SYMPB(b_q, g_qb); SYMPB(b_k, g_kb); SYMPB(b_v, g_vb); SYMPB(b_probs, g_probsb);
    SYMPB(b_att, g_attb); SYMPB(b_xf, g_xfb); SYMPB(b_h, g_hb);
    SYMPB(b_Win, g_Winb); SYMPB(b_Wout, g_Woutb); SYMPB(b_Wqkv, g_Wqkvb); SYMPB(b_Wo, g_Wob);
    SYMPB(b_Wg1, g_Wg1b); SYMPB(b_w1, g_w1b); SYMPB(b_w2, g_w2b); SYMPB(b_w3, g_w3b);
    SYMPB(b_Wcat, g_Wcatb);

    // ---- weight conversions ----
    #define CONV(src, dst, n) f2bf_k<<<(int)(((n)/4 + 255)/256), 256>>>(src, dst, (long)(n))
    CONV(W_in,   b_Win,  (long)DM*2*DI);
    CONV(W_out_m,b_Wout, (long)DI*DM);
    CONV(W_qkv,  b_Wqkv, (long)DM*3*DM);
    CONV(W_o,    b_Wo,   (long)DM*DM);
    CONV(Wg1,    b_Wg1,  (long)DM*512);
    CONV(w1,     b_w1,   (long)NEXP*DM*DFF);
    CONV(w2,     b_w2,   (long)NEXP*DM*DFF);
    CONV(w3,     b_w3,   (long)NEXP*DFF*DM);
    packw_k<<<(DI*64+255)/256, 256>>>(W_dt, W_B, W_C, b_Wcat);

    // ---- 1. Mamba ----
    rmsnorm_bf_k<<<NTOK, 256>>>(x, rms1_w, b_rms1);
    {   dim3 g(2*DI/128, NTOK/128, 1);
        bgemm_k<0,0,0><<<g, 256>>>(b_rms1, b_Win, p_xz, NTOK, 2*DI, DM, DM, 2*DI, 2*DI,
                                   0,0,0, nullptr); }
    conv_k<<<(int)(((long)NTOK*DI+255)/256), 256>>>(p_xz, conv_w, conv_b, p_xc, b_xc);
    {   dim3 g(1, NTOK/128, 1);
        bgemm_k<0,0,0><<<g, 256>>>(b_xc, b_Wcat, p_dtBC, NTOK, 64, DI, DI, 64, 64,
                                   0,0,0, nullptr); }
    scanprep_k<<<(NTOK*16+255)/256, 256>>>(p_dtBC, b_dt, Avec, p_scanp);
    scan2_k<<<32, 128>>>(p_scanp, p_xc, p_xz, Dp, b_ymul);
    {   dim3 g(DM/128, NTOK/128, 1);
        bgemm_k<0,0,0><<<g, 256>>>(b_ymul, b_Wout, p_tmp, NTOK, DM, DI, DI, DM, DM,
                                   0,0,0, nullptr); }
    resid_k<<<(int)(((long)NTOK*DM+255)/256), 256>>>(x, ls1, p_tmp, p_x1, (long)NTOK*DM);

    // ---- 2. Attention ----
    rmsnorm_bf_k<<<NTOK, 256>>>(p_x1, rms2_w, b_rms2);
    {   dim3 g(3*DM/128, NTOK/128, 1);
        bgemm_k<0,0,0><<<g, 256>>>(b_rms2, b_Wqkv, p_qkv, NTOK, 3*DM, DM, DM, 3*DM, 3*DM,
                                   0,0,0, nullptr); }
    rope2_k<<<NTOK, 256>>>(p_qkv, b_q, b_k, b_v);
    for (int b = 0; b < BB; b++){
        dim3 g(LSEQ/128, LSEQ/128, NH);
        bgemm_k<1,0,0><<<g, 256>>>(b_q + (long)b*NH*LSEQ*DH,
                                   b_k + (long)b*NH*LSEQ*DH,
                                   p_scores + (long)b*NH*LSEQ*LSEQ,
                                   LSEQ, LSEQ, DH, DH, DH, LSEQ,
                                   (long)LSEQ*DH, (long)LSEQ*DH, (long)LSEQ*LSEQ, nullptr);
    }
    softmax_k<<<BB*NH*LSEQ, 256>>>(p_scores, ascale, b_probs);
    for (int b = 0; b < BB; b++){
        dim3 g(1, LSEQ/128, NH);
        bgemm_k<0,0,1><<<g, 256>>>(b_probs + (long)b*NH*LSEQ*LSEQ,
                                   b_v + (long)b*NH*LSEQ*DH,
                                   b_att + (long)b*LSEQ*DM,
                                   LSEQ, DH, LSEQ, LSEQ, DH, DM,
                                   (long)LSEQ*LSEQ, (long)LSEQ*DH, (long)DH, nullptr);
    }
    {   dim3 g(DM/128, NTOK/128, 1);
        bgemm_k<0,0,0><<<g, 256>>>(b_att, b_Wo, p_tmp, NTOK, DM, DM, DM, DM, DM,
                                   0,0,0, nullptr); }
    resid_k<<<(int)(((long)NTOK*DM+255)/256), 256>>>(p_x1, ls2, p_tmp, p_x2, (long)NTOK*DM);

    // ---- 3. MoE ----
    rmsnorm_bf_k<<<NTOK, 256>>>(p_x2, rms3_w, b_xf);
    {   dim3 g(512/128, NTOK/128, 1);
        bgemm_k<0,1,0><<<g, 256>>>(b_xf, b_Wg1, p_g1, NTOK, 512, DM, DM, 512, 512,
                                   0,0,0, bg1); }
    gate2_k<<<NTOK, 64>>>(p_g1, Wg2, p_gs, p_topi, p_topw);
    if (out_size > NTOK*DM)
        bal_k<<<1, 256>>>(p_gs, out + (long)NTOK*DM);
    for (int e = 0; e < NEXP; e++){
        dim3 g1d(DFF/128, NTOK/128, 1);
        bgemm_k<0,0,0><<<g1d, 256>>>(b_xf, b_w1 + (long)e*DM*DFF, p_h1,
                                     NTOK, DFF, DM, DM, DFF, DFF, 0,0,0, nullptr);
        bgemm_k<0,0,0><<<g1d, 256>>>(b_xf, b_w2 + (long)e*DM*DFF, p_h2,
                                     NTOK, DFF, DM, DM, DFF, DFF, 0,0,0, nullptr);
        silumul_bf_k<<<(int)(((long)NTOK*DFF+255)/256), 256>>>(p_h1, p_h2, b_h, (long)NTOK*DFF);
        dim3 g3(DM/128, NTOK/128, 1);
        bgemm_k<0,0,0><<<g3, 256>>>(b_h, b_w3 + (long)e*DFF*DM, p_eo + (long)e*NTOK*DM,
                                    NTOK, DM, DFF, DFF, DM, DM, 0,0,0, nullptr);
    }
    combine_k<<<(int)(((long)NTOK*DM+255)/256), 256>>>(p_x2, ls3, p_eo, p_topi, p_topw, out);
}

// round 4
// speedup vs baseline: 4.1905x; 1.2841x over previous
#include <cuda_runtime.h>
#include <cuda_bf16.h>
#include <math.h>

#define BB   2
#define LSEQ 2048
#define DM   1024
#define DI   2048
#define NH   8
#define DH   128
#define NEXP 4
#define DFF  4096
#define NTOK (BB*LSEQ)   // 4096

typedef __nv_bfloat16 bf16;

// ---------------- static scratch ----------------
__device__ float g_xz[NTOK*2*DI];
__device__ float g_xc[NTOK*DI];
__device__ float g_dtBC[NTOK*64];
__device__ float g_scanp[NTOK*48];
__device__ float g_tmp[NTOK*DM];
__device__ float g_x1[NTOK*DM];
__device__ float g_qkv[NTOK*3*DM];
__device__ float g_x2[NTOK*DM];
__device__ float g_g1[NTOK*512];
__device__ float g_gs[NTOK*NEXP];
__device__ int   g_topi[NTOK*2];
__device__ float g_topw[NTOK*2];
__device__ float g_eo[NEXP*NTOK*DM];
__device__ int   g_cnt[NEXP];
__device__ int   g_slot[NTOK*2];

// bf16 activations
__device__ bf16 g_rms1b[NTOK*DM];
__device__ bf16 g_xcb[NTOK*DI];
__device__ bf16 g_ymulb[NTOK*DI];
__device__ bf16 g_rms2b[NTOK*DM];
__device__ bf16 g_qb[NTOK*DM];
__device__ bf16 g_kb[NTOK*DM];
__device__ bf16 g_vb[NTOK*DM];
__device__ bf16 g_probsb[BB*NH*LSEQ*LSEQ];    // 134 MB, scores then probs in place
__device__ bf16 g_attb[NTOK*DM];
__device__ bf16 g_xfb[NTOK*DM];
__device__ bf16 g_xgb[NEXP*NTOK*DM];          // gathered tokens per expert segment
__device__ bf16 g_h1b[NEXP*NTOK*DFF];         // 128 MB
__device__ bf16 g_h2b[NEXP*NTOK*DFF];         // 128 MB

// bf16 weights
__device__ bf16 g_Winb[DM*2*DI];
__device__ bf16 g_Woutb[DI*DM];
__device__ bf16 g_Wqkvb[DM*3*DM];
__device__ bf16 g_Wob[DM*DM];
__device__ bf16 g_Wg1b[DM*512];
__device__ bf16 g_w1b[NEXP*DM*DFF];
__device__ bf16 g_w2b[NEXP*DM*DFF];
__device__ bf16 g_w3b[NEXP*DFF*DM];
__device__ bf16 g_Wcatb[DI*64];

__device__ __forceinline__ float siluf(float x){ return x / (1.f + expf(-x)); }

// ---------------- fp32 -> bf16 convert ----------------
__global__ void f2bf_k(const float* __restrict__ s, bf16* __restrict__ d, long n){
    long i = ((long)blockIdx.x*blockDim.x + threadIdx.x)*4;
    if (i >= n) return;
    float4 v = *reinterpret_cast<const float4*>(s+i);
    *reinterpret_cast<__nv_bfloat162*>(d+i)   = __floats2bfloat162_rn(v.x, v.y);
    *reinterpret_cast<__nv_bfloat162*>(d+i+2) = __floats2bfloat162_rn(v.z, v.w);
}

// pack [W_dt | W_B | W_C | 0] -> [2048][64] bf16
__global__ void packw_k(const float* __restrict__ Wdt, const float* __restrict__ WB,
                        const float* __restrict__ WC, bf16* __restrict__ o){
    int idx = blockIdx.x*256 + threadIdx.x;
    if (idx >= DI*64) return;
    int j = idx >> 6, n = idx & 63;
    float v = 0.f;
    if (n < 16) v = Wdt[j*16+n];
    else if (n < 32) v = WB[j*16+n-16];
    else if (n < 48) v = WC[j*16+n-32];
    o[idx] = __float2bfloat16(v);
}

// ---------------- RMSNorm -> bf16 ----------------
__global__ void rmsnorm_bf_k(const float* __restrict__ x, const float* __restrict__ w,
                             bf16* __restrict__ o){
    int row = blockIdx.x;
    const float* xr = x + (long)row*DM;
    __shared__ float red[256];
    float s = 0.f;
    for (int i = threadIdx.x; i < DM; i += 256){ float v = xr[i]; s += v*v; }
    red[threadIdx.x] = s; __syncthreads();
    for (int st = 128; st > 0; st >>= 1){
        if (threadIdx.x < st) red[threadIdx.x] += red[threadIdx.x+st];
        __syncthreads();
    }
    float r = rsqrtf(red[0]/(float)DM + 1e-6f);
    for (int i = threadIdx.x; i < DM; i += 256)
        o[(long)row*DM+i] = __float2bfloat16(w[i]*xr[i]*r);
}

// ---------------- bf16 tensor-core GEMM, cp.async 2-stage ----------------
__device__ __forceinline__ void cpasync16(unsigned dst, const void* src, int ssz){
    asm volatile("cp.async.ca.shared.global [%0], [%1], 16, %2;"
        :: "r"(dst), "l"(src), "r"(ssz));
}
__device__ __forceinline__ void cp_commit(){
    asm volatile("cp.async.commit_group;");
}
__device__ __forceinline__ void cp_wait0(){
    asm volatile("cp.async.wait_group 0;");
}
__device__ __forceinline__ void ldsm_x4(unsigned saddr, unsigned &o0, unsigned &o1,
                                        unsigned &o2, unsigned &o3){
    asm volatile("ldmatrix.sync.aligned.m8n8.x4.shared.b16 {%0,%1,%2,%3},[%4];"
        : "=r"(o0),"=r"(o1),"=r"(o2),"=r"(o3) : "r"(saddr));
}
__device__ __forceinline__ void ldsm_x4_t(unsigned saddr, unsigned &o0, unsigned &o1,
                                          unsigned &o2, unsigned &o3){
    asm volatile("ldmatrix.sync.aligned.m8n8.x4.trans.shared.b16 {%0,%1,%2,%3},[%4];"
        : "=r"(o0),"=r"(o1),"=r"(o2),"=r"(o3) : "r"(saddr));
}
__device__ __forceinline__ void mma16816(float* d, const unsigned* am, const unsigned* bm){
    asm volatile("mma.sync.aligned.m16n8k16.row.col.f32.bf16.bf16.f32 "
        "{%0,%1,%2,%3},{%4,%5,%6,%7},{%8,%9},{%0,%1,%2,%3};"
        : "+f"(d[0]),"+f"(d[1]),"+f"(d[2]),"+f"(d[3])
        : "r"(am[0]),"r"(am[1]),"r"(am[2]),"r"(am[3]), "r"(bm[0]),"r"(bm[1]));
}

template<int TRANSB>
__device__ __forceinline__ void stage_tiles(const bf16* Ab, const bf16* Bb,
    int bm, int bn, int N, int lda, int ldb, int k0, int tid,
    unsigned Adst, unsigned Bdst)
{
    #pragma unroll
    for (int c = tid; c < 512; c += 256){
        int r  = c >> 2;
        int ko = (c & 3) << 3;
        cpasync16(Adst + 2u*(unsigned)(r*40 + ko),
                  Ab + (long)(bm + r)*lda + k0 + ko, 16);
    }
    if (TRANSB == 0){
        #pragma unroll
        for (int c = tid; c < 512; c += 256){
            int r  = c >> 4;
            int no = (c & 15) << 3;
            const bf16* src = Bb + (long)(k0 + r)*ldb + bn + no;
            int ssz = 16;
            if (bn + no >= N){ src = Bb; ssz = 0; }
            cpasync16(Bdst + 2u*(unsigned)(r*136 + no), src, ssz);
        }
    } else {
        #pragma unroll
        for (int c = tid; c < 512; c += 256){
            int r  = c >> 2;
            int ko = (c & 3) << 3;
            cpasync16(Bdst + 2u*(unsigned)(r*40 + ko),
                      Bb + (long)(bn + r)*ldb + k0 + ko, 16);
        }
    }
}

// C[M,N] = A[M,K] * op(B).  A bf16 row-major.
// TRANSB==0: B bf16 [K][N].  TRANSB==1: B bf16 [N][K] (A*B^T).
// EPI==1: relu(acc + bias[n]).  OUTBF==1: bf16 C, else fp32 C.
// mcnt: optional device row count (sparse M); blocks with bm >= *mcnt exit.
template<int TRANSB, int EPI, int OUTBF>
__global__ void __launch_bounds__(256) bgemm_k(
    const bf16* __restrict__ Aptr, const bf16* __restrict__ Bptr, void* __restrict__ Cv,
    int M, int N, int K, int lda, int ldb, int ldc,
    long sA, long sB, long sC, const float* __restrict__ bias,
    const int* __restrict__ mcnt)
{
    __shared__ bf16 As[2*5120];
    __shared__ bf16 Bs[2*5120];
    const int bm = blockIdx.y * 128;
    int Meff = M;
    if (mcnt) Meff = *mcnt;
    if (bm >= Meff) return;
    const bf16* Ab = Aptr + (long)blockIdx.z * sA;
    const bf16* Bb = Bptr + (long)blockIdx.z * sB;
    const int bn = blockIdx.x * 128;
    const int tid  = threadIdx.x;
    const int lane = tid & 31;
    const int warp = tid >> 5;
    const int wm = warp >> 1;       // 0..3
    const int wn = warp & 1;        // 0..1

    float acc[2][8][4];
    #pragma unroll
    for (int i = 0; i < 2; i++)
        #pragma unroll
        for (int j = 0; j < 8; j++)
            #pragma unroll
            for (int q = 0; q < 4; q++) acc[i][j][q] = 0.f;

    unsigned Afrag[2][4];
    unsigned Bfrag[8][2];

    const unsigned As_base = (unsigned)__cvta_generic_to_shared(As);
    const unsigned Bs_base = (unsigned)__cvta_generic_to_shared(Bs);

    const int rowA = wm*32 + (lane & 15);
    const int colA = (lane >> 4) * 8;
    unsigned aoff0 = As_base + 2u*(unsigned)( rowA       *40 + colA);
    unsigned aoff1 = As_base + 2u*(unsigned)((rowA + 16) *40 + colA);

    unsigned boff[4];
    #pragma unroll
    for (int p = 0; p < 4; p++){
        if (TRANSB == 0){
            int brow = lane & 15;
            int bcol = (lane >> 4) * 8;
            boff[p] = Bs_base + 2u*(unsigned)(brow*136 + wn*64 + p*16 + bcol);
        } else {
            int brow = (lane & 7) + (((lane >> 4) & 1) << 3);
            int bcol = ((lane >> 3) & 1) << 3;
            boff[p] = Bs_base + 2u*(unsigned)((wn*64 + p*16 + brow)*40 + bcol);
        }
    }

    const int nk = K >> 5;
    stage_tiles<TRANSB>(Ab, Bb, bm, bn, N, lda, ldb, 0, tid, As_base, Bs_base);
    cp_commit();

    for (int it = 0; it < nk; it++){
        cp_wait0();
        __syncthreads();
        if (it + 1 < nk){
            unsigned off = ((it + 1) & 1) ? 10240u : 0u;
            stage_tiles<TRANSB>(Ab, Bb, bm, bn, N, lda, ldb, (it+1) << 5, tid,
                                As_base + off, Bs_base + off);
            cp_commit();
        }
        unsigned sb = (it & 1) ? 10240u : 0u;
        #pragma unroll
        for (int ks = 0; ks < 32; ks += 16){
            ldsm_x4(aoff0 + sb + 2u*ks, Afrag[0][0], Afrag[0][1], Afrag[0][2], Afrag[0][3]);
            ldsm_x4(aoff1 + sb + 2u*ks, Afrag[1][0], Afrag[1][1], Afrag[1][2], Afrag[1][3]);
            #pragma unroll
            for (int p = 0; p < 4; p++){
                if (TRANSB == 0){
                    unsigned ba = boff[p] + sb + 2u*(unsigned)(ks*136);
                    ldsm_x4_t(ba, Bfrag[2*p][0], Bfrag[2*p][1],
                                  Bfrag[2*p+1][0], Bfrag[2*p+1][1]);
                } else {
                    unsigned ba = boff[p] + sb + 2u*(unsigned)ks;
                    ldsm_x4(ba, Bfrag[2*p][0], Bfrag[2*p][1],
                                Bfrag[2*p+1][0], Bfrag[2*p+1][1]);
                }
            }
            #pragma unroll
            for (int mt = 0; mt < 2; mt++)
                #pragma unroll
                for (int nt = 0; nt < 8; nt++)
                    mma16816(acc[mt][nt], Afrag[mt], Bfrag[nt]);
        }
        __syncthreads();
    }

    // epilogue
    #pragma unroll
    for (int mt = 0; mt < 2; mt++){
        int r0 = bm + wm*32 + mt*16 + (lane >> 2);
        #pragma unroll
        for (int nt = 0; nt < 8; nt++){
            int col = bn + wn*64 + nt*8 + ((lane & 3) << 1);
            if (col < N){
                float v0 = acc[mt][nt][0];
                float v1 = acc[mt][nt][1];
                float v2 = acc[mt][nt][2];
                float v3 = acc[mt][nt][3];
                if (EPI == 1){
                    float b0 = bias[col];
                    float b1 = bias[col+1];
                    v0 = fmaxf(v0+b0, 0.f); v1 = fmaxf(v1+b1, 0.f);
                    v2 = fmaxf(v2+b0, 0.f); v3 = fmaxf(v3+b1, 0.f);
                }
                if (OUTBF){
                    bf16* Cb = (bf16*)Cv + (long)blockIdx.z * sC;
                    *reinterpret_cast<__nv_bfloat162*>(&Cb[(long)r0*ldc + col]) =
                        __floats2bfloat162_rn(v0, v1);
                    *reinterpret_cast<__nv_bfloat162*>(&Cb[(long)(r0+8)*ldc + col]) =
                        __floats2bfloat162_rn(v2, v3);
                } else {
                    float* Cb = (float*)Cv + (long)blockIdx.z * sC;
                    *reinterpret_cast<float2*>(&Cb[(long)r0*ldc + col]) = make_float2(v0, v1);
                    *reinterpret_cast<float2*>(&Cb[(long)(r0+8)*ldc + col]) = make_float2(v2, v3);
                }
            }
        }
    }
}

// ---------------- depthwise conv + bias + SiLU ----------------
__global__ void conv_k(const float* __restrict__ xz, const float* __restrict__ cw,
                       const float* __restrict__ cb, float* __restrict__ xc,
                       bf16* __restrict__ xcb){
    long idx = (long)blockIdx.x*blockDim.x + threadIdx.x;
    if (idx >= (long)NTOK*DI) return;
    int d = (int)(idx % DI);
    int row = (int)(idx / DI);
    int t = row % LSEQ, b = row / LSEQ;
    float s = cb[d];
    #pragma unroll
    for (int k = 0; k < 4; k++){
        int tt = t + k - 2;
        if (tt >= 0 && tt < LSEQ)
            s = fmaf(cw[d*4+k], xz[(long)(b*LSEQ+tt)*(2*DI) + d], s);
    }
    float v = siluf(s);
    xc[idx] = v;
    xcb[idx] = __float2bfloat16(v);
}

// ---------------- scan preprocessing ----------------
__global__ void scanprep_k(const float* __restrict__ dtBC, const float* __restrict__ bdt,
                           const float* __restrict__ A, float* __restrict__ sp){
    int idx = blockIdx.x*blockDim.x + threadIdx.x;
    if (idx >= NTOK*16) return;
    int n = idx & 15, row = idx >> 4;
    float dtp = dtBC[(long)row*64 + n] + bdt[n];
    float dt  = fmaxf(dtp, 0.f) + log1pf(expf(-fabsf(dtp)));
    sp[(long)row*48 + n]      = expf(dt * A[n]);
    sp[(long)row*48 + 16 + n] = dt * dtBC[(long)row*64 + 16 + n];
    sp[(long)row*48 + 32 + n] = dtBC[(long)row*64 + 32 + n];
}

// ---------------- selective scan ----------------
__global__ void scan2_k(const float* __restrict__ sp, const float* __restrict__ xc,
                        const float* __restrict__ xz, const float* __restrict__ Dp,
                        bf16* __restrict__ ymulb){
    int b = blockIdx.x >> 4;
    int d = (blockIdx.x & 15)*128 + threadIdx.x;
    __shared__ float s[64*48];
    float h[16];
    #pragma unroll
    for (int n = 0; n < 16; n++) h[n] = 0.f;
    const float dpv = Dp[d];
    for (int t0 = 0; t0 < LSEQ; t0 += 64){
        __syncthreads();
        const float* src = sp + ((long)b*LSEQ + t0)*48;
        for (int i = threadIdx.x; i < 64*48; i += 128) s[i] = src[i];
        __syncthreads();
        for (int tt = 0; tt < 64; tt++){
            long row = (long)b*LSEQ + t0 + tt;
            float xv = xc[row*DI + d];
            const float* e = s + tt*48;
            float y = 0.f;
            #pragma unroll
            for (int n = 0; n < 16; n++){
                h[n] = fmaf(e[n], h[n], e[16+n]*xv);
                y = fmaf(h[n], e[32+n], y);
            }
            float z = xz[row*(2*DI) + DI + d];
            ymulb[row*DI + d] = __float2bfloat16((y + dpv*xv) * siluf(z));
        }
    }
}

// ---------------- residual ----------------
__global__ void resid_k(const float* __restrict__ x, const float* __restrict__ ls,
                        const float* __restrict__ dlt, float* __restrict__ o, long n){
    long idx = (long)blockIdx.x*blockDim.x + threadIdx.x;
    if (idx >= n) return;
    int d = (int)(idx % DM);
    o[idx] = fmaf(ls[d], dlt[idx], x[idx]);
}

// ---------------- RoPE -> qb,kb,vb bf16 in [b*NH+h][L][DH] layout ----------------
__global__ void rope2_k(const float* __restrict__ qkv, bf16* __restrict__ qb,
                        bf16* __restrict__ kb, bf16* __restrict__ vb){
    int row = blockIdx.x;
    int t = row % LSEQ, b = row / LSEQ;
    __shared__ float q[DM], kk[DM];
    const float* base = qkv + (long)row*3*DM;
    for (int i = threadIdx.x; i < DM; i += 256){ q[i] = base[i]; kk[i] = base[DM+i]; }
    __syncthreads();
    const float sq = sqrtf((float)DH);
    const float lg = logf(10000.f) / 64.f;
    for (int idx = threadIdx.x; idx < DM; idx += 256){
        int h = idx / DH, i = idx % DH;
        int j = i & 63;
        float inv = expf(-(float)j * lg);
        float ang = (float)t * inv;
        float c = cosf(ang), s = sinf(ang);
        int off = h * DH;
        float rq, rk;
        if (i < 64){ rq = -q[off + 2*i + 1]; rk = -kk[off + 2*i + 1]; }
        else       { rq =  q[off + 2*(i-64)]; rk =  kk[off + 2*(i-64)]; }
        long o = ((long)(b*NH + h)*LSEQ + t)*DH + i;
        qb[o] = __float2bfloat16((q[idx]*c + rq*s) * sq);
        kb[o] = __float2bfloat16(kk[idx]*c + rk*s);
        vb[o] = __float2bfloat16(base[2*DM + idx]);
    }
}

// ---------------- in-place bf16 row softmax ----------------
__global__ void softmax_bf_k(bf16* __restrict__ sc, const float* __restrict__ ascale){
    long row = blockIdx.x;
    int h = (int)((row / LSEQ) % NH);
    float a = ascale[h];
    bf16* p = sc + row*(long)LSEQ;
    int tid = threadIdx.x;
    float v[8]; float mx = -1e30f;
    #pragma unroll
    for (int j = 0; j < 8; j++){
        v[j] = __bfloat162float(p[tid + j*256])*a;
        mx = fmaxf(mx, v[j]);
    }
    __shared__ float red[256];
    red[tid] = mx; __syncthreads();
    for (int st = 128; st > 0; st >>= 1){ if (tid < st) red[tid] = fmaxf(red[tid], red[tid+st]); __syncthreads(); }
    mx = red[0]; __syncthreads();
    float s = 0.f;
    #pragma unroll
    for (int j = 0; j < 8; j++){ v[j] = expf(v[j]-mx); s += v[j]; }
    red[tid] = s; __syncthreads();
    for (int st = 128; st > 0; st >>= 1){ if (tid < st) red[tid] += red[tid+st]; __syncthreads(); }
    float inv = 1.f / red[0];
    #pragma unroll
    for (int j = 0; j < 8; j++) p[tid + j*256] = __float2bfloat16(v[j]*inv);
}

// ---------------- gate stage 2 ----------------
__global__ void gate2_k(const float* __restrict__ g1, const float* __restrict__ Wg2,
                        float* __restrict__ gs, int* __restrict__ topi, float* __restrict__ topw){
    int row = blockIdx.x;
    int tid = threadIdx.x; // 64 threads
    __shared__ float red[64*4];
    float a[4] = {0.f,0.f,0.f,0.f};
    for (int j = tid; j < 512; j += 64){
        float v = g1[(long)row*512 + j];
        #pragma unroll
        for (int e = 0; e < 4; e++) a[e] = fmaf(v, Wg2[j*4+e], a[e]);
    }
    #pragma unroll
    for (int e = 0; e < 4; e++) red[e*64 + tid] = a[e];
    __syncthreads();
    for (int st = 32; st > 0; st >>= 1){
        if (tid < st){
            #pragma unroll
            for (int e = 0; e < 4; e++) red[e*64+tid] += red[e*64+tid+st];
        }
        __syncthreads();
    }
    if (tid == 0){
        float l[4]; for (int e = 0; e < 4; e++) l[e] = red[e*64];
        float m = fmaxf(fmaxf(l[0],l[1]), fmaxf(l[2],l[3]));
        float ex[4]; float s = 0.f;
        for (int e = 0; e < 4; e++){ ex[e] = expf(l[e]-m); s += ex[e]; }
        float gsv[4];
        for (int e = 0; e < 4; e++){ gsv[e] = ex[e]/s; gs[(long)row*4+e] = gsv[e]; }
        int i0 = 0;
        for (int e = 1; e < 4; e++) if (gsv[e] > gsv[i0]) i0 = e;
        int i1 = -1;
        for (int e = 0; e < 4; e++) if (e != i0 && (i1 < 0 || gsv[e] > gsv[i1])) i1 = e;
        float v0 = gsv[i0], v1 = gsv[i1];
        float mm = fmaxf(v0, v1);
        float w0 = expf(v0-mm), w1 = expf(v1-mm);
        float ws = w0 + w1;
        topi[row*2] = i0; topi[row*2+1] = i1;
        topw[row*2] = w0/ws; topw[row*2+1] = w1/ws;
    }
}

// ---------------- balance loss ----------------
__global__ void bal_k(const float* __restrict__ gs, float* __restrict__ out){
    int tid = threadIdx.x;
    __shared__ float red[256*4];
    float a[4] = {0.f,0.f,0.f,0.f};
    for (int r = tid; r < NTOK; r += 256){
        #pragma unroll
        for (int e = 0; e < 4; e++) a[e] += gs[(long)r*4+e];
    }
    #pragma unroll
    for (int e = 0; e < 4; e++) red[e*256+tid] = a[e];
    __syncthreads();
    for (int st = 128; st > 0; st >>= 1){
        if (tid < st){
            #pragma unroll
            for (int e = 0; e < 4; e++) red[e*256+tid] += red[e*256+tid+st];
        }
        __syncthreads();
    }
    if (tid == 0){
        float bal = 0.f;
        for (int e = 0; e < 4; e++){
            float gm = red[e*256] / (float)NTOK;
            bal += gm * logf(gm + 1e-8f);
        }
        out[0] = (float)NEXP * bal;
    }
}

// ---------------- MoE routing ----------------
__global__ void zero4_k(int* c){ if (threadIdx.x < NEXP) c[threadIdx.x] = 0; }

__global__ void assign_k(const int* __restrict__ topi, int* __restrict__ cnt,
                         int* __restrict__ slot){
    int idx = blockIdx.x*256 + threadIdx.x;
    if (idx >= NTOK*2) return;
    int e = topi[idx];
    int s = atomicAdd(&cnt[e], 1);
    slot[idx] = e*NTOK + s;
}

__global__ void gather_k(const bf16* __restrict__ xf, const int* __restrict__ slot,
                         bf16* __restrict__ xg){
    int idx = blockIdx.x;             // 0..NTOK*2-1
    int tok = idx >> 1;
    int dst = slot[idx];
    const unsigned* src = reinterpret_cast<const unsigned*>(xf) + (long)tok*(DM/2);
    unsigned* d = reinterpret_cast<unsigned*>(xg) + (long)dst*(DM/2);
    for (int i = threadIdx.x; i < DM/2; i += 128) d[i] = src[i];
}

// h1 = silu(h1)*h2 in place (bf16), row-aware
__global__ void silumul2_k(bf16* __restrict__ h1, const bf16* __restrict__ h2,
                           const int* __restrict__ cnt){
    int seg = blockIdx.x;             // 0 .. NEXP*NTOK-1
    int e = seg / NTOK, r = seg % NTOK;
    if (r >= cnt[e]) return;
    long base = (long)seg*DFF;
    for (int i = threadIdx.x; i < DFF; i += 256){
        float a = __bfloat162float(h1[base+i]);
        float b = __bfloat162float(h2[base+i]);
        h1[base+i] = __float2bfloat16(siluf(a)*b);
    }
}

// ---------------- MoE combine + final residual ----------------
__global__ void combine2_k(const float* __restrict__ x2, const float* __restrict__ ls3,
                           const float* __restrict__ eo, const int* __restrict__ slot,
                           const float* __restrict__ topw, float* __restrict__ out){
    long idx = (long)blockIdx.x*blockDim.x + threadIdx.x;
    if (idx >= (long)NTOK*DM) return;
    int row = (int)(idx / DM), d = (int)(idx % DM);
    int s0 = slot[row*2], s1 = slot[row*2+1];
    float m = topw[row*2]   * eo[(long)s0*DM + d]
            + topw[row*2+1] * eo[(long)s1*DM + d];
    out[idx] = fmaf(ls3[d], m, x2[idx]);
}

// ============================== host ==============================
#define SYMPF(p, s) do { void* _t; cudaGetSymbolAddress(&_t, s); p = (float*)_t; } while(0)
#define SYMPB(p, s) do { void* _t; cudaGetSymbolAddress(&_t, s); p = (bf16*)_t; } while(0)
#define SYMPI(p, s) do { void* _t; cudaGetSymbolAddress(&_t, s); p = (int*)_t; } while(0)

extern "C" void kernel_launch(void* const* d_in, const int* in_sizes, int n_in,
                              void* d_out, int out_size){
    const float* x      = (const float*)d_in[0];
    const float* rms1_w = (const float*)d_in[1];
    const float* rms2_w = (const float*)d_in[2];
    const float* rms3_w = (const float*)d_in[3];
    const float* ls1    = (const float*)d_in[4];
    const float* ls2    = (const float*)d_in[5];
    const float* ls3    = (const float*)d_in[6];
    const float* W_in   = (const float*)d_in[7];
    const float* conv_w = (const float*)d_in[8];
    const float* conv_b = (const float*)d_in[9];
    const float* W_B    = (const float*)d_in[10];
    const float* W_C    = (const float*)d_in[11];
    const float* W_dt   = (const float*)d_in[12];
    const float* b_dt   = (const float*)d_in[13];
    const float* W_out_m= (const float*)d_in[14];
    const float* Avec   = (const float*)d_in[15];
    const float* Dp     = (const float*)d_in[16];
    const float* W_qkv  = (const float*)d_in[17];
    const float* W_o    = (const float*)d_in[18];
    const float* ascale = (const float*)d_in[19];
    const float* Wg1    = (const float*)d_in[20];
    const float* bg1    = (const float*)d_in[21];
    const float* Wg2    = (const float*)d_in[22];
    const float* w1     = (const float*)d_in[23];
    const float* w2     = (const float*)d_in[24];
    const float* w3     = (const float*)d_in[25];
    float* out = (float*)d_out;

    float *p_xz, *p_xc, *p_dtBC, *p_scanp, *p_tmp, *p_x1, *p_qkv,
          *p_x2, *p_g1, *p_gs, *p_topw, *p_eo;
    int *p_topi, *p_cnt, *p_slot;
    bf16 *b_rms1, *b_xc, *b_ymul, *b_rms2, *b_q, *b_k, *b_v, *b_probs, *b_att, *b_xf,
         *b_xg, *b_h1, *b_h2;
    bf16 *b_Win, *b_Wout, *b_Wqkv, *b_Wo, *b_Wg1, *b_w1, *b_w2, *b_w3, *b_Wcat;

    SYMPF(p_xz, g_xz); SYMPF(p_xc, g_xc); SYMPF(p_dtBC, g_dtBC); SYMPF(p_scanp, g_scanp);
    SYMPF(p_tmp, g_tmp); SYMPF(p_x1, g_x1); SYMPF(p_qkv, g_qkv);
    SYMPF(p_x2, g_x2); SYMPF(p_g1, g_g1); SYMPF(p_gs, g_gs); SYMPF(p_topw, g_topw);
    SYMPF(p_eo, g_eo);
    SYMPI(p_topi, g_topi); SYMPI(p_cnt, g_cnt); SYMPI(p_slot, g_slot);
    SYMPB(b_rms1, g_rms1b); SYMPB(b_xc, g_xcb); SYMPB(b_ymul, g_ymulb); SYMPB(b_rms2, g_rms2b);
    SYMPB(b_q, g_qb); SYMPB(b_k, g_kb); SYMPB(b_v, g_vb); SYMPB(b_probs, g_probsb);
    SYMPB(b_att, g_attb); SYMPB(b_xf, g_xfb); SYMPB(b_xg, g_xgb);
    SYMPB(b_h1, g_h1b); SYMPB(b_h2, g_h2b);
    SYMPB(b_Win, g_Winb); SYMPB(b_Wout, g_Woutb); SYMPB(b_Wqkv, g_Wqkvb); SYMPB(b_Wo, g_Wob);
    SYMPB(b_Wg1, g_Wg1b); SYMPB(b_w1, g_w1b); SYMPB(b_w2, g_w2b); SYMPB(b_w3, g_w3b);
    SYMPB(b_Wcat, g_Wcatb);

    // ---- weight conversions ----
    #define CONV(src, dst, n) f2bf_k<<<(int)(((n)/4 + 255)/256), 256>>>(src, dst, (long)(n))
    CONV(W_in,   b_Win,  (long)DM*2*DI);
    CONV(W_out_m,b_Wout, (long)DI*DM);
    CONV(W_qkv,  b_Wqkv, (long)DM*3*DM);
    CONV(W_o,    b_Wo,   (long)DM*DM);
    CONV(Wg1,    b_Wg1,  (long)DM*512);
    CONV(w1,     b_w1,   (long)NEXP*DM*DFF);
    CONV(w2,     b_w2,   (long)NEXP*DM*DFF);
    CONV(w3,     b_w3,   (long)NEXP*DFF*DM);
    packw_k<<<(DI*64+255)/256, 256>>>(W_dt, W_B, W_C, b_Wcat);

    // ---- 1. Mamba ----
    rmsnorm_bf_k<<<NTOK, 256>>>(x, rms1_w, b_rms1);
    {   dim3 g(2*DI/128, NTOK/128, 1);
        bgemm_k<0,0,0><<<g, 256>>>(b_rms1, b_Win, p_xz, NTOK, 2*DI, DM, DM, 2*DI, 2*DI,
                                   0,0,0, nullptr, nullptr); }
    conv_k<<<(int)(((long)NTOK*DI+255)/256), 256>>>(p_xz, conv_w, conv_b, p_xc, b_xc);
    {   dim3 g(1, NTOK/128, 1);
        bgemm_k<0,0,0><<<g, 256>>>(b_xc, b_Wcat, p_dtBC, NTOK, 64, DI, DI, 64, 64,
                                   0,0,0, nullptr, nullptr); }
    scanprep_k<<<(NTOK*16+255)/256, 256>>>(p_dtBC, b_dt, Avec, p_scanp);
    scan2_k<<<32, 128>>>(p_scanp, p_xc, p_xz, Dp, b_ymul);
    {   dim3 g(DM/128, NTOK/128, 1);
        bgemm_k<0,0,0><<<g, 256>>>(b_ymul, b_Wout, p_tmp, NTOK, DM, DI, DI, DM, DM,
                                   0,0,0, nullptr, nullptr); }
    resid_k<<<(int)(((long)NTOK*DM+255)/256), 256>>>(x, ls1, p_tmp, p_x1, (long)NTOK*DM);

    // ---- 2. Attention ----
    rmsnorm_bf_k<<<NTOK, 256>>>(p_x1, rms2_w, b_rms2);
    {   dim3 g(3*DM/128, NTOK/128, 1);
        bgemm_k<0,0,0><<<g, 256>>>(b_rms2, b_Wqkv, p_qkv, NTOK, 3*DM, DM, DM, 3*DM, 3*DM,
                                   0,0,0, nullptr, nullptr); }
    rope2_k<<<NTOK, 256>>>(p_qkv, b_q, b_k, b_v);
    for (int b = 0; b < BB; b++){
        dim3 g(LSEQ/128, LSEQ/128, NH);
        bgemm_k<1,0,1><<<g, 256>>>(b_q + (long)b*NH*LSEQ*DH,
                                   b_k + (long)b*NH*LSEQ*DH,
                                   b_probs + (long)b*NH*LSEQ*LSEQ,
                                   LSEQ, LSEQ, DH, DH, DH, LSEQ,
                                   (long)LSEQ*DH, (long)LSEQ*DH, (long)LSEQ*LSEQ,
                                   nullptr, nullptr);
    }
    softmax_bf_k<<<BB*NH*LSEQ, 256>>>(b_probs, ascale);
    for (int b = 0; b < BB; b++){
        dim3 g(1, LSEQ/128, NH);
        bgemm_k<0,0,1><<<g, 256>>>(b_probs + (long)b*NH*LSEQ*LSEQ,
                                   b_v + (long)b*NH*LSEQ*DH,
                                   b_att + (long)b*LSEQ*DM,
                                   LSEQ, DH, LSEQ, LSEQ, DH, DM,
                                   (long)LSEQ*LSEQ, (long)LSEQ*DH, (long)DH,
                                   nullptr, nullptr);
    }
    {   dim3 g(DM/128, NTOK/128, 1);
        bgemm_k<0,0,0><<<g, 256>>>(b_att, b_Wo, p_tmp, NTOK, DM, DM, DM, DM, DM,
                                   0,0,0, nullptr, nullptr); }
    resid_k<<<(int)(((long)NTOK*DM+255)/256), 256>>>(p_x1, ls2, p_tmp, p_x2, (long)NTOK*DM);

    // ---- 3. MoE (top-2 sparse) ----
    rmsnorm_bf_k<<<NTOK, 256>>>(p_x2, rms3_w, b_xf);
    {   dim3 g(512/128, NTOK/128, 1);
        bgemm_k<0,1,0><<<g, 256>>>(b_xf, b_Wg1, p_g1, NTOK, 512, DM, DM, 512, 512,
                                   0,0,0, bg1, nullptr); }
    gate2_k<<<NTOK, 64>>>(p_g1, Wg2, p_gs, p_topi, p_topw);
    if (out_size > NTOK*DM)
        bal_k<<<1, 256>>>(p_gs, out + (long)NTOK*DM);
    zero4_k<<<1, 32>>>(p_cnt);
    assign_k<<<(NTOK*2+255)/256, 256>>>(p_topi, p_cnt, p_slot);
    gather_k<<<NTOK*2, 128>>>(b_xf, p_slot, b_xg);
    for (int e = 0; e < NEXP; e++){
        dim3 g1d(DFF/128, NTOK/128, 1);
        bgemm_k<0,0,1><<<g1d, 256>>>(b_xg + (long)e*NTOK*DM, b_w1 + (long)e*DM*DFF,
                                     b_h1 + (long)e*NTOK*DFF,
                                     NTOK, DFF, DM, DM, DFF, DFF, 0,0,0,
                                     nullptr, p_cnt + e);
        bgemm_k<0,0,1><<<g1d, 256>>>(b_xg + (long)e*NTOK*DM, b_w2 + (long)e*DM*DFF,
                                     b_h2 + (long)e*NTOK*DFF,
                                     NTOK, DFF, DM, DM, DFF, DFF, 0,0,0,
                                     nullptr, p_cnt + e);
    }
    silumul2_k<<<NEXP*NTOK, 256>>>(b_h1, b_h2, p_cnt);
    for (int e = 0; e < NEXP; e++){
        dim3 g3(DM/128, NTOK/128, 1);
        bgemm_k<0,0,0><<<g3, 256>>>(b_h1 + (long)e*NTOK*DFF, b_w3 + (long)e*DFF*DM,
                                    p_eo + (long)e*NTOK*DM,
                                    NTOK, DM, DFF, DFF, DM, DM, 0,0,0,
                                    nullptr, p_cnt + e);
    }
    combine2_k<<<(int)(((long)NTOK*DM+255)/256), 256>>>(p_x2, ls3, p_eo, p_slot, p_topw, out);
}

// round 6
// speedup vs baseline: 4.4609x; 1.0645x over previous
#include <cuda_runtime.h>
#include <cuda_bf16.h>
#include <math.h>

#define BB   2
#define LSEQ 2048
#define DM   1024
#define DI   2048
#define NH   8
#define DH   128
#define NEXP 4
#define DFF  4096
#define NTOK (BB*LSEQ)   // 4096

typedef __nv_bfloat16 bf16;

// ---------------- static scratch ----------------
__device__ float g_xz[NTOK*2*DI];
__device__ float g_xc[NTOK*DI];
__device__ float g_dtBC[NTOK*64];
__device__ float g_scanp[NTOK*48];
__device__ float g_x1[NTOK*DM];
__device__ float g_qkv[NTOK*3*DM];
__device__ float g_x2[NTOK*DM];
__device__ float g_g1[NTOK*512];
__device__ float g_gs[NTOK*NEXP];
__device__ int   g_topi[NTOK*2];
__device__ float g_topw[NTOK*2];
__device__ int   g_cnt[NEXP];
__device__ int   g_slot[NTOK*2];

// bf16 activations
__device__ bf16 g_rms1b[NTOK*DM];
__device__ bf16 g_xcb[NTOK*DI];
__device__ bf16 g_ymulb[NTOK*DI];
__device__ bf16 g_rms2b[NTOK*DM];
__device__ bf16 g_qb[NTOK*DM];
__device__ bf16 g_kb[NTOK*DM];
__device__ bf16 g_vb[NTOK*DM];
__device__ bf16 g_attb[NTOK*DM];
__device__ bf16 g_xfb[NTOK*DM];
__device__ bf16 g_xgb[NEXP*NTOK*DM];
__device__ bf16 g_h12b[(long)NEXP*NTOK*2*DFF];  // 268 MB
__device__ bf16 g_hb[(long)NEXP*NTOK*DFF];
__device__ bf16 g_eob[NEXP*NTOK*DM];

// bf16 weights
__device__ bf16 g_Winb[DM*2*DI];
__device__ bf16 g_Woutb[DI*DM];
__device__ bf16 g_Wqkvb[DM*3*DM];
__device__ bf16 g_Wob[DM*DM];
__device__ bf16 g_Wg1b[DM*512];
__device__ bf16 g_w12b[(long)NEXP*DM*2*DFF];
__device__ bf16 g_w3b[(long)NEXP*DFF*DM];
__device__ bf16 g_Wcatb[DI*64];

__device__ __forceinline__ float siluf(float x){ return x / (1.f + expf(-x)); }

// ---------------- fp32 -> bf16 convert ----------------
__global__ void f2bf_k(const float* __restrict__ s, bf16* __restrict__ d, long n){
    long i = ((long)blockIdx.x*blockDim.x + threadIdx.x)*4;
    if (i >= n) return;
    float4 v = *reinterpret_cast<const float4*>(s+i);
    *reinterpret_cast<__nv_bfloat162*>(d+i)   = __floats2bfloat162_rn(v.x, v.y);
    *reinterpret_cast<__nv_bfloat162*>(d+i+2) = __floats2bfloat162_rn(v.z, v.w);
}

// pack w1|w2 -> [e][DM][2*DFF]
__global__ void pack12_k(const float* __restrict__ w1, const float* __restrict__ w2,
                         bf16* __restrict__ o){
    long i = ((long)blockIdx.x*blockDim.x + threadIdx.x)*4;
    if (i >= (long)NEXP*DM*DFF) return;
    long row = i >> 12;           // e*DM + d
    int  j   = (int)(i & 4095);
    float4 a = *reinterpret_cast<const float4*>(w1 + i);
    float4 b = *reinterpret_cast<const float4*>(w2 + i);
    bf16* d1 = o + row*(2*DFF) + j;
    *reinterpret_cast<__nv_bfloat162*>(d1)   = __floats2bfloat162_rn(a.x, a.y);
    *reinterpret_cast<__nv_bfloat162*>(d1+2) = __floats2bfloat162_rn(a.z, a.w);
    bf16* d2 = d1 + DFF;
    *reinterpret_cast<__nv_bfloat162*>(d2)   = __floats2bfloat162_rn(b.x, b.y);
    *reinterpret_cast<__nv_bfloat162*>(d2+2) = __floats2bfloat162_rn(b.z, b.w);
}

// pack [W_dt | W_B | W_C | 0] -> [2048][64] bf16
__global__ void packw_k(const float* __restrict__ Wdt, const float* __restrict__ WB,
                        const float* __restrict__ WC, bf16* __restrict__ o){
    int idx = blockIdx.x*256 + threadIdx.x;
    if (idx >= DI*64) return;
    int j = idx >> 6, n = idx & 63;
    float v = 0.f;
    if (n < 16) v = Wdt[j*16+n];
    else if (n < 32) v = WB[j*16+n-16];
    else if (n < 48) v = WC[j*16+n-32];
    o[idx] = __float2bfloat16(v);
}

// ---------------- RMSNorm -> bf16 ----------------
__global__ void rmsnorm_bf_k(const float* __restrict__ x, const float* __restrict__ w,
                             bf16* __restrict__ o){
    int row = blockIdx.x;
    const float* xr = x + (long)row*DM;
    __shared__ float red[256];
    float s = 0.f;
    for (int i = threadIdx.x; i < DM; i += 256){ float v = xr[i]; s += v*v; }
    red[threadIdx.x] = s; __syncthreads();
    for (int st = 128; st > 0; st >>= 1){
        if (threadIdx.x < st) red[threadIdx.x] += red[threadIdx.x+st];
        __syncthreads();
    }
    float r = rsqrtf(red[0]/(float)DM + 1e-6f);
    for (int i = threadIdx.x; i < DM; i += 256)
        o[(long)row*DM+i] = __float2bfloat16(w[i]*xr[i]*r);
}

// ---------------- MMA primitives ----------------
__device__ __forceinline__ void cpasync16(unsigned dst, const void* src, int ssz){
    asm volatile("cp.async.ca.shared.global [%0], [%1], 16, %2;"
        :: "r"(dst), "l"(src), "r"(ssz));
}
__device__ __forceinline__ void cp_commit(){ asm volatile("cp.async.commit_group;"); }
__device__ __forceinline__ void cp_wait0(){ asm volatile("cp.async.wait_group 0;"); }
__device__ __forceinline__ void ldsm_x4(unsigned saddr, unsigned &o0, unsigned &o1,
                                        unsigned &o2, unsigned &o3){
    asm volatile("ldmatrix.sync.aligned.m8n8.x4.shared.b16 {%0,%1,%2,%3},[%4];"
        : "=r"(o0),"=r"(o1),"=r"(o2),"=r"(o3) : "r"(saddr));
}
__device__ __forceinline__ void ldsm_x4_t(unsigned saddr, unsigned &o0, unsigned &o1,
                                          unsigned &o2, unsigned &o3){
    asm volatile("ldmatrix.sync.aligned.m8n8.x4.trans.shared.b16 {%0,%1,%2,%3},[%4];"
        : "=r"(o0),"=r"(o1),"=r"(o2),"=r"(o3) : "r"(saddr));
}
__device__ __forceinline__ void mma16816(float* d, const unsigned* am, const unsigned* bm){
    asm volatile("mma.sync.aligned.m16n8k16.row.col.f32.bf16.bf16.f32 "
        "{%0,%1,%2,%3},{%4,%5,%6,%7},{%8,%9},{%0,%1,%2,%3};"
        : "+f"(d[0]),"+f"(d[1]),"+f"(d[2]),"+f"(d[3])
        : "r"(am[0]),"r"(am[1]),"r"(am[2]),"r"(am[3]), "r"(bm[0]),"r"(bm[1]));
}
__device__ __forceinline__ unsigned pkbf2(float x, float y){
    __nv_bfloat162 t = __floats2bfloat162_rn(x, y);
    return *reinterpret_cast<unsigned*>(&t);
}

// ---------------- bf16 tensor-core GEMM, cp.async 2-stage ----------------
template<int TRANSB>
__device__ __forceinline__ void stage_tiles(const bf16* Ab, const bf16* Bb,
    int bm, int bn, int N, int lda, int ldb, int k0, int tid,
    unsigned Adst, unsigned Bdst)
{
    #pragma unroll
    for (int c = tid; c < 512; c += 256){
        int r  = c >> 2;
        int ko = (c & 3) << 3;
        cpasync16(Adst + 2u*(unsigned)(r*40 + ko),
                  Ab + (long)(bm + r)*lda + k0 + ko, 16);
    }
    if (TRANSB == 0){
        #pragma unroll
        for (int c = tid; c < 512; c += 256){
            int r  = c >> 4;
            int no = (c & 15) << 3;
            const bf16* src = Bb + (long)(k0 + r)*ldb + bn + no;
            int ssz = 16;
            if (bn + no >= N){ src = Bb; ssz = 0; }
            cpasync16(Bdst + 2u*(unsigned)(r*136 + no), src, ssz);
        }
    } else {
        #pragma unroll
        for (int c = tid; c < 512; c += 256){
            int r  = c >> 2;
            int ko = (c & 3) << 3;
            cpasync16(Bdst + 2u*(unsigned)(r*40 + ko),
                      Bb + (long)(bn + r)*ldb + k0 + ko, 16);
        }
    }
}

// EPI: 0 none, 1 relu(acc+bias), 2 resid: C = resx + bias[col]*acc (fp32)
template<int TRANSB, int EPI, int OUTBF>
__global__ void __launch_bounds__(256) bgemm_k(
    const bf16* __restrict__ Aptr, const bf16* __restrict__ Bptr, void* __restrict__ Cv,
    int M, int N, int K, int lda, int ldb, int ldc,
    long sA, long sB, long sC, const float* __restrict__ bias,
    const float* __restrict__ resx, const int* __restrict__ mcnt)
{
    __shared__ bf16 As[2*5120];
    __shared__ bf16 Bs[2*5120];
    const int bm = blockIdx.y * 128;
    int Meff = M;
    if (mcnt) Meff = *mcnt;
    if (bm >= Meff) return;
    const bf16* Ab = Aptr + (long)blockIdx.z * sA;
    const bf16* Bb = Bptr + (long)blockIdx.z * sB;
    const int bn = blockIdx.x * 128;
    const int tid  = threadIdx.x;
    const int lane = tid & 31;
    const int warp = tid >> 5;
    const int wm = warp >> 1;
    const int wn = warp & 1;

    float acc[2][8][4];
    #pragma unroll
    for (int i = 0; i < 2; i++)
        #pragma unroll
        for (int j = 0; j < 8; j++)
            #pragma unroll
            for (int q = 0; q < 4; q++) acc[i][j][q] = 0.f;

    unsigned Afrag[2][4];
    unsigned Bfrag[8][2];

    const unsigned As_base = (unsigned)__cvta_generic_to_shared(As);
    const unsigned Bs_base = (unsigned)__cvta_generic_to_shared(Bs);

    const int rowA = wm*32 + (lane & 15);
    const int colA = (lane >> 4) * 8;
    unsigned aoff0 = As_base + 2u*(unsigned)( rowA       *40 + colA);
    unsigned aoff1 = As_base + 2u*(unsigned)((rowA + 16) *40 + colA);

    unsigned boff[4];
    #pragma unroll
    for (int p = 0; p < 4; p++){
        if (TRANSB == 0){
            int brow = lane & 15;
            int bcol = (lane >> 4) * 8;
            boff[p] = Bs_base + 2u*(unsigned)(brow*136 + wn*64 + p*16 + bcol);
        } else {
            int brow = (lane & 7) + (((lane >> 4) & 1) << 3);
            int bcol = ((lane >> 3) & 1) << 3;
            boff[p] = Bs_base + 2u*(unsigned)((wn*64 + p*16 + brow)*40 + bcol);
        }
    }

    const int nk = K >> 5;
    stage_tiles<TRANSB>(Ab, Bb, bm, bn, N, lda, ldb, 0, tid, As_base, Bs_base);
    cp_commit();

    for (int it = 0; it < nk; it++){
        cp_wait0();
        __syncthreads();
        if (it + 1 < nk){
            unsigned off = ((it + 1) & 1) ? 10240u : 0u;
            stage_tiles<TRANSB>(Ab, Bb, bm, bn, N, lda, ldb, (it+1) << 5, tid,
                                As_base + off, Bs_base + off);
            cp_commit();
        }
        unsigned sb = (it & 1) ? 10240u : 0u;
        #pragma unroll
        for (int ks = 0; ks < 32; ks += 16){
            ldsm_x4(aoff0 + sb + 2u*ks, Afrag[0][0], Afrag[0][1], Afrag[0][2], Afrag[0][3]);
            ldsm_x4(aoff1 + sb + 2u*ks, Afrag[1][0], Afrag[1][1], Afrag[1][2], Afrag[1][3]);
            #pragma unroll
            for (int p = 0; p < 4; p++){
                if (TRANSB == 0){
                    unsigned ba = boff[p] + sb + 2u*(unsigned)(ks*136);
                    ldsm_x4_t(ba, Bfrag[2*p][0], Bfrag[2*p][1],
                                  Bfrag[2*p+1][0], Bfrag[2*p+1][1]);
                } else {
                    unsigned ba = boff[p] + sb + 2u*(unsigned)ks;
                    ldsm_x4(ba, Bfrag[2*p][0], Bfrag[2*p][1],
                                Bfrag[2*p+1][0], Bfrag[2*p+1][1]);
                }
            }
            #pragma unroll
            for (int mt = 0; mt < 2; mt++)
                #pragma unroll
                for (int nt = 0; nt < 8; nt++)
                    mma16816(acc[mt][nt], Afrag[mt], Bfrag[nt]);
        }
        __syncthreads();
    }

    #pragma unroll
    for (int mt = 0; mt < 2; mt++){
        int r0 = bm + wm*32 + mt*16 + (lane >> 2);
        #pragma unroll
        for (int nt = 0; nt < 8; nt++){
            int col = bn + wn*64 + nt*8 + ((lane & 3) << 1);
            if (col < N){
                float v0 = acc[mt][nt][0];
                float v1 = acc[mt][nt][1];
                float v2 = acc[mt][nt][2];
                float v3 = acc[mt][nt][3];
                if (EPI == 1){
                    float b0 = bias[col];
                    float b1 = bias[col+1];
                    v0 = fmaxf(v0+b0, 0.f); v1 = fmaxf(v1+b1, 0.f);
                    v2 = fmaxf(v2+b0, 0.f); v3 = fmaxf(v3+b1, 0.f);
                }
                if (EPI == 2){
                    float b0 = bias[col];
                    float b1 = bias[col+1];
                    v0 = fmaf(b0, v0, resx[(long)r0*ldc + col]);
                    v1 = fmaf(b1, v1, resx[(long)r0*ldc + col + 1]);
                    v2 = fmaf(b0, v2, resx[(long)(r0+8)*ldc + col]);
                    v3 = fmaf(b1, v3, resx[(long)(r0+8)*ldc + col + 1]);
                }
                if (OUTBF){
                    bf16* Cb = (bf16*)Cv + (long)blockIdx.z * sC;
                    *reinterpret_cast<__nv_bfloat162*>(&Cb[(long)r0*ldc + col]) =
                        __floats2bfloat162_rn(v0, v1);
                    *reinterpret_cast<__nv_bfloat162*>(&Cb[(long)(r0+8)*ldc + col]) =
                        __floats2bfloat162_rn(v2, v3);
                } else {
                    float* Cb = (float*)Cv + (long)blockIdx.z * sC;
                    *reinterpret_cast<float2*>(&Cb[(long)r0*ldc + col]) = make_float2(v0, v1);
                    *reinterpret_cast<float2*>(&Cb[(long)(r0+8)*ldc + col]) = make_float2(v2, v3);
                }
            }
        }
    }
}

// ---------------- fused flash attention ----------------
// grid (16 qtiles, BB*NH). 256 thr / 8 warps; warp owns 16 q-rows.
#define FTILE (128*136)
#define FSMEM (5*FTILE*2)

__device__ __forceinline__ void fstage(const bf16* src, unsigned dst, int tid){
    // full 128x128 bf16 tile: 128 rows x 16 chunks(16B) per row
    for (int i = tid; i < 2048; i += 256){
        int r = i >> 4, c = (i & 15) << 3;
        cpasync16(dst + 2u*(unsigned)(r*136 + c), src + r*DH + c, 16);
    }
}

__global__ void __launch_bounds__(256, 1) flash_k(
    const bf16* __restrict__ q, const bf16* __restrict__ k, const bf16* __restrict__ v,
    const float* __restrict__ ascale, bf16* __restrict__ att)
{
    extern __shared__ bf16 fs[];
    const int qt = blockIdx.x, bh = blockIdx.y;
    const int bb = bh >> 3, hh = bh & 7;
    const int tid = threadIdx.x, lane = tid & 31, w = tid >> 5;
    const float a = ascale[hh];

    const bf16* qg = q + ((long)bh*LSEQ + qt*128)*DH;
    const bf16* kg = k + (long)bh*LSEQ*DH;
    const bf16* vg = v + (long)bh*LSEQ*DH;

    const unsigned Qb = (unsigned)__cvta_generic_to_shared(fs);
    const unsigned Kb = Qb + 2u*FTILE;
    const unsigned Vb = Qb + 6u*FTILE;
    const unsigned TILEB = 2u*FTILE;

    fstage(qg, Qb, tid);
    fstage(kg, Kb, tid);
    fstage(vg, Vb, tid);
    cp_commit();
    cp_wait0();
    __syncthreads();

    unsigned qf[8][4];
    {
        int rq = w*16 + (lane & 15);
        int cq = (lane >> 4) << 3;
        #pragma unroll
        for (int ks = 0; ks < 8; ks++)
            ldsm_x4(Qb + 2u*(unsigned)(rq*136 + ks*16 + cq),
                    qf[ks][0], qf[ks][1], qf[ks][2], qf[ks][3]);
    }

    const int brow = (lane & 7) + (((lane >> 4) & 1) << 3);
    const int bcol = ((lane >> 3) & 1) << 3;
    unsigned kadr[8], vadr[8];
    #pragma unroll
    for (int p = 0; p < 8; p++){
        kadr[p] = Kb + 2u*(unsigned)((p*16 + brow)*136 + bcol);
        vadr[p] = Vb + 2u*(unsigned)((lane & 15)*136 + p*16 + ((lane >> 4) << 3));
    }

    float oacc[16][4];
    #pragma unroll
    for (int nt = 0; nt < 16; nt++)
        #pragma unroll
        for (int qq = 0; qq < 4; qq++) oacc[nt][qq] = 0.f;
    float m0 = -1e30f, m1 = -1e30f, l0 = 0.f, l1 = 0.f;

    for (int kt = 0; kt < 16; kt++){
        if (kt > 0){ cp_wait0(); __syncthreads(); }
        if (kt + 1 < 16){
            unsigned off = ((kt + 1) & 1) ? TILEB : 0u;
            fstage(kg + (long)(kt+1)*128*DH, Kb + off, tid);
            fstage(vg + (long)(kt+1)*128*DH, Vb + off, tid);
            cp_commit();
        }
        const unsigned sb = (kt & 1) ? TILEB : 0u;

        float sacc[16][4];
        #pragma unroll
        for (int nt = 0; nt < 16; nt++)
            #pragma unroll
            for (int qq = 0; qq < 4; qq++) sacc[nt][qq] = 0.f;

        #pragma unroll
        for (int ks = 0; ks < 8; ks++){
            #pragma unroll
            for (int p = 0; p < 8; p++){
                unsigned bf0[2], bf1[2];
                ldsm_x4(kadr[p] + sb + 2u*(unsigned)(ks*16),
                        bf0[0], bf0[1], bf1[0], bf1[1]);
                mma16816(sacc[2*p],   qf[ks], bf0);
                mma16816(sacc[2*p+1], qf[ks], bf1);
            }
        }

        float ax0 = -1e30f, ax1 = -1e30f;
        #pragma unroll
        for (int nt = 0; nt < 16; nt++){
            sacc[nt][0] *= a; sacc[nt][1] *= a; sacc[nt][2] *= a; sacc[nt][3] *= a;
            ax0 = fmaxf(ax0, fmaxf(sacc[nt][0], sacc[nt][1]));
            ax1 = fmaxf(ax1, fmaxf(sacc[nt][2], sacc[nt][3]));
        }
        ax0 = fmaxf(ax0, __shfl_xor_sync(0xffffffffu, ax0, 1));
        ax0 = fmaxf(ax0, __shfl_xor_sync(0xffffffffu, ax0, 2));
        ax1 = fmaxf(ax1, __shfl_xor_sync(0xffffffffu, ax1, 1));
        ax1 = fmaxf(ax1, __shfl_xor_sync(0xffffffffu, ax1, 2));
        float mn0 = fmaxf(m0, ax0), mn1 = fmaxf(m1, ax1);
        float f0 = expf(m0 - mn0), f1 = expf(m1 - mn1);

        float rs0 = 0.f, rs1 = 0.f;
        #pragma unroll
        for (int nt = 0; nt < 16; nt++){
            sacc[nt][0] = expf(sacc[nt][0] - mn0);
            sacc[nt][1] = expf(sacc[nt][1] - mn0);
            sacc[nt][2] = expf(sacc[nt][2] - mn1);
            sacc[nt][3] = expf(sacc[nt][3] - mn1);
            rs0 += sacc[nt][0] + sacc[nt][1];
            rs1 += sacc[nt][2] + sacc[nt][3];
        }
        rs0 += __shfl_xor_sync(0xffffffffu, rs0, 1);
        rs0 += __shfl_xor_sync(0xffffffffu, rs0, 2);
        rs1 += __shfl_xor_sync(0xffffffffu, rs1, 1);
        rs1 += __shfl_xor_sync(0xffffffffu, rs1, 2);
        l0 = l0*f0 + rs0; l1 = l1*f1 + rs1;
        m0 = mn0; m1 = mn1;

        #pragma unroll
        for (int nt = 0; nt < 16; nt++){
            oacc[nt][0] *= f0; oacc[nt][1] *= f0;
            oacc[nt][2] *= f1; oacc[nt][3] *= f1;
        }

        unsigned pa[8][4];
        #pragma unroll
        for (int ksp = 0; ksp < 8; ksp++){
            pa[ksp][0] = pkbf2(sacc[2*ksp][0],   sacc[2*ksp][1]);
            pa[ksp][1] = pkbf2(sacc[2*ksp][2],   sacc[2*ksp][3]);
            pa[ksp][2] = pkbf2(sacc[2*ksp+1][0], sacc[2*ksp+1][1]);
            pa[ksp][3] = pkbf2(sacc[2*ksp+1][2], sacc[2*ksp+1][3]);
        }

        #pragma unroll
        for (int ksp = 0; ksp < 8; ksp++){
            #pragma unroll
            for (int p = 0; p < 8; p++){
                unsigned bf0[2], bf1[2];
                ldsm_x4_t(vadr[p] + sb + 2u*(unsigned)(ksp*16*136),
                          bf0[0], bf0[1], bf1[0], bf1[1]);
                mma16816(oacc[2*p],   pa[ksp], bf0);
                mma16816(oacc[2*p+1], pa[ksp], bf1);
            }
        }
    }

    float inv0 = 1.f / l0, inv1 = 1.f / l1;
    long row0 = (long)bb*LSEQ + qt*128 + w*16 + (lane >> 2);
    long row1 = row0 + 8;
    int  cbase = hh*DH + ((lane & 3) << 1);
    #pragma unroll
    for (int nt = 0; nt < 16; nt++){
        int col = cbase + nt*8;
        *reinterpret_cast<__nv_bfloat162*>(&att[row0*DM + col]) =
            __floats2bfloat162_rn(oacc[nt][0]*inv0, oacc[nt][1]*inv0);
        *reinterpret_cast<__nv_bfloat162*>(&att[row1*DM + col]) =
            __floats2bfloat162_rn(oacc[nt][2]*inv1, oacc[nt][3]*inv1);
    }
}

// ---------------- depthwise conv + bias + SiLU ----------------
__global__ void conv_k(const float* __restrict__ xz, const float* __restrict__ cw,
                       const float* __restrict__ cb, float* __restrict__ xc,
                       bf16* __restrict__ xcb){
    long idx = (long)blockIdx.x*blockDim.x + threadIdx.x;
    if (idx >= (long)NTOK*DI) return;
    int d = (int)(idx % DI);
    int row = (int)(idx / DI);
    int t = row % LSEQ, b = row / LSEQ;
    float s = cb[d];
    #pragma unroll
    for (int k = 0; k < 4; k++){
        int tt = t + k - 2;
        if (tt >= 0 && tt < LSEQ)
            s = fmaf(cw[d*4+k], xz[(long)(b*LSEQ+tt)*(2*DI) + d], s);
    }
    float v = siluf(s);
    xc[idx] = v;
    xcb[idx] = __float2bfloat16(v);
}

// ---------------- scan preprocessing ----------------
__global__ void scanprep_k(const float* __restrict__ dtBC, const float* __restrict__ bdt,
                           const float* __restrict__ A, float* __restrict__ sp){
    int idx = blockIdx.x*blockDim.x + threadIdx.x;
    if (idx >= NTOK*16) return;
    int n = idx & 15, row = idx >> 4;
    float dtp = dtBC[(long)row*64 + n] + bdt[n];
    float dt  = fmaxf(dtp, 0.f) + log1pf(expf(-fabsf(dtp)));
    sp[(long)row*48 + n]      = expf(dt * A[n]);
    sp[(long)row*48 + 16 + n] = dt * dtBC[(long)row*64 + 16 + n];
    sp[(long)row*48 + 32 + n] = dtBC[(long)row*64 + 32 + n];
}

// ---------------- selective scan ----------------
__global__ void scan2_k(const float* __restrict__ sp, const float* __restrict__ xc,
                        const float* __restrict__ xz, const float* __restrict__ Dp,
                        bf16* __restrict__ ymulb){
    int b = blockIdx.x >> 4;
    int d = (blockIdx.x & 15)*128 + threadIdx.x;
    __shared__ float s[64*48];
    float h[16];
    #pragma unroll
    for (int n = 0; n < 16; n++) h[n] = 0.f;
    const float dpv = Dp[d];
    for (int t0 = 0; t0 < LSEQ; t0 += 64){
        __syncthreads();
        const float* src = sp + ((long)b*LSEQ + t0)*48;
        for (int i = threadIdx.x; i < 64*48; i += 128) s[i] = src[i];
        __syncthreads();
        for (int tt = 0; tt < 64; tt++){
            long row = (long)b*LSEQ + t0 + tt;
            float xv = xc[row*DI + d];
            const float* e = s + tt*48;
            float y = 0.f;
            #pragma unroll
            for (int n = 0; n < 16; n++){
                h[n] = fmaf(e[n], h[n], e[16+n]*xv);
                y = fmaf(h[n], e[32+n], y);
            }
            float z = xz[row*(2*DI) + DI + d];
            ymulb[row*DI + d] = __float2bfloat16((y + dpv*xv) * siluf(z));
        }
    }
}

// ---------------- RoPE -> qb,kb,vb bf16 in [b*NH+h][L][DH] layout ----------------
__global__ void rope2_k(const float* __restrict__ qkv, bf16* __restrict__ qb,
                        bf16* __restrict__ kb, bf16* __restrict__ vb){
    int row = blockIdx.x;
    int t = row % LSEQ, b = row / LSEQ;
    __shared__ float q[DM], kk[DM];
    const float* base = qkv + (long)row*3*DM;
    for (int i = threadIdx.x; i < DM; i += 256){ q[i] = base[i]; kk[i] = base[DM+i]; }
    __syncthreads();
    const float sq = sqrtf((float)DH);
    const float lg = logf(10000.f) / 64.f;
    for (int idx = threadIdx.x; idx < DM; idx += 256){
        int h = idx / DH, i = idx % DH;
        int j = i & 63;
        float inv = expf(-(float)j * lg);
        float ang = (float)t * inv;
        float c = cosf(ang), s = sinf(ang);
        int off = h * DH;
        float rq, rk;
        if (i < 64){ rq = -q[off + 2*i + 1]; rk = -kk[off + 2*i + 1]; }
        else       { rq =  q[off + 2*(i-64)]; rk =  kk[off + 2*(i-64)]; }
        long o = ((long)(b*NH + h)*LSEQ + t)*DH + i;
        qb[o] = __float2bfloat16((q[idx]*c + rq*s) * sq);
        kb[o] = __float2bfloat16(kk[idx]*c + rk*s);
        vb[o] = __float2bfloat16(base[2*DM + idx]);
    }
}

// ---------------- gate stage 2 ----------------
__global__ void gate2_k(const float* __restrict__ g1, const float* __restrict__ Wg2,
                        float* __restrict__ gs, int* __restrict__ topi, float* __restrict__ topw){
    int row = blockIdx.x;
    int tid = threadIdx.x; // 64 threads
    __shared__ float red[64*4];
    float a[4] = {0.f,0.f,0.f,0.f};
    for (int j = tid; j < 512; j += 64){
        float v = g1[(long)row*512 + j];
        #pragma unroll
        for (int e = 0; e < 4; e++) a[e] = fmaf(v, Wg2[j*4+e], a[e]);
    }
    #pragma unroll
    for (int e = 0; e < 4; e++) red[e*64 + tid] = a[e];
    __syncthreads();
    for (int st = 32; st > 0; st >>= 1){
        if (tid < st){
            #pragma unroll
            for (int e = 0; e < 4; e++) red[e*64+tid] += red[e*64+tid+st];
        }
        __syncthreads();
    }
    if (tid == 0){
        float l[4]; for (int e = 0; e < 4; e++) l[e] = red[e*64];
        float m = fmaxf(fmaxf(l[0],l[1]), fmaxf(l[2],l[3]));
        float ex[4]; float s = 0.f;
        for (int e = 0; e < 4; e++){ ex[e] = expf(l[e]-m); s += ex[e]; }
        float gsv[4];
        for (int e = 0; e < 4; e++){ gsv[e] = ex[e]/s; gs[(long)row*4+e] = gsv[e]; }
        int i0 = 0;
        for (int e = 1; e < 4; e++) if (gsv[e] > gsv[i0]) i0 = e;
        int i1 = -1;
        for (int e = 0; e < 4; e++) if (e != i0 && (i1 < 0 || gsv[e] > gsv[i1])) i1 = e;
        float v0 = gsv[i0], v1 = gsv[i1];
        float mm = fmaxf(v0, v1);
        float w0 = expf(v0-mm), w1 = expf(v1-mm);
        float ws = w0 + w1;
        topi[row*2] = i0; topi[row*2+1] = i1;
        topw[row*2] = w0/ws; topw[row*2+1] = w1/ws;
    }
}

// ---------------- balance loss ----------------
__global__ void bal_k(const float* __restrict__ gs, float* __restrict__ out){
    int tid = threadIdx.x;
    __shared__ float red[256*4];
    float a[4] = {0.f,0.f,0.f,0.f};
    for (int r = tid; r < NTOK; r += 256){
        #pragma unroll
        for (int e = 0; e < 4; e++) a[e] += gs[(long)r*4+e];
    }
    #pragma unroll
    for (int e = 0; e < 4; e++) red[e*256+tid] = a[e];
    __syncthreads();
    for (int st = 128; st > 0; st >>= 1){
        if (tid < st){
            #pragma unroll
            for (int e = 0; e < 4; e++) red[e*256+tid] += red[e*256+tid+st];
        }
        __syncthreads();
    }
    if (tid == 0){
        float bal = 0.f;
        for (int e = 0; e < 4; e++){
            float gm = red[e*256] / (float)NTOK;
            bal += gm * logf(gm + 1e-8f);
        }
        out[0] = (float)NEXP * bal;
    }
}

// ---------------- MoE routing ----------------
__global__ void zero4_k(int* c){ if (threadIdx.x < NEXP) c[threadIdx.x] = 0; }

__global__ void assign_k(const int* __restrict__ topi, int* __restrict__ cnt,
                         int* __restrict__ slot){
    int idx = blockIdx.x*256 + threadIdx.x;
    if (idx >= NTOK*2) return;
    int e = topi[idx];
    int s = atomicAdd(&cnt[e], 1);
    slot[idx] = e*NTOK + s;
}

__global__ void gather_k(const bf16* __restrict__ xf, const int* __restrict__ slot,
                         bf16* __restrict__ xg){
    int idx = blockIdx.x;
    int tok = idx >> 1;
    int dst = slot[idx];
    const unsigned* src = reinterpret_cast<const unsigned*>(xf) + (long)tok*(DM/2);
    unsigned* d = reinterpret_cast<unsigned*>(xg) + (long)dst*(DM/2);
    for (int i = threadIdx.x; i < DM/2; i += 128) d[i] = src[i];
}

// h = silu(h12[:,:DFF]) * h12[:,DFF:]
__global__ void silumul12_k(const bf16* __restrict__ h12, bf16* __restrict__ hb,
                            const int* __restrict__ cnt){
    int seg = blockIdx.x;             // 0 .. NEXP*NTOK-1
    int e = seg / NTOK, r = seg % NTOK;
    if (r >= cnt[e]) return;
    long b12 = (long)seg*(2*DFF);
    long bh  = (long)seg*DFF;
    for (int i = threadIdx.x; i < DFF; i += 256){
        float a = __bfloat162float(h12[b12 + i]);
        float b = __bfloat162float(h12[b12 + DFF + i]);
        hb[bh + i] = __float2bfloat16(siluf(a)*b);
    }
}

// ---------------- MoE combine + final residual ----------------
__global__ void combine2_k(const float* __restrict__ x2, const float* __restrict__ ls3,
                           const bf16* __restrict__ eo, const int* __restrict__ slot,
                           const float* __restrict__ topw, float* __restrict__ out){
    long idx = (long)blockIdx.x*blockDim.x + threadIdx.x;
    if (idx >= (long)NTOK*DM) return;
    int row = (int)(idx / DM), d = (int)(idx % DM);
    int s0 = slot[row*2], s1 = slot[row*2+1];
    float m = topw[row*2]   * __bfloat162float(eo[(long)s0*DM + d])
            + topw[row*2+1] * __bfloat162float(eo[(long)s1*DM + d]);
    out[idx] = fmaf(ls3[d], m, x2[idx]);
}

// ============================== host ==============================
#define SYMPF(p, s) do { void* _t; cudaGetSymbolAddress(&_t, s); p = (float*)_t; } while(0)
#define SYMPB(p, s) do { void* _t; cudaGetSymbolAddress(&_t, s); p = (bf16*)_t; } while(0)
#define SYMPI(p, s) do { void* _t; cudaGetSymbolAddress(&_t, s); p = (int*)_t; } while(0)

extern "C" void kernel_launch(void* const* d_in, const int* in_sizes, int n_in,
                              void* d_out, int out_size){
    const float* x      = (const float*)d_in[0];
    const float* rms1_w = (const float*)d_in[1];
    const float* rms2_w = (const float*)d_in[2];
    const float* rms3_w = (const float*)d_in[3];
    const float* ls1    = (const float*)d_in[4];
    const float* ls2    = (const float*)d_in[5];
    const float* ls3    = (const float*)d_in[6];
    const float* W_in   = (const float*)d_in[7];
    const float* conv_w = (const float*)d_in[8];
    const float* conv_b = (const float*)d_in[9];
    const float* W_B    = (const float*)d_in[10];
    const float* W_C    = (const float*)d_in[11];
    const float* W_dt   = (const float*)d_in[12];
    const float* b_dt   = (const float*)d_in[13];
    const float* W_out_m= (const float*)d_in[14];
    const float* Avec   = (const float*)d_in[15];
    const float* Dp     = (const float*)d_in[16];
    const float* W_qkv  = (const float*)d_in[17];
    const float* W_o    = (const float*)d_in[18];
    const float* ascale = (const float*)d_in[19];
    const float* Wg1    = (const float*)d_in[20];
    const float* bg1    = (const float*)d_in[21];
    const float* Wg2    = (const float*)d_in[22];
    const float* w1     = (const float*)d_in[23];
    const float* w2     = (const float*)d_in[24];
    const float* w3     = (const float*)d_in[25];
    float* out = (float*)d_out;

    float *p_xz, *p_xc, *p_dtBC, *p_scanp, *p_x1, *p_qkv, *p_x2, *p_g1, *p_gs, *p_topw;
    int *p_topi, *p_cnt, *p_slot;
    bf16 *b_rms1, *b_xc, *b_ymul, *b_rms2, *b_q, *b_k, *b_v, *b_att, *b_xf,
         *b_xg, *b_h12, *b_h, *b_eo;
    bf16 *b_Win, *b_Wout, *b_Wqkv, *b_Wo, *b_Wg1, *b_w12, *b_w3, *b_Wcat;

    SYMPF(p_xz, g_xz); SYMPF(p_xc, g_xc); SYMPF(p_dtBC, g_dtBC); SYMPF(p_scanp, g_scanp);
    SYMPF(p_x1, g_x1); SYMPF(p_qkv, g_qkv);
    SYMPF(p_x2, g_x2); SYMPF(p_g1, g_g1); SYMPF(p_gs, g_gs); SYMPF(p_topw, g_topw);
    SYMPI(p_topi, g_topi); SYMPI(p_cnt, g_cnt); SYMPI(p_slot, g_slot);
    SYMPB(b_rms1, g_rms1b); SYMPB(b_xc, g_xcb); SYMPB(b_ymul, g_ymulb); SYMPB(b_rms2, g_rms2b);
    SYMPB(b_q, g_qb); SYMPB(b_k, g_kb); SYMPB(b_v, g_vb);
    SYMPB(b_att, g_attb); SYMPB(b_xf, g_xfb); SYMPB(b_xg, g_xgb);
    SYMPB(b_h12, g_h12b); SYMPB(b_h, g_hb); SYMPB(b_eo, g_eob);
    SYMPB(b_Win, g_Winb); SYMPB(b_Wout, g_Woutb); SYMPB(b_Wqkv, g_Wqkvb); SYMPB(b_Wo, g_Wob);
    SYMPB(b_Wg1, g_Wg1b); SYMPB(b_w12, g_w12b); SYMPB(b_w3, g_w3b); SYMPB(b_Wcat, g_Wcatb);

    // ---- weight conversions ----
    #define CONV(src, dst, n) f2bf_k<<<(int)(((n)/4 + 255)/256), 256>>>(src, dst, (long)(n))
    CONV(W_in,   b_Win,  (long)DM*2*DI);
    CONV(W_out_m,b_Wout, (long)DI*DM);
    CONV(W_qkv,  b_Wqkv, (long)DM*3*DM);
    CONV(W_o,    b_Wo,   (long)DM*DM);
    CONV(Wg1,    b_Wg1,  (long)DM*512);
    CONV(w3,     b_w3,   (long)NEXP*DFF*DM);
    pack12_k<<<(int)(((long)NEXP*DM*DFF/4 + 255)/256), 256>>>(w1, w2, b_w12);
    packw_k<<<(DI*64+255)/256, 256>>>(W_dt, W_B, W_C, b_Wcat);

    // ---- 1. Mamba ----
    rmsnorm_bf_k<<<NTOK, 256>>>(x, rms1_w, b_rms1);
    {   dim3 g(2*DI/128, NTOK/128, 1);
        bgemm_k<0,0,0><<<g, 256>>>(b_rms1, b_Win, p_xz, NTOK, 2*DI, DM, DM, 2*DI, 2*DI,
                                   0,0,0, nullptr, nullptr, nullptr); }
    conv_k<<<(int)(((long)NTOK*DI+255)/256), 256>>>(p_xz, conv_w, conv_b, p_xc, b_xc);
    {   dim3 g(1, NTOK/128, 1);
        bgemm_k<0,0,0><<<g, 256>>>(b_xc, b_Wcat, p_dtBC, NTOK, 64, DI, DI, 64, 64,
                                   0,0,0, nullptr, nullptr, nullptr); }
    scanprep_k<<<(NTOK*16+255)/256, 256>>>(p_dtBC, b_dt, Avec, p_scanp);
    scan2_k<<<32, 128>>>(p_scanp, p_xc, p_xz, Dp, b_ymul);
    {   dim3 g(DM/128, NTOK/128, 1);   // x1 = x + ls1 * (ymul @ Wout)
        bgemm_k<0,2,0><<<g, 256>>>(b_ymul, b_Wout, p_x1, NTOK, DM, DI, DI, DM, DM,
                                   0,0,0, ls1, x, nullptr); }

    // ---- 2. Attention ----
    rmsnorm_bf_k<<<NTOK, 256>>>(p_x1, rms2_w, b_rms2);
    {   dim3 g(3*DM/128, NTOK/128, 1);
        bgemm_k<0,0,0><<<g, 256>>>(b_rms2, b_Wqkv, p_qkv, NTOK, 3*DM, DM, DM, 3*DM, 3*DM,
                                   0,0,0, nullptr, nullptr, nullptr); }
    rope2_k<<<NTOK, 256>>>(p_qkv, b_q, b_k, b_v);
    {   cudaFuncSetAttribute(flash_k, cudaFuncAttributeMaxDynamicSharedMemorySize, FSMEM);
        dim3 g(LSEQ/128, BB*NH, 1);
        flash_k<<<g, 256, FSMEM>>>(b_q, b_k, b_v, ascale, b_att); }
    {   dim3 g(DM/128, NTOK/128, 1);   // x2 = x1 + ls2 * (att @ Wo)
        bgemm_k<0,2,0><<<g, 256>>>(b_att, b_Wo, p_x2, NTOK, DM, DM, DM, DM, DM,
                                   0,0,0, ls2, p_x1, nullptr); }

    // ---- 3. MoE (top-2 sparse) ----
    rmsnorm_bf_k<<<NTOK, 256>>>(p_x2, rms3_w, b_xf);
    {   dim3 g(512/128, NTOK/128, 1);
        bgemm_k<0,1,0><<<g, 256>>>(b_xf, b_Wg1, p_g1, NTOK, 512, DM, DM, 512, 512,
                                   0,0,0, bg1, nullptr, nullptr); }
    gate2_k<<<NTOK, 64>>>(p_g1, Wg2, p_gs, p_topi, p_topw);
    if (out_size > NTOK*DM)
        bal_k<<<1, 256>>>(p_gs, out + (long)NTOK*DM);
    zero4_k<<<1, 32>>>(p_cnt);
    assign_k<<<(NTOK*2+255)/256, 256>>>(p_topi, p_cnt, p_slot);
    gather_k<<<NTOK*2, 128>>>(b_xf, p_slot, b_xg);
    for (int e = 0; e < NEXP; e++){
        dim3 g12(2*DFF/128, NTOK/128, 1);
        bgemm_k<0,0,1><<<g12, 256>>>(b_xg + (long)e*NTOK*DM, b_w12 + (long)e*DM*2*DFF,
                                     b_h12 + (long)e*NTOK*2*DFF,
                                     NTOK, 2*DFF, DM, DM, 2*DFF, 2*DFF, 0,0,0,
                                     nullptr, nullptr, p_cnt + e);
    }
    silumul12_k<<<NEXP*NTOK, 256>>>(b_h12, b_h, p_cnt);
    for (int e = 0; e < NEXP; e++){
        dim3 g3(DM/128, NTOK/128, 1);
        bgemm_k<0,0,1><<<g3, 256>>>(b_h + (long)e*NTOK*DFF, b_w3 + (long)e*DFF*DM,
                                    b_eo + (long)e*NTOK*DM,
                                    NTOK, DM, DFF, DFF, DM, DM, 0,0,0,
                                    nullptr, nullptr, p_cnt + e);
    }
    combine2_k<<<(int)(((long)NTOK*DM+255)/256), 256>>>(p_x2, ls3, b_eo, p_slot, p_topw, out);
}

// round 7
// speedup vs baseline: 4.6493x; 1.0422x over previous
#include <cuda_runtime.h>
#include <cuda_bf16.h>
#include <math.h>

#define BB   2
#define LSEQ 2048
#define DM   1024
#define DI   2048
#define NH   8
#define DH   128
#define NEXP 4
#define DFF  4096
#define NTOK (BB*LSEQ)   // 4096

typedef __nv_bfloat16 bf16;

// ---------------- static scratch ----------------
__device__ float g_xz[NTOK*2*DI];
__device__ float g_xc[NTOK*DI];
__device__ float g_dtBC[NTOK*64];
__device__ float g_scanp[NTOK*48];
__device__ float g_x1[NTOK*DM];
__device__ float g_qkv[NTOK*3*DM];
__device__ float g_x2[NTOK*DM];
__device__ float g_g1[NTOK*512];
__device__ float g_gs[NTOK*NEXP];
__device__ int   g_topi[NTOK*2];
__device__ float g_topw[NTOK*2];
__device__ int   g_cnt[NEXP];
__device__ int   g_slot[NTOK*2];

// bf16 activations
__device__ bf16 g_rms1b[NTOK*DM];
__device__ bf16 g_xcb[NTOK*DI];
__device__ bf16 g_ymulb[NTOK*DI];
__device__ bf16 g_rms2b[NTOK*DM];
__device__ bf16 g_qb[NTOK*DM];
__device__ bf16 g_kb[NTOK*DM];
__device__ bf16 g_vb[NTOK*DM];
__device__ bf16 g_attb[NTOK*DM];
__device__ bf16 g_xfb[NTOK*DM];
__device__ bf16 g_xgb[NEXP*NTOK*DM];
__device__ bf16 g_hb[(long)NEXP*NTOK*DFF];
__device__ bf16 g_eob[NEXP*NTOK*DM];

// bf16 weights
__device__ bf16 g_Winb[DM*2*DI];
__device__ bf16 g_Woutb[DI*DM];
__device__ bf16 g_Wqkvb[DM*3*DM];
__device__ bf16 g_Wob[DM*DM];
__device__ bf16 g_Wg1b[DM*512];
__device__ bf16 g_w12b[(long)NEXP*DM*2*DFF];   // interleaved (w1_j, w2_j) pairs
__device__ bf16 g_w3b[(long)NEXP*DFF*DM];
__device__ bf16 g_Wcatb[DI*64];

__device__ __forceinline__ float siluf(float x){ return x / (1.f + expf(-x)); }

// ---------------- fp32 -> bf16 convert ----------------
__global__ void f2bf_k(const float* __restrict__ s, bf16* __restrict__ d, long n){
    long i = ((long)blockIdx.x*blockDim.x + threadIdx.x)*4;
    if (i >= n) return;
    float4 v = *reinterpret_cast<const float4*>(s+i);
    *reinterpret_cast<__nv_bfloat162*>(d+i)   = __floats2bfloat162_rn(v.x, v.y);
    *reinterpret_cast<__nv_bfloat162*>(d+i+2) = __floats2bfloat162_rn(v.z, v.w);
}

// pack w1|w2 INTERLEAVED: out[e][d][2j] = w1[e][d][j], out[e][d][2j+1] = w2[e][d][j]
__global__ void pack12_k(const float* __restrict__ w1, const float* __restrict__ w2,
                         bf16* __restrict__ o){
    long i = ((long)blockIdx.x*blockDim.x + threadIdx.x)*4;
    if (i >= (long)NEXP*DM*DFF) return;
    long row = i >> 12;           // e*DM + d
    int  j   = (int)(i & 4095);
    float4 a = *reinterpret_cast<const float4*>(w1 + i);
    float4 b = *reinterpret_cast<const float4*>(w2 + i);
    bf16* d1 = o + row*(2*DFF) + 2*j;
    *reinterpret_cast<__nv_bfloat162*>(d1)   = __floats2bfloat162_rn(a.x, b.x);
    *reinterpret_cast<__nv_bfloat162*>(d1+2) = __floats2bfloat162_rn(a.y, b.y);
    *reinterpret_cast<__nv_bfloat162*>(d1+4) = __floats2bfloat162_rn(a.z, b.z);
    *reinterpret_cast<__nv_bfloat162*>(d1+6) = __floats2bfloat162_rn(a.w, b.w);
}

// pack [W_dt | W_B | W_C | 0] -> [2048][64] bf16
__global__ void packw_k(const float* __restrict__ Wdt, const float* __restrict__ WB,
                        const float* __restrict__ WC, bf16* __restrict__ o){
    int idx = blockIdx.x*256 + threadIdx.x;
    if (idx >= DI*64) return;
    int j = idx >> 6, n = idx & 63;
    float v = 0.f;
    if (n < 16) v = Wdt[j*16+n];
    else if (n < 32) v = WB[j*16+n-16];
    else if (n < 48) v = WC[j*16+n-32];
    o[idx] = __float2bfloat16(v);
}

// ---------------- RMSNorm -> bf16 ----------------
__global__ void rmsnorm_bf_k(const float* __restrict__ x, const float* __restrict__ w,
                             bf16* __restrict__ o){
    int row = blockIdx.x;
    const float* xr = x + (long)row*DM;
    __shared__ float red[256];
    float s = 0.f;
    for (int i = threadIdx.x; i < DM; i += 256){ float v = xr[i]; s += v*v; }
    red[threadIdx.x] = s; __syncthreads();
    for (int st = 128; st > 0; st >>= 1){
        if (threadIdx.x < st) red[threadIdx.x] += red[threadIdx.x+st];
        __syncthreads();
    }
    float r = rsqrtf(red[0]/(float)DM + 1e-6f);
    for (int i = threadIdx.x; i < DM; i += 256)
        o[(long)row*DM+i] = __float2bfloat16(w[i]*xr[i]*r);
}

// ---------------- MMA primitives ----------------
__device__ __forceinline__ void cpasync16(unsigned dst, const void* src, int ssz){
    asm volatile("cp.async.ca.shared.global [%0], [%1], 16, %2;"
        :: "r"(dst), "l"(src), "r"(ssz));
}
__device__ __forceinline__ void cp_commit(){ asm volatile("cp.async.commit_group;"); }
__device__ __forceinline__ void cp_wait0(){ asm volatile("cp.async.wait_group 0;"); }
__device__ __forceinline__ void cp_wait1(){ asm volatile("cp.async.wait_group 1;"); }
__device__ __forceinline__ void ldsm_x4(unsigned saddr, unsigned &o0, unsigned &o1,
                                        unsigned &o2, unsigned &o3){
    asm volatile("ldmatrix.sync.aligned.m8n8.x4.shared.b16 {%0,%1,%2,%3},[%4];"
        : "=r"(o0),"=r"(o1),"=r"(o2),"=r"(o3) : "r"(saddr));
}
__device__ __forceinline__ void ldsm_x4_t(unsigned saddr, unsigned &o0, unsigned &o1,
                                          unsigned &o2, unsigned &o3){
    asm volatile("ldmatrix.sync.aligned.m8n8.x4.trans.shared.b16 {%0,%1,%2,%3},[%4];"
        : "=r"(o0),"=r"(o1),"=r"(o2),"=r"(o3) : "r"(saddr));
}
__device__ __forceinline__ void mma16816(float* d, const unsigned* am, const unsigned* bm){
    asm volatile("mma.sync.aligned.m16n8k16.row.col.f32.bf16.bf16.f32 "
        "{%0,%1,%2,%3},{%4,%5,%6,%7},{%8,%9},{%0,%1,%2,%3};"
        : "+f"(d[0]),"+f"(d[1]),"+f"(d[2]),"+f"(d[3])
        : "r"(am[0]),"r"(am[1]),"r"(am[2]),"r"(am[3]), "r"(bm[0]),"r"(bm[1]));
}
__device__ __forceinline__ unsigned pkbf2(float x, float y){
    __nv_bfloat162 t = __floats2bfloat162_rn(x, y);
    return *reinterpret_cast<unsigned*>(&t);
}

// ---------------- bf16 tensor-core GEMM, cp.async 3-stage ----------------
template<int TRANSB>
__device__ __forceinline__ void stage_tiles(const bf16* Ab, const bf16* Bb,
    int bm, int bn, int N, int lda, int ldb, int k0, int tid,
    unsigned Adst, unsigned Bdst)
{
    #pragma unroll
    for (int c = tid; c < 512; c += 256){
        int r  = c >> 2;
        int ko = (c & 3) << 3;
        cpasync16(Adst + 2u*(unsigned)(r*40 + ko),
                  Ab + (long)(bm + r)*lda + k0 + ko, 16);
    }
    if (TRANSB == 0){
        #pragma unroll
        for (int c = tid; c < 512; c += 256){
            int r  = c >> 4;
            int no = (c & 15) << 3;
            const bf16* src = Bb + (long)(k0 + r)*ldb + bn + no;
            int ssz = 16;
            if (bn + no >= N){ src = Bb; ssz = 0; }
            cpasync16(Bdst + 2u*(unsigned)(r*136 + no), src, ssz);
        }
    } else {
        #pragma unroll
        for (int c = tid; c < 512; c += 256){
            int r  = c >> 2;
            int ko = (c & 3) << 3;
            cpasync16(Bdst + 2u*(unsigned)(r*40 + ko),
                      Bb + (long)(bn + r)*ldb + k0 + ko, 16);
        }
    }
}

// EPI: 0 none, 1 relu(acc+bias), 2 resid C=resx+bias[col]*acc (fp32),
//      3 siluGLU: interleaved pairs -> bf16 h[r][col/2] = silu(v_even)*v_odd
template<int TRANSB, int EPI, int OUTBF>
__global__ void __launch_bounds__(256) bgemm_k(
    const bf16* __restrict__ Aptr, const bf16* __restrict__ Bptr, void* __restrict__ Cv,
    int M, int N, int K, int lda, int ldb, int ldc,
    long sA, long sB, long sC, const float* __restrict__ bias,
    const float* __restrict__ resx, const int* __restrict__ mcnt)
{
    __shared__ bf16 As[3*5120];
    __shared__ bf16 Bs[3*5120];
    const int bm = blockIdx.y * 128;
    int Meff = M;
    if (mcnt) Meff = *mcnt;
    if (bm >= Meff) return;
    const bf16* Ab = Aptr + (long)blockIdx.z * sA;
    const bf16* Bb = Bptr + (long)blockIdx.z * sB;
    const int bn = blockIdx.x * 128;
    const int tid  = threadIdx.x;
    const int lane = tid & 31;
    const int warp = tid >> 5;
    const int wm = warp >> 1;
    const int wn = warp & 1;

    float acc[2][8][4];
    #pragma unroll
    for (int i = 0; i < 2; i++)
        #pragma unroll
        for (int j = 0; j < 8; j++)
            #pragma unroll
            for (int q = 0; q < 4; q++) acc[i][j][q] = 0.f;

    unsigned Afrag[2][4];
    unsigned Bfrag[8][2];

    const unsigned As_base = (unsigned)__cvta_generic_to_shared(As);
    const unsigned Bs_base = (unsigned)__cvta_generic_to_shared(Bs);

    const int rowA = wm*32 + (lane & 15);
    const int colA = (lane >> 4) * 8;
    unsigned aoff0 = As_base + 2u*(unsigned)( rowA       *40 + colA);
    unsigned aoff1 = As_base + 2u*(unsigned)((rowA + 16) *40 + colA);

    unsigned boff[4];
    #pragma unroll
    for (int p = 0; p < 4; p++){
        if (TRANSB == 0){
            int brow = lane & 15;
            int bcol = (lane >> 4) * 8;
            boff[p] = Bs_base + 2u*(unsigned)(brow*136 + wn*64 + p*16 + bcol);
        } else {
            int brow = (lane & 7) + (((lane >> 4) & 1) << 3);
            int bcol = ((lane >> 3) & 1) << 3;
            boff[p] = Bs_base + 2u*(unsigned)((wn*64 + p*16 + brow)*40 + bcol);
        }
    }

    const int nk = K >> 5;
    stage_tiles<TRANSB>(Ab, Bb, bm, bn, N, lda, ldb, 0, tid, As_base, Bs_base);
    cp_commit();
    if (nk > 1){
        stage_tiles<TRANSB>(Ab, Bb, bm, bn, N, lda, ldb, 32, tid,
                            As_base + 10240u, Bs_base + 10240u);
        cp_commit();
    }

    unsigned sb = 0u;
    for (int it = 0; it < nk; it++){
        if (it + 1 < nk) cp_wait1(); else cp_wait0();
        __syncthreads();
        if (it + 2 < nk){
            unsigned off = (unsigned)((it + 2) % 3) * 10240u;
            stage_tiles<TRANSB>(Ab, Bb, bm, bn, N, lda, ldb, (it+2) << 5, tid,
                                As_base + off, Bs_base + off);
            cp_commit();
        }
        #pragma unroll
        for (int ks = 0; ks < 32; ks += 16){
            ldsm_x4(aoff0 + sb + 2u*ks, Afrag[0][0], Afrag[0][1], Afrag[0][2], Afrag[0][3]);
            ldsm_x4(aoff1 + sb + 2u*ks, Afrag[1][0], Afrag[1][1], Afrag[1][2], Afrag[1][3]);
            #pragma unroll
            for (int p = 0; p < 4; p++){
                if (TRANSB == 0){
                    unsigned ba = boff[p] + sb + 2u*(unsigned)(ks*136);
                    ldsm_x4_t(ba, Bfrag[2*p][0], Bfrag[2*p][1],
                                  Bfrag[2*p+1][0], Bfrag[2*p+1][1]);
                } else {
                    unsigned ba = boff[p] + sb + 2u*(unsigned)ks;
                    ldsm_x4(ba, Bfrag[2*p][0], Bfrag[2*p][1],
                                Bfrag[2*p+1][0], Bfrag[2*p+1][1]);
                }
            }
            #pragma unroll
            for (int mt = 0; mt < 2; mt++)
                #pragma unroll
                for (int nt = 0; nt < 8; nt++)
                    mma16816(acc[mt][nt], Afrag[mt], Bfrag[nt]);
        }
        __syncthreads();
        sb += 10240u;
        if (sb == 30720u) sb = 0u;
    }

    #pragma unroll
    for (int mt = 0; mt < 2; mt++){
        int r0 = bm + wm*32 + mt*16 + (lane >> 2);
        #pragma unroll
        for (int nt = 0; nt < 8; nt++){
            int col = bn + wn*64 + nt*8 + ((lane & 3) << 1);
            if (col < N){
                float v0 = acc[mt][nt][0];
                float v1 = acc[mt][nt][1];
                float v2 = acc[mt][nt][2];
                float v3 = acc[mt][nt][3];
                if (EPI == 3){
                    // interleaved siluGLU: col even, pair (v0,v1) / (v2,v3)
                    bf16* Cb = (bf16*)Cv;
                    int jc = col >> 1;
                    Cb[(long)r0*(N>>1) + jc]     = __float2bfloat16(siluf(v0)*v1);
                    Cb[(long)(r0+8)*(N>>1) + jc] = __float2bfloat16(siluf(v2)*v3);
                    continue;
                }
                if (EPI == 1){
                    float b0 = bias[col];
                    float b1 = bias[col+1];
                    v0 = fmaxf(v0+b0, 0.f); v1 = fmaxf(v1+b1, 0.f);
                    v2 = fmaxf(v2+b0, 0.f); v3 = fmaxf(v3+b1, 0.f);
                }
                if (EPI == 2){
                    float b0 = bias[col];
                    float b1 = bias[col+1];
                    v0 = fmaf(b0, v0, resx[(long)r0*ldc + col]);
                    v1 = fmaf(b1, v1, resx[(long)r0*ldc + col + 1]);
                    v2 = fmaf(b0, v2, resx[(long)(r0+8)*ldc + col]);
                    v3 = fmaf(b1, v3, resx[(long)(r0+8)*ldc + col + 1]);
                }
                if (OUTBF){
                    bf16* Cb = (bf16*)Cv + (long)blockIdx.z * sC;
                    *reinterpret_cast<__nv_bfloat162*>(&Cb[(long)r0*ldc + col]) =
                        __floats2bfloat162_rn(v0, v1);
                    *reinterpret_cast<__nv_bfloat162*>(&Cb[(long)(r0+8)*ldc + col]) =
                        __floats2bfloat162_rn(v2, v3);
                } else {
                    float* Cb = (float*)Cv + (long)blockIdx.z * sC;
                    *reinterpret_cast<float2*>(&Cb[(long)r0*ldc + col]) = make_float2(v0, v1);
                    *reinterpret_cast<float2*>(&Cb[(long)(r0+8)*ldc + col]) = make_float2(v2, v3);
                }
            }
        }
    }
}

// ---------------- fused flash attention ----------------
#define FTILE (128*136)
#define FSMEM (5*FTILE*2)

__device__ __forceinline__ void fstage(const bf16* src, unsigned dst, int tid){
    for (int i = tid; i < 2048; i += 256){
        int r = i >> 4, c = (i & 15) << 3;
        cpasync16(dst + 2u*(unsigned)(r*136 + c), src + r*DH + c, 16);
    }
}

__global__ void __launch_bounds__(256, 1) flash_k(
    const bf16* __restrict__ q, const bf16* __restrict__ k, const bf16* __restrict__ v,
    const float* __restrict__ ascale, bf16* __restrict__ att)
{
    extern __shared__ bf16 fs[];
    const int qt = blockIdx.x, bh = blockIdx.y;
    const int bb = bh >> 3, hh = bh & 7;
    const int tid = threadIdx.x, lane = tid & 31, w = tid >> 5;
    const float a = ascale[hh];

    const bf16* qg = q + ((long)bh*LSEQ + qt*128)*DH;
    const bf16* kg = k + (long)bh*LSEQ*DH;
    const bf16* vg = v + (long)bh*LSEQ*DH;

    const unsigned Qb = (unsigned)__cvta_generic_to_shared(fs);
    const unsigned Kb = Qb + 2u*FTILE;
    const unsigned Vb = Qb + 6u*FTILE;
    const unsigned TILEB = 2u*FTILE;

    fstage(qg, Qb, tid);
    fstage(kg, Kb, tid);
    fstage(vg, Vb, tid);
    cp_commit();
    cp_wait0();
    __syncthreads();

    unsigned qf[8][4];
    {
        int rq = w*16 + (lane & 15);
        int cq = (lane >> 4) << 3;
        #pragma unroll
        for (int ks = 0; ks < 8; ks++)
            ldsm_x4(Qb + 2u*(unsigned)(rq*136 + ks*16 + cq),
                    qf[ks][0], qf[ks][1], qf[ks][2], qf[ks][3]);
    }

    const int brow = (lane & 7) + (((lane >> 4) & 1) << 3);
    const int bcol = ((lane >> 3) & 1) << 3;
    unsigned kadr[8], vadr[8];
    #pragma unroll
    for (int p = 0; p < 8; p++){
        kadr[p] = Kb + 2u*(unsigned)((p*16 + brow)*136 + bcol);
        vadr[p] = Vb + 2u*(unsigned)((lane & 15)*136 + p*16 + ((lane >> 4) << 3));
    }

    float oacc[16][4];
    #pragma unroll
    for (int nt = 0; nt < 16; nt++)
        #pragma unroll
        for (int qq = 0; qq < 4; qq++) oacc[nt][qq] = 0.f;
    float m0 = -1e30f, m1 = -1e30f, l0 = 0.f, l1 = 0.f;

    for (int kt = 0; kt < 16; kt++){
        if (kt > 0){ cp_wait0(); __syncthreads(); }
        if (kt + 1 < 16){
            unsigned off = ((kt + 1) & 1) ? TILEB : 0u;
            fstage(kg + (long)(kt+1)*128*DH, Kb + off, tid);
            fstage(vg + (long)(kt+1)*128*DH, Vb + off, tid);
            cp_commit();
        }
        const unsigned sb = (kt & 1) ? TILEB : 0u;

        float sacc[16][4];
        #pragma unroll
        for (int nt = 0; nt < 16; nt++)
            #pragma unroll
            for (int qq = 0; qq < 4; qq++) sacc[nt][qq] = 0.f;

        #pragma unroll
        for (int ks = 0; ks < 8; ks++){
            #pragma unroll
            for (int p = 0; p < 8; p++){
                unsigned bf0[2], bf1[2];
                ldsm_x4(kadr[p] + sb + 2u*(unsigned)(ks*16),
                        bf0[0], bf0[1], bf1[0], bf1[1]);
                mma16816(sacc[2*p],   qf[ks], bf0);
                mma16816(sacc[2*p+1], qf[ks], bf1);
            }
        }

        float ax0 = -1e30f, ax1 = -1e30f;
        #pragma unroll
        for (int nt = 0; nt < 16; nt++){
            sacc[nt][0] *= a; sacc[nt][1] *= a; sacc[nt][2] *= a; sacc[nt][3] *= a;
            ax0 = fmaxf(ax0, fmaxf(sacc[nt][0], sacc[nt][1]));
            ax1 = fmaxf(ax1, fmaxf(sacc[nt][2], sacc[nt][3]));
        }
        ax0 = fmaxf(ax0, __shfl_xor_sync(0xffffffffu, ax0, 1));
        ax0 = fmaxf(ax0, __shfl_xor_sync(0xffffffffu, ax0, 2));
        ax1 = fmaxf(ax1, __shfl_xor_sync(0xffffffffu, ax1, 1));
        ax1 = fmaxf(ax1, __shfl_xor_sync(0xffffffffu, ax1, 2));
        float mn0 = fmaxf(m0, ax0), mn1 = fmaxf(m1, ax1);
        float f0 = expf(m0 - mn0), f1 = expf(m1 - mn1);

        float rs0 = 0.f, rs1 = 0.f;
        #pragma unroll
        for (int nt = 0; nt < 16; nt++){
            sacc[nt][0] = expf(sacc[nt][0] - mn0);
            sacc[nt][1] = expf(sacc[nt][1] - mn0);
            sacc[nt][2] = expf(sacc[nt][2] - mn1);
            sacc[nt][3] = expf(sacc[nt][3] - mn1);
            rs0 += sacc[nt][0] + sacc[nt][1];
            rs1 += sacc[nt][2] + sacc[nt][3];
        }
        rs0 += __shfl_xor_sync(0xffffffffu, rs0, 1);
        rs0 += __shfl_xor_sync(0xffffffffu, rs0, 2);
        rs1 += __shfl_xor_sync(0xffffffffu, rs1, 1);
        rs1 += __shfl_xor_sync(0xffffffffu, rs1, 2);
        l0 = l0*f0 + rs0; l1 = l1*f1 + rs1;
        m0 = mn0; m1 = mn1;

        #pragma unroll
        for (int nt = 0; nt < 16; nt++){
            oacc[nt][0] *= f0; oacc[nt][1] *= f0;
            oacc[nt][2] *= f1; oacc[nt][3] *= f1;
        }

        unsigned pa[8][4];
        #pragma unroll
        for (int ksp = 0; ksp < 8; ksp++){
            pa[ksp][0] = pkbf2(sacc[2*ksp][0],   sacc[2*ksp][1]);
            pa[ksp][1] = pkbf2(sacc[2*ksp][2],   sacc[2*ksp][3]);
            pa[ksp][2] = pkbf2(sacc[2*ksp+1][0], sacc[2*ksp+1][1]);
            pa[ksp][3] = pkbf2(sacc[2*ksp+1][2], sacc[2*ksp+1][3]);
        }

        #pragma unroll
        for (int ksp = 0; ksp < 8; ksp++){
            #pragma unroll
            for (int p = 0; p < 8; p++){
                unsigned bf0[2], bf1[2];
                ldsm_x4_t(vadr[p] + sb + 2u*(unsigned)(ksp*16*136),
                          bf0[0], bf0[1], bf1[0], bf1[1]);
                mma16816(oacc[2*p],   pa[ksp], bf0);
                mma16816(oacc[2*p+1], pa[ksp], bf1);
            }
        }
    }

    float inv0 = 1.f / l0, inv1 = 1.f / l1;
    long row0 = (long)bb*LSEQ + qt*128 + w*16 + (lane >> 2);
    long row1 = row0 + 8;
    int  cbase = hh*DH + ((lane & 3) << 1);
    #pragma unroll
    for (int nt = 0; nt < 16; nt++){
        int col = cbase + nt*8;
        *reinterpret_cast<__nv_bfloat162*>(&att[row0*DM + col]) =
            __floats2bfloat162_rn(oacc[nt][0]*inv0, oacc[nt][1]*inv0);
        *reinterpret_cast<__nv_bfloat162*>(&att[row1*DM + col]) =
            __floats2bfloat162_rn(oacc[nt][2]*inv1, oacc[nt][3]*inv1);
    }
}

// ---------------- depthwise conv + bias + SiLU ----------------
__global__ void conv_k(const float* __restrict__ xz, const float* __restrict__ cw,
                       const float* __restrict__ cb, float* __restrict__ xc,
                       bf16* __restrict__ xcb){
    long idx = (long)blockIdx.x*blockDim.x + threadIdx.x;
    if (idx >= (long)NTOK*DI) return;
    int d = (int)(idx % DI);
    int row = (int)(idx / DI);
    int t = row % LSEQ, b = row / LSEQ;
    float s = cb[d];
    #pragma unroll
    for (int k = 0; k < 4; k++){
        int tt = t + k - 2;
        if (tt >= 0 && tt < LSEQ)
            s = fmaf(cw[d*4+k], xz[(long)(b*LSEQ+tt)*(2*DI) + d], s);
    }
    float v = siluf(s);
    xc[idx] = v;
    xcb[idx] = __float2bfloat16(v);
}

// ---------------- scan preprocessing ----------------
__global__ void scanprep_k(const float* __restrict__ dtBC, const float* __restrict__ bdt,
                           const float* __restrict__ A, float* __restrict__ sp){
    int idx = blockIdx.x*blockDim.x + threadIdx.x;
    if (idx >= NTOK*16) return;
    int n = idx & 15, row = idx >> 4;
    float dtp = dtBC[(long)row*64 + n] + bdt[n];
    float dt  = fmaxf(dtp, 0.f) + log1pf(expf(-fabsf(dtp)));
    sp[(long)row*48 + n]      = expf(dt * A[n]);
    sp[(long)row*48 + 16 + n] = dt * dtBC[(long)row*64 + 16 + n];
    sp[(long)row*48 + 32 + n] = dtBC[(long)row*64 + 32 + n];
}

// ---------------- selective scan ----------------
__global__ void scan2_k(const float* __restrict__ sp, const float* __restrict__ xc,
                        const float* __restrict__ xz, const float* __restrict__ Dp,
                        bf16* __restrict__ ymulb){
    int b = blockIdx.x >> 4;
    int d = (blockIdx.x & 15)*128 + threadIdx.x;
    __shared__ float s[64*48];
    float h[16];
    #pragma unroll
    for (int n = 0; n < 16; n++) h[n] = 0.f;
    const float dpv = Dp[d];
    for (int t0 = 0; t0 < LSEQ; t0 += 64){
        __syncthreads();
        const float* src = sp + ((long)b*LSEQ + t0)*48;
        for (int i = threadIdx.x; i < 64*48; i += 128) s[i] = src[i];
        __syncthreads();
        for (int tt = 0; tt < 64; tt++){
            long row = (long)b*LSEQ + t0 + tt;
            float xv = xc[row*DI + d];
            const float* e = s + tt*48;
            float y = 0.f;
            #pragma unroll
            for (int n = 0; n < 16; n++){
                h[n] = fmaf(e[n], h[n], e[16+n]*xv);
                y = fmaf(h[n], e[32+n], y);
            }
            float z = xz[row*(2*DI) + DI + d];
            ymulb[row*DI + d] = __float2bfloat16((y + dpv*xv) * siluf(z));
        }
    }
}

// ---------------- RoPE -> qb,kb,vb bf16 in [b*NH+h][L][DH] layout ----------------
__global__ void rope2_k(const float* __restrict__ qkv, bf16* __restrict__ qb,
                        bf16* __restrict__ kb, bf16* __restrict__ vb){
    int row = blockIdx.x;
    int t = row % LSEQ, b = row / LSEQ;
    __shared__ float q[DM], kk[DM];
    const float* base = qkv + (long)row*3*DM;
    for (int i = threadIdx.x; i < DM; i += 256){ q[i] = base[i]; kk[i] = base[DM+i]; }
    __syncthreads();
    const float sq = sqrtf((float)DH);
    const float lg = logf(10000.f) / 64.f;
    for (int idx = threadIdx.x; idx < DM; idx += 256){
        int h = idx / DH, i = idx % DH;
        int j = i & 63;
        float inv = expf(-(float)j * lg);
        float ang = (float)t * inv;
        float c = cosf(ang), s = sinf(ang);
        int off = h * DH;
        float rq, rk;
        if (i < 64){ rq = -q[off + 2*i + 1]; rk = -kk[off + 2*i + 1]; }
        else       { rq =  q[off + 2*(i-64)]; rk =  kk[off + 2*(i-64)]; }
        long o = ((long)(b*NH + h)*LSEQ + t)*DH + i;
        qb[o] = __float2bfloat16((q[idx]*c + rq*s) * sq);
        kb[o] = __float2bfloat16(kk[idx]*c + rk*s);
        vb[o] = __float2bfloat16(base[2*DM + idx]);
    }
}

// ---------------- gate stage 2 ----------------
__global__ void gate2_k(const float* __restrict__ g1, const float* __restrict__ Wg2,
                        float* __restrict__ gs, int* __restrict__ topi, float* __restrict__ topw){
    int row = blockIdx.x;
    int tid = threadIdx.x; // 64 threads
    __shared__ float red[64*4];
    float a[4] = {0.f,0.f,0.f,0.f};
    for (int j = tid; j < 512; j += 64){
        float v = g1[(long)row*512 + j];
        #pragma unroll
        for (int e = 0; e < 4; e++) a[e] = fmaf(v, Wg2[j*4+e], a[e]);
    }
    #pragma unroll
    for (int e = 0; e < 4; e++) red[e*64 + tid] = a[e];
    __syncthreads();
    for (int st = 32; st > 0; st >>= 1){
        if (tid < st){
            #pragma unroll
            for (int e = 0; e < 4; e++) red[e*64+tid] += red[e*64+tid+st];
        }
        __syncthreads();
    }
    if (tid == 0){
        float l[4]; for (int e = 0; e < 4; e++) l[e] = red[e*64];
        float m = fmaxf(fmaxf(l[0],l[1]), fmaxf(l[2],l[3]));
        float ex[4]; float s = 0.f;
        for (int e = 0; e < 4; e++){ ex[e] = expf(l[e]-m); s += ex[e]; }
        float gsv[4];
        for (int e = 0; e < 4; e++){ gsv[e] = ex[e]/s; gs[(long)row*4+e] = gsv[e]; }
        int i0 = 0;
        for (int e = 1; e < 4; e++) if (gsv[e] > gsv[i0]) i0 = e;
        int i1 = -1;
        for (int e = 0; e < 4; e++) if (e != i0 && (i1 < 0 || gsv[e] > gsv[i1])) i1 = e;
        float v0 = gsv[i0], v1 = gsv[i1];
        float mm = fmaxf(v0, v1);
        float w0 = expf(v0-mm), w1 = expf(v1-mm);
        float ws = w0 + w1;
        topi[row*2] = i0; topi[row*2+1] = i1;
        topw[row*2] = w0/ws; topw[row*2+1] = w1/ws;
    }
}

// ---------------- balance loss ----------------
__global__ void bal_k(const float* __restrict__ gs, float* __restrict__ out){
    int tid = threadIdx.x;
    __shared__ float red[256*4];
    float a[4] = {0.f,0.f,0.f,0.f};
    for (int r = tid; r < NTOK; r += 256){
        #pragma unroll
        for (int e = 0; e < 4; e++) a[e] += gs[(long)r*4+e];
    }
    #pragma unroll
    for (int e = 0; e < 4; e++) red[e*256+tid] = a[e];
    __syncthreads();
    for (int st = 128; st > 0; st >>= 1){
        if (tid < st){
            #pragma unroll
            for (int e = 0; e < 4; e++) red[e*256+tid] += red[e*256+tid+st];
        }
        __syncthreads();
    }
    if (tid == 0){
        float bal = 0.f;
        for (int e = 0; e < 4; e++){
            float gm = red[e*256] / (float)NTOK;
            bal += gm * logf(gm + 1e-8f);
        }
        out[0] = (float)NEXP * bal;
    }
}

// ---------------- MoE routing ----------------
__global__ void zero4_k(int* c){ if (threadIdx.x < NEXP) c[threadIdx.x] = 0; }

__global__ void assign_k(const int* __restrict__ topi, int* __restrict__ cnt,
                         int* __restrict__ slot){
    int idx = blockIdx.x*256 + threadIdx.x;
    if (idx >= NTOK*2) return;
    int e = topi[idx];
    int s = atomicAdd(&cnt[e], 1);
    slot[idx] = e*NTOK + s;
}

__global__ void gather_k(const bf16* __restrict__ xf, const int* __restrict__ slot,
                         bf16* __restrict__ xg){
    int idx = blockIdx.x;
    int tok = idx >> 1;
    int dst = slot[idx];
    const unsigned* src = reinterpret_cast<const unsigned*>(xf) + (long)tok*(DM/2);
    unsigned* d = reinterpret_cast<unsigned*>(xg) + (long)dst*(DM/2);
    for (int i = threadIdx.x; i < DM/2; i += 128) d[i] = src[i];
}

// ---------------- MoE combine + final residual ----------------
__global__ void combine2_k(const float* __restrict__ x2, const float* __restrict__ ls3,
                           const bf16* __restrict__ eo, const int* __restrict__ slot,
                           const float* __restrict__ topw, float* __restrict__ out){
    long idx = (long)blockIdx.x*blockDim.x + threadIdx.x;
    if (idx >= (long)NTOK*DM) return;
    int row = (int)(idx / DM), d = (int)(idx % DM);
    int s0 = slot[row*2], s1 = slot[row*2+1];
    float m = topw[row*2]   * __bfloat162float(eo[(long)s0*DM + d])
            + topw[row*2+1] * __bfloat162float(eo[(long)s1*DM + d]);
    out[idx] = fmaf(ls3[d], m, x2[idx]);
}

// ============================== host ==============================
#define SYMPF(p, s) do { void* _t; cudaGetSymbolAddress(&_t, s); p = (float*)_t; } while(0)
#define SYMPB(p, s) do { void* _t; cudaGetSymbolAddress(&_t, s); p = (bf16*)_t; } while(0)
#define SYMPI(p, s) do { void* _t; cudaGetSymbolAddress(&_t, s); p = (int*)_t; } while(0)

extern "C" void kernel_launch(void* const* d_in, const int* in_sizes, int n_in,
                              void* d_out, int out_size){
    const float* x      = (const float*)d_in[0];
    const float* rms1_w = (const float*)d_in[1];
    const float* rms2_w = (const float*)d_in[2];
    const float* rms3_w = (const float*)d_in[3];
    const float* ls1    = (const float*)d_in[4];
    const float* ls2    = (const float*)d_in[5];
    const float* ls3    = (const float*)d_in[6];
    const float* W_in   = (const float*)d_in[7];
    const float* conv_w = (const float*)d_in[8];
    const float* conv_b = (const float*)d_in[9];
    const float* W_B    = (const float*)d_in[10];
    const float* W_C    = (const float*)d_in[11];
    const float* W_dt   = (const float*)d_in[12];
    const float* b_dt   = (const float*)d_in[13];
    const float* W_out_m= (const float*)d_in[14];
    const float* Avec   = (const float*)d_in[15];
    const float* Dp     = (const float*)d_in[16];
    const float* W_qkv  = (const float*)d_in[17];
    const float* W_o    = (const float*)d_in[18];
    const float* ascale = (const float*)d_in[19];
    const float* Wg1    = (const float*)d_in[20];
    const float* bg1    = (const float*)d_in[21];
    const float* Wg2    = (const float*)d_in[22];
    const float* w1     = (const float*)d_in[23];
    const float* w2     = (const float*)d_in[24];
    const float* w3     = (const float*)d_in[25];
    float* out = (float*)d_out;

    float *p_xz, *p_xc, *p_dtBC, *p_scanp, *p_x1, *p_qkv, *p_x2, *p_g1, *p_gs, *p_topw;
    int *p_topi, *p_cnt, *p_slot;
    bf16 *b_rms1, *b_xc, *b_ymul, *b_rms2, *b_q, *b_k, *b_v, *b_att, *b_xf,
         *b_xg, *b_h, *b_eo;
    bf16 *b_Win, *b_Wout, *b_Wqkv, *b_Wo, *b_Wg1, *b_w12, *b_w3, *b_Wcat;

    SYMPF(p_xz, g_xz); SYMPF(p_xc, g_xc); SYMPF(p_dtBC, g_dtBC); SYMPF(p_scanp, g_scanp);
    SYMPF(p_x1, g_x1); SYMPF(p_qkv, g_qkv);
    SYMPF(p_x2, g_x2); SYMPF(p_g1, g_g1); SYMPF(p_gs, g_gs); SYMPF(p_topw, g_topw);
    SYMPI(p_topi, g_topi); SYMPI(p_cnt, g_cnt); SYMPI(p_slot, g_slot);
    SYMPB(b_rms1, g_rms1b); SYMPB(b_xc, g_xcb); SYMPB(b_ymul, g_ymulb); SYMPB(b_rms2, g_rms2b);
    SYMPB(b_q, g_qb); SYMPB(b_k, g_kb); SYMPB(b_v, g_vb);
    SYMPB(b_att, g_attb); SYMPB(b_xf, g_xfb); SYMPB(b_xg, g_xgb);
    SYMPB(b_h, g_hb); SYMPB(b_eo, g_eob);
    SYMPB(b_Win, g_Winb); SYMPB(b_Wout, g_Woutb); SYMPB(b_Wqkv, g_Wqkvb); SYMPB(b_Wo, g_Wob);
    SYMPB(b_Wg1, g_Wg1b); SYMPB(b_w12, g_w12b); SYMPB(b_w3, g_w3b); SYMPB(b_Wcat, g_Wcatb);

    // ---- weight conversions ----
    #define CONV(src, dst, n) f2bf_k<<<(int)(((n)/4 + 255)/256), 256>>>(src, dst, (long)(n))
    CONV(W_in,   b_Win,  (long)DM*2*DI);
    CONV(W_out_m,b_Wout, (long)DI*DM);
    CONV(W_qkv,  b_Wqkv, (long)DM*3*DM);
    CONV(W_o,    b_Wo,   (long)DM*DM);
    CONV(Wg1,    b_Wg1,  (long)DM*512);
    CONV(w3,     b_w3,   (long)NEXP*DFF*DM);
    pack12_k<<<(int)(((long)NEXP*DM*DFF/4 + 255)/256), 256>>>(w1, w2, b_w12);
    packw_k<<<(DI*64+255)/256, 256>>>(W_dt, W_B, W_C, b_Wcat);

    // ---- 1. Mamba ----
    rmsnorm_bf_k<<<NTOK, 256>>>(x, rms1_w, b_rms1);
    {   dim3 g(2*DI/128, NTOK/128, 1);
        bgemm_k<0,0,0><<<g, 256>>>(b_rms1, b_Win, p_xz, NTOK, 2*DI, DM, DM, 2*DI, 2*DI,
                                   0,0,0, nullptr, nullptr, nullptr); }
    conv_k<<<(int)(((long)NTOK*DI+255)/256), 256>>>(p_xz, conv_w, conv_b, p_xc, b_xc);
    {   dim3 g(1, NTOK/128, 1);
        bgemm_k<0,0,0><<<g, 256>>>(b_xc, b_Wcat, p_dtBC, NTOK, 64, DI, DI, 64, 64,
                                   0,0,0, nullptr, nullptr, nullptr); }
    scanprep_k<<<(NTOK*16+255)/256, 256>>>(p_dtBC, b_dt, Avec, p_scanp);
    scan2_k<<<32, 128>>>(p_scanp, p_xc, p_xz, Dp, b_ymul);
    {   dim3 g(DM/128, NTOK/128, 1);   // x1 = x + ls1 * (ymul @ Wout)
        bgemm_k<0,2,0><<<g, 256>>>(b_ymul, b_Wout, p_x1, NTOK, DM, DI, DI, DM, DM,
                                   0,0,0, ls1, x, nullptr); }

    // ---- 2. Attention ----
    rmsnorm_bf_k<<<NTOK, 256>>>(p_x1, rms2_w, b_rms2);
    {   dim3 g(3*DM/128, NTOK/128, 1);
        bgemm_k<0,0,0><<<g, 256>>>(b_rms2, b_Wqkv, p_qkv, NTOK, 3*DM, DM, DM, 3*DM, 3*DM,
                                   0,0,0, nullptr, nullptr, nullptr); }
    rope2_k<<<NTOK, 256>>>(p_qkv, b_q, b_k, b_v);
    {   cudaFuncSetAttribute(flash_k, cudaFuncAttributeMaxDynamicSharedMemorySize, FSMEM);
        dim3 g(LSEQ/128, BB*NH, 1);
        flash_k<<<g, 256, FSMEM>>>(b_q, b_k, b_v, ascale, b_att); }
    {   dim3 g(DM/128, NTOK/128, 1);   // x2 = x1 + ls2 * (att @ Wo)
        bgemm_k<0,2,0><<<g, 256>>>(b_att, b_Wo, p_x2, NTOK, DM, DM, DM, DM, DM,
                                   0,0,0, ls2, p_x1, nullptr); }

    // ---- 3. MoE (top-2 sparse) ----
    rmsnorm_bf_k<<<NTOK, 256>>>(p_x2, rms3_w, b_xf);
    {   dim3 g(512/128, NTOK/128, 1);
        bgemm_k<0,1,0><<<g, 256>>>(b_xf, b_Wg1, p_g1, NTOK, 512, DM, DM, 512, 512,
                                   0,0,0, bg1, nullptr, nullptr); }
    gate2_k<<<NTOK, 64>>>(p_g1, Wg2, p_gs, p_topi, p_topw);
    if (out_size > NTOK*DM)
        bal_k<<<1, 256>>>(p_gs, out + (long)NTOK*DM);
    zero4_k<<<1, 32>>>(p_cnt);
    assign_k<<<(NTOK*2+255)/256, 256>>>(p_topi, p_cnt, p_slot);
    gather_k<<<NTOK*2, 128>>>(b_xf, p_slot, b_xg);
    for (int e = 0; e < NEXP; e++){
        // fused w1|w2 GEMM with siluGLU epilogue -> h (bf16, ld DFF)
        dim3 g12(2*DFF/128, NTOK/128, 1);
        bgemm_k<0,3,1><<<g12, 256>>>(b_xg + (long)e*NTOK*DM, b_w12 + (long)e*DM*2*DFF,
                                     b_h + (long)e*NTOK*DFF,
                                     NTOK, 2*DFF, DM, DM, 2*DFF, 2*DFF, 0,0,0,
                                     nullptr, nullptr, p_cnt + e);
    }
    for (int e = 0; e < NEXP; e++){
        dim3 g3(DM/128, NTOK/128, 1);
        bgemm_k<0,0,1><<<g3, 256>>>(b_h + (long)e*NTOK*DFF, b_w3 + (long)e*DFF*DM,
                                    b_eo + (long)e*NTOK*DM,
                                    NTOK, DM, DFF, DFF, DM, DM, 0,0,0,
                                    nullptr, nullptr, p_cnt + e);
    }
    combine2_k<<<(int)(((long)NTOK*DM+255)/256), 256>>>(p_x2, ls3, b_eo, p_slot, p_topw, out);
}

// round 8
// speedup vs baseline: 4.7066x; 1.0123x over previous
#include <cuda_runtime.h>
#include <cuda_bf16.h>
#include <math.h>

#define BB   2
#define LSEQ 2048
#define DM   1024
#define DI   2048
#define NH   8
#define DH   128
#define NEXP 4
#define DFF  4096
#define NTOK (BB*LSEQ)   // 4096

typedef __nv_bfloat16 bf16;

// ---------------- static scratch ----------------
__device__ float g_xz[NTOK*2*DI];
__device__ float g_xc[NTOK*DI];
__device__ float g_dtBC[NTOK*64];
__device__ float g_scanp[NTOK*48];
__device__ float g_x1[NTOK*DM];
__device__ float g_qkv[NTOK*3*DM];
__device__ float g_x2[NTOK*DM];
__device__ float g_g1[NTOK*512];
__device__ float g_gs[NTOK*NEXP];
__device__ int   g_topi[NTOK*2];
__device__ float g_topw[NTOK*2];
__device__ int   g_cnt[NEXP];
__device__ int   g_slot[NTOK*2];

// bf16 activations
__device__ bf16 g_rms1b[NTOK*DM];
__device__ bf16 g_xcb[NTOK*DI];
__device__ bf16 g_ymulb[NTOK*DI];
__device__ bf16 g_rms2b[NTOK*DM];
__device__ bf16 g_qb[NTOK*DM];
__device__ bf16 g_kb[NTOK*DM];
__device__ bf16 g_vb[NTOK*DM];
__device__ bf16 g_attb[NTOK*DM];
__device__ bf16 g_xfb[NTOK*DM];
__device__ bf16 g_xgb[NEXP*NTOK*DM];
__device__ bf16 g_hb[(long)NEXP*NTOK*DFF];
__device__ bf16 g_eob[NEXP*NTOK*DM];

// bf16 weights
__device__ bf16 g_Winb[DM*2*DI];
__device__ bf16 g_Woutb[DI*DM];
__device__ bf16 g_Wqkvb[DM*3*DM];
__device__ bf16 g_Wob[DM*DM];
__device__ bf16 g_Wg1b[DM*512];
__device__ bf16 g_w12b[(long)NEXP*DM*2*DFF];   // interleaved (w1_j, w2_j) pairs
__device__ bf16 g_w3b[(long)NEXP*DFF*DM];
__device__ bf16 g_Wcatb[DI*64];

__device__ __forceinline__ float siluf(float x){ return x / (1.f + expf(-x)); }

// ---------------- fp32 -> bf16 convert ----------------
__global__ void f2bf_k(const float* __restrict__ s, bf16* __restrict__ d, long n){
    long i = ((long)blockIdx.x*blockDim.x + threadIdx.x)*4;
    if (i >= n) return;
    float4 v = *reinterpret_cast<const float4*>(s+i);
    *reinterpret_cast<__nv_bfloat162*>(d+i)   = __floats2bfloat162_rn(v.x, v.y);
    *reinterpret_cast<__nv_bfloat162*>(d+i+2) = __floats2bfloat162_rn(v.z, v.w);
}

// pack w1|w2 INTERLEAVED
__global__ void pack12_k(const float* __restrict__ w1, const float* __restrict__ w2,
                         bf16* __restrict__ o){
    long i = ((long)blockIdx.x*blockDim.x + threadIdx.x)*4;
    if (i >= (long)NEXP*DM*DFF) return;
    long row = i >> 12;
    int  j   = (int)(i & 4095);
    float4 a = *reinterpret_cast<const float4*>(w1 + i);
    float4 b = *reinterpret_cast<const float4*>(w2 + i);
    bf16* d1 = o + row*(2*DFF) + 2*j;
    *reinterpret_cast<__nv_bfloat162*>(d1)   = __floats2bfloat162_rn(a.x, b.x);
    *reinterpret_cast<__nv_bfloat162*>(d1+2) = __floats2bfloat162_rn(a.y, b.y);
    *reinterpret_cast<__nv_bfloat162*>(d1+4) = __floats2bfloat162_rn(a.z, b.z);
    *reinterpret_cast<__nv_bfloat162*>(d1+6) = __floats2bfloat162_rn(a.w, b.w);
}

// pack [W_dt | W_B | W_C | 0] -> [2048][64] bf16
__global__ void packw_k(const float* __restrict__ Wdt, const float* __restrict__ WB,
                        const float* __restrict__ WC, bf16* __restrict__ o){
    int idx = blockIdx.x*256 + threadIdx.x;
    if (idx >= DI*64) return;
    int j = idx >> 6, n = idx & 63;
    float v = 0.f;
    if (n < 16) v = Wdt[j*16+n];
    else if (n < 32) v = WB[j*16+n-16];
    else if (n < 48) v = WC[j*16+n-32];
    o[idx] = __float2bfloat16(v);
}

// ---------------- RMSNorm -> bf16 ----------------
__global__ void rmsnorm_bf_k(const float* __restrict__ x, const float* __restrict__ w,
                             bf16* __restrict__ o){
    int row = blockIdx.x;
    const float* xr = x + (long)row*DM;
    __shared__ float red[256];
    float s = 0.f;
    for (int i = threadIdx.x; i < DM; i += 256){ float v = xr[i]; s += v*v; }
    red[threadIdx.x] = s; __syncthreads();
    for (int st = 128; st > 0; st >>= 1){
        if (threadIdx.x < st) red[threadIdx.x] += red[threadIdx.x+st];
        __syncthreads();
    }
    float r = rsqrtf(red[0]/(float)DM + 1e-6f);
    for (int i = threadIdx.x; i < DM; i += 256)
        o[(long)row*DM+i] = __float2bfloat16(w[i]*xr[i]*r);
}

// ---------------- MMA primitives ----------------
__device__ __forceinline__ void cpasync16(unsigned dst, const void* src, int ssz){
    asm volatile("cp.async.ca.shared.global [%0], [%1], 16, %2;"
        :: "r"(dst), "l"(src), "r"(ssz));
}
__device__ __forceinline__ void cp_commit(){ asm volatile("cp.async.commit_group;"); }
__device__ __forceinline__ void cp_wait0(){ asm volatile("cp.async.wait_group 0;"); }
__device__ __forceinline__ void cp_wait1(){ asm volatile("cp.async.wait_group 1;"); }
__device__ __forceinline__ void ldsm_x4(unsigned saddr, unsigned &o0, unsigned &o1,
                                        unsigned &o2, unsigned &o3){
    asm volatile("ldmatrix.sync.aligned.m8n8.x4.shared.b16 {%0,%1,%2,%3},[%4];"
        : "=r"(o0),"=r"(o1),"=r"(o2),"=r"(o3) : "r"(saddr));
}
__device__ __forceinline__ void ldsm_x4_t(unsigned saddr, unsigned &o0, unsigned &o1,
                                          unsigned &o2, unsigned &o3){
    asm volatile("ldmatrix.sync.aligned.m8n8.x4.trans.shared.b16 {%0,%1,%2,%3},[%4];"
        : "=r"(o0),"=r"(o1),"=r"(o2),"=r"(o3) : "r"(saddr));
}
__device__ __forceinline__ void mma16816(float* d, const unsigned* am, const unsigned* bm){
    asm volatile("mma.sync.aligned.m16n8k16.row.col.f32.bf16.bf16.f32 "
        "{%0,%1,%2,%3},{%4,%5,%6,%7},{%8,%9},{%0,%1,%2,%3};"
        : "+f"(d[0]),"+f"(d[1]),"+f"(d[2]),"+f"(d[3])
        : "r"(am[0]),"r"(am[1]),"r"(am[2]),"r"(am[3]), "r"(bm[0]),"r"(bm[1]));
}
__device__ __forceinline__ unsigned pkbf2(float x, float y){
    __nv_bfloat162 t = __floats2bfloat162_rn(x, y);
    return *reinterpret_cast<unsigned*>(&t);
}

// ---------------- 128x128 GEMM (small N / TRANSB) ----------------
template<int TRANSB>
__device__ __forceinline__ void stage_tiles(const bf16* Ab, const bf16* Bb,
    int bm, int bn, int N, int lda, int ldb, int k0, int tid,
    unsigned Adst, unsigned Bdst)
{
    #pragma unroll
    for (int c = tid; c < 512; c += 256){
        int r  = c >> 2;
        int ko = (c & 3) << 3;
        cpasync16(Adst + 2u*(unsigned)(r*40 + ko),
                  Ab + (long)(bm + r)*lda + k0 + ko, 16);
    }
    if (TRANSB == 0){
        #pragma unroll
        for (int c = tid; c < 512; c += 256){
            int r  = c >> 4;
            int no = (c & 15) << 3;
            const bf16* src = Bb + (long)(k0 + r)*ldb + bn + no;
            int ssz = 16;
            if (bn + no >= N){ src = Bb; ssz = 0; }
            cpasync16(Bdst + 2u*(unsigned)(r*136 + no), src, ssz);
        }
    } else {
        #pragma unroll
        for (int c = tid; c < 512; c += 256){
            int r  = c >> 2;
            int ko = (c & 3) << 3;
            cpasync16(Bdst + 2u*(unsigned)(r*40 + ko),
                      Bb + (long)(bn + r)*ldb + k0 + ko, 16);
        }
    }
}

// EPI: 0 none, 1 relu(acc+bias), 2 resid C=resx+bias[col]*acc (fp32)
template<int TRANSB, int EPI, int OUTBF>
__global__ void __launch_bounds__(256) bgemm_k(
    const bf16* __restrict__ Aptr, const bf16* __restrict__ Bptr, void* __restrict__ Cv,
    int M, int N, int K, int lda, int ldb, int ldc,
    long sA, long sB, long sC, const float* __restrict__ bias,
    const float* __restrict__ resx, const int* __restrict__ mcnt)
{
    __shared__ bf16 As[3*5120];
    __shared__ bf16 Bs[3*5120];
    const int bm = blockIdx.y * 128;
    int Meff = M;
    if (mcnt) Meff = mcnt[blockIdx.z];
    if (bm >= Meff) return;
    const bf16* Ab = Aptr + (long)blockIdx.z * sA;
    const bf16* Bb = Bptr + (long)blockIdx.z * sB;
    const int bn = blockIdx.x * 128;
    const int tid  = threadIdx.x;
    const int lane = tid & 31;
    const int warp = tid >> 5;
    const int wm = warp >> 1;
    const int wn = warp & 1;

    float acc[2][8][4];
    #pragma unroll
    for (int i = 0; i < 2; i++)
        #pragma unroll
        for (int j = 0; j < 8; j++)
            #pragma unroll
            for (int q = 0; q < 4; q++) acc[i][j][q] = 0.f;

    unsigned Afrag[2][4];
    unsigned Bfrag[8][2];

    const unsigned As_base = (unsigned)__cvta_generic_to_shared(As);
    const unsigned Bs_base = (unsigned)__cvta_generic_to_shared(Bs);

    const int rowA = wm*32 + (lane & 15);
    const int colA = (lane >> 4) * 8;
    unsigned aoff0 = As_base + 2u*(unsigned)( rowA       *40 + colA);
    unsigned aoff1 = As_base + 2u*(unsigned)((rowA + 16) *40 + colA);

    unsigned boff[4];
    #pragma unroll
    for (int p = 0; p < 4; p++){
        if (TRANSB == 0){
            int brow = lane & 15;
            int bcol = (lane >> 4) * 8;
            boff[p] = Bs_base + 2u*(unsigned)(brow*136 + wn*64 + p*16 + bcol);
        } else {
            int brow = (lane & 7) + (((lane >> 4) & 1) << 3);
            int bcol = ((lane >> 3) & 1) << 3;
            boff[p] = Bs_base + 2u*(unsigned)((wn*64 + p*16 + brow)*40 + bcol);
        }
    }

    const int nk = K >> 5;
    stage_tiles<TRANSB>(Ab, Bb, bm, bn, N, lda, ldb, 0, tid, As_base, Bs_base);
    cp_commit();
    if (nk > 1){
        stage_tiles<TRANSB>(Ab, Bb, bm, bn, N, lda, ldb, 32, tid,
                            As_base + 10240u, Bs_base + 10240u);
        cp_commit();
    }

    unsigned sb = 0u;
    for (int it = 0; it < nk; it++){
        if (it + 1 < nk) cp_wait1(); else cp_wait0();
        __syncthreads();
        if (it + 2 < nk){
            unsigned off = (unsigned)((it + 2) % 3) * 10240u;
            stage_tiles<TRANSB>(Ab, Bb, bm, bn, N, lda, ldb, (it+2) << 5, tid,
                                As_base + off, Bs_base + off);
            cp_commit();
        }
        #pragma unroll
        for (int ks = 0; ks < 32; ks += 16){
            ldsm_x4(aoff0 + sb + 2u*ks, Afrag[0][0], Afrag[0][1], Afrag[0][2], Afrag[0][3]);
            ldsm_x4(aoff1 + sb + 2u*ks, Afrag[1][0], Afrag[1][1], Afrag[1][2], Afrag[1][3]);
            #pragma unroll
            for (int p = 0; p < 4; p++){
                if (TRANSB == 0){
                    unsigned ba = boff[p] + sb + 2u*(unsigned)(ks*136);
                    ldsm_x4_t(ba, Bfrag[2*p][0], Bfrag[2*p][1],
                                  Bfrag[2*p+1][0], Bfrag[2*p+1][1]);
                } else {
                    unsigned ba = boff[p] + sb + 2u*(unsigned)ks;
                    ldsm_x4(ba, Bfrag[2*p][0], Bfrag[2*p][1],
                                Bfrag[2*p+1][0], Bfrag[2*p+1][1]);
                }
            }
            #pragma unroll
            for (int mt = 0; mt < 2; mt++)
                #pragma unroll
                for (int nt = 0; nt < 8; nt++)
                    mma16816(acc[mt][nt], Afrag[mt], Bfrag[nt]);
        }
        __syncthreads();
        sb += 10240u;
        if (sb == 30720u) sb = 0u;
    }

    #pragma unroll
    for (int mt = 0; mt < 2; mt++){
        int r0 = bm + wm*32 + mt*16 + (lane >> 2);
        #pragma unroll
        for (int nt = 0; nt < 8; nt++){
            int col = bn + wn*64 + nt*8 + ((lane & 3) << 1);
            if (col < N){
                float v0 = acc[mt][nt][0];
                float v1 = acc[mt][nt][1];
                float v2 = acc[mt][nt][2];
                float v3 = acc[mt][nt][3];
                if (EPI == 1){
                    float b0 = bias[col];
                    float b1 = bias[col+1];
                    v0 = fmaxf(v0+b0, 0.f); v1 = fmaxf(v1+b1, 0.f);
                    v2 = fmaxf(v2+b0, 0.f); v3 = fmaxf(v3+b1, 0.f);
                }
                if (EPI == 2){
                    float b0 = bias[col];
                    float b1 = bias[col+1];
                    v0 = fmaf(b0, v0, resx[(long)r0*ldc + col]);
                    v1 = fmaf(b1, v1, resx[(long)r0*ldc + col + 1]);
                    v2 = fmaf(b0, v2, resx[(long)(r0+8)*ldc + col]);
                    v3 = fmaf(b1, v3, resx[(long)(r0+8)*ldc + col + 1]);
                }
                if (OUTBF){
                    bf16* Cb = (bf16*)Cv + (long)blockIdx.z * sC;
                    *reinterpret_cast<__nv_bfloat162*>(&Cb[(long)r0*ldc + col]) =
                        __floats2bfloat162_rn(v0, v1);
                    *reinterpret_cast<__nv_bfloat162*>(&Cb[(long)(r0+8)*ldc + col]) =
                        __floats2bfloat162_rn(v2, v3);
                } else {
                    float* Cb = (float*)Cv + (long)blockIdx.z * sC;
                    *reinterpret_cast<float2*>(&Cb[(long)r0*ldc + col]) = make_float2(v0, v1);
                    *reinterpret_cast<float2*>(&Cb[(long)(r0+8)*ldc + col]) = make_float2(v2, v3);
                }
            }
        }
    }
}

// ---------------- 256x128 GEMM (TRANSB=0 only), 3-stage ----------------
// EPI: 0 none, 1 relu(acc+bias) fp32, 2 resid fp32, 3 siluGLU bf16
__device__ __forceinline__ void stage256(const bf16* Ab, const bf16* Bb,
    int bm, int bn, int N, int lda, int ldb, int k0, int tid,
    unsigned Adst, unsigned Bdst)
{
    #pragma unroll
    for (int c = tid; c < 1024; c += 256){
        int r  = c >> 2;
        int ko = (c & 3) << 3;
        cpasync16(Adst + 2u*(unsigned)(r*40 + ko),
                  Ab + (long)(bm + r)*lda + k0 + ko, 16);
    }
    #pragma unroll
    for (int c = tid; c < 512; c += 256){
        int r  = c >> 4;
        int no = (c & 15) << 3;
        const bf16* src = Bb + (long)(k0 + r)*ldb + bn + no;
        int ssz = 16;
        if (bn + no >= N){ src = Bb; ssz = 0; }
        cpasync16(Bdst + 2u*(unsigned)(r*136 + no), src, ssz);
    }
}

template<int EPI, int OUTBF>
__global__ void __launch_bounds__(256) bgemm256_k(
    const bf16* __restrict__ Aptr, const bf16* __restrict__ Bptr, void* __restrict__ Cv,
    int M, int N, int K, int lda, int ldb, int ldc,
    long sA, long sB, long sC, const float* __restrict__ bias,
    const float* __restrict__ resx, const int* __restrict__ mcnt)
{
    __shared__ bf16 As[3*10240];   // 3 x 256x40
    __shared__ bf16 Bs[3*4352];    // 3 x 32x136
    const int bm = blockIdx.y * 256;
    int Meff = M;
    if (mcnt) Meff = mcnt[blockIdx.z];
    if (bm >= Meff) return;
    const bf16* Ab = Aptr + (long)blockIdx.z * sA;
    const bf16* Bb = Bptr + (long)blockIdx.z * sB;
    const int bn = blockIdx.x * 128;
    const int tid  = threadIdx.x;
    const int lane = tid & 31;
    const int warp = tid >> 5;
    const int wm = warp >> 1;       // 0..3 -> 64-row strips
    const int wn = warp & 1;        // 0..1 -> 64-col strips

    float acc[4][8][4];
    #pragma unroll
    for (int i = 0; i < 4; i++)
        #pragma unroll
        for (int j = 0; j < 8; j++)
            #pragma unroll
            for (int q = 0; q < 4; q++) acc[i][j][q] = 0.f;

    unsigned Afrag[4][4];
    unsigned Bfrag[8][2];

    const unsigned As_base = (unsigned)__cvta_generic_to_shared(As);
    const unsigned Bs_base = (unsigned)__cvta_generic_to_shared(Bs);

    const int rowA = wm*64 + (lane & 15);
    const int colA = (lane >> 4) * 8;
    unsigned aoff[4];
    #pragma unroll
    for (int mt = 0; mt < 4; mt++)
        aoff[mt] = As_base + 2u*(unsigned)((rowA + mt*16)*40 + colA);

    unsigned boff[4];
    {
        int brow = lane & 15;
        int bcol = (lane >> 4) * 8;
        #pragma unroll
        for (int p = 0; p < 4; p++)
            boff[p] = Bs_base + 2u*(unsigned)(brow*136 + wn*64 + p*16 + bcol);
    }

    const int nk = K >> 5;
    stage256(Ab, Bb, bm, bn, N, lda, ldb, 0, tid, As_base, Bs_base);
    cp_commit();
    if (nk > 1){
        stage256(Ab, Bb, bm, bn, N, lda, ldb, 32, tid,
                 As_base + 20480u, Bs_base + 8704u);
        cp_commit();
    }

    unsigned sa = 0u, sbb = 0u;
    for (int it = 0; it < nk; it++){
        if (it + 1 < nk) cp_wait1(); else cp_wait0();
        __syncthreads();
        if (it + 2 < nk){
            unsigned st = (unsigned)((it + 2) % 3);
            stage256(Ab, Bb, bm, bn, N, lda, ldb, (it+2) << 5, tid,
                     As_base + st*20480u, Bs_base + st*8704u);
            cp_commit();
        }
        #pragma unroll
        for (int ks = 0; ks < 32; ks += 16){
            #pragma unroll
            for (int mt = 0; mt < 4; mt++)
                ldsm_x4(aoff[mt] + sa + 2u*ks,
                        Afrag[mt][0], Afrag[mt][1], Afrag[mt][2], Afrag[mt][3]);
            #pragma unroll
            for (int p = 0; p < 4; p++){
                unsigned ba = boff[p] + sbb + 2u*(unsigned)(ks*136);
                ldsm_x4_t(ba, Bfrag[2*p][0], Bfrag[2*p][1],
                              Bfrag[2*p+1][0], Bfrag[2*p+1][1]);
            }
            #pragma unroll
            for (int mt = 0; mt < 4; mt++)
                #pragma unroll
                for (int nt = 0; nt < 8; nt++)
                    mma16816(acc[mt][nt], Afrag[mt], Bfrag[nt]);
        }
        __syncthreads();
        sa += 20480u;  if (sa == 61440u) sa = 0u;
        sbb += 8704u;  if (sbb == 26112u) sbb = 0u;
    }

    #pragma unroll
    for (int mt = 0; mt < 4; mt++){
        int r0 = bm + wm*64 + mt*16 + (lane >> 2);
        #pragma unroll
        for (int nt = 0; nt < 8; nt++){
            int col = bn + wn*64 + nt*8 + ((lane & 3) << 1);
            if (col < N){
                float v0 = acc[mt][nt][0];
                float v1 = acc[mt][nt][1];
                float v2 = acc[mt][nt][2];
                float v3 = acc[mt][nt][3];
                if (EPI == 3){
                    bf16* Cb = (bf16*)Cv + (long)blockIdx.z * sC;
                    int jc = col >> 1;
                    Cb[(long)r0*(N>>1) + jc]     = __float2bfloat16(siluf(v0)*v1);
                    Cb[(long)(r0+8)*(N>>1) + jc] = __float2bfloat16(siluf(v2)*v3);
                    continue;
                }
                if (EPI == 1){
                    float b0 = bias[col];
                    float b1 = bias[col+1];
                    v0 = fmaxf(v0+b0, 0.f); v1 = fmaxf(v1+b1, 0.f);
                    v2 = fmaxf(v2+b0, 0.f); v3 = fmaxf(v3+b1, 0.f);
                }
                if (EPI == 2){
                    float b0 = bias[col];
                    float b1 = bias[col+1];
                    v0 = fmaf(b0, v0, resx[(long)r0*ldc + col]);
                    v1 = fmaf(b1, v1, resx[(long)r0*ldc + col + 1]);
                    v2 = fmaf(b0, v2, resx[(long)(r0+8)*ldc + col]);
                    v3 = fmaf(b1, v3, resx[(long)(r0+8)*ldc + col + 1]);
                }
                if (OUTBF){
                    bf16* Cb = (bf16*)Cv + (long)blockIdx.z * sC;
                    *reinterpret_cast<__nv_bfloat162*>(&Cb[(long)r0*ldc + col]) =
                        __floats2bfloat162_rn(v0, v1);
                    *reinterpret_cast<__nv_bfloat162*>(&Cb[(long)(r0+8)*ldc + col]) =
                        __floats2bfloat162_rn(v2, v3);
                } else {
                    float* Cb = (float*)Cv + (long)blockIdx.z * sC;
                    *reinterpret_cast<float2*>(&Cb[(long)r0*ldc + col]) = make_float2(v0, v1);
                    *reinterpret_cast<float2*>(&Cb[(long)(r0+8)*ldc + col]) = make_float2(v2, v3);
                }
            }
        }
    }
}

// ---------------- fused flash attention ----------------
#define FTILE (128*136)
#define FSMEM (5*FTILE*2)

__device__ __forceinline__ void fstage(const bf16* src, unsigned dst, int tid){
    for (int i = tid; i < 2048; i += 256){
        int r = i >> 4, c = (i & 15) << 3;
        cpasync16(dst + 2u*(unsigned)(r*136 + c), src + r*DH + c, 16);
    }
}

__global__ void __launch_bounds__(256, 1) flash_k(
    const bf16* __restrict__ q, const bf16* __restrict__ k, const bf16* __restrict__ v,
    const float* __restrict__ ascale, bf16* __restrict__ att)
{
    extern __shared__ bf16 fs[];
    const int qt = blockIdx.x, bh = blockIdx.y;
    const int bb = bh >> 3, hh = bh & 7;
    const int tid = threadIdx.x, lane = tid & 31, w = tid >> 5;
    const float a = ascale[hh];

    const bf16* qg = q + ((long)bh*LSEQ + qt*128)*DH;
    const bf16* kg = k + (long)bh*LSEQ*DH;
    const bf16* vg = v + (long)bh*LSEQ*DH;

    const unsigned Qb = (unsigned)__cvta_generic_to_shared(fs);
    const unsigned Kb = Qb + 2u*FTILE;
    const unsigned Vb = Qb + 6u*FTILE;
    const unsigned TILEB = 2u*FTILE;

    fstage(qg, Qb, tid);
    fstage(kg, Kb, tid);
    fstage(vg, Vb, tid);
    cp_commit();
    cp_wait0();
    __syncthreads();

    unsigned qf[8][4];
    {
        int rq = w*16 + (lane & 15);
        int cq = (lane >> 4) << 3;
        #pragma unroll
        for (int ks = 0; ks < 8; ks++)
            ldsm_x4(Qb + 2u*(unsigned)(rq*136 + ks*16 + cq),
                    qf[ks][0], qf[ks][1], qf[ks][2], qf[ks][3]);
    }

    const int brow = (lane & 7) + (((lane >> 4) & 1) << 3);
    const int bcol = ((lane >> 3) & 1) << 3;
    unsigned kadr[8], vadr[8];
    #pragma unroll
    for (int p = 0; p < 8; p++){
        kadr[p] = Kb + 2u*(unsigned)((p*16 + brow)*136 + bcol);
        vadr[p] = Vb + 2u*(unsigned)((lane & 15)*136 + p*16 + ((lane >> 4) << 3));
    }

    float oacc[16][4];
    #pragma unroll
    for (int nt = 0; nt < 16; nt++)
        #pragma unroll
        for (int qq = 0; qq < 4; qq++) oacc[nt][qq] = 0.f;
    float m0 = -1e30f, m1 = -1e30f, l0 = 0.f, l1 = 0.f;

    for (int kt = 0; kt < 16; kt++){
        if (kt > 0){ cp_wait0(); __syncthreads(); }
        if (kt + 1 < 16){
            unsigned off = ((kt + 1) & 1) ? TILEB : 0u;
            fstage(kg + (long)(kt+1)*128*DH, Kb + off, tid);
            fstage(vg + (long)(kt+1)*128*DH, Vb + off, tid);
            cp_commit();
        }
        const unsigned sb = (kt & 1) ? TILEB : 0u;

        float sacc[16][4];
        #pragma unroll
        for (int nt = 0; nt < 16; nt++)
            #pragma unroll
            for (int qq = 0; qq < 4; qq++) sacc[nt][qq] = 0.f;

        #pragma unroll
        for (int ks = 0; ks < 8; ks++){
            #pragma unroll
            for (int p = 0; p < 8; p++){
                unsigned bf0[2], bf1[2];
                ldsm_x4(kadr[p] + sb + 2u*(unsigned)(ks*16),
                        bf0[0], bf0[1], bf1[0], bf1[1]);
                mma16816(sacc[2*p],   qf[ks], bf0);
                mma16816(sacc[2*p+1], qf[ks], bf1);
            }
        }

        float ax0 = -1e30f, ax1 = -1e30f;
        #pragma unroll
        for (int nt = 0; nt < 16; nt++){
            sacc[nt][0] *= a; sacc[nt][1] *= a; sacc[nt][2] *= a; sacc[nt][3] *= a;
            ax0 = fmaxf(ax0, fmaxf(sacc[nt][0], sacc[nt][1]));
            ax1 = fmaxf(ax1, fmaxf(sacc[nt][2], sacc[nt][3]));
        }
        ax0 = fmaxf(ax0, __shfl_xor_sync(0xffffffffu, ax0, 1));
        ax0 = fmaxf(ax0, __shfl_xor_sync(0xffffffffu, ax0, 2));
        ax1 = fmaxf(ax1, __shfl_xor_sync(0xffffffffu, ax1, 1));
        ax1 = fmaxf(ax1, __shfl_xor_sync(0xffffffffu, ax1, 2));
        float mn0 = fmaxf(m0, ax0), mn1 = fmaxf(m1, ax1);
        float f0 = expf(m0 - mn0), f1 = expf(m1 - mn1);

        float rs0 = 0.f, rs1 = 0.f;
        #pragma unroll
        for (int nt = 0; nt < 16; nt++){
            sacc[nt][0] = expf(sacc[nt][0] - mn0);
            sacc[nt][1] = expf(sacc[nt][1] - mn0);
            sacc[nt][2] = expf(sacc[nt][2] - mn1);
            sacc[nt][3] = expf(sacc[nt][3] - mn1);
            rs0 += sacc[nt][0] + sacc[nt][1];
            rs1 += sacc[nt][2] + sacc[nt][3];
        }
        rs0 += __shfl_xor_sync(0xffffffffu, rs0, 1);
        rs0 += __shfl_xor_sync(0xffffffffu, rs0, 2);
        rs1 += __shfl_xor_sync(0xffffffffu, rs1, 1);
        rs1 += __shfl_xor_sync(0xffffffffu, rs1, 2);
        l0 = l0*f0 + rs0; l1 = l1*f1 + rs1;
        m0 = mn0; m1 = mn1;

        #pragma unroll
        for (int nt = 0; nt < 16; nt++){
            oacc[nt][0] *= f0; oacc[nt][1] *= f0;
            oacc[nt][2] *= f1; oacc[nt][3] *= f1;
        }

        unsigned pa[8][4];
        #pragma unroll
        for (int ksp = 0; ksp < 8; ksp++){
            pa[ksp][0] = pkbf2(sacc[2*ksp][0],   sacc[2*ksp][1]);
            pa[ksp][1] = pkbf2(sacc[2*ksp][2],   sacc[2*ksp][3]);
            pa[ksp][2] = pkbf2(sacc[2*ksp+1][0], sacc[2*ksp+1][1]);
            pa[ksp][3] = pkbf2(sacc[2*ksp+1][2], sacc[2*ksp+1][3]);
        }

        #pragma unroll
        for (int ksp = 0; ksp < 8; ksp++){
            #pragma unroll
            for (int p = 0; p < 8; p++){
                unsigned bf0[2], bf1[2];
                ldsm_x4_t(vadr[p] + sb + 2u*(unsigned)(ksp*16*136),
                          bf0[0], bf0[1], bf1[0], bf1[1]);
                mma16816(oacc[2*p],   pa[ksp], bf0);
                mma16816(oacc[2*p+1], pa[ksp], bf1);
            }
        }
    }

    float inv0 = 1.f / l0, inv1 = 1.f / l1;
    long row0 = (long)bb*LSEQ + qt*128 + w*16 + (lane >> 2);
    long row1 = row0 + 8;
    int  cbase = hh*DH + ((lane & 3) << 1);
    #pragma unroll
    for (int nt = 0; nt < 16; nt++){
        int col = cbase + nt*8;
        *reinterpret_cast<__nv_bfloat162*>(&att[row0*DM + col]) =
            __floats2bfloat162_rn(oacc[nt][0]*inv0, oacc[nt][1]*inv0);
        *reinterpret_cast<__nv_bfloat162*>(&att[row1*DM + col]) =
            __floats2bfloat162_rn(oacc[nt][2]*inv1, oacc[nt][3]*inv1);
    }
}

// ---------------- depthwise conv + bias + SiLU ----------------
__global__ void conv_k(const float* __restrict__ xz, const float* __restrict__ cw,
                       const float* __restrict__ cb, float* __restrict__ xc,
                       bf16* __restrict__ xcb){
    long idx = (long)blockIdx.x*blockDim.x + threadIdx.x;
    if (idx >= (long)NTOK*DI) return;
    int d = (int)(idx % DI);
    int row = (int)(idx / DI);
    int t = row % LSEQ, b = row / LSEQ;
    float s = cb[d];
    #pragma unroll
    for (int k = 0; k < 4; k++){
        int tt = t + k - 2;
        if (tt >= 0 && tt < LSEQ)
            s = fmaf(cw[d*4+k], xz[(long)(b*LSEQ+tt)*(2*DI) + d], s);
    }
    float v = siluf(s);
    xc[idx] = v;
    xcb[idx] = __float2bfloat16(v);
}

// ---------------- scan preprocessing ----------------
__global__ void scanprep_k(const float* __restrict__ dtBC, const float* __restrict__ bdt,
                           const float* __restrict__ A, float* __restrict__ sp){
    int idx = blockIdx.x*blockDim.x + threadIdx.x;
    if (idx >= NTOK*16) return;
    int n = idx & 15, row = idx >> 4;
    float dtp = dtBC[(long)row*64 + n] + bdt[n];
    float dt  = fmaxf(dtp, 0.f) + log1pf(expf(-fabsf(dtp)));
    sp[(long)row*48 + n]      = expf(dt * A[n]);
    sp[(long)row*48 + 16 + n] = dt * dtBC[(long)row*64 + 16 + n];
    sp[(long)row*48 + 32 + n] = dtBC[(long)row*64 + 32 + n];
}

// ---------------- selective scan ----------------
__global__ void scan2_k(const float* __restrict__ sp, const float* __restrict__ xc,
                        const float* __restrict__ xz, const float* __restrict__ Dp,
                        bf16* __restrict__ ymulb){
    int b = blockIdx.x >> 4;
    int d = (blockIdx.x & 15)*128 + threadIdx.x;
    __shared__ float s[64*48];
    float h[16];
    #pragma unroll
    for (int n = 0; n < 16; n++) h[n] = 0.f;
    const float dpv = Dp[d];
    for (int t0 = 0; t0 < LSEQ; t0 += 64){
        __syncthreads();
        const float* src = sp + ((long)b*LSEQ + t0)*48;
        for (int i = threadIdx.x; i < 64*48; i += 128) s[i] = src[i];
        __syncthreads();
        for (int tt = 0; tt < 64; tt++){
            long row = (long)b*LSEQ + t0 + tt;
            float xv = xc[row*DI + d];
            const float* e = s + tt*48;
            float y = 0.f;
            #pragma unroll
            for (int n = 0; n < 16; n++){
                h[n] = fmaf(e[n], h[n], e[16+n]*xv);
                y = fmaf(h[n], e[32+n], y);
            }
            float z = xz[row*(2*DI) + DI + d];
            ymulb[row*DI + d] = __float2bfloat16((y + dpv*xv) * siluf(z));
        }
    }
}

// ---------------- RoPE -> qb,kb,vb bf16 ----------------
__global__ void rope2_k(const float* __restrict__ qkv, bf16* __restrict__ qb,
                        bf16* __restrict__ kb, bf16* __restrict__ vb){
    int row = blockIdx.x;
    int t = row % LSEQ, b = row / LSEQ;
    __shared__ float q[DM], kk[DM];
    const float* base = qkv + (long)row*3*DM;
    for (int i = threadIdx.x; i < DM; i += 256){ q[i] = base[i]; kk[i] = base[DM+i]; }
    __syncthreads();
    const float sq = sqrtf((float)DH);
    const float lg = logf(10000.f) / 64.f;
    for (int idx = threadIdx.x; idx < DM; idx += 256){
        int h = idx / DH, i = idx % DH;
        int j = i & 63;
        float inv = expf(-(float)j * lg);
        float ang = (float)t * inv;
        float c = cosf(ang), s = sinf(ang);
        int off = h * DH;
        float rq, rk;
        if (i < 64){ rq = -q[off + 2*i + 1]; rk = -kk[off + 2*i + 1]; }
        else       { rq =  q[off + 2*(i-64)]; rk =  kk[off + 2*(i-64)]; }
        long o = ((long)(b*NH + h)*LSEQ + t)*DH + i;
        qb[o] = __float2bfloat16((q[idx]*c + rq*s) * sq);
        kb[o] = __float2bfloat16(kk[idx]*c + rk*s);
        vb[o] = __float2bfloat16(base[2*DM + idx]);
    }
}

// ---------------- gate stage 2 ----------------
__global__ void gate2_k(const float* __restrict__ g1, const float* __restrict__ Wg2,
                        float* __restrict__ gs, int* __restrict__ topi, float* __restrict__ topw){
    int row = blockIdx.x;
    int tid = threadIdx.x; // 64 threads
    __shared__ float red[64*4];
    float a[4] = {0.f,0.f,0.f,0.f};
    for (int j = tid; j < 512; j += 64){
        float v = g1[(long)row*512 + j];
        #pragma unroll
        for (int e = 0; e < 4; e++) a[e] = fmaf(v, Wg2[j*4+e], a[e]);
    }
    #pragma unroll
    for (int e = 0; e < 4; e++) red[e*64 + tid] = a[e];
    __syncthreads();
    for (int st = 32; st > 0; st >>= 1){
        if (tid < st){
            #pragma unroll
            for (int e = 0; e < 4; e++) red[e*64+tid] += red[e*64+tid+st];
        }
        __syncthreads();
    }
    if (tid == 0){
        float l[4]; for (int e = 0; e < 4; e++) l[e] = red[e*64];
        float m = fmaxf(fmaxf(l[0],l[1]), fmaxf(l[2],l[3]));
        float ex[4]; float s = 0.f;
        for (int e = 0; e < 4; e++){ ex[e] = expf(l[e]-m); s += ex[e]; }
        float gsv[4];
        for (int e = 0; e < 4; e++){ gsv[e] = ex[e]/s; gs[(long)row*4+e] = gsv[e]; }
        int i0 = 0;
        for (int e = 1; e < 4; e++) if (gsv[e] > gsv[i0]) i0 = e;
        int i1 = -1;
        for (int e = 0; e < 4; e++) if (e != i0 && (i1 < 0 || gsv[e] > gsv[i1])) i1 = e;
        float v0 = gsv[i0], v1 = gsv[i1];
        float mm = fmaxf(v0, v1);
        float w0 = expf(v0-mm), w1 = expf(v1-mm);
        float ws = w0 + w1;
        topi[row*2] = i0; topi[row*2+1] = i1;
        topw[row*2] = w0/ws; topw[row*2+1] = w1/ws;
    }
}

// ---------------- balance loss ----------------
__global__ void bal_k(const float* __restrict__ gs, float* __restrict__ out){
    int tid = threadIdx.x;
    __shared__ float red[256*4];
    float a[4] = {0.f,0.f,0.f,0.f};
    for (int r = tid; r < NTOK; r += 256){
        #pragma unroll
        for (int e = 0; e < 4; e++) a[e] += gs[(long)r*4+e];
    }
    #pragma unroll
    for (int e = 0; e < 4; e++) red[e*256+tid] = a[e];
    __syncthreads();
    for (int st = 128; st > 0; st >>= 1){
        if (tid < st){
            #pragma unroll
            for (int e = 0; e < 4; e++) red[e*256+tid] += red[e*256+tid+st];
        }
        __syncthreads();
    }
    if (tid == 0){
        float bal = 0.f;
        for (int e = 0; e < 4; e++){
            float gm = red[e*256] / (float)NTOK;
            bal += gm * logf(gm + 1e-8f);
        }
        out[0] = (float)NEXP * bal;
    }
}

// ---------------- MoE routing ----------------
__global__ void zero4_k(int* c){ if (threadIdx.x < NEXP) c[threadIdx.x] = 0; }

__global__ void assign_k(const int* __restrict__ topi, int* __restrict__ cnt,
                         int* __restrict__ slot){
    int idx = blockIdx.x*256 + threadIdx.x;
    if (idx >= NTOK*2) return;
    int e = topi[idx];
    int s = atomicAdd(&cnt[e], 1);
    slot[idx] = e*NTOK + s;
}

__global__ void gather_k(const bf16* __restrict__ xf, const int* __restrict__ slot,
                         bf16* __restrict__ xg){
    int idx = blockIdx.x;
    int tok = idx >> 1;
    int dst = slot[idx];
    const unsigned* src = reinterpret_cast<const unsigned*>(xf) + (long)tok*(DM/2);
    unsigned* d = reinterpret_cast<unsigned*>(xg) + (long)dst*(DM/2);
    for (int i = threadIdx.x; i < DM/2; i += 128) d[i] = src[i];
}

// ---------------- MoE combine + final residual ----------------
__global__ void combine2_k(const float* __restrict__ x2, const float* __restrict__ ls3,
                           const bf16* __restrict__ eo, const int* __restrict__ slot,
                           const float* __restrict__ topw, float* __restrict__ out){
    long idx = (long)blockIdx.x*blockDim.x + threadIdx.x;
    if (idx >= (long)NTOK*DM) return;
    int row = (int)(idx / DM), d = (int)(idx % DM);
    int s0 = slot[row*2], s1 = slot[row*2+1];
    float m = topw[row*2]   * __bfloat162float(eo[(long)s0*DM + d])
            + topw[row*2+1] * __bfloat162float(eo[(long)s1*DM + d]);
    out[idx] = fmaf(ls3[d], m, x2[idx]);
}

// ============================== host ==============================
#define SYMPF(p, s) do { void* _t; cudaGetSymbolAddress(&_t, s); p = (float*)_t; } while(0)
#define SYMPB(p, s) do { void* _t; cudaGetSymbolAddress(&_t, s); p = (bf16*)_t; } while(0)
#define SYMPI(p, s) do { void* _t; cudaGetSymbolAddress(&_t, s); p = (int*)_t; } while(0)

extern "C" void kernel_launch(void* const* d_in, const int* in_sizes, int n_in,
                              void* d_out, int out_size){
    const float* x      = (const float*)d_in[0];
    const float* rms1_w = (const float*)d_in[1];
    const float* rms2_w = (const float*)d_in[2];
    const float* rms3_w = (const float*)d_in[3];
    const float* ls1    = (const float*)d_in[4];
    const float* ls2    = (const float*)d_in[5];
    const float* ls3    = (const float*)d_in[6];
    const float* W_in   = (const float*)d_in[7];
    const float* conv_w = (const float*)d_in[8];
    const float* conv_b = (const float*)d_in[9];
    const float* W_B    = (const float*)d_in[10];
    const float* W_C    = (const float*)d_in[11];
    const float* W_dt   = (const float*)d_in[12];
    const float* b_dt   = (const float*)d_in[13];
    const float* W_out_m= (const float*)d_in[14];
    const float* Avec   = (const float*)d_in[15];
    const float* Dp     = (const float*)d_in[16];
    const float* W_qkv  = (const float*)d_in[17];
    const float* W_o    = (const float*)d_in[18];
    const float* ascale = (const float*)d_in[19];
    const float* Wg1    = (const float*)d_in[20];
    const float* bg1    = (const float*)d_in[21];
    const float* Wg2    = (const float*)d_in[22];
    const float* w1     = (const float*)d_in[23];
    const float* w2     = (const float*)d_in[24];
    const float* w3     = (const float*)d_in[25];
    float* out = (float*)d_out;

    float *p_xz, *p_xc, *p_dtBC, *p_scanp, *p_x1, *p_qkv, *p_x2, *p_g1, *p_gs, *p_topw;
    int *p_topi, *p_cnt, *p_slot;
    bf16 *b_rms1, *b_xc, *b_ymul, *b_rms2, *b_q, *b_k, *b_v, *b_att, *b_xf,
         *b_xg, *b_h, *b_eo;
    bf16 *b_Win, *b_Wout, *b_Wqkv, *b_Wo, *b_Wg1, *b_w12, *b_w3, *b_Wcat;

    SYMPF(p_xz, g_xz); SYMPF(p_xc, g_xc); SYMPF(p_dtBC, g_dtBC); SYMPF(p_scanp, g_scanp);
    SYMPF(p_x1, g_x1); SYMPF(p_qkv, g_qkv);
    SYMPF(p_x2, g_x2); SYMPF(p_g1, g_g1); SYMPF(p_gs, g_gs); SYMPF(p_topw, g_topw);
    SYMPI(p_topi, g_topi); SYMPI(p_cnt, g_cnt); SYMPI(p_slot, g_slot);
    SYMPB(b_rms1, g_rms1b); SYMPB(b_xc, g_xcb); SYMPB(b_ymul, g_ymulb); SYMPB(b_rms2, g_rms2b);
    SYMPB(b_q, g_qb); SYMPB(b_k, g_kb); SYMPB(b_v, g_vb);
    SYMPB(b_att, g_attb); SYMPB(b_xf, g_xfb); SYMPB(b_xg, g_xgb);
    SYMPB(b_h, g_hb); SYMPB(b_eo, g_eob);
    SYMPB(b_Win, g_Winb); SYMPB(b_Wout, g_Woutb); SYMPB(b_Wqkv, g_Wqkvb); SYMPB(b_Wo, g_Wob);
    SYMPB(b_Wg1, g_Wg1b); SYMPB(b_w12, g_w12b); SYMPB(b_w3, g_w3b); SYMPB(b_Wcat, g_Wcatb);

    // ---- weight conversions ----
    #define CONV(src, dst, n) f2bf_k<<<(int)(((n)/4 + 255)/256), 256>>>(src, dst, (long)(n))
    CONV(W_in,   b_Win,  (long)DM*2*DI);
    CONV(W_out_m,b_Wout, (long)DI*DM);
    CONV(W_qkv,  b_Wqkv, (long)DM*3*DM);
    CONV(W_o,    b_Wo,   (long)DM*DM);
    CONV(Wg1,    b_Wg1,  (long)DM*512);
    CONV(w3,     b_w3,   (long)NEXP*DFF*DM);
    pack12_k<<<(int)(((long)NEXP*DM*DFF/4 + 255)/256), 256>>>(w1, w2, b_w12);
    packw_k<<<(DI*64+255)/256, 256>>>(W_dt, W_B, W_C, b_Wcat);

    // ---- 1. Mamba ----
    rmsnorm_bf_k<<<NTOK, 256>>>(x, rms1_w, b_rms1);
    {   dim3 g(2*DI/128, NTOK/256, 1);
        bgemm256_k<0,0><<<g, 256>>>(b_rms1, b_Win, p_xz, NTOK, 2*DI, DM, DM, 2*DI, 2*DI,
                                    0,0,0, nullptr, nullptr, nullptr); }
    conv_k<<<(int)(((long)NTOK*DI+255)/256), 256>>>(p_xz, conv_w, conv_b, p_xc, b_xc);
    {   dim3 g(1, NTOK/128, 1);
        bgemm_k<0,0,0><<<g, 256>>>(b_xc, b_Wcat, p_dtBC, NTOK, 64, DI, DI, 64, 64,
                                   0,0,0, nullptr, nullptr, nullptr); }
    scanprep_k<<<(NTOK*16+255)/256, 256>>>(p_dtBC, b_dt, Avec, p_scanp);
    scan2_k<<<32, 128>>>(p_scanp, p_xc, p_xz, Dp, b_ymul);
    {   dim3 g(DM/128, NTOK/256, 1);   // x1 = x + ls1 * (ymul @ Wout)
        bgemm256_k<2,0><<<g, 256>>>(b_ymul, b_Wout, p_x1, NTOK, DM, DI, DI, DM, DM,
                                    0,0,0, ls1, x, nullptr); }

    // ---- 2. Attention ----
    rmsnorm_bf_k<<<NTOK, 256>>>(p_x1, rms2_w, b_rms2);
    {   dim3 g(3*DM/128, NTOK/256, 1);
        bgemm256_k<0,0><<<g, 256>>>(b_rms2, b_Wqkv, p_qkv, NTOK, 3*DM, DM, DM, 3*DM, 3*DM,
                                    0,0,0, nullptr, nullptr, nullptr); }
    rope2_k<<<NTOK, 256>>>(p_qkv, b_q, b_k, b_v);
    {   cudaFuncSetAttribute(flash_k, cudaFuncAttributeMaxDynamicSharedMemorySize, FSMEM);
        dim3 g(LSEQ/128, BB*NH, 1);
        flash_k<<<g, 256, FSMEM>>>(b_q, b_k, b_v, ascale, b_att); }
    {   dim3 g(DM/128, NTOK/256, 1);   // x2 = x1 + ls2 * (att @ Wo)
        bgemm256_k<2,0><<<g, 256>>>(b_att, b_Wo, p_x2, NTOK, DM, DM, DM, DM, DM,
                                    0,0,0, ls2, p_x1, nullptr); }

    // ---- 3. MoE (top-2 sparse) ----
    rmsnorm_bf_k<<<NTOK, 256>>>(p_x2, rms3_w, b_xf);
    {   dim3 g(512/128, NTOK/256, 1);
        bgemm256_k<1,0><<<g, 256>>>(b_xf, b_Wg1, p_g1, NTOK, 512, DM, DM, 512, 512,
                                    0,0,0, bg1, nullptr, nullptr); }
    gate2_k<<<NTOK, 64>>>(p_g1, Wg2, p_gs, p_topi, p_topw);
    if (out_size > NTOK*DM)
        bal_k<<<1, 256>>>(p_gs, out + (long)NTOK*DM);
    zero4_k<<<1, 32>>>(p_cnt);
    assign_k<<<(NTOK*2+255)/256, 256>>>(p_topi, p_cnt, p_slot);
    gather_k<<<NTOK*2, 128>>>(b_xf, p_slot, b_xg);
    {   // batched over experts: w12 GEMM + siluGLU epilogue -> h
        dim3 g12(2*DFF/128, NTOK/256, NEXP);
        bgemm256_k<3,1><<<g12, 256>>>(b_xg, b_w12, b_h,
                                      NTOK, 2*DFF, DM, DM, 2*DFF, 2*DFF,
                                      (long)NTOK*DM, (long)DM*2*DFF, (long)NTOK*DFF,
                                      nullptr, nullptr, p_cnt);
    }
    {   // batched w3 GEMM -> eo (bf16)
        dim3 g3(DM/128, NTOK/256, NEXP);
        bgemm256_k<0,1><<<g3, 256>>>(b_h, b_w3, b_eo,
                                     NTOK, DM, DFF, DFF, DM, DM,
                                     (long)NTOK*DFF, (long)DFF*DM, (long)NTOK*DM,
                                     nullptr, nullptr, p_cnt);
    }
    combine2_k<<<(int)(((long)NTOK*DM+255)/256), 256>>>(p_x2, ls3, b_eo, p_slot, p_topw, out);
}

// round 9
// speedup vs baseline: 10.3804x; 2.2055x over previous
#include <cuda_runtime.h>
#include <cuda_bf16.h>
#include <math.h>

#define BB   2
#define LSEQ 2048
#define DM   1024
#define DI   2048
#define NH   8
#define DH   128
#define NEXP 4
#define DFF  4096
#define NTOK (BB*LSEQ)   // 4096
#define NCH  16
#define CLEN 128         // LSEQ/NCH

typedef __nv_bfloat16 bf16;

// ---------------- static scratch ----------------
__device__ float g_xz[NTOK*2*DI];
__device__ float g_xc[NTOK*DI];
__device__ float g_dtBC[NTOK*64];
__device__ float g_scanp[NTOK*48];
__device__ float g_x1[NTOK*DM];
__device__ float g_qkv[NTOK*3*DM];
__device__ float g_x2[NTOK*DM];
__device__ float g_g1[NTOK*512];
__device__ float g_gs[NTOK*NEXP];
__device__ int   g_topi[NTOK*2];
__device__ float g_topw[NTOK*2];
__device__ int   g_cnt[NEXP];
__device__ int   g_slot[NTOK*2];
__device__ float g_hend[BB*NCH*DI*16];   // 4 MB
__device__ float g_h0[BB*NCH*DI*16];     // 4 MB
__device__ float g_P[BB*NCH*16];

// bf16 activations
__device__ bf16 g_rms1b[NTOK*DM];
__device__ bf16 g_xcb[NTOK*DI];
__device__ bf16 g_ymulb[NTOK*DI];
__device__ bf16 g_rms2b[NTOK*DM];
__device__ bf16 g_qb[NTOK*DM];
__device__ bf16 g_kb[NTOK*DM];
__device__ bf16 g_vb[NTOK*DM];
__device__ bf16 g_attb[NTOK*DM];
__device__ bf16 g_xfb[NTOK*DM];
__device__ bf16 g_xgb[NEXP*NTOK*DM];
__device__ bf16 g_hb[(long)NEXP*NTOK*DFF];
__device__ bf16 g_eob[NEXP*NTOK*DM];

// bf16 weights
__device__ bf16 g_Winb[DM*2*DI];
__device__ bf16 g_Woutb[DI*DM];
__device__ bf16 g_Wqkvb[DM*3*DM];
__device__ bf16 g_Wob[DM*DM];
__device__ bf16 g_Wg1b[DM*512];
__device__ bf16 g_w12b[(long)NEXP*DM*2*DFF];
__device__ bf16 g_w3b[(long)NEXP*DFF*DM];
__device__ bf16 g_Wcatb[DI*64];

__device__ __forceinline__ float siluf(float x){ return x / (1.f + expf(-x)); }

// ---------------- fp32 -> bf16 convert ----------------
__global__ void f2bf_k(const float* __restrict__ s, bf16* __restrict__ d, long n){
    long i = ((long)blockIdx.x*blockDim.x + threadIdx.x)*4;
    if (i >= n) return;
    float4 v = *reinterpret_cast<const float4*>(s+i);
    *reinterpret_cast<__nv_bfloat162*>(d+i)   = __floats2bfloat162_rn(v.x, v.y);
    *reinterpret_cast<__nv_bfloat162*>(d+i+2) = __floats2bfloat162_rn(v.z, v.w);
}

// pack w1|w2 INTERLEAVED
__global__ void pack12_k(const float* __restrict__ w1, const float* __restrict__ w2,
                         bf16* __restrict__ o){
    long i = ((long)blockIdx.x*blockDim.x + threadIdx.x)*4;
    if (i >= (long)NEXP*DM*DFF) return;
    long row = i >> 12;
    int  j   = (int)(i & 4095);
    float4 a = *reinterpret_cast<const float4*>(w1 + i);
    float4 b = *reinterpret_cast<const float4*>(w2 + i);
    bf16* d1 = o + row*(2*DFF) + 2*j;
    *reinterpret_cast<__nv_bfloat162*>(d1)   = __floats2bfloat162_rn(a.x, b.x);
    *reinterpret_cast<__nv_bfloat162*>(d1+2) = __floats2bfloat162_rn(a.y, b.y);
    *reinterpret_cast<__nv_bfloat162*>(d1+4) = __floats2bfloat162_rn(a.z, b.z);
    *reinterpret_cast<__nv_bfloat162*>(d1+6) = __floats2bfloat162_rn(a.w, b.w);
}

// pack [W_dt | W_B | W_C | 0] -> [2048][64] bf16
__global__ void packw_k(const float* __restrict__ Wdt, const float* __restrict__ WB,
                        const float* __restrict__ WC, bf16* __restrict__ o){
    int idx = blockIdx.x*256 + threadIdx.x;
    if (idx >= DI*64) return;
    int j = idx >> 6, n = idx & 63;
    float v = 0.f;
    if (n < 16) v = Wdt[j*16+n];
    else if (n < 32) v = WB[j*16+n-16];
    else if (n < 48) v = WC[j*16+n-32];
    o[idx] = __float2bfloat16(v);
}

// ---------------- RMSNorm -> bf16 ----------------
__global__ void rmsnorm_bf_k(const float* __restrict__ x, const float* __restrict__ w,
                             bf16* __restrict__ o){
    int row = blockIdx.x;
    const float* xr = x + (long)row*DM;
    __shared__ float red[256];
    float s = 0.f;
    for (int i = threadIdx.x; i < DM; i += 256){ float v = xr[i]; s += v*v; }
    red[threadIdx.x] = s; __syncthreads();
    for (int st = 128; st > 0; st >>= 1){
        if (threadIdx.x < st) red[threadIdx.x] += red[threadIdx.x+st];
        __syncthreads();
    }
    float r = rsqrtf(red[0]/(float)DM + 1e-6f);
    for (int i = threadIdx.x; i < DM; i += 256)
        o[(long)row*DM+i] = __float2bfloat16(w[i]*xr[i]*r);
}

// ---------------- MMA primitives ----------------
__device__ __forceinline__ void cpasync16(unsigned dst, const void* src, int ssz){
    asm volatile("cp.async.ca.shared.global [%0], [%1], 16, %2;"
        :: "r"(dst), "l"(src), "r"(ssz));
}
__device__ __forceinline__ void cp_commit(){ asm volatile("cp.async.commit_group;"); }
__device__ __forceinline__ void cp_wait0(){ asm volatile("cp.async.wait_group 0;"); }
__device__ __forceinline__ void cp_wait1(){ asm volatile("cp.async.wait_group 1;"); }
__device__ __forceinline__ void ldsm_x4(unsigned saddr, unsigned &o0, unsigned &o1,
                                        unsigned &o2, unsigned &o3){
    asm volatile("ldmatrix.sync.aligned.m8n8.x4.shared.b16 {%0,%1,%2,%3},[%4];"
        : "=r"(o0),"=r"(o1),"=r"(o2),"=r"(o3) : "r"(saddr));
}
__device__ __forceinline__ void ldsm_x4_t(unsigned saddr, unsigned &o0, unsigned &o1,
                                          unsigned &o2, unsigned &o3){
    asm volatile("ldmatrix.sync.aligned.m8n8.x4.trans.shared.b16 {%0,%1,%2,%3},[%4];"
        : "=r"(o0),"=r"(o1),"=r"(o2),"=r"(o3) : "r"(saddr));
}
__device__ __forceinline__ void mma16816(float* d, const unsigned* am, const unsigned* bm){
    asm volatile("mma.sync.aligned.m16n8k16.row.col.f32.bf16.bf16.f32 "
        "{%0,%1,%2,%3},{%4,%5,%6,%7},{%8,%9},{%0,%1,%2,%3};"
        : "+f"(d[0]),"+f"(d[1]),"+f"(d[2]),"+f"(d[3])
        : "r"(am[0]),"r"(am[1]),"r"(am[2]),"r"(am[3]), "r"(bm[0]),"r"(bm[1]));
}
__device__ __forceinline__ unsigned pkbf2(float x, float y){
    __nv_bfloat162 t = __floats2bfloat162_rn(x, y);
    return *reinterpret_cast<unsigned*>(&t);
}

// ---------------- 128x128 GEMM ----------------
template<int TRANSB>
__device__ __forceinline__ void stage_tiles(const bf16* Ab, const bf16* Bb,
    int bm, int bn, int N, int lda, int ldb, int k0, int tid,
    unsigned Adst, unsigned Bdst)
{
    #pragma unroll
    for (int c = tid; c < 512; c += 256){
        int r  = c >> 2;
        int ko = (c & 3) << 3;
        cpasync16(Adst + 2u*(unsigned)(r*40 + ko),
                  Ab + (long)(bm + r)*lda + k0 + ko, 16);
    }
    if (TRANSB == 0){
        #pragma unroll
        for (int c = tid; c < 512; c += 256){
            int r  = c >> 4;
            int no = (c & 15) << 3;
            const bf16* src = Bb + (long)(k0 + r)*ldb + bn + no;
            int ssz = 16;
            if (bn + no >= N){ src = Bb; ssz = 0; }
            cpasync16(Bdst + 2u*(unsigned)(r*136 + no), src, ssz);
        }
    } else {
        #pragma unroll
        for (int c = tid; c < 512; c += 256){
            int r  = c >> 2;
            int ko = (c & 3) << 3;
            cpasync16(Bdst + 2u*(unsigned)(r*40 + ko),
                      Bb + (long)(bn + r)*ldb + k0 + ko, 16);
        }
    }
}

template<int TRANSB, int EPI, int OUTBF>
__global__ void __launch_bounds__(256) bgemm_k(
    const bf16* __restrict__ Aptr, const bf16* __restrict__ Bptr, void* __restrict__ Cv,
    int M, int N, int K, int lda, int ldb, int ldc,
    long sA, long sB, long sC, const float* __restrict__ bias,
    const float* __restrict__ resx, const int* __restrict__ mcnt)
{
    __shared__ bf16 As[3*5120];
    __shared__ bf16 Bs[3*5120];
    const int bm = blockIdx.y * 128;
    int Meff = M;
    if (mcnt) Meff = mcnt[blockIdx.z];
    if (bm >= Meff) return;
    const bf16* Ab = Aptr + (long)blockIdx.z * sA;
    const bf16* Bb = Bptr + (long)blockIdx.z * sB;
    const int bn = blockIdx.x * 128;
    const int tid  = threadIdx.x;
    const int lane = tid & 31;
    const int warp = tid >> 5;
    const int wm = warp >> 1;
    const int wn = warp & 1;

    float acc[2][8][4];
    #pragma unroll
    for (int i = 0; i < 2; i++)
        #pragma unroll
        for (int j = 0; j < 8; j++)
            #pragma unroll
            for (int q = 0; q < 4; q++) acc[i][j][q] = 0.f;

    unsigned Afrag[2][4];
    unsigned Bfrag[8][2];

    const unsigned As_base = (unsigned)__cvta_generic_to_shared(As);
    const unsigned Bs_base = (unsigned)__cvta_generic_to_shared(Bs);

    const int rowA = wm*32 + (lane & 15);
    const int colA = (lane >> 4) * 8;
    unsigned aoff0 = As_base + 2u*(unsigned)( rowA       *40 + colA);
    unsigned aoff1 = As_base + 2u*(unsigned)((rowA + 16) *40 + colA);

    unsigned boff[4];
    #pragma unroll
    for (int p = 0; p < 4; p++){
        if (TRANSB == 0){
            int brow = lane & 15;
            int bcol = (lane >> 4) * 8;
            boff[p] = Bs_base + 2u*(unsigned)(brow*136 + wn*64 + p*16 + bcol);
        } else {
            int brow = (lane & 7) + (((lane >> 4) & 1) << 3);
            int bcol = ((lane >> 3) & 1) << 3;
            boff[p] = Bs_base + 2u*(unsigned)((wn*64 + p*16 + brow)*40 + bcol);
        }
    }

    const int nk = K >> 5;
    stage_tiles<TRANSB>(Ab, Bb, bm, bn, N, lda, ldb, 0, tid, As_base, Bs_base);
    cp_commit();
    if (nk > 1){
        stage_tiles<TRANSB>(Ab, Bb, bm, bn, N, lda, ldb, 32, tid,
                            As_base + 10240u, Bs_base + 10240u);
        cp_commit();
    }

    unsigned sb = 0u;
    for (int it = 0; it < nk; it++){
        if (it + 1 < nk) cp_wait1(); else cp_wait0();
        __syncthreads();
        if (it + 2 < nk){
            unsigned off = (unsigned)((it + 2) % 3) * 10240u;
            stage_tiles<TRANSB>(Ab, Bb, bm, bn, N, lda, ldb, (it+2) << 5, tid,
                                As_base + off, Bs_base + off);
            cp_commit();
        }
        #pragma unroll
        for (int ks = 0; ks < 32; ks += 16){
            ldsm_x4(aoff0 + sb + 2u*ks, Afrag[0][0], Afrag[0][1], Afrag[0][2], Afrag[0][3]);
            ldsm_x4(aoff1 + sb + 2u*ks, Afrag[1][0], Afrag[1][1], Afrag[1][2], Afrag[1][3]);
            #pragma unroll
            for (int p = 0; p < 4; p++){
                if (TRANSB == 0){
                    unsigned ba = boff[p] + sb + 2u*(unsigned)(ks*136);
                    ldsm_x4_t(ba, Bfrag[2*p][0], Bfrag[2*p][1],
                                  Bfrag[2*p+1][0], Bfrag[2*p+1][1]);
                } else {
                    unsigned ba = boff[p] + sb + 2u*(unsigned)ks;
                    ldsm_x4(ba, Bfrag[2*p][0], Bfrag[2*p][1],
                                Bfrag[2*p+1][0], Bfrag[2*p+1][1]);
                }
            }
            #pragma unroll
            for (int mt = 0; mt < 2; mt++)
                #pragma unroll
                for (int nt = 0; nt < 8; nt++)
                    mma16816(acc[mt][nt], Afrag[mt], Bfrag[nt]);
        }
        __syncthreads();
        sb += 10240u;
        if (sb == 30720u) sb = 0u;
    }

    #pragma unroll
    for (int mt = 0; mt < 2; mt++){
        int r0 = bm + wm*32 + mt*16 + (lane >> 2);
        #pragma unroll
        for (int nt = 0; nt < 8; nt++){
            int col = bn + wn*64 + nt*8 + ((lane & 3) << 1);
            if (col < N){
                float v0 = acc[mt][nt][0];
                float v1 = acc[mt][nt][1];
                float v2 = acc[mt][nt][2];
                float v3 = acc[mt][nt][3];
                if (EPI == 1){
                    float b0 = bias[col];
                    float b1 = bias[col+1];
                    v0 = fmaxf(v0+b0, 0.f); v1 = fmaxf(v1+b1, 0.f);
                    v2 = fmaxf(v2+b0, 0.f); v3 = fmaxf(v3+b1, 0.f);
                }
                if (EPI == 2){
                    float b0 = bias[col];
                    float b1 = bias[col+1];
                    v0 = fmaf(b0, v0, resx[(long)r0*ldc + col]);
                    v1 = fmaf(b1, v1, resx[(long)r0*ldc + col + 1]);
                    v2 = fmaf(b0, v2, resx[(long)(r0+8)*ldc + col]);
                    v3 = fmaf(b1, v3, resx[(long)(r0+8)*ldc + col + 1]);
                }
                if (OUTBF){
                    bf16* Cb = (bf16*)Cv + (long)blockIdx.z * sC;
                    *reinterpret_cast<__nv_bfloat162*>(&Cb[(long)r0*ldc + col]) =
                        __floats2bfloat162_rn(v0, v1);
                    *reinterpret_cast<__nv_bfloat162*>(&Cb[(long)(r0+8)*ldc + col]) =
                        __floats2bfloat162_rn(v2, v3);
                } else {
                    float* Cb = (float*)Cv + (long)blockIdx.z * sC;
                    *reinterpret_cast<float2*>(&Cb[(long)r0*ldc + col]) = make_float2(v0, v1);
                    *reinterpret_cast<float2*>(&Cb[(long)(r0+8)*ldc + col]) = make_float2(v2, v3);
                }
            }
        }
    }
}

// ---------------- 256x128 GEMM (TRANSB=0 only) ----------------
__device__ __forceinline__ void stage256(const bf16* Ab, const bf16* Bb,
    int bm, int bn, int N, int lda, int ldb, int k0, int tid,
    unsigned Adst, unsigned Bdst)
{
    #pragma unroll
    for (int c = tid; c < 1024; c += 256){
        int r  = c >> 2;
        int ko = (c & 3) << 3;
        cpasync16(Adst + 2u*(unsigned)(r*40 + ko),
                  Ab + (long)(bm + r)*lda + k0 + ko, 16);
    }
    #pragma unroll
    for (int c = tid; c < 512; c += 256){
        int r  = c >> 4;
        int no = (c & 15) << 3;
        const bf16* src = Bb + (long)(k0 + r)*ldb + bn + no;
        int ssz = 16;
        if (bn + no >= N){ src = Bb; ssz = 0; }
        cpasync16(Bdst + 2u*(unsigned)(r*136 + no), src, ssz);
    }
}

template<int EPI, int OUTBF>
__global__ void __launch_bounds__(256) bgemm256_k(
    const bf16* __restrict__ Aptr, const bf16* __restrict__ Bptr, void* __restrict__ Cv,
    int M, int N, int K, int lda, int ldb, int ldc,
    long sA, long sB, long sC, const float* __restrict__ bias,
    const float* __restrict__ resx, const int* __restrict__ mcnt)
{
    __shared__ bf16 As[3*10240];
    __shared__ bf16 Bs[3*4352];
    const int bm = blockIdx.y * 256;
    int Meff = M;
    if (mcnt) Meff = mcnt[blockIdx.z];
    if (bm >= Meff) return;
    const bf16* Ab = Aptr + (long)blockIdx.z * sA;
    const bf16* Bb = Bptr + (long)blockIdx.z * sB;
    const int bn = blockIdx.x * 128;
    const int tid  = threadIdx.x;
    const int lane = tid & 31;
    const int warp = tid >> 5;
    const int wm = warp >> 1;
    const int wn = warp & 1;

    float acc[4][8][4];
    #pragma unroll
    for (int i = 0; i < 4; i++)
        #pragma unroll
        for (int j = 0; j < 8; j++)
            #pragma unroll
            for (int q = 0; q < 4; q++) acc[i][j][q] = 0.f;

    unsigned Afrag[4][4];
    unsigned Bfrag[8][2];

    const unsigned As_base = (unsigned)__cvta_generic_to_shared(As);
    const unsigned Bs_base = (unsigned)__cvta_generic_to_shared(Bs);

    const int rowA = wm*64 + (lane & 15);
    const int colA = (lane >> 4) * 8;
    unsigned aoff[4];
    #pragma unroll
    for (int mt = 0; mt < 4; mt++)
        aoff[mt] = As_base + 2u*(unsigned)((rowA + mt*16)*40 + colA);

    unsigned boff[4];
    {
        int brow = lane & 15;
        int bcol = (lane >> 4) * 8;
        #pragma unroll
        for (int p = 0; p < 4; p++)
            boff[p] = Bs_base + 2u*(unsigned)(brow*136 + wn*64 + p*16 + bcol);
    }

    const int nk = K >> 5;
    stage256(Ab, Bb, bm, bn, N, lda, ldb, 0, tid, As_base, Bs_base);
    cp_commit();
    if (nk > 1){
        stage256(Ab, Bb, bm, bn, N, lda, ldb, 32, tid,
                 As_base + 20480u, Bs_base + 8704u);
        cp_commit();
    }

    unsigned sa = 0u, sbb = 0u;
    for (int it = 0; it < nk; it++){
        if (it + 1 < nk) cp_wait1(); else cp_wait0();
        __syncthreads();
        if (it + 2 < nk){
            unsigned st = (unsigned)((it + 2) % 3);
            stage256(Ab, Bb, bm, bn, N, lda, ldb, (it+2) << 5, tid,
                     As_base + st*20480u, Bs_base + st*8704u);
            cp_commit();
        }
        #pragma unroll
        for (int ks = 0; ks < 32; ks += 16){
            #pragma unroll
            for (int mt = 0; mt < 4; mt++)
                ldsm_x4(aoff[mt] + sa + 2u*ks,
                        Afrag[mt][0], Afrag[mt][1], Afrag[mt][2], Afrag[mt][3]);
            #pragma unroll
            for (int p = 0; p < 4; p++){
                unsigned ba = boff[p] + sbb + 2u*(unsigned)(ks*136);
                ldsm_x4_t(ba, Bfrag[2*p][0], Bfrag[2*p][1],
                              Bfrag[2*p+1][0], Bfrag[2*p+1][1]);
            }
            #pragma unroll
            for (int mt = 0; mt < 4; mt++)
                #pragma unroll
                for (int nt = 0; nt < 8; nt++)
                    mma16816(acc[mt][nt], Afrag[mt], Bfrag[nt]);
        }
        __syncthreads();
        sa += 20480u;  if (sa == 61440u) sa = 0u;
        sbb += 8704u;  if (sbb == 26112u) sbb = 0u;
    }

    #pragma unroll
    for (int mt = 0; mt < 4; mt++){
        int r0 = bm + wm*64 + mt*16 + (lane >> 2);
        #pragma unroll
        for (int nt = 0; nt < 8; nt++){
            int col = bn + wn*64 + nt*8 + ((lane & 3) << 1);
            if (col < N){
                float v0 = acc[mt][nt][0];
                float v1 = acc[mt][nt][1];
                float v2 = acc[mt][nt][2];
                float v3 = acc[mt][nt][3];
                if (EPI == 3){
                    bf16* Cb = (bf16*)Cv + (long)blockIdx.z * sC;
                    int jc = col >> 1;
                    Cb[(long)r0*(N>>1) + jc]     = __float2bfloat16(siluf(v0)*v1);
                    Cb[(long)(r0+8)*(N>>1) + jc] = __float2bfloat16(siluf(v2)*v3);
                    continue;
                }
                if (EPI == 1){
                    float b0 = bias[col];
                    float b1 = bias[col+1];
                    v0 = fmaxf(v0+b0, 0.f); v1 = fmaxf(v1+b1, 0.f);
                    v2 = fmaxf(v2+b0, 0.f); v3 = fmaxf(v3+b1, 0.f);
                }
                if (EPI == 2){
                    float b0 = bias[col];
                    float b1 = bias[col+1];
                    v0 = fmaf(b0, v0, resx[(long)r0*ldc + col]);
                    v1 = fmaf(b1, v1, resx[(long)r0*ldc + col + 1]);
                    v2 = fmaf(b0, v2, resx[(long)(r0+8)*ldc + col]);
                    v3 = fmaf(b1, v3, resx[(long)(r0+8)*ldc + col + 1]);
                }
                if (OUTBF){
                    bf16* Cb = (bf16*)Cv + (long)blockIdx.z * sC;
                    *reinterpret_cast<__nv_bfloat162*>(&Cb[(long)r0*ldc + col]) =
                        __floats2bfloat162_rn(v0, v1);
                    *reinterpret_cast<__nv_bfloat162*>(&Cb[(long)(r0+8)*ldc + col]) =
                        __floats2bfloat162_rn(v2, v3);
                } else {
                    float* Cb = (float*)Cv + (long)blockIdx.z * sC;
                    *reinterpret_cast<float2*>(&Cb[(long)r0*ldc + col]) = make_float2(v0, v1);
                    *reinterpret_cast<float2*>(&Cb[(long)(r0+8)*ldc + col]) = make_float2(v2, v3);
                }
            }
        }
    }
}

// ---------------- fused flash attention ----------------
#define FTILE (128*136)
#define FSMEM (5*FTILE*2)

__device__ __forceinline__ void fstage(const bf16* src, unsigned dst, int tid){
    for (int i = tid; i < 2048; i += 256){
        int r = i >> 4, c = (i & 15) << 3;
        cpasync16(dst + 2u*(unsigned)(r*136 + c), src + r*DH + c, 16);
    }
}

__global__ void __launch_bounds__(256, 1) flash_k(
    const bf16* __restrict__ q, const bf16* __restrict__ k, const bf16* __restrict__ v,
    const float* __restrict__ ascale, bf16* __restrict__ att)
{
    extern __shared__ bf16 fs[];
    const int qt = blockIdx.x, bh = blockIdx.y;
    const int bb = bh >> 3, hh = bh & 7;
    const int tid = threadIdx.x, lane = tid & 31, w = tid >> 5;
    const float a = ascale[hh];

    const bf16* qg = q + ((long)bh*LSEQ + qt*128)*DH;
    const bf16* kg = k + (long)bh*LSEQ*DH;
    const bf16* vg = v + (long)bh*LSEQ*DH;

    const unsigned Qb = (unsigned)__cvta_generic_to_shared(fs);
    const unsigned Kb = Qb + 2u*FTILE;
    const unsigned Vb = Qb + 6u*FTILE;
    const unsigned TILEB = 2u*FTILE;

    fstage(qg, Qb, tid);
    fstage(kg, Kb, tid);
    fstage(vg, Vb, tid);
    cp_commit();
    cp_wait0();
    __syncthreads();

    unsigned qf[8][4];
    {
        int rq = w*16 + (lane & 15);
        int cq = (lane >> 4) << 3;
        #pragma unroll
        for (int ks = 0; ks < 8; ks++)
            ldsm_x4(Qb + 2u*(unsigned)(rq*136 + ks*16 + cq),
                    qf[ks][0], qf[ks][1], qf[ks][2], qf[ks][3]);
    }

    const int brow = (lane & 7) + (((lane >> 4) & 1) << 3);
    const int bcol = ((lane >> 3) & 1) << 3;
    unsigned kadr[8], vadr[8];
    #pragma unroll
    for (int p = 0; p < 8; p++){
        kadr[p] = Kb + 2u*(unsigned)((p*16 + brow)*136 + bcol);
        vadr[p] = Vb + 2u*(unsigned)((lane & 15)*136 + p*16 + ((lane >> 4) << 3));
    }

    float oacc[16][4];
    #pragma unroll
    for (int nt = 0; nt < 16; nt++)
        #pragma unroll
        for (int qq = 0; qq < 4; qq++) oacc[nt][qq] = 0.f;
    float m0 = -1e30f, m1 = -1e30f, l0 = 0.f, l1 = 0.f;

    for (int kt = 0; kt < 16; kt++){
        if (kt > 0){ cp_wait0(); __syncthreads(); }
        if (kt + 1 < 16){
            unsigned off = ((kt + 1) & 1) ? TILEB : 0u;
            fstage(kg + (long)(kt+1)*128*DH, Kb + off, tid);
            fstage(vg + (long)(kt+1)*128*DH, Vb + off, tid);
            cp_commit();
        }
        const unsigned sb = (kt & 1) ? TILEB : 0u;

        float sacc[16][4];
        #pragma unroll
        for (int nt = 0; nt < 16; nt++)
            #pragma unroll
            for (int qq = 0; qq < 4; qq++) sacc[nt][qq] = 0.f;

        #pragma unroll
        for (int ks = 0; ks < 8; ks++){
            #pragma unroll
            for (int p = 0; p < 8; p++){
                unsigned bf0[2], bf1[2];
                ldsm_x4(kadr[p] + sb + 2u*(unsigned)(ks*16),
                        bf0[0], bf0[1], bf1[0], bf1[1]);
                mma16816(sacc[2*p],   qf[ks], bf0);
                mma16816(sacc[2*p+1], qf[ks], bf1);
            }
        }

        float ax0 = -1e30f, ax1 = -1e30f;
        #pragma unroll
        for (int nt = 0; nt < 16; nt++){
            sacc[nt][0] *= a; sacc[nt][1] *= a; sacc[nt][2] *= a; sacc[nt][3] *= a;
            ax0 = fmaxf(ax0, fmaxf(sacc[nt][0], sacc[nt][1]));
            ax1 = fmaxf(ax1, fmaxf(sacc[nt][2], sacc[nt][3]));
        }
        ax0 = fmaxf(ax0, __shfl_xor_sync(0xffffffffu, ax0, 1));
        ax0 = fmaxf(ax0, __shfl_xor_sync(0xffffffffu, ax0, 2));
        ax1 = fmaxf(ax1, __shfl_xor_sync(0xffffffffu, ax1, 1));
        ax1 = fmaxf(ax1, __shfl_xor_sync(0xffffffffu, ax1, 2));
        float mn0 = fmaxf(m0, ax0), mn1 = fmaxf(m1, ax1);
        float f0 = expf(m0 - mn0), f1 = expf(m1 - mn1);

        float rs0 = 0.f, rs1 = 0.f;
        #pragma unroll
        for (int nt = 0; nt < 16; nt++){
            sacc[nt][0] = expf(sacc[nt][0] - mn0);
            sacc[nt][1] = expf(sacc[nt][1] - mn0);
            sacc[nt][2] = expf(sacc[nt][2] - mn1);
            sacc[nt][3] = expf(sacc[nt][3] - mn1);
            rs0 += sacc[nt][0] + sacc[nt][1];
            rs1 += sacc[nt][2] + sacc[nt][3];
        }
        rs0 += __shfl_xor_sync(0xffffffffu, rs0, 1);
        rs0 += __shfl_xor_sync(0xffffffffu, rs0, 2);
        rs1 += __shfl_xor_sync(0xffffffffu, rs1, 1);
        rs1 += __shfl_xor_sync(0xffffffffu, rs1, 2);
        l0 = l0*f0 + rs0; l1 = l1*f1 + rs1;
        m0 = mn0; m1 = mn1;

        #pragma unroll
        for (int nt = 0; nt < 16; nt++){
            oacc[nt][0] *= f0; oacc[nt][1] *= f0;
            oacc[nt][2] *= f1; oacc[nt][3] *= f1;
        }

        unsigned pa[8][4];
        #pragma unroll
        for (int ksp = 0; ksp < 8; ksp++){
            pa[ksp][0] = pkbf2(sacc[2*ksp][0],   sacc[2*ksp][1]);
            pa[ksp][1] = pkbf2(sacc[2*ksp][2],   sacc[2*ksp][3]);
            pa[ksp][2] = pkbf2(sacc[2*ksp+1][0], sacc[2*ksp+1][1]);
            pa[ksp][3] = pkbf2(sacc[2*ksp+1][2], sacc[2*ksp+1][3]);
        }

        #pragma unroll
        for (int ksp = 0; ksp < 8; ksp++){
            #pragma unroll
            for (int p = 0; p < 8; p++){
                unsigned bf0[2], bf1[2];
                ldsm_x4_t(vadr[p] + sb + 2u*(unsigned)(ksp*16*136),
                          bf0[0], bf0[1], bf1[0], bf1[1]);
                mma16816(oacc[2*p],   pa[ksp], bf0);
                mma16816(oacc[2*p+1], pa[ksp], bf1);
            }
        }
    }

    float inv0 = 1.f / l0, inv1 = 1.f / l1;
    long row0 = (long)bb*LSEQ + qt*128 + w*16 + (lane >> 2);
    long row1 = row0 + 8;
    int  cbase = hh*DH + ((lane & 3) << 1);
    #pragma unroll
    for (int nt = 0; nt < 16; nt++){
        int col = cbase + nt*8;
        *reinterpret_cast<__nv_bfloat162*>(&att[row0*DM + col]) =
            __floats2bfloat162_rn(oacc[nt][0]*inv0, oacc[nt][1]*inv0);
        *reinterpret_cast<__nv_bfloat162*>(&att[row1*DM + col]) =
            __floats2bfloat162_rn(oacc[nt][2]*inv1, oacc[nt][3]*inv1);
    }
}

// ---------------- depthwise conv + bias + SiLU ----------------
__global__ void conv_k(const float* __restrict__ xz, const float* __restrict__ cw,
                       const float* __restrict__ cb, float* __restrict__ xc,
                       bf16* __restrict__ xcb){
    long idx = (long)blockIdx.x*blockDim.x + threadIdx.x;
    if (idx >= (long)NTOK*DI) return;
    int d = (int)(idx % DI);
    int row = (int)(idx / DI);
    int t = row % LSEQ, b = row / LSEQ;
    float s = cb[d];
    #pragma unroll
    for (int k = 0; k < 4; k++){
        int tt = t + k - 2;
        if (tt >= 0 && tt < LSEQ)
            s = fmaf(cw[d*4+k], xz[(long)(b*LSEQ+tt)*(2*DI) + d], s);
    }
    float v = siluf(s);
    xc[idx] = v;
    xcb[idx] = __float2bfloat16(v);
}

// ---------------- scan preprocessing ----------------
__global__ void scanprep_k(const float* __restrict__ dtBC, const float* __restrict__ bdt,
                           const float* __restrict__ A, float* __restrict__ sp){
    int idx = blockIdx.x*blockDim.x + threadIdx.x;
    if (idx >= NTOK*16) return;
    int n = idx & 15, row = idx >> 4;
    float dtp = dtBC[(long)row*64 + n] + bdt[n];
    float dt  = fmaxf(dtp, 0.f) + log1pf(expf(-fabsf(dtp)));
    sp[(long)row*48 + n]      = expf(dt * A[n]);
    sp[(long)row*48 + 16 + n] = dt * dtBC[(long)row*64 + 16 + n];
    sp[(long)row*48 + 32 + n] = dtBC[(long)row*64 + 32 + n];
}

// ---------------- chunked selective scan ----------------
// pass P: per-chunk decay product (d-independent)
__global__ void scanP_k(const float* __restrict__ sp, float* __restrict__ P){
    int b = blockIdx.x / NCH, ch = blockIdx.x % NCH;
    int n = threadIdx.x;   // 16 threads
    if (n >= 16) return;
    float p = 1.f;
    long base = ((long)b*LSEQ + ch*CLEN)*48;
    for (int t = 0; t < CLEN; t++) p *= sp[base + t*48 + n];
    P[(b*NCH+ch)*16 + n] = p;
}

// pass A: per-chunk scan from h=0, store h_end
__global__ void scanA_k(const float* __restrict__ sp, const float* __restrict__ xc,
                        float* __restrict__ hend){
    int b = blockIdx.z, ch = blockIdx.y;
    int d = blockIdx.x*128 + threadIdx.x;
    __shared__ float s[CLEN*48];
    const float* src = sp + ((long)b*LSEQ + ch*CLEN)*48;
    for (int i = threadIdx.x; i < CLEN*48; i += 128) s[i] = src[i];
    __syncthreads();
    float h[16];
    #pragma unroll
    for (int n = 0; n < 16; n++) h[n] = 0.f;
    long rowbase = (long)b*LSEQ + ch*CLEN;
    float xv_next = xc[rowbase*DI + d];
    for (int tt = 0; tt < CLEN; tt++){
        float xv = xv_next;
        if (tt + 1 < CLEN) xv_next = xc[(rowbase + tt + 1)*DI + d];
        const float* e = s + tt*48;
        #pragma unroll
        for (int n = 0; n < 16; n++)
            h[n] = fmaf(e[n], h[n], e[16+n]*xv);
    }
    float* o = hend + (((long)(b*NCH + ch)*DI + d) << 4);
    #pragma unroll
    for (int n = 0; n < 16; n += 4)
        *reinterpret_cast<float4*>(o + n) = make_float4(h[n], h[n+1], h[n+2], h[n+3]);
}

// combine: h0[c] = P[c-1]*h0[c-1] + hend[c-1] (sequential over 16 chunks)
__global__ void scanComb_k(const float* __restrict__ hend, const float* __restrict__ P,
                           float* __restrict__ h0){
    int g = blockIdx.x*128 + threadIdx.x;    // 0..BB*DI-1; one b per block range
    int b = g / DI, d = g % DI;
    __shared__ float sP[NCH*16];
    for (int i = threadIdx.x; i < NCH*16; i += 128) sP[i] = P[b*NCH*16 + i];
    __syncthreads();
    float h[16];
    #pragma unroll
    for (int n = 0; n < 16; n++) h[n] = 0.f;
    {   // chunk 0 starts from zero
        float* o = h0 + (((long)(b*NCH)*DI + d) << 4);
        #pragma unroll
        for (int n = 0; n < 16; n += 4)
            *reinterpret_cast<float4*>(o + n) = make_float4(0.f, 0.f, 0.f, 0.f);
    }
    for (int c = 1; c < NCH; c++){
        const float* he = hend + (((long)(b*NCH + c - 1)*DI + d) << 4);
        #pragma unroll
        for (int n = 0; n < 16; n++)
            h[n] = fmaf(sP[(c-1)*16 + n], h[n], he[n]);
        float* o = h0 + (((long)(b*NCH + c)*DI + d) << 4);
        #pragma unroll
        for (int n = 0; n < 16; n += 4)
            *reinterpret_cast<float4*>(o + n) = make_float4(h[n], h[n+1], h[n+2], h[n+3]);
    }
}

// pass C: rescan chunk from exact h0, emit ymul (bf16)
__global__ void scanC_k(const float* __restrict__ sp, const float* __restrict__ xc,
                        const float* __restrict__ xz, const float* __restrict__ Dp,
                        const float* __restrict__ h0, bf16* __restrict__ ymulb){
    int b = blockIdx.z, ch = blockIdx.y;
    int d = blockIdx.x*128 + threadIdx.x;
    __shared__ float s[CLEN*48];
    const float* src = sp + ((long)b*LSEQ + ch*CLEN)*48;
    for (int i = threadIdx.x; i < CLEN*48; i += 128) s[i] = src[i];
    __syncthreads();
    float h[16];
    {   const float* hi = h0 + (((long)(b*NCH + ch)*DI + d) << 4);
        #pragma unroll
        for (int n = 0; n < 16; n += 4){
            float4 v = *reinterpret_cast<const float4*>(hi + n);
            h[n] = v.x; h[n+1] = v.y; h[n+2] = v.z; h[n+3] = v.w;
        }
    }
    const float dpv = Dp[d];
    long rowbase = (long)b*LSEQ + ch*CLEN;
    float xv_next = xc[rowbase*DI + d];
    float z_next  = xz[rowbase*(2*DI) + DI + d];
    for (int tt = 0; tt < CLEN; tt++){
        float xv = xv_next;
        float z  = z_next;
        if (tt + 1 < CLEN){
            xv_next = xc[(rowbase + tt + 1)*DI + d];
            z_next  = xz[(rowbase + tt + 1)*(2*DI) + DI + d];
        }
        const float* e = s + tt*48;
        float y = 0.f;
        #pragma unroll
        for (int n = 0; n < 16; n++){
            h[n] = fmaf(e[n], h[n], e[16+n]*xv);
            y = fmaf(h[n], e[32+n], y);
        }
        ymulb[(rowbase + tt)*DI + d] = __float2bfloat16((y + dpv*xv) * siluf(z));
    }
}

// ---------------- RoPE -> qb,kb,vb bf16 ----------------
__global__ void rope2_k(const float* __restrict__ qkv, bf16* __restrict__ qb,
                        bf16* __restrict__ kb, bf16* __restrict__ vb){
    int row = blockIdx.x;
    int t = row % LSEQ, b = row / LSEQ;
    __shared__ float q[DM], kk[DM];
    const float* base = qkv + (long)row*3*DM;
    for (int i = threadIdx.x; i < DM; i += 256){ q[i] = base[i]; kk[i] = base[DM+i]; }
    __syncthreads();
    const float sq = sqrtf((float)DH);
    const float lg = logf(10000.f) / 64.f;
    for (int idx = threadIdx.x; idx < DM; idx += 256){
        int h = idx / DH, i = idx % DH;
        int j = i & 63;
        float inv = expf(-(float)j * lg);
        float ang = (float)t * inv;
        float c = cosf(ang), s = sinf(ang);
        int off = h * DH;
        float rq, rk;
        if (i < 64){ rq = -q[off + 2*i + 1]; rk = -kk[off + 2*i + 1]; }
        else       { rq =  q[off + 2*(i-64)]; rk =  kk[off + 2*(i-64)]; }
        long o = ((long)(b*NH + h)*LSEQ + t)*DH + i;
        qb[o] = __float2bfloat16((q[idx]*c + rq*s) * sq);
        kb[o] = __float2bfloat16(kk[idx]*c + rk*s);
        vb[o] = __float2bfloat16(base[2*DM + idx]);
    }
}

// ---------------- gate stage 2 ----------------
__global__ void gate2_k(const float* __restrict__ g1, const float* __restrict__ Wg2,
                        float* __restrict__ gs, int* __restrict__ topi, float* __restrict__ topw){
    int row = blockIdx.x;
    int tid = threadIdx.x; // 64 threads
    __shared__ float red[64*4];
    float a[4] = {0.f,0.f,0.f,0.f};
    for (int j = tid; j < 512; j += 64){
        float v = g1[(long)row*512 + j];
        #pragma unroll
        for (int e = 0; e < 4; e++) a[e] = fmaf(v, Wg2[j*4+e], a[e]);
    }
    #pragma unroll
    for (int e = 0; e < 4; e++) red[e*64 + tid] = a[e];
    __syncthreads();
    for (int st = 32; st > 0; st >>= 1){
        if (tid < st){
            #pragma unroll
            for (int e = 0; e < 4; e++) red[e*64+tid] += red[e*64+tid+st];
        }
        __syncthreads();
    }
    if (tid == 0){
        float l[4]; for (int e = 0; e < 4; e++) l[e] = red[e*64];
        float m = fmaxf(fmaxf(l[0],l[1]), fmaxf(l[2],l[3]));
        float ex[4]; float s = 0.f;
        for (int e = 0; e < 4; e++){ ex[e] = expf(l[e]-m); s += ex[e]; }
        float gsv[4];
        for (int e = 0; e < 4; e++){ gsv[e] = ex[e]/s; gs[(long)row*4+e] = gsv[e]; }
        int i0 = 0;
        for (int e = 1; e < 4; e++) if (gsv[e] > gsv[i0]) i0 = e;
        int i1 = -1;
        for (int e = 0; e < 4; e++) if (e != i0 && (i1 < 0 || gsv[e] > gsv[i1])) i1 = e;
        float v0 = gsv[i0], v1 = gsv[i1];
        float mm = fmaxf(v0, v1);
        float w0 = expf(v0-mm), w1 = expf(v1-mm);
        float ws = w0 + w1;
        topi[row*2] = i0; topi[row*2+1] = i1;
        topw[row*2] = w0/ws; topw[row*2+1] = w1/ws;
    }
}

// ---------------- balance loss ----------------
__global__ void bal_k(const float* __restrict__ gs, float* __restrict__ out){
    int tid = threadIdx.x;
    __shared__ float red[256*4];
    float a[4] = {0.f,0.f,0.f,0.f};
    for (int r = tid; r < NTOK; r += 256){
        #pragma unroll
        for (int e = 0; e < 4; e++) a[e] += gs[(long)r*4+e];
    }
    #pragma unroll
    for (int e = 0; e < 4; e++) red[e*256+tid] = a[e];
    __syncthreads();
    for (int st = 128; st > 0; st >>= 1){
        if (tid < st){
            #pragma unroll
            for (int e = 0; e < 4; e++) red[e*256+tid] += red[e*256+tid+st];
        }
        __syncthreads();
    }
    if (tid == 0){
        float bal = 0.f;
        for (int e = 0; e < 4; e++){
            float gm = red[e*256] / (float)NTOK;
            bal += gm * logf(gm + 1e-8f);
        }
        out[0] = (float)NEXP * bal;
    }
}

// ---------------- MoE routing ----------------
__global__ void zero4_k(int* c){ if (threadIdx.x < NEXP) c[threadIdx.x] = 0; }

__global__ void assign_k(const int* __restrict__ topi, int* __restrict__ cnt,
                         int* __restrict__ slot){
    int idx = blockIdx.x*256 + threadIdx.x;
    if (idx >= NTOK*2) return;
    int e = topi[idx];
    int s = atomicAdd(&cnt[e], 1);
    slot[idx] = e*NTOK + s;
}

__global__ void gather_k(const bf16* __restrict__ xf, const int* __restrict__ slot,
                         bf16* __restrict__ xg){
    int idx = blockIdx.x;
    int tok = idx >> 1;
    int dst = slot[idx];
    const unsigned* src = reinterpret_cast<const unsigned*>(xf) + (long)tok*(DM/2);
    unsigned* d = reinterpret_cast<unsigned*>(xg) + (long)dst*(DM/2);
    for (int i = threadIdx.x; i < DM/2; i += 128) d[i] = src[i];
}

// ---------------- MoE combine + final residual ----------------
__global__ void combine2_k(const float* __restrict__ x2, const float* __restrict__ ls3,
                           const bf16* __restrict__ eo, const int* __restrict__ slot,
                           const float* __restrict__ topw, float* __restrict__ out){
    long idx = (long)blockIdx.x*blockDim.x + threadIdx.x;
    if (idx >= (long)NTOK*DM) return;
    int row = (int)(idx / DM), d = (int)(idx % DM);
    int s0 = slot[row*2], s1 = slot[row*2+1];
    float m = topw[row*2]   * __bfloat162float(eo[(long)s0*DM + d])
            + topw[row*2+1] * __bfloat162float(eo[(long)s1*DM + d]);
    out[idx] = fmaf(ls3[d], m, x2[idx]);
}

// ============================== host ==============================
#define SYMPF(p, s) do { void* _t; cudaGetSymbolAddress(&_t, s); p = (float*)_t; } while(0)
#define SYMPB(p, s) do { void* _t; cudaGetSymbolAddress(&_t, s); p = (bf16*)_t; } while(0)
#define SYMPI(p, s) do { void* _t; cudaGetSymbolAddress(&_t, s); p = (int*)_t; } while(0)

extern "C" void kernel_launch(void* const* d_in, const int* in_sizes, int n_in,
                              void* d_out, int out_size){
    const float* x      = (const float*)d_in[0];
    const float* rms1_w = (const float*)d_in[1];
    const float* rms2_w = (const float*)d_in[2];
    const float* rms3_w = (const float*)d_in[3];
    const float* ls1    = (const float*)d_in[4];
    const float* ls2    = (const float*)d_in[5];
    const float* ls3    = (const float*)d_in[6];
    const float* W_in   = (const float*)d_in[7];
    const float* conv_w = (const float*)d_in[8];
    const float* conv_b = (const float*)d_in[9];
    const float* W_B    = (const float*)d_in[10];
    const float* W_C    = (const float*)d_in[11];
    const float* W_dt   = (const float*)d_in[12];
    const float* b_dt   = (const float*)d_in[13];
    const float* W_out_m= (const float*)d_in[14];
    const float* Avec   = (const float*)d_in[15];
    const float* Dp     = (const float*)d_in[16];
    const float* W_qkv  = (const float*)d_in[17];
    const float* W_o    = (const float*)d_in[18];
    const float* ascale = (const float*)d_in[19];
    const float* Wg1    = (const float*)d_in[20];
    const float* bg1    = (const float*)d_in[21];
    const float* Wg2    = (const float*)d_in[22];
    const float* w1     = (const float*)d_in[23];
    const float* w2     = (const float*)d_in[24];
    const float* w3     = (const float*)d_in[25];
    float* out = (float*)d_out;

    float *p_xz, *p_xc, *p_dtBC, *p_scanp, *p_x1, *p_qkv, *p_x2, *p_g1, *p_gs, *p_topw;
    float *p_hend, *p_h0, *p_P;
    int *p_topi, *p_cnt, *p_slot;
    bf16 *b_rms1, *b_xc, *b_ymul, *b_rms2, *b_q, *b_k, *b_v, *b_att, *b_xf,
         *b_xg, *b_h, *b_eo;
    bf16 *b_Win, *b_Wout, *b_Wqkv, *b_Wo, *b_Wg1, *b_w12, *b_w3, *b_Wcat;

    SYMPF(p_xz, g_xz); SYMPF(p_xc, g_xc); SYMPF(p_dtBC, g_dtBC); SYMPF(p_scanp, g_scanp);
    SYMPF(p_x1, g_x1); SYMPF(p_qkv, g_qkv);
    SYMPF(p_x2, g_x2); SYMPF(p_g1, g_g1); SYMPF(p_gs, g_gs); SYMPF(p_topw, g_topw);
    SYMPF(p_hend, g_hend); SYMPF(p_h0, g_h0); SYMPF(p_P, g_P);
    SYMPI(p_topi, g_topi); SYMPI(p_cnt, g_cnt); SYMPI(p_slot, g_slot);
    SYMPB(b_rms1, g_rms1b); SYMPB(b_xc, g_xcb); SYMPB(b_ymul, g_ymulb); SYMPB(b_rms2, g_rms2b);
    SYMPB(b_q, g_qb); SYMPB(b_k, g_kb); SYMPB(b_v, g_vb);
    SYMPB(b_att, g_attb); SYMPB(b_xf, g_xfb); SYMPB(b_xg, g_xgb);
    SYMPB(b_h, g_hb); SYMPB(b_eo, g_eob);
    SYMPB(b_Win, g_Winb); SYMPB(b_Wout, g_Woutb); SYMPB(b_Wqkv, g_Wqkvb); SYMPB(b_Wo, g_Wob);
    SYMPB(b_Wg1, g_Wg1b); SYMPB(b_w12, g_w12b); SYMPB(b_w3, g_w3b); SYMPB(b_Wcat, g_Wcatb);

    // ---- weight conversions ----
    #define CONV(src, dst, n) f2bf_k<<<(int)(((n)/4 + 255)/256), 256>>>(src, dst, (long)(n))
    CONV(W_in,   b_Win,  (long)DM*2*DI);
    CONV(W_out_m,b_Wout, (long)DI*DM);
    CONV(W_qkv,  b_Wqkv, (long)DM*3*DM);
    CONV(W_o,    b_Wo,   (long)DM*DM);
    CONV(Wg1,    b_Wg1,  (long)DM*512);
    CONV(w3,     b_w3,   (long)NEXP*DFF*DM);
    pack12_k<<<(int)(((long)NEXP*DM*DFF/4 + 255)/256), 256>>>(w1, w2, b_w12);
    packw_k<<<(DI*64+255)/256, 256>>>(W_dt, W_B, W_C, b_Wcat);

    // ---- 1. Mamba ----
    rmsnorm_bf_k<<<NTOK, 256>>>(x, rms1_w, b_rms1);
    {   dim3 g(2*DI/128, NTOK/256, 1);
        bgemm256_k<0,0><<<g, 256>>>(b_rms1, b_Win, p_xz, NTOK, 2*DI, DM, DM, 2*DI, 2*DI,
                                    0,0,0, nullptr, nullptr, nullptr); }
    conv_k<<<(int)(((long)NTOK*DI+255)/256), 256>>>(p_xz, conv_w, conv_b, p_xc, b_xc);
    {   dim3 g(1, NTOK/128, 1);
        bgemm_k<0,0,0><<<g, 256>>>(b_xc, b_Wcat, p_dtBC, NTOK, 64, DI, DI, 64, 64,
                                   0,0,0, nullptr, nullptr, nullptr); }
    scanprep_k<<<(NTOK*16+255)/256, 256>>>(p_dtBC, b_dt, Avec, p_scanp);
    scanP_k<<<BB*NCH, 16>>>(p_scanp, p_P);
    {   dim3 g(16, NCH, BB);
        scanA_k<<<g, 128>>>(p_scanp, p_xc, p_hend); }
    scanComb_k<<<BB*DI/128, 128>>>(p_hend, p_P, p_h0);
    {   dim3 g(16, NCH, BB);
        scanC_k<<<g, 128>>>(p_scanp, p_xc, p_xz, Dp, p_h0, b_ymul); }
    {   dim3 g(DM/128, NTOK/256, 1);   // x1 = x + ls1 * (ymul @ Wout)
        bgemm256_k<2,0><<<g, 256>>>(b_ymul, b_Wout, p_x1, NTOK, DM, DI, DI, DM, DM,
                                    0,0,0, ls1, x, nullptr); }

    // ---- 2. Attention ----
    rmsnorm_bf_k<<<NTOK, 256>>>(p_x1, rms2_w, b_rms2);
    {   dim3 g(3*DM/128, NTOK/256, 1);
        bgemm256_k<0,0><<<g, 256>>>(b_rms2, b_Wqkv, p_qkv, NTOK, 3*DM, DM, DM, 3*DM, 3*DM,
                                    0,0,0, nullptr, nullptr, nullptr); }
    rope2_k<<<NTOK, 256>>>(p_qkv, b_q, b_k, b_v);
    {   cudaFuncSetAttribute(flash_k, cudaFuncAttributeMaxDynamicSharedMemorySize, FSMEM);
        dim3 g(LSEQ/128, BB*NH, 1);
        flash_k<<<g, 256, FSMEM>>>(b_q, b_k, b_v, ascale, b_att); }
    {   dim3 g(DM/128, NTOK/256, 1);   // x2 = x1 + ls2 * (att @ Wo)
        bgemm256_k<2,0><<<g, 256>>>(b_att, b_Wo, p_x2, NTOK, DM, DM, DM, DM, DM,
                                    0,0,0, ls2, p_x1, nullptr); }

    // ---- 3. MoE (top-2 sparse) ----
    rmsnorm_bf_k<<<NTOK, 256>>>(p_x2, rms3_w, b_xf);
    {   dim3 g(512/128, NTOK/256, 1);
        bgemm256_k<1,0><<<g, 256>>>(b_xf, b_Wg1, p_g1, NTOK, 512, DM, DM, 512, 512,
                                    0,0,0, bg1, nullptr, nullptr); }
    gate2_k<<<NTOK, 64>>>(p_g1, Wg2, p_gs, p_topi, p_topw);
    if (out_size > NTOK*DM)
        bal_k<<<1, 256>>>(p_gs, out + (long)NTOK*DM);
    zero4_k<<<1, 32>>>(p_cnt);
    assign_k<<<(NTOK*2+255)/256, 256>>>(p_topi, p_cnt, p_slot);
    gather_k<<<NTOK*2, 128>>>(b_xf, p_slot, b_xg);
    {   dim3 g12(2*DFF/128, NTOK/256, NEXP);
        bgemm256_k<3,1><<<g12, 256>>>(b_xg, b_w12, b_h,
                                      NTOK, 2*DFF, DM, DM, 2*DFF, 2*DFF,
                                      (long)NTOK*DM, (long)DM*2*DFF, (long)NTOK*DFF,
                                      nullptr, nullptr, p_cnt);
    }
    {   dim3 g3(DM/128, NTOK/256, NEXP);
        bgemm256_k<0,1><<<g3, 256>>>(b_h, b_w3, b_eo,
                                     NTOK, DM, DFF, DFF, DM, DM,
                                     (long)NTOK*DFF, (long)DFF*DM, (long)NTOK*DM,
                                     nullptr, nullptr, p_cnt);
    }
    combine2_k<<<(int)(((long)NTOK*DM+255)/256), 256>>>(p_x2, ls3, b_eo, p_slot, p_topw, out);
}

// round 11
// speedup vs baseline: 10.4031x; 1.0022x over previous
#include <cuda_runtime.h>
#include <cuda_bf16.h>
#include <math.h>

#define BB   2
#define LSEQ 2048
#define DM   1024
#define DI   2048
#define NH   8
#define DH   128
#define NEXP 4
#define DFF  4096
#define NTOK (BB*LSEQ)   // 4096
#define NCH  16
#define CLEN 128         // LSEQ/NCH

typedef __nv_bfloat16 bf16;

// ---------------- static scratch ----------------
__device__ float g_xz[NTOK*2*DI];
__device__ float g_xc[NTOK*DI];
__device__ float g_dtBC[NTOK*64];
__device__ float g_scanp[NTOK*48];
__device__ float g_x1[NTOK*DM];
__device__ float g_qkv[NTOK*3*DM];
__device__ float g_x2[NTOK*DM];
__device__ float g_g1[NTOK*512];
__device__ float g_gs[NTOK*NEXP];
__device__ int   g_topi[NTOK*2];
__device__ float g_topw[NTOK*2];
__device__ int   g_cnt[NEXP];
__device__ int   g_slot[NTOK*2];
__device__ float g_hend[BB*NCH*DI*16];
__device__ float g_h0[BB*NCH*DI*16];
__device__ float g_P[BB*NCH*16];

// bf16 activations
__device__ bf16 g_rms1b[NTOK*DM];
__device__ bf16 g_xcb[NTOK*DI];
__device__ bf16 g_ymulb[NTOK*DI];
__device__ bf16 g_rms2b[NTOK*DM];
__device__ bf16 g_qb[NTOK*DM];
__device__ bf16 g_kb[NTOK*DM];
__device__ bf16 g_vb[NTOK*DM];
__device__ bf16 g_attb[NTOK*DM];
__device__ bf16 g_xfb[NTOK*DM];
__device__ bf16 g_xgb[NEXP*NTOK*DM];
__device__ bf16 g_hb[(long)NEXP*NTOK*DFF];
__device__ bf16 g_eob[NEXP*NTOK*DM];

// bf16 weights
__device__ bf16 g_Winb[DM*2*DI];
__device__ bf16 g_Woutb[DI*DM];
__device__ bf16 g_Wqkvb[DM*3*DM];
__device__ bf16 g_Wob[DM*DM];
__device__ bf16 g_Wg1b[DM*512];
__device__ bf16 g_w12b[(long)NEXP*DM*2*DFF];   // interleaved (w1_j, w2_j) pairs
__device__ bf16 g_w3b[(long)NEXP*DFF*DM];
__device__ bf16 g_Wcatb[DI*64];

__device__ __forceinline__ float siluf(float x){ return x / (1.f + expf(-x)); }

// ---------------- fp32 -> bf16 convert ----------------
__global__ void f2bf_k(const float* __restrict__ s, bf16* __restrict__ d, long n){
    long i = ((long)blockIdx.x*blockDim.x + threadIdx.x)*4;
    if (i >= n) return;
    float4 v = *reinterpret_cast<const float4*>(s+i);
    *reinterpret_cast<__nv_bfloat162*>(d+i)   = __floats2bfloat162_rn(v.x, v.y);
    *reinterpret_cast<__nv_bfloat162*>(d+i+2) = __floats2bfloat162_rn(v.z, v.w);
}

// pack w1|w2 INTERLEAVED
__global__ void pack12_k(const float* __restrict__ w1, const float* __restrict__ w2,
                         bf16* __restrict__ o){
    long i = ((long)blockIdx.x*blockDim.x + threadIdx.x)*4;
    if (i >= (long)NEXP*DM*DFF) return;
    long row = i >> 12;
    int  j   = (int)(i & 4095);
    float4 a = *reinterpret_cast<const float4*>(w1 + i);
    float4 b = *reinterpret_cast<const float4*>(w2 + i);
    bf16* d1 = o + row*(2*DFF) + 2*j;
    *reinterpret_cast<__nv_bfloat162*>(d1)   = __floats2bfloat162_rn(a.x, b.x);
    *reinterpret_cast<__nv_bfloat162*>(d1+2) = __floats2bfloat162_rn(a.y, b.y);
    *reinterpret_cast<__nv_bfloat162*>(d1+4) = __floats2bfloat162_rn(a.z, b.z);
    *reinterpret_cast<__nv_bfloat162*>(d1+6) = __floats2bfloat162_rn(a.w, b.w);
}

// pack [W_dt | W_B | W_C | 0] -> [2048][64] bf16
__global__ void packw_k(const float* __restrict__ Wdt, const float* __restrict__ WB,
                        const float* __restrict__ WC, bf16* __restrict__ o){
    int idx = blockIdx.x*256 + threadIdx.x;
    if (idx >= DI*64) return;
    int j = idx >> 6, n = idx & 63;
    float v = 0.f;
    if (n < 16) v = Wdt[j*16+n];
    else if (n < 32) v = WB[j*16+n-16];
    else if (n < 48) v = WC[j*16+n-32];
    o[idx] = __float2bfloat16(v);
}

// ---------------- RMSNorm -> bf16 ----------------
__global__ void rmsnorm_bf_k(const float* __restrict__ x, const float* __restrict__ w,
                             bf16* __restrict__ o){
    int row = blockIdx.x;
    const float* xr = x + (long)row*DM;
    __shared__ float red[256];
    float s = 0.f;
    for (int i = threadIdx.x; i < DM; i += 256){ float v = xr[i]; s += v*v; }
    red[threadIdx.x] = s; __syncthreads();
    for (int st = 128; st > 0; st >>= 1){
        if (threadIdx.x < st) red[threadIdx.x] += red[threadIdx.x+st];
        __syncthreads();
    }
    float r = rsqrtf(red[0]/(float)DM + 1e-6f);
    for (int i = threadIdx.x; i < DM; i += 256)
        o[(long)row*DM+i] = __float2bfloat16(w[i]*xr[i]*r);
}

// ---------------- MMA primitives ----------------
__device__ __forceinline__ void cpasync16(unsigned dst, const void* src, int ssz){
    asm volatile("cp.async.ca.shared.global [%0], [%1], 16, %2;"
        :: "r"(dst), "l"(src), "r"(ssz));
}
__device__ __forceinline__ void cp_commit(){ asm volatile("cp.async.commit_group;"); }
__device__ __forceinline__ void cp_wait0(){ asm volatile("cp.async.wait_group 0;"); }
__device__ __forceinline__ void cp_wait1(){ asm volatile("cp.async.wait_group 1;"); }
__device__ __forceinline__ void ldsm_x4(unsigned saddr, unsigned &o0, unsigned &o1,
                                        unsigned &o2, unsigned &o3){
    asm volatile("ldmatrix.sync.aligned.m8n8.x4.shared.b16 {%0,%1,%2,%3},[%4];"
        : "=r"(o0),"=r"(o1),"=r"(o2),"=r"(o3) : "r"(saddr));
}
__device__ __forceinline__ void ldsm_x4_t(unsigned saddr, unsigned &o0, unsigned &o1,
                                          unsigned &o2, unsigned &o3){
    asm volatile("ldmatrix.sync.aligned.m8n8.x4.trans.shared.b16 {%0,%1,%2,%3},[%4];"
        : "=r"(o0),"=r"(o1),"=r"(o2),"=r"(o3) : "r"(saddr));
}
__device__ __forceinline__ void mma16816(float* d, const unsigned* am, const unsigned* bm){
    asm volatile("mma.sync.aligned.m16n8k16.row.col.f32.bf16.bf16.f32 "
        "{%0,%1,%2,%3},{%4,%5,%6,%7},{%8,%9},{%0,%1,%2,%3};"
        : "+f"(d[0]),"+f"(d[1]),"+f"(d[2]),"+f"(d[3])
        : "r"(am[0]),"r"(am[1]),"r"(am[2]),"r"(am[3]), "r"(bm[0]),"r"(bm[1]));
}
__device__ __forceinline__ unsigned pkbf2(float x, float y){
    __nv_bfloat162 t = __floats2bfloat162_rn(x, y);
    return *reinterpret_cast<unsigned*>(&t);
}

// ---------------- 128x128 GEMM ----------------
template<int TRANSB>
__device__ __forceinline__ void stage_tiles(const bf16* Ab, const bf16* Bb,
    int bm, int bn, int N, int lda, int ldb, int k0, int tid,
    unsigned Adst, unsigned Bdst)
{
    #pragma unroll
    for (int c = tid; c < 512; c += 256){
        int r  = c >> 2;
        int ko = (c & 3) << 3;
        cpasync16(Adst + 2u*(unsigned)(r*40 + ko),
                  Ab + (long)(bm + r)*lda + k0 + ko, 16);
    }
    #pragma unroll
    for (int c = tid; c < 512; c += 256){
        int r  = c >> 4;
        int no = (c & 15) << 3;
        const bf16* src = Bb + (long)(k0 + r)*ldb + bn + no;
        int ssz = 16;
        if (bn + no >= N){ src = Bb; ssz = 0; }
        cpasync16(Bdst + 2u*(unsigned)(r*136 + no), src, ssz);
    }
}

template<int TRANSB, int EPI, int OUTBF>
__global__ void __launch_bounds__(256) bgemm_k(
    const bf16* __restrict__ Aptr, const bf16* __restrict__ Bptr, void* __restrict__ Cv,
    int M, int N, int K, int lda, int ldb, int ldc,
    long sA, long sB, long sC, const float* __restrict__ bias,
    const float* __restrict__ resx, const int* __restrict__ mcnt)
{
    __shared__ bf16 As[3*5120];
    __shared__ bf16 Bs[3*5120];
    const int bm = blockIdx.y * 128;
    int Meff = M;
    if (mcnt) Meff = mcnt[blockIdx.z];
    if (bm >= Meff) return;
    const bf16* Ab = Aptr + (long)blockIdx.z * sA;
    const bf16* Bb = Bptr + (long)blockIdx.z * sB;
    const int bn = blockIdx.x * 128;
    const int tid  = threadIdx.x;
    const int lane = tid & 31;
    const int warp = tid >> 5;
    const int wm = warp >> 1;
    const int wn = warp & 1;

    float acc[2][8][4];
    #pragma unroll
    for (int i = 0; i < 2; i++)
        #pragma unroll
        for (int j = 0; j < 8; j++)
            #pragma unroll
            for (int q = 0; q < 4; q++) acc[i][j][q] = 0.f;

    unsigned Afrag[2][4];
    unsigned Bfrag[8][2];

    const unsigned As_base = (unsigned)__cvta_generic_to_shared(As);
    const unsigned Bs_base = (unsigned)__cvta_generic_to_shared(Bs);

    const int rowA = wm*32 + (lane & 15);
    const int colA = (lane >> 4) * 8;
    unsigned aoff0 = As_base + 2u*(unsigned)( rowA       *40 + colA);
    unsigned aoff1 = As_base + 2u*(unsigned)((rowA + 16) *40 + colA);

    unsigned boff[4];
    #pragma unroll
    for (int p = 0; p < 4; p++){
        int brow = lane & 15;
        int bcol = (lane >> 4) * 8;
        boff[p] = Bs_base + 2u*(unsigned)(brow*136 + wn*64 + p*16 + bcol);
    }

    const int nk = K >> 5;
    stage_tiles<TRANSB>(Ab, Bb, bm, bn, N, lda, ldb, 0, tid, As_base, Bs_base);
    cp_commit();
    if (nk > 1){
        stage_tiles<TRANSB>(Ab, Bb, bm, bn, N, lda, ldb, 32, tid,
                            As_base + 10240u, Bs_base + 10240u);
        cp_commit();
    }

    unsigned sb = 0u;
    for (int it = 0; it < nk; it++){
        if (it + 1 < nk) cp_wait1(); else cp_wait0();
        __syncthreads();
        if (it + 2 < nk){
            unsigned off = (unsigned)((it + 2) % 3) * 10240u;
            stage_tiles<TRANSB>(Ab, Bb, bm, bn, N, lda, ldb, (it+2) << 5, tid,
                                As_base + off, Bs_base + off);
            cp_commit();
        }
        #pragma unroll
        for (int ks = 0; ks < 32; ks += 16){
            ldsm_x4(aoff0 + sb + 2u*ks, Afrag[0][0], Afrag[0][1], Afrag[0][2], Afrag[0][3]);
            ldsm_x4(aoff1 + sb + 2u*ks, Afrag[1][0], Afrag[1][1], Afrag[1][2], Afrag[1][3]);
            #pragma unroll
            for (int p = 0; p < 4; p++){
                unsigned ba = boff[p] + sb + 2u*(unsigned)(ks*136);
                ldsm_x4_t(ba, Bfrag[2*p][0], Bfrag[2*p][1],
                              Bfrag[2*p+1][0], Bfrag[2*p+1][1]);
            }
            #pragma unroll
            for (int mt = 0; mt < 2; mt++)
                #pragma unroll
                for (int nt = 0; nt < 8; nt++)
                    mma16816(acc[mt][nt], Afrag[mt], Bfrag[nt]);
        }
        __syncthreads();
        sb += 10240u;
        if (sb == 30720u) sb = 0u;
    }

    #pragma unroll
    for (int mt = 0; mt < 2; mt++){
        int r0 = bm + wm*32 + mt*16 + (lane >> 2);
        #pragma unroll
        for (int nt = 0; nt < 8; nt++){
            int col = bn + wn*64 + nt*8 + ((lane & 3) << 1);
            if (col < N){
                float v0 = acc[mt][nt][0];
                float v1 = acc[mt][nt][1];
                float v2 = acc[mt][nt][2];
                float v3 = acc[mt][nt][3];
                float* Cb = (float*)Cv + (long)blockIdx.z * sC;
                *reinterpret_cast<float2*>(&Cb[(long)r0*ldc + col]) = make_float2(v0, v1);
                *reinterpret_cast<float2*>(&Cb[(long)(r0+8)*ldc + col]) = make_float2(v2, v3);
            }
        }
    }
}

// ---------------- 256x128 GEMM (TRANSB=0 only) ----------------
__device__ __forceinline__ void stage256(const bf16* Ab, const bf16* Bb,
    int bm, int bn, int N, int lda, int ldb, int k0, int tid,
    unsigned Adst, unsigned Bdst)
{
    #pragma unroll
    for (int c = tid; c < 1024; c += 256){
        int r  = c >> 2;
        int ko = (c & 3) << 3;
        cpasync16(Adst + 2u*(unsigned)(r*40 + ko),
                  Ab + (long)(bm + r)*lda + k0 + ko, 16);
    }
    #pragma unroll
    for (int c = tid; c < 512; c += 256){
        int r  = c >> 4;
        int no = (c & 15) << 3;
        const bf16* src = Bb + (long)(k0 + r)*ldb + bn + no;
        int ssz = 16;
        if (bn + no >= N){ src = Bb; ssz = 0; }
        cpasync16(Bdst + 2u*(unsigned)(r*136 + no), src, ssz);
    }
}

template<int EPI, int OUTBF>
__global__ void __launch_bounds__(256) bgemm256_k(
    const bf16* __restrict__ Aptr, const bf16* __restrict__ Bptr, void* __restrict__ Cv,
    int M, int N, int K, int lda, int ldb, int ldc,
    long sA, long sB, long sC, const float* __restrict__ bias,
    const float* __restrict__ resx, const int* __restrict__ mcnt)
{
    __shared__ bf16 As[3*10240];
    __shared__ bf16 Bs[3*4352];
    const int bm = blockIdx.y * 256;
    int Meff = M;
    if (mcnt) Meff = mcnt[blockIdx.z];
    if (bm >= Meff) return;
    const bf16* Ab = Aptr + (long)blockIdx.z * sA;
    const bf16* Bb = Bptr + (long)blockIdx.z * sB;
    const int bn = blockIdx.x * 128;
    const int tid  = threadIdx.x;
    const int lane = tid & 31;
    const int warp = tid >> 5;
    const int wm = warp >> 1;
    const int wn = warp & 1;

    float acc[4][8][4];
    #pragma unroll
    for (int i = 0; i < 4; i++)
        #pragma unroll
        for (int j = 0; j < 8; j++)
            #pragma unroll
            for (int q = 0; q < 4; q++) acc[i][j][q] = 0.f;

    unsigned Afrag[4][4];
    unsigned Bfrag[8][2];

    const unsigned As_base = (unsigned)__cvta_generic_to_shared(As);
    const unsigned Bs_base = (unsigned)__cvta_generic_to_shared(Bs);

    const int rowA = wm*64 + (lane & 15);
    const int colA = (lane >> 4) * 8;
    unsigned aoff[4];
    #pragma unroll
    for (int mt = 0; mt < 4; mt++)
        aoff[mt] = As_base + 2u*(unsigned)((rowA + mt*16)*40 + colA);

    unsigned boff[4];
    {
        int brow = lane & 15;
        int bcol = (lane >> 4) * 8;
        #pragma unroll
        for (int p = 0; p < 4; p++)
            boff[p] = Bs_base + 2u*(unsigned)(brow*136 + wn*64 + p*16 + bcol);
    }

    const int nk = K >> 5;
    stage256(Ab, Bb, bm, bn, N, lda, ldb, 0, tid, As_base, Bs_base);
    cp_commit();
    if (nk > 1){
        stage256(Ab, Bb, bm, bn, N, lda, ldb, 32, tid,
                 As_base + 20480u, Bs_base + 8704u);
        cp_commit();
    }

    unsigned sa = 0u, sbb = 0u;
    for (int it = 0; it < nk; it++){
        if (it + 1 < nk) cp_wait1(); else cp_wait0();
        __syncthreads();
        if (it + 2 < nk){
            unsigned st = (unsigned)((it + 2) % 3);
            stage256(Ab, Bb, bm, bn, N, lda, ldb, (it+2) << 5, tid,
                     As_base + st*20480u, Bs_base + st*8704u);
            cp_commit();
        }
        #pragma unroll
        for (int ks = 0; ks < 32; ks += 16){
            #pragma unroll
            for (int mt = 0; mt < 4; mt++)
                ldsm_x4(aoff[mt] + sa + 2u*ks,
                        Afrag[mt][0], Afrag[mt][1], Afrag[mt][2], Afrag[mt][3]);
            #pragma unroll
            for (int p = 0; p < 4; p++){
                unsigned ba = boff[p] + sbb + 2u*(unsigned)(ks*136);
                ldsm_x4_t(ba, Bfrag[2*p][0], Bfrag[2*p][1],
                              Bfrag[2*p+1][0], Bfrag[2*p+1][1]);
            }
            #pragma unroll
            for (int mt = 0; mt < 4; mt++)
                #pragma unroll
                for (int nt = 0; nt < 8; nt++)
                    mma16816(acc[mt][nt], Afrag[mt], Bfrag[nt]);
        }
        __syncthreads();
        sa += 20480u;  if (sa == 61440u) sa = 0u;
        sbb += 8704u;  if (sbb == 26112u) sbb = 0u;
    }

    #pragma unroll
    for (int mt = 0; mt < 4; mt++){
        int r0 = bm + wm*64 + mt*16 + (lane >> 2);
        #pragma unroll
        for (int nt = 0; nt < 8; nt++){
            int col = bn + wn*64 + nt*8 + ((lane & 3) << 1);
            if (col < N){
                float v0 = acc[mt][nt][0];
                float v1 = acc[mt][nt][1];
                float v2 = acc[mt][nt][2];
                float v3 = acc[mt][nt][3];
                if (EPI == 3){
                    bf16* Cb = (bf16*)Cv + (long)blockIdx.z * sC;
                    int jc = col >> 1;
                    Cb[(long)r0*(N>>1) + jc]     = __float2bfloat16(siluf(v0)*v1);
                    Cb[(long)(r0+8)*(N>>1) + jc] = __float2bfloat16(siluf(v2)*v3);
                    continue;
                }
                if (EPI == 1){
                    float b0 = bias[col];
                    float b1 = bias[col+1];
                    v0 = fmaxf(v0+b0, 0.f); v1 = fmaxf(v1+b1, 0.f);
                    v2 = fmaxf(v2+b0, 0.f); v3 = fmaxf(v3+b1, 0.f);
                }
                if (EPI == 2){
                    float b0 = bias[col];
                    float b1 = bias[col+1];
                    v0 = fmaf(b0, v0, resx[(long)r0*ldc + col]);
                    v1 = fmaf(b1, v1, resx[(long)r0*ldc + col + 1]);
                    v2 = fmaf(b0, v2, resx[(long)(r0+8)*ldc + col]);
                    v3 = fmaf(b1, v3, resx[(long)(r0+8)*ldc + col + 1]);
                }
                if (OUTBF){
                    bf16* Cb = (bf16*)Cv + (long)blockIdx.z * sC;
                    *reinterpret_cast<__nv_bfloat162*>(&Cb[(long)r0*ldc + col]) =
                        __floats2bfloat162_rn(v0, v1);
                    *reinterpret_cast<__nv_bfloat162*>(&Cb[(long)(r0+8)*ldc + col]) =
                        __floats2bfloat162_rn(v2, v3);
                } else {
                    float* Cb = (float*)Cv + (long)blockIdx.z * sC;
                    *reinterpret_cast<float2*>(&Cb[(long)r0*ldc + col]) = make_float2(v0, v1);
                    *reinterpret_cast<float2*>(&Cb[(long)(r0+8)*ldc + col]) = make_float2(v2, v3);
                }
            }
        }
    }
}

// ---------------- fused flash attention ----------------
#define FTILE (128*136)
#define FSMEM (5*FTILE*2)

__device__ __forceinline__ void fstage(const bf16* src, unsigned dst, int tid){
    for (int i = tid; i < 2048; i += 256){
        int r = i >> 4, c = (i & 15) << 3;
        cpasync16(dst + 2u*(unsigned)(r*136 + c), src + r*DH + c, 16);
    }
}

__global__ void __launch_bounds__(256, 1) flash_k(
    const bf16* __restrict__ q, const bf16* __restrict__ k, const bf16* __restrict__ v,
    const float* __restrict__ ascale, bf16* __restrict__ att)
{
    extern __shared__ bf16 fs[];
    const int qt = blockIdx.x, bh = blockIdx.y;
    const int bb = bh >> 3, hh = bh & 7;
    const int tid = threadIdx.x, lane = tid & 31, w = tid >> 5;
    const float a = ascale[hh];

    const bf16* qg = q + ((long)bh*LSEQ + qt*128)*DH;
    const bf16* kg = k + (long)bh*LSEQ*DH;
    const bf16* vg = v + (long)bh*LSEQ*DH;

    const unsigned Qb = (unsigned)__cvta_generic_to_shared(fs);
    const unsigned Kb = Qb + 2u*FTILE;
    const unsigned Vb = Qb + 6u*FTILE;
    const unsigned TILEB = 2u*FTILE;

    fstage(qg, Qb, tid);
    fstage(kg, Kb, tid);
    fstage(vg, Vb, tid);
    cp_commit();
    cp_wait0();
    __syncthreads();

    unsigned qf[8][4];
    {
        int rq = w*16 + (lane & 15);
        int cq = (lane >> 4) << 3;
        #pragma unroll
        for (int ks = 0; ks < 8; ks++)
            ldsm_x4(Qb + 2u*(unsigned)(rq*136 + ks*16 + cq),
                    qf[ks][0], qf[ks][1], qf[ks][2], qf[ks][3]);
    }

    const int brow = (lane & 7) + (((lane >> 4) & 1) << 3);
    const int bcol = ((lane >> 3) & 1) << 3;
    unsigned kadr[8], vadr[8];
    #pragma unroll
    for (int p = 0; p < 8; p++){
        kadr[p] = Kb + 2u*(unsigned)((p*16 + brow)*136 + bcol);
        vadr[p] = Vb + 2u*(unsigned)((lane & 15)*136 + p*16 + ((lane >> 4) << 3));
    }

    float oacc[16][4];
    #pragma unroll
    for (int nt = 0; nt < 16; nt++)
        #pragma unroll
        for (int qq = 0; qq < 4; qq++) oacc[nt][qq] = 0.f;
    float m0 = -1e30f, m1 = -1e30f, l0 = 0.f, l1 = 0.f;

    for (int kt = 0; kt < 16; kt++){
        if (kt > 0){ cp_wait0(); __syncthreads(); }
        if (kt + 1 < 16){
            unsigned off = ((kt + 1) & 1) ? TILEB : 0u;
            fstage(kg + (long)(kt+1)*128*DH, Kb + off, tid);
            fstage(vg + (long)(kt+1)*128*DH, Vb + off, tid);
            cp_commit();
        }
        const unsigned sb = (kt & 1) ? TILEB : 0u;

        float sacc[16][4];
        #pragma unroll
        for (int nt = 0; nt < 16; nt++)
            #pragma unroll
            for (int qq = 0; qq < 4; qq++) sacc[nt][qq] = 0.f;

        #pragma unroll
        for (int ks = 0; ks < 8; ks++){
            #pragma unroll
            for (int p = 0; p < 8; p++){
                unsigned bf0[2], bf1[2];
                ldsm_x4(kadr[p] + sb + 2u*(unsigned)(ks*16),
                        bf0[0], bf0[1], bf1[0], bf1[1]);
                mma16816(sacc[2*p],   qf[ks], bf0);
                mma16816(sacc[2*p+1], qf[ks], bf1);
            }
        }

        float ax0 = -1e30f, ax1 = -1e30f;
        #pragma unroll
        for (int nt = 0; nt < 16; nt++){
            sacc[nt][0] *= a; sacc[nt][1] *= a; sacc[nt][2] *= a; sacc[nt][3] *= a;
            ax0 = fmaxf(ax0, fmaxf(sacc[nt][0], sacc[nt][1]));
            ax1 = fmaxf(ax1, fmaxf(sacc[nt][2], sacc[nt][3]));
        }
        ax0 = fmaxf(ax0, __shfl_xor_sync(0xffffffffu, ax0, 1));
        ax0 = fmaxf(ax0, __shfl_xor_sync(0xffffffffu, ax0, 2));
        ax1 = fmaxf(ax1, __shfl_xor_sync(0xffffffffu, ax1, 1));
        ax1 = fmaxf(ax1, __shfl_xor_sync(0xffffffffu, ax1, 2));
        float mn0 = fmaxf(m0, ax0), mn1 = fmaxf(m1, ax1);
        float f0 = expf(m0 - mn0), f1 = expf(m1 - mn1);

        float rs0 = 0.f, rs1 = 0.f;
        #pragma unroll
        for (int nt = 0; nt < 16; nt++){
            sacc[nt][0] = expf(sacc[nt][0] - mn0);
            sacc[nt][1] = expf(sacc[nt][1] - mn0);
            sacc[nt][2] = expf(sacc[nt][2] - mn1);
            sacc[nt][3] = expf(sacc[nt][3] - mn1);
            rs0 += sacc[nt][0] + sacc[nt][1];
            rs1 += sacc[nt][2] + sacc[nt][3];
        }
        rs0 += __shfl_xor_sync(0xffffffffu, rs0, 1);
        rs0 += __shfl_xor_sync(0xffffffffu, rs0, 2);
        rs1 += __shfl_xor_sync(0xffffffffu, rs1, 1);
        rs1 += __shfl_xor_sync(0xffffffffu, rs1, 2);
        l0 = l0*f0 + rs0; l1 = l1*f1 + rs1;
        m0 = mn0; m1 = mn1;

        #pragma unroll
        for (int nt = 0; nt < 16; nt++){
            oacc[nt][0] *= f0; oacc[nt][1] *= f0;
            oacc[nt][2] *= f1; oacc[nt][3] *= f1;
        }

        unsigned pa[8][4];
        #pragma unroll
        for (int ksp = 0; ksp < 8; ksp++){
            pa[ksp][0] = pkbf2(sacc[2*ksp][0],   sacc[2*ksp][1]);
            pa[ksp][1] = pkbf2(sacc[2*ksp][2],   sacc[2*ksp][3]);
            pa[ksp][2] = pkbf2(sacc[2*ksp+1][0], sacc[2*ksp+1][1]);
            pa[ksp][3] = pkbf2(sacc[2*ksp+1][2], sacc[2*ksp+1][3]);
        }

        #pragma unroll
        for (int ksp = 0; ksp < 8; ksp++){
            #pragma unroll
            for (int p = 0; p < 8; p++){
                unsigned bf0[2], bf1[2];
                ldsm_x4_t(vadr[p] + sb + 2u*(unsigned)(ksp*16*136),
                          bf0[0], bf0[1], bf1[0], bf1[1]);
                mma16816(oacc[2*p],   pa[ksp], bf0);
                mma16816(oacc[2*p+1], pa[ksp], bf1);
            }
        }
    }

    float inv0 = 1.f / l0, inv1 = 1.f / l1;
    long row0 = (long)bb*LSEQ + qt*128 + w*16 + (lane >> 2);
    long row1 = row0 + 8;
    int  cbase = hh*DH + ((lane & 3) << 1);
    #pragma unroll
    for (int nt = 0; nt < 16; nt++){
        int col = cbase + nt*8;
        *reinterpret_cast<__nv_bfloat162*>(&att[row0*DM + col]) =
            __floats2bfloat162_rn(oacc[nt][0]*inv0, oacc[nt][1]*inv0);
        *reinterpret_cast<__nv_bfloat162*>(&att[row1*DM + col]) =
            __floats2bfloat162_rn(oacc[nt][2]*inv1, oacc[nt][3]*inv1);
    }
}

// ---------------- depthwise conv + bias + SiLU ----------------
__global__ void conv_k(const float* __restrict__ xz, const float* __restrict__ cw,
                       const float* __restrict__ cb, float* __restrict__ xc,
                       bf16* __restrict__ xcb){
    long idx = (long)blockIdx.x*blockDim.x + threadIdx.x;
    if (idx >= (long)NTOK*DI) return;
    int d = (int)(idx % DI);
    int row = (int)(idx / DI);
    int t = row % LSEQ, b = row / LSEQ;
    float s = cb[d];
    #pragma unroll
    for (int k = 0; k < 4; k++){
        int tt = t + k - 2;
        if (tt >= 0 && tt < LSEQ)
            s = fmaf(cw[d*4+k], xz[(long)(b*LSEQ+tt)*(2*DI) + d], s);
    }
    float v = siluf(s);
    xc[idx] = v;
    xcb[idx] = __float2bfloat16(v);
}

// ---------------- scan preprocessing ----------------
__global__ void scanprep_k(const float* __restrict__ dtBC, const float* __restrict__ bdt,
                           const float* __restrict__ A, float* __restrict__ sp){
    int idx = blockIdx.x*blockDim.x + threadIdx.x;
    if (idx >= NTOK*16) return;
    int n = idx & 15, row = idx >> 4;
    float dtp = dtBC[(long)row*64 + n] + bdt[n];
    float dt  = fmaxf(dtp, 0.f) + log1pf(expf(-fabsf(dtp)));
    sp[(long)row*48 + n]      = expf(dt * A[n]);
    sp[(long)row*48 + 16 + n] = dt * dtBC[(long)row*64 + 16 + n];
    sp[(long)row*48 + 32 + n] = dtBC[(long)row*64 + 32 + n];
}

// ---------------- chunked selective scan ----------------
__global__ void scanP_k(const float* __restrict__ sp, float* __restrict__ P){
    int b = blockIdx.x / NCH, ch = blockIdx.x % NCH;
    int n = threadIdx.x;
    if (n >= 16) return;
    float p = 1.f;
    long base = ((long)b*LSEQ + ch*CLEN)*48;
    for (int t = 0; t < CLEN; t++) p *= sp[base + t*48 + n];
    P[(b*NCH+ch)*16 + n] = p;
}

__global__ void scanA_k(const float* __restrict__ sp, const float* __restrict__ xc,
                        float* __restrict__ hend){
    int b = blockIdx.z, ch = blockIdx.y;
    int d = blockIdx.x*128 + threadIdx.x;
    __shared__ float s[CLEN*48];
    const float* src = sp + ((long)b*LSEQ + ch*CLEN)*48;
    for (int i = threadIdx.x; i < CLEN*48; i += 128) s[i] = src[i];
    __syncthreads();
    float h[16];
    #pragma unroll
    for (int n = 0; n < 16; n++) h[n] = 0.f;
    long rowbase = (long)b*LSEQ + ch*CLEN;
    float xv_next = xc[rowbase*DI + d];
    for (int tt = 0; tt < CLEN; tt++){
        float xv = xv_next;
        if (tt + 1 < CLEN) xv_next = xc[(rowbase + tt + 1)*DI + d];
        const float* e = s + tt*48;
        #pragma unroll
        for (int n = 0; n < 16; n++)
            h[n] = fmaf(e[n], h[n], e[16+n]*xv);
    }
    float* o = hend + (((long)(b*NCH + ch)*DI + d) << 4);
    #pragma unroll
    for (int n = 0; n < 16; n += 4)
        *reinterpret_cast<float4*>(o + n) = make_float4(h[n], h[n+1], h[n+2], h[n+3]);
}

__global__ void scanComb_k(const float* __restrict__ hend, const float* __restrict__ P,
                           float* __restrict__ h0){
    int g = blockIdx.x*128 + threadIdx.x;
    int b = g / DI, d = g % DI;
    __shared__ float sP[NCH*16];
    for (int i = threadIdx.x; i < NCH*16; i += 128) sP[i] = P[b*NCH*16 + i];
    __syncthreads();
    float h[16];
    #pragma unroll
    for (int n = 0; n < 16; n++) h[n] = 0.f;
    {
        float* o = h0 + (((long)(b*NCH)*DI + d) << 4);
        #pragma unroll
        for (int n = 0; n < 16; n += 4)
            *reinterpret_cast<float4*>(o + n) = make_float4(0.f, 0.f, 0.f, 0.f);
    }
    for (int c = 1; c < NCH; c++){
        const float* he = hend + (((long)(b*NCH + c - 1)*DI + d) << 4);
        #pragma unroll
        for (int n = 0; n < 16; n++)
            h[n] = fmaf(sP[(c-1)*16 + n], h[n], he[n]);
        float* o = h0 + (((long)(b*NCH + c)*DI + d) << 4);
        #pragma unroll
        for (int n = 0; n < 16; n += 4)
            *reinterpret_cast<float4*>(o + n) = make_float4(h[n], h[n+1], h[n+2], h[n+3]);
    }
}

__global__ void scanC_k(const float* __restrict__ sp, const float* __restrict__ xc,
                        const float* __restrict__ xz, const float* __restrict__ Dp,
                        const float* __restrict__ h0, bf16* __restrict__ ymulb){
    int b = blockIdx.z, ch = blockIdx.y;
    int d = blockIdx.x*128 + threadIdx.x;
    __shared__ float s[CLEN*48];
    const float* src = sp + ((long)b*LSEQ + ch*CLEN)*48;
    for (int i = threadIdx.x; i < CLEN*48; i += 128) s[i] = src[i];
    __syncthreads();
    float h[16];
    {   const float* hi = h0 + (((long)(b*NCH + ch)*DI + d) << 4);
        #pragma unroll
        for (int n = 0; n < 16; n += 4){
            float4 v = *reinterpret_cast<const float4*>(hi + n);
            h[n] = v.x; h[n+1] = v.y; h[n+2] = v.z; h[n+3] = v.w;
        }
    }
    const float dpv = Dp[d];
    long rowbase = (long)b*LSEQ + ch*CLEN;
    float xv_next = xc[rowbase*DI + d];
    float z_next  = xz[rowbase*(2*DI) + DI + d];
    for (int tt = 0; tt < CLEN; tt++){
        float xv = xv_next;
        float z  = z_next;
        if (tt + 1 < CLEN){
            xv_next = xc[(rowbase + tt + 1)*DI + d];
            z_next  = xz[(rowbase + tt + 1)*(2*DI) + DI + d];
        }
        const float* e = s + tt*48;
        float y = 0.f;
        #pragma unroll
        for (int n = 0; n < 16; n++){
            h[n] = fmaf(e[n], h[n], e[16+n]*xv);
            y = fmaf(h[n], e[32+n], y);
        }
        ymulb[(rowbase + tt)*DI + d] = __float2bfloat16((y + dpv*xv) * siluf(z));
    }
}

// ---------------- RoPE -> qb,kb,vb bf16 ----------------
__global__ void rope2_k(const float* __restrict__ qkv, bf16* __restrict__ qb,
                        bf16* __restrict__ kb, bf16* __restrict__ vb){
    int row = blockIdx.x;
    int t = row % LSEQ, b = row / LSEQ;
    __shared__ float q[DM], kk[DM];
    const float* base = qkv + (long)row*3*DM;
    for (int i = threadIdx.x; i < DM; i += 256){ q[i] = base[i]; kk[i] = base[DM+i]; }
    __syncthreads();
    const float sq = sqrtf((float)DH);
    const float lg = logf(10000.f) / 64.f;
    for (int idx = threadIdx.x; idx < DM; idx += 256){
        int h = idx / DH, i = idx % DH;
        int j = i & 63;
        float inv = expf(-(float)j * lg);
        float ang = (float)t * inv;
        float c = cosf(ang), s = sinf(ang);
        int off = h * DH;
        float rq, rk;
        if (i < 64){ rq = -q[off + 2*i + 1]; rk = -kk[off + 2*i + 1]; }
        else       { rq =  q[off + 2*(i-64)]; rk =  kk[off + 2*(i-64)]; }
        long o = ((long)(b*NH + h)*LSEQ + t)*DH + i;
        qb[o] = __float2bfloat16((q[idx]*c + rq*s) * sq);
        kb[o] = __float2bfloat16(kk[idx]*c + rk*s);
        vb[o] = __float2bfloat16(base[2*DM + idx]);
    }
}

// ---------------- gate stage 2 (also zeroes expert counters) ----------------
__global__ void gate2_k(const float* __restrict__ g1, const float* __restrict__ Wg2,
                        float* __restrict__ gs, int* __restrict__ topi, float* __restrict__ topw,
                        int* __restrict__ cnt){
    int row = blockIdx.x;
    int tid = threadIdx.x;
    if (row == 0 && tid < NEXP) cnt[tid] = 0;   // safe: assign_k launches after this kernel retires
    __shared__ float red[64*4];
    float a[4] = {0.f,0.f,0.f,0.f};
    for (int j = tid; j < 512; j += 64){
        float v = g1[(long)row*512 + j];
        #pragma unroll
        for (int e = 0; e < 4; e++) a[e] = fmaf(v, Wg2[j*4+e], a[e]);
    }
    #pragma unroll
    for (int e = 0; e < 4; e++) red[e*64 + tid] = a[e];
    __syncthreads();
    for (int st = 32; st > 0; st >>= 1){
        if (tid < st){
            #pragma unroll
            for (int e = 0; e < 4; e++) red[e*64+tid] += red[e*64+tid+st];
        }
        __syncthreads();
    }
    if (tid == 0){
        float l[4]; for (int e = 0; e < 4; e++) l[e] = red[e*64];
        float m = fmaxf(fmaxf(l[0],l[1]), fmaxf(l[2],l[3]));
        float ex[4]; float s = 0.f;
        for (int e = 0; e < 4; e++){ ex[e] = expf(l[e]-m); s += ex[e]; }
        float gsv[4];
        for (int e = 0; e < 4; e++){ gsv[e] = ex[e]/s; gs[(long)row*4+e] = gsv[e]; }
        int i0 = 0;
        for (int e = 1; e < 4; e++) if (gsv[e] > gsv[i0]) i0 = e;
        int i1 = -1;
        for (int e = 0; e < 4; e++) if (e != i0 && (i1 < 0 || gsv[e] > gsv[i1])) i1 = e;
        float v0 = gsv[i0], v1 = gsv[i1];
        float mm = fmaxf(v0, v1);
        float w0 = expf(v0-mm), w1 = expf(v1-mm);
        float ws = w0 + w1;
        topi[row*2] = i0; topi[row*2+1] = i1;
        topw[row*2] = w0/ws; topw[row*2+1] = w1/ws;
    }
}

// ---------------- balance loss ----------------
__global__ void bal_k(const float* __restrict__ gs, float* __restrict__ out){
    int tid = threadIdx.x;
    __shared__ float red[256*4];
    float a[4] = {0.f,0.f,0.f,0.f};
    for (int r = tid; r < NTOK; r += 256){
        #pragma unroll
        for (int e = 0; e < 4; e++) a[e] += gs[(long)r*4+e];
    }
    #pragma unroll
    for (int e = 0; e < 4; e++) red[e*256+tid] = a[e];
    __syncthreads();
    for (int st = 128; st > 0; st >>= 1){
        if (tid < st){
            #pragma unroll
            for (int e = 0; e < 4; e++) red[e*256+tid] += red[e*256+tid+st];
        }
        __syncthreads();
    }
    if (tid == 0){
        float bal = 0.f;
        for (int e = 0; e < 4; e++){
            float gm = red[e*256] / (float)NTOK;
            bal += gm * logf(gm + 1e-8f);
        }
        out[0] = (float)NEXP * bal;
    }
}

// ---------------- MoE routing ----------------
__global__ void assign_k(const int* __restrict__ topi, int* __restrict__ cnt,
                         int* __restrict__ slot){
    int idx = blockIdx.x*256 + threadIdx.x;
    if (idx >= NTOK*2) return;
    int e = topi[idx];
    int s = atomicAdd(&cnt[e], 1);
    slot[idx] = e*NTOK + s;
}

__global__ void gather_k(const bf16* __restrict__ xf, const int* __restrict__ slot,
                         bf16* __restrict__ xg){
    int idx = blockIdx.x;
    int tok = idx >> 1;
    int dst = slot[idx];
    const unsigned* src = reinterpret_cast<const unsigned*>(xf) + (long)tok*(DM/2);
    unsigned* d = reinterpret_cast<unsigned*>(xg) + (long)dst*(DM/2);
    for (int i = threadIdx.x; i < DM/2; i += 128) d[i] = src[i];
}

// ---------------- MoE combine + final residual ----------------
__global__ void combine2_k(const float* __restrict__ x2, const float* __restrict__ ls3,
                           const bf16* __restrict__ eo, const int* __restrict__ slot,
                           const float* __restrict__ topw, float* __restrict__ out){
    long idx = (long)blockIdx.x*blockDim.x + threadIdx.x;
    if (idx >= (long)NTOK*DM) return;
    int row = (int)(idx / DM), d = (int)(idx % DM);
    int s0 = slot[row*2], s1 = slot[row*2+1];
    float m = topw[row*2]   * __bfloat162float(eo[(long)s0*DM + d])
            + topw[row*2+1] * __bfloat162float(eo[(long)s1*DM + d]);
    out[idx] = fmaf(ls3[d], m, x2[idx]);
}

// ============================== host ==============================
#define SYMPF(p, s) do { void* _t; cudaGetSymbolAddress(&_t, s); p = (float*)_t; } while(0)
#define SYMPB(p, s) do { void* _t; cudaGetSymbolAddress(&_t, s); p = (bf16*)_t; } while(0)
#define SYMPI(p, s) do { void* _t; cudaGetSymbolAddress(&_t, s); p = (int*)_t; } while(0)

extern "C" void kernel_launch(void* const* d_in, const int* in_sizes, int n_in,
                              void* d_out, int out_size){
    const float* x      = (const float*)d_in[0];
    const float* rms1_w = (const float*)d_in[1];
    const float* rms2_w = (const float*)d_in[2];
    const float* rms3_w = (const float*)d_in[3];
    const float* ls1    = (const float*)d_in[4];
    const float* ls2    = (const float*)d_in[5];
    const float* ls3    = (const float*)d_in[6];
    const float* W_in   = (const float*)d_in[7];
    const float* conv_w = (const float*)d_in[8];
    const float* conv_b = (const float*)d_in[9];
    const float* W_B    = (const float*)d_in[10];
    const float* W_C    = (const float*)d_in[11];
    const float* W_dt   = (const float*)d_in[12];
    const float* b_dt   = (const float*)d_in[13];
    const float* W_out_m= (const float*)d_in[14];
    const float* Avec   = (const float*)d_in[15];
    const float* Dp     = (const float*)d_in[16];
    const float* W_qkv  = (const float*)d_in[17];
    const float* W_o    = (const float*)d_in[18];
    const float* ascale = (const float*)d_in[19];
    const float* Wg1    = (const float*)d_in[20];
    const float* bg1    = (const float*)d_in[21];
    const float* Wg2    = (const float*)d_in[22];
    const float* w1     = (const float*)d_in[23];
    const float* w2     = (const float*)d_in[24];
    const float* w3     = (const float*)d_in[25];
    float* out = (float*)d_out;

    float *p_xz, *p_xc, *p_dtBC, *p_scanp, *p_x1, *p_qkv, *p_x2, *p_g1, *p_gs, *p_topw;
    float *p_hend, *p_h0, *p_P;
    int *p_topi, *p_cnt, *p_slot;
    bf16 *b_rms1, *b_xc, *b_ymul, *b_rms2, *b_q, *b_k, *b_v, *b_att, *b_xf,
         *b_xg, *b_h, *b_eo;
    bf16 *b_Win, *b_Wout, *b_Wqkv, *b_Wo, *b_Wg1, *b_w12, *b_w3, *b_Wcat;

    SYMPF(p_xz, g_xz); SYMPF(p_xc, g_xc); SYMPF(p_dtBC, g_dtBC); SYMPF(p_scanp, g_scanp);
    SYMPF(p_x1, g_x1); SYMPF(p_qkv, g_qkv);
    SYMPF(p_x2, g_x2); SYMPF(p_g1, g_g1); SYMPF(p_gs, g_gs); SYMPF(p_topw, g_topw);
    SYMPF(p_hend, g_hend); SYMPF(p_h0, g_h0); SYMPF(p_P, g_P);
    SYMPI(p_topi, g_topi); SYMPI(p_cnt, g_cnt); SYMPI(p_slot, g_slot);
    SYMPB(b_rms1, g_rms1b); SYMPB(b_xc, g_xcb); SYMPB(b_ymul, g_ymulb); SYMPB(b_rms2, g_rms2b);
    SYMPB(b_q, g_qb); SYMPB(b_k, g_kb); SYMPB(b_v, g_vb);
    SYMPB(b_att, g_attb); SYMPB(b_xf, g_xfb); SYMPB(b_xg, g_xgb);
    SYMPB(b_h, g_hb); SYMPB(b_eo, g_eob);
    SYMPB(b_Win, g_Winb); SYMPB(b_Wout, g_Woutb); SYMPB(b_Wqkv, g_Wqkvb); SYMPB(b_Wo, g_Wob);
    SYMPB(b_Wg1, g_Wg1b); SYMPB(b_w12, g_w12b); SYMPB(b_w3, g_w3b); SYMPB(b_Wcat, g_Wcatb);

    // ---- weight conversions ----
    #define CONV(src, dst, n) f2bf_k<<<(int)(((n)/4 + 255)/256), 256>>>(src, dst, (long)(n))
    CONV(W_in,   b_Win,  (long)DM*2*DI);
    CONV(W_out_m,b_Wout, (long)DI*DM);
    CONV(W_qkv,  b_Wqkv, (long)DM*3*DM);
    CONV(W_o,    b_Wo,   (long)DM*DM);
    CONV(Wg1,    b_Wg1,  (long)DM*512);
    CONV(w3,     b_w3,   (long)NEXP*DFF*DM);
    pack12_k<<<(int)(((long)NEXP*DM*DFF/4 + 255)/256), 256>>>(w1, w2, b_w12);
    packw_k<<<(DI*64+255)/256, 256>>>(W_dt, W_B, W_C, b_Wcat);

    // ---- 1. Mamba ----
    rmsnorm_bf_k<<<NTOK, 256>>>(x, rms1_w, b_rms1);
    {   dim3 g(2*DI/128, NTOK/256, 1);
        bgemm256_k<0,0><<<g, 256>>>(b_rms1, b_Win, p_xz, NTOK, 2*DI, DM, DM, 2*DI, 2*DI,
                                    0,0,0, nullptr, nullptr, nullptr); }
    conv_k<<<(int)(((long)NTOK*DI+255)/256), 256>>>(p_xz, conv_w, conv_b, p_xc, b_xc);
    {   dim3 g(1, NTOK/128, 1);
        bgemm_k<0,0,0><<<g, 256>>>(b_xc, b_Wcat, p_dtBC, NTOK, 64, DI, DI, 64, 64,
                                   0,0,0, nullptr, nullptr, nullptr); }
    scanprep_k<<<(NTOK*16+255)/256, 256>>>(p_dtBC, b_dt, Avec, p_scanp);
    scanP_k<<<BB*NCH, 16>>>(p_scanp, p_P);
    {   dim3 g(16, NCH, BB);
        scanA_k<<<g, 128>>>(p_scanp, p_xc, p_hend); }
    scanComb_k<<<BB*DI/128, 128>>>(p_hend, p_P, p_h0);
    {   dim3 g(16, NCH, BB);
        scanC_k<<<g, 128>>>(p_scanp, p_xc, p_xz, Dp, p_h0, b_ymul); }
    {   dim3 g(DM/128, NTOK/256, 1);   // x1 = x + ls1 * (ymul @ Wout)
        bgemm256_k<2,0><<<g, 256>>>(b_ymul, b_Wout, p_x1, NTOK, DM, DI, DI, DM, DM,
                                    0,0,0, ls1, x, nullptr); }

    // ---- 2. Attention ----
    rmsnorm_bf_k<<<NTOK, 256>>>(p_x1, rms2_w, b_rms2);
    {   dim3 g(3*DM/128, NTOK/256, 1);
        bgemm256_k<0,0><<<g, 256>>>(b_rms2, b_Wqkv, p_qkv, NTOK, 3*DM, DM, DM, 3*DM, 3*DM,
                                    0,0,0, nullptr, nullptr, nullptr); }
    rope2_k<<<NTOK, 256>>>(p_qkv, b_q, b_k, b_v);
    {   cudaFuncSetAttribute(flash_k, cudaFuncAttributeMaxDynamicSharedMemorySize, FSMEM);
        dim3 g(LSEQ/128, BB*NH, 1);
        flash_k<<<g, 256, FSMEM>>>(b_q, b_k, b_v, ascale, b_att); }
    {   dim3 g(DM/128, NTOK/256, 1);   // x2 = x1 + ls2 * (att @ Wo)
        bgemm256_k<2,0><<<g, 256>>>(b_att, b_Wo, p_x2, NTOK, DM, DM, DM, DM, DM,
                                    0,0,0, ls2, p_x1, nullptr); }

    // ---- 3. MoE (top-2 sparse) ----
    rmsnorm_bf_k<<<NTOK, 256>>>(p_x2, rms3_w, b_xf);
    {   dim3 g(512/128, NTOK/256, 1);
        bgemm256_k<1,0><<<g, 256>>>(b_xf, b_Wg1, p_g1, NTOK, 512, DM, DM, 512, 512,
                                    0,0,0, bg1, nullptr, nullptr); }
    gate2_k<<<NTOK, 64>>>(p_g1, Wg2, p_gs, p_topi, p_topw, p_cnt);
    if (out_size > NTOK*DM)
        bal_k<<<1, 256>>>(p_gs, out + (long)NTOK*DM);
    assign_k<<<(NTOK*2+255)/256, 256>>>(p_topi, p_cnt, p_slot);
    gather_k<<<NTOK*2, 128>>>(b_xf, p_slot, b_xg);
    {   dim3 g12(2*DFF/128, NTOK/256, NEXP);
        bgemm256_k<3,1><<<g12, 256>>>(b_xg, b_w12, b_h,
                                      NTOK, 2*DFF, DM, DM, 2*DFF, 2*DFF,
                                      (long)NTOK*DM, (long)DM*2*DFF, (long)NTOK*DFF,
                                      nullptr, nullptr, p_cnt);
    }
    {   dim3 g3(DM/128, NTOK/256, NEXP);
        bgemm256_k<0,1><<<g3, 256>>>(b_h, b_w3, b_eo,
                                     NTOK, DM, DFF, DFF, DM, DM,
                                     (long)NTOK*DFF, (long)DFF*DM, (long)NTOK*DM,
                                     nullptr, nullptr, p_cnt);
    }
    combine2_k<<<(int)(((long)NTOK*DM+255)/256), 256>>>(p_x2, ls3, b_eo, p_slot, p_topw, out);
}

// round 12
// speedup vs baseline: 10.5475x; 1.0139x over previous
#include <cuda_runtime.h>
#include <cuda_bf16.h>
#include <math.h>

#define BB   2
#define LSEQ 2048
#define DM   1024
#define DI   2048
#define NH   8
#define DH   128
#define NEXP 4
#define DFF  4096
#define NTOK (BB*LSEQ)   // 4096
#define NCH  16
#define CLEN 128         // LSEQ/NCH

typedef __nv_bfloat16 bf16;

// ---------------- static scratch ----------------
__device__ float g_xz[NTOK*2*DI];
__device__ float g_xc[NTOK*DI];
__device__ float g_dtBC[NTOK*64];
__device__ float g_scanp[NTOK*48];
__device__ float g_x1[NTOK*DM];
__device__ float g_x2[NTOK*DM];
__device__ float g_g1[NTOK*512];
__device__ float g_gs[NTOK*NEXP];
__device__ int   g_topi[NTOK*2];
__device__ float g_topw[NTOK*2];
__device__ int   g_cnt[NEXP];
__device__ int   g_slot[NTOK*2];
__device__ float g_hend[BB*NCH*DI*16];
__device__ float g_h0[BB*NCH*DI*16];
__device__ float g_P[BB*NCH*16];

// bf16 activations
__device__ bf16 g_rms1b[NTOK*DM];
__device__ bf16 g_xcb[NTOK*DI];
__device__ bf16 g_ymulb[NTOK*DI];
__device__ bf16 g_rms2b[NTOK*DM];
__device__ bf16 g_qkvb[NTOK*3*DM];
__device__ bf16 g_qb[NTOK*DM];
__device__ bf16 g_kb[NTOK*DM];
__device__ bf16 g_vb[NTOK*DM];
__device__ bf16 g_attb[NTOK*DM];
__device__ bf16 g_xfb[NTOK*DM];
__device__ bf16 g_xgb[NEXP*NTOK*DM];
__device__ bf16 g_hb[(long)NEXP*NTOK*DFF];
__device__ bf16 g_eob[NEXP*NTOK*DM];

// bf16 weights
__device__ bf16 g_Winb[DM*2*DI];
__device__ bf16 g_Woutb[DI*DM];
__device__ bf16 g_Wqkvb[DM*3*DM];
__device__ bf16 g_Wob[DM*DM];
__device__ bf16 g_Wg1b[DM*512];
__device__ bf16 g_w12b[(long)NEXP*DM*2*DFF];   // interleaved (w1_j, w2_j) pairs
__device__ bf16 g_w3b[(long)NEXP*DFF*DM];
__device__ bf16 g_Wcatb[DI*64];

__device__ __forceinline__ float siluf(float x){ return x / (1.f + expf(-x)); }

// ---------------- fp32 -> bf16 convert ----------------
__global__ void f2bf_k(const float* __restrict__ s, bf16* __restrict__ d, long n){
    long i = ((long)blockIdx.x*blockDim.x + threadIdx.x)*4;
    if (i >= n) return;
    float4 v = *reinterpret_cast<const float4*>(s+i);
    *reinterpret_cast<__nv_bfloat162*>(d+i)   = __floats2bfloat162_rn(v.x, v.y);
    *reinterpret_cast<__nv_bfloat162*>(d+i+2) = __floats2bfloat162_rn(v.z, v.w);
}

// pack w1|w2 INTERLEAVED
__global__ void pack12_k(const float* __restrict__ w1, const float* __restrict__ w2,
                         bf16* __restrict__ o){
    long i = ((long)blockIdx.x*blockDim.x + threadIdx.x)*4;
    if (i >= (long)NEXP*DM*DFF) return;
    long row = i >> 12;
    int  j   = (int)(i & 4095);
    float4 a = *reinterpret_cast<const float4*>(w1 + i);
    float4 b = *reinterpret_cast<const float4*>(w2 + i);
    bf16* d1 = o + row*(2*DFF) + 2*j;
    *reinterpret_cast<__nv_bfloat162*>(d1)   = __floats2bfloat162_rn(a.x, b.x);
    *reinterpret_cast<__nv_bfloat162*>(d1+2) = __floats2bfloat162_rn(a.y, b.y);
    *reinterpret_cast<__nv_bfloat162*>(d1+4) = __floats2bfloat162_rn(a.z, b.z);
    *reinterpret_cast<__nv_bfloat162*>(d1+6) = __floats2bfloat162_rn(a.w, b.w);
}

// pack [W_dt | W_B | W_C | 0] -> [2048][64] bf16
__global__ void packw_k(const float* __restrict__ Wdt, const float* __restrict__ WB,
                        const float* __restrict__ WC, bf16* __restrict__ o){
    int idx = blockIdx.x*256 + threadIdx.x;
    if (idx >= DI*64) return;
    int j = idx >> 6, n = idx & 63;
    float v = 0.f;
    if (n < 16) v = Wdt[j*16+n];
    else if (n < 32) v = WB[j*16+n-16];
    else if (n < 48) v = WC[j*16+n-32];
    o[idx] = __float2bfloat16(v);
}

// ---------------- RMSNorm -> bf16 ----------------
__global__ void rmsnorm_bf_k(const float* __restrict__ x, const float* __restrict__ w,
                             bf16* __restrict__ o){
    int row = blockIdx.x;
    const float* xr = x + (long)row*DM;
    __shared__ float red[256];
    float s = 0.f;
    for (int i = threadIdx.x; i < DM; i += 256){ float v = xr[i]; s += v*v; }
    red[threadIdx.x] = s; __syncthreads();
    for (int st = 128; st > 0; st >>= 1){
        if (threadIdx.x < st) red[threadIdx.x] += red[threadIdx.x+st];
        __syncthreads();
    }
    float r = rsqrtf(red[0]/(float)DM + 1e-6f);
    for (int i = threadIdx.x; i < DM; i += 256)
        o[(long)row*DM+i] = __float2bfloat16(w[i]*xr[i]*r);
}

// ---------------- MMA primitives ----------------
__device__ __forceinline__ void cpasync16(unsigned dst, const void* src, int ssz){
    asm volatile("cp.async.ca.shared.global [%0], [%1], 16, %2;"
        :: "r"(dst), "l"(src), "r"(ssz));
}
__device__ __forceinline__ void cp_commit(){ asm volatile("cp.async.commit_group;"); }
__device__ __forceinline__ void cp_wait0(){ asm volatile("cp.async.wait_group 0;"); }
__device__ __forceinline__ void cp_wait1(){ asm volatile("cp.async.wait_group 1;"); }
__device__ __forceinline__ void ldsm_x4(unsigned saddr, unsigned &o0, unsigned &o1,
                                        unsigned &o2, unsigned &o3){
    asm volatile("ldmatrix.sync.aligned.m8n8.x4.shared.b16 {%0,%1,%2,%3},[%4];"
        : "=r"(o0),"=r"(o1),"=r"(o2),"=r"(o3) : "r"(saddr));
}
__device__ __forceinline__ void ldsm_x4_t(unsigned saddr, unsigned &o0, unsigned &o1,
                                          unsigned &o2, unsigned &o3){
    asm volatile("ldmatrix.sync.aligned.m8n8.x4.trans.shared.b16 {%0,%1,%2,%3},[%4];"
        : "=r"(o0),"=r"(o1),"=r"(o2),"=r"(o3) : "r"(saddr));
}
__device__ __forceinline__ void mma16816(float* d, const unsigned* am, const unsigned* bm){
    asm volatile("mma.sync.aligned.m16n8k16.row.col.f32.bf16.bf16.f32 "
        "{%0,%1,%2,%3},{%4,%5,%6,%7},{%8,%9},{%0,%1,%2,%3};"
        : "+f"(d[0]),"+f"(d[1]),"+f"(d[2]),"+f"(d[3])
        : "r"(am[0]),"r"(am[1]),"r"(am[2]),"r"(am[3]), "r"(bm[0]),"r"(bm[1]));
}
__device__ __forceinline__ unsigned pkbf2(float x, float y){
    __nv_bfloat162 t = __floats2bfloat162_rn(x, y);
    return *reinterpret_cast<unsigned*>(&t);
}

// ---------------- 128x128 GEMM (fp32 out, no epilogue) ----------------
__device__ __forceinline__ void stage_tiles(const bf16* Ab, const bf16* Bb,
    int bm, int bn, int N, int lda, int ldb, int k0, int tid,
    unsigned Adst, unsigned Bdst)
{
    #pragma unroll
    for (int c = tid; c < 512; c += 256){
        int r  = c >> 2;
        int ko = (c & 3) << 3;
        cpasync16(Adst + 2u*(unsigned)(r*40 + ko),
                  Ab + (long)(bm + r)*lda + k0 + ko, 16);
    }
    #pragma unroll
    for (int c = tid; c < 512; c += 256){
        int r  = c >> 4;
        int no = (c & 15) << 3;
        const bf16* src = Bb + (long)(k0 + r)*ldb + bn + no;
        int ssz = 16;
        if (bn + no >= N){ src = Bb; ssz = 0; }
        cpasync16(Bdst + 2u*(unsigned)(r*136 + no), src, ssz);
    }
}

__global__ void __launch_bounds__(256) bgemm_k(
    const bf16* __restrict__ Aptr, const bf16* __restrict__ Bptr, float* __restrict__ Cv,
    int M, int N, int K, int lda, int ldb, int ldc)
{
    __shared__ bf16 As[3*5120];
    __shared__ bf16 Bs[3*5120];
    const int bm = blockIdx.y * 128;
    const int bn = blockIdx.x * 128;
    const int tid  = threadIdx.x;
    const int lane = tid & 31;
    const int warp = tid >> 5;
    const int wm = warp >> 1;
    const int wn = warp & 1;

    float acc[2][8][4];
    #pragma unroll
    for (int i = 0; i < 2; i++)
        #pragma unroll
        for (int j = 0; j < 8; j++)
            #pragma unroll
            for (int q = 0; q < 4; q++) acc[i][j][q] = 0.f;

    unsigned Afrag[2][4];
    unsigned Bfrag[8][2];

    const unsigned As_base = (unsigned)__cvta_generic_to_shared(As);
    const unsigned Bs_base = (unsigned)__cvta_generic_to_shared(Bs);

    const int rowA = wm*32 + (lane & 15);
    const int colA = (lane >> 4) * 8;
    unsigned aoff0 = As_base + 2u*(unsigned)( rowA       *40 + colA);
    unsigned aoff1 = As_base + 2u*(unsigned)((rowA + 16) *40 + colA);

    unsigned boff[4];
    #pragma unroll
    for (int p = 0; p < 4; p++){
        int brow = lane & 15;
        int bcol = (lane >> 4) * 8;
        boff[p] = Bs_base + 2u*(unsigned)(brow*136 + wn*64 + p*16 + bcol);
    }

    const int nk = K >> 5;
    stage_tiles(Aptr, Bptr, bm, bn, N, lda, ldb, 0, tid, As_base, Bs_base);
    cp_commit();
    if (nk > 1){
        stage_tiles(Aptr, Bptr, bm, bn, N, lda, ldb, 32, tid,
                    As_base + 10240u, Bs_base + 10240u);
        cp_commit();
    }

    unsigned sb = 0u;
    for (int it = 0; it < nk; it++){
        if (it + 1 < nk) cp_wait1(); else cp_wait0();
        __syncthreads();
        if (it + 2 < nk){
            unsigned off = (unsigned)((it + 2) % 3) * 10240u;
            stage_tiles(Aptr, Bptr, bm, bn, N, lda, ldb, (it+2) << 5, tid,
                        As_base + off, Bs_base + off);
            cp_commit();
        }
        #pragma unroll
        for (int ks = 0; ks < 32; ks += 16){
            ldsm_x4(aoff0 + sb + 2u*ks, Afrag[0][0], Afrag[0][1], Afrag[0][2], Afrag[0][3]);
            ldsm_x4(aoff1 + sb + 2u*ks, Afrag[1][0], Afrag[1][1], Afrag[1][2], Afrag[1][3]);
            #pragma unroll
            for (int p = 0; p < 4; p++){
                unsigned ba = boff[p] + sb + 2u*(unsigned)(ks*136);
                ldsm_x4_t(ba, Bfrag[2*p][0], Bfrag[2*p][1],
                              Bfrag[2*p+1][0], Bfrag[2*p+1][1]);
            }
            #pragma unroll
            for (int mt = 0; mt < 2; mt++)
                #pragma unroll
                for (int nt = 0; nt < 8; nt++)
                    mma16816(acc[mt][nt], Afrag[mt], Bfrag[nt]);
        }
        // no trailing barrier: next iter's leading barrier orders buffer reuse
        sb += 10240u;
        if (sb == 30720u) sb = 0u;
    }

    #pragma unroll
    for (int mt = 0; mt < 2; mt++){
        int r0 = bm + wm*32 + mt*16 + (lane >> 2);
        #pragma unroll
        for (int nt = 0; nt < 8; nt++){
            int col = bn + wn*64 + nt*8 + ((lane & 3) << 1);
            if (col < N){
                *reinterpret_cast<float2*>(&Cv[(long)r0*ldc + col]) =
                    make_float2(acc[mt][nt][0], acc[mt][nt][1]);
                *reinterpret_cast<float2*>(&Cv[(long)(r0+8)*ldc + col]) =
                    make_float2(acc[mt][nt][2], acc[mt][nt][3]);
            }
        }
    }
}

// ---------------- 256x128 GEMM (TRANSB=0 only) ----------------
__device__ __forceinline__ void stage256(const bf16* Ab, const bf16* Bb,
    int bm, int bn, int N, int lda, int ldb, int k0, int tid,
    unsigned Adst, unsigned Bdst)
{
    #pragma unroll
    for (int c = tid; c < 1024; c += 256){
        int r  = c >> 2;
        int ko = (c & 3) << 3;
        cpasync16(Adst + 2u*(unsigned)(r*40 + ko),
                  Ab + (long)(bm + r)*lda + k0 + ko, 16);
    }
    #pragma unroll
    for (int c = tid; c < 512; c += 256){
        int r  = c >> 4;
        int no = (c & 15) << 3;
        const bf16* src = Bb + (long)(k0 + r)*ldb + bn + no;
        int ssz = 16;
        if (bn + no >= N){ src = Bb; ssz = 0; }
        cpasync16(Bdst + 2u*(unsigned)(r*136 + no), src, ssz);
    }
}

// EPI: 0 none, 1 relu(acc+bias) fp32, 2 resid fp32, 3 siluGLU bf16
template<int EPI, int OUTBF>
__global__ void __launch_bounds__(256) bgemm256_k(
    const bf16* __restrict__ Aptr, const bf16* __restrict__ Bptr, void* __restrict__ Cv,
    int M, int N, int K, int lda, int ldb, int ldc,
    long sA, long sB, long sC, const float* __restrict__ bias,
    const float* __restrict__ resx, const int* __restrict__ mcnt)
{
    __shared__ bf16 As[3*10240];
    __shared__ bf16 Bs[3*4352];
    const int bm = blockIdx.y * 256;
    int Meff = M;
    if (mcnt) Meff = mcnt[blockIdx.z];
    if (bm >= Meff) return;
    const bf16* Ab = Aptr + (long)blockIdx.z * sA;
    const bf16* Bb = Bptr + (long)blockIdx.z * sB;
    const int bn = blockIdx.x * 128;
    const int tid  = threadIdx.x;
    const int lane = tid & 31;
    const int warp = tid >> 5;
    const int wm = warp >> 1;
    const int wn = warp & 1;

    float acc[4][8][4];
    #pragma unroll
    for (int i = 0; i < 4; i++)
        #pragma unroll
        for (int j = 0; j < 8; j++)
            #pragma unroll
            for (int q = 0; q < 4; q++) acc[i][j][q] = 0.f;

    unsigned Afrag[4][4];
    unsigned Bfrag[8][2];

    const unsigned As_base = (unsigned)__cvta_generic_to_shared(As);
    const unsigned Bs_base = (unsigned)__cvta_generic_to_shared(Bs);

    const int rowA = wm*64 + (lane & 15);
    const int colA = (lane >> 4) * 8;
    unsigned aoff[4];
    #pragma unroll
    for (int mt = 0; mt < 4; mt++)
        aoff[mt] = As_base + 2u*(unsigned)((rowA + mt*16)*40 + colA);

    unsigned boff[4];
    {
        int brow = lane & 15;
        int bcol = (lane >> 4) * 8;
        #pragma unroll
        for (int p = 0; p < 4; p++)
            boff[p] = Bs_base + 2u*(unsigned)(brow*136 + wn*64 + p*16 + bcol);
    }

    const int nk = K >> 5;
    stage256(Ab, Bb, bm, bn, N, lda, ldb, 0, tid, As_base, Bs_base);
    cp_commit();
    if (nk > 1){
        stage256(Ab, Bb, bm, bn, N, lda, ldb, 32, tid,
                 As_base + 20480u, Bs_base + 8704u);
        cp_commit();
    }

    unsigned sa = 0u, sbb = 0u;
    for (int it = 0; it < nk; it++){
        if (it + 1 < nk) cp_wait1(); else cp_wait0();
        __syncthreads();
        if (it + 2 < nk){
            unsigned st = (unsigned)((it + 2) % 3);
            stage256(Ab, Bb, bm, bn, N, lda, ldb, (it+2) << 5, tid,
                     As_base + st*20480u, Bs_base + st*8704u);
            cp_commit();
        }
        #pragma unroll
        for (int ks = 0; ks < 32; ks += 16){
            #pragma unroll
            for (int mt = 0; mt < 4; mt++)
                ldsm_x4(aoff[mt] + sa + 2u*ks,
                        Afrag[mt][0], Afrag[mt][1], Afrag[mt][2], Afrag[mt][3]);
            #pragma unroll
            for (int p = 0; p < 4; p++){
                unsigned ba = boff[p] + sbb + 2u*(unsigned)(ks*136);
                ldsm_x4_t(ba, Bfrag[2*p][0], Bfrag[2*p][1],
                              Bfrag[2*p+1][0], Bfrag[2*p+1][1]);
            }
            #pragma unroll
            for (int mt = 0; mt < 4; mt++)
                #pragma unroll
                for (int nt = 0; nt < 8; nt++)
                    mma16816(acc[mt][nt], Afrag[mt], Bfrag[nt]);
        }
        // no trailing barrier: next iter's leading barrier orders buffer reuse
        sa += 20480u;  if (sa == 61440u) sa = 0u;
        sbb += 8704u;  if (sbb == 26112u) sbb = 0u;
    }

    #pragma unroll
    for (int mt = 0; mt < 4; mt++){
        int r0 = bm + wm*64 + mt*16 + (lane >> 2);
        #pragma unroll
        for (int nt = 0; nt < 8; nt++){
            int col = bn + wn*64 + nt*8 + ((lane & 3) << 1);
            if (col < N){
                float v0 = acc[mt][nt][0];
                float v1 = acc[mt][nt][1];
                float v2 = acc[mt][nt][2];
                float v3 = acc[mt][nt][3];
                if (EPI == 3){
                    bf16* Cb = (bf16*)Cv + (long)blockIdx.z * sC;
                    int jc = col >> 1;
                    Cb[(long)r0*(N>>1) + jc]     = __float2bfloat16(siluf(v0)*v1);
                    Cb[(long)(r0+8)*(N>>1) + jc] = __float2bfloat16(siluf(v2)*v3);
                    continue;
                }
                if (EPI == 1){
                    float b0 = bias[col];
                    float b1 = bias[col+1];
                    v0 = fmaxf(v0+b0, 0.f); v1 = fmaxf(v1+b1, 0.f);
                    v2 = fmaxf(v2+b0, 0.f); v3 = fmaxf(v3+b1, 0.f);
                }
                if (EPI == 2){
                    float b0 = bias[col];
                    float b1 = bias[col+1];
                    v0 = fmaf(b0, v0, resx[(long)r0*ldc + col]);
                    v1 = fmaf(b1, v1, resx[(long)r0*ldc + col + 1]);
                    v2 = fmaf(b0, v2, resx[(long)(r0+8)*ldc + col]);
                    v3 = fmaf(b1, v3, resx[(long)(r0+8)*ldc + col + 1]);
                }
                if (OUTBF){
                    bf16* Cb = (bf16*)Cv + (long)blockIdx.z * sC;
                    *reinterpret_cast<__nv_bfloat162*>(&Cb[(long)r0*ldc + col]) =
                        __floats2bfloat162_rn(v0, v1);
                    *reinterpret_cast<__nv_bfloat162*>(&Cb[(long)(r0+8)*ldc + col]) =
                        __floats2bfloat162_rn(v2, v3);
                } else {
                    float* Cb = (float*)Cv + (long)blockIdx.z * sC;
                    *reinterpret_cast<float2*>(&Cb[(long)r0*ldc + col]) = make_float2(v0, v1);
                    *reinterpret_cast<float2*>(&Cb[(long)(r0+8)*ldc + col]) = make_float2(v2, v3);
                }
            }
        }
    }
}

// ---------------- fused flash attention ----------------
#define FTILE (128*136)
#define FSMEM (5*FTILE*2)

__device__ __forceinline__ void fstage(const bf16* src, unsigned dst, int tid){
    for (int i = tid; i < 2048; i += 256){
        int r = i >> 4, c = (i & 15) << 3;
        cpasync16(dst + 2u*(unsigned)(r*136 + c), src + r*DH + c, 16);
    }
}

__global__ void __launch_bounds__(256, 1) flash_k(
    const bf16* __restrict__ q, const bf16* __restrict__ k, const bf16* __restrict__ v,
    const float* __restrict__ ascale, bf16* __restrict__ att)
{
    extern __shared__ bf16 fs[];
    const int qt = blockIdx.x, bh = blockIdx.y;
    const int bb = bh >> 3, hh = bh & 7;
    const int tid = threadIdx.x, lane = tid & 31, w = tid >> 5;
    const float a = ascale[hh];

    const bf16* qg = q + ((long)bh*LSEQ + qt*128)*DH;
    const bf16* kg = k + (long)bh*LSEQ*DH;
    const bf16* vg = v + (long)bh*LSEQ*DH;

    const unsigned Qb = (unsigned)__cvta_generic_to_shared(fs);
    const unsigned Kb = Qb + 2u*FTILE;
    const unsigned Vb = Qb + 6u*FTILE;
    const unsigned TILEB = 2u*FTILE;

    fstage(qg, Qb, tid);
    fstage(kg, Kb, tid);
    fstage(vg, Vb, tid);
    cp_commit();
    cp_wait0();
    __syncthreads();

    unsigned qf[8][4];
    {
        int rq = w*16 + (lane & 15);
        int cq = (lane >> 4) << 3;
        #pragma unroll
        for (int ks = 0; ks < 8; ks++)
            ldsm_x4(Qb + 2u*(unsigned)(rq*136 + ks*16 + cq),
                    qf[ks][0], qf[ks][1], qf[ks][2], qf[ks][3]);
    }

    const int brow = (lane & 7) + (((lane >> 4) & 1) << 3);
    const int bcol = ((lane >> 3) & 1) << 3;
    unsigned kadr[8], vadr[8];
    #pragma unroll
    for (int p = 0; p < 8; p++){
        kadr[p] = Kb + 2u*(unsigned)((p*16 + brow)*136 + bcol);
        vadr[p] = Vb + 2u*(unsigned)((lane & 15)*136 + p*16 + ((lane >> 4) << 3));
    }

    float oacc[16][4];
    #pragma unroll
    for (int nt = 0; nt < 16; nt++)
        #pragma unroll
        for (int qq = 0; qq < 4; qq++) oacc[nt][qq] = 0.f;
    float m0 = -1e30f, m1 = -1e30f, l0 = 0.f, l1 = 0.f;

    for (int kt = 0; kt < 16; kt++){
        if (kt > 0){ cp_wait0(); __syncthreads(); }
        if (kt + 1 < 16){
            unsigned off = ((kt + 1) & 1) ? TILEB : 0u;
            fstage(kg + (long)(kt+1)*128*DH, Kb + off, tid);
            fstage(vg + (long)(kt+1)*128*DH, Vb + off, tid);
            cp_commit();
        }
        const unsigned sb = (kt & 1) ? TILEB : 0u;

        float sacc[16][4];
        #pragma unroll
        for (int nt = 0; nt < 16; nt++)
            #pragma unroll
            for (int qq = 0; qq < 4; qq++) sacc[nt][qq] = 0.f;

        #pragma unroll
        for (int ks = 0; ks < 8; ks++){
            #pragma unroll
            for (int p = 0; p < 8; p++){
                unsigned bf0[2], bf1[2];
                ldsm_x4(kadr[p] + sb + 2u*(unsigned)(ks*16),
                        bf0[0], bf0[1], bf1[0], bf1[1]);
                mma16816(sacc[2*p],   qf[ks], bf0);
                mma16816(sacc[2*p+1], qf[ks], bf1);
            }
        }

        float ax0 = -1e30f, ax1 = -1e30f;
        #pragma unroll
        for (int nt = 0; nt < 16; nt++){
            sacc[nt][0] *= a; sacc[nt][1] *= a; sacc[nt][2] *= a; sacc[nt][3] *= a;
            ax0 = fmaxf(ax0, fmaxf(sacc[nt][0], sacc[nt][1]));
            ax1 = fmaxf(ax1, fmaxf(sacc[nt][2], sacc[nt][3]));
        }
        ax0 = fmaxf(ax0, __shfl_xor_sync(0xffffffffu, ax0, 1));
        ax0 = fmaxf(ax0, __shfl_xor_sync(0xffffffffu, ax0, 2));
        ax1 = fmaxf(ax1, __shfl_xor_sync(0xffffffffu, ax1, 1));
        ax1 = fmaxf(ax1, __shfl_xor_sync(0xffffffffu, ax1, 2));
        float mn0 = fmaxf(m0, ax0), mn1 = fmaxf(m1, ax1);
        float f0 = expf(m0 - mn0), f1 = expf(m1 - mn1);

        float rs0 = 0.f, rs1 = 0.f;
        #pragma unroll
        for (int nt = 0; nt < 16; nt++){
            sacc[nt][0] = expf(sacc[nt][0] - mn0);
            sacc[nt][1] = expf(sacc[nt][1] - mn0);
            sacc[nt][2] = expf(sacc[nt][2] - mn1);
            sacc[nt][3] = expf(sacc[nt][3] - mn1);
            rs0 += sacc[nt][0] + sacc[nt][1];
            rs1 += sacc[nt][2] + sacc[nt][3];
        }
        rs0 += __shfl_xor_sync(0xffffffffu, rs0, 1);
        rs0 += __shfl_xor_sync(0xffffffffu, rs0, 2);
        rs1 += __shfl_xor_sync(0xffffffffu, rs1, 1);
        rs1 += __shfl_xor_sync(0xffffffffu, rs1, 2);
        l0 = l0*f0 + rs0; l1 = l1*f1 + rs1;
        m0 = mn0; m1 = mn1;

        #pragma unroll
        for (int nt = 0; nt < 16; nt++){
            oacc[nt][0] *= f0; oacc[nt][1] *= f0;
            oacc[nt][2] *= f1; oacc[nt][3] *= f1;
        }

        unsigned pa[8][4];
        #pragma unroll
        for (int ksp = 0; ksp < 8; ksp++){
            pa[ksp][0] = pkbf2(sacc[2*ksp][0],   sacc[2*ksp][1]);
            pa[ksp][1] = pkbf2(sacc[2*ksp][2],   sacc[2*ksp][3]);
            pa[ksp][2] = pkbf2(sacc[2*ksp+1][0], sacc[2*ksp+1][1]);
            pa[ksp][3] = pkbf2(sacc[2*ksp+1][2], sacc[2*ksp+1][3]);
        }

        #pragma unroll
        for (int ksp = 0; ksp < 8; ksp++){
            #pragma unroll
            for (int p = 0; p < 8; p++){
                unsigned bf0[2], bf1[2];
                ldsm_x4_t(vadr[p] + sb + 2u*(unsigned)(ksp*16*136),
                          bf0[0], bf0[1], bf1[0], bf1[1]);
                mma16816(oacc[2*p],   pa[ksp], bf0);
                mma16816(oacc[2*p+1], pa[ksp], bf1);
            }
        }
    }

    float inv0 = 1.f / l0, inv1 = 1.f / l1;
    long row0 = (long)bb*LSEQ + qt*128 + w*16 + (lane >> 2);
    long row1 = row0 + 8;
    int  cbase = hh*DH + ((lane & 3) << 1);
    #pragma unroll
    for (int nt = 0; nt < 16; nt++){
        int col = cbase + nt*8;
        *reinterpret_cast<__nv_bfloat162*>(&att[row0*DM + col]) =
            __floats2bfloat162_rn(oacc[nt][0]*inv0, oacc[nt][1]*inv0);
        *reinterpret_cast<__nv_bfloat162*>(&att[row1*DM + col]) =
            __floats2bfloat162_rn(oacc[nt][2]*inv1, oacc[nt][3]*inv1);
    }
}

// ---------------- depthwise conv + bias + SiLU ----------------
__global__ void conv_k(const float* __restrict__ xz, const float* __restrict__ cw,
                       const float* __restrict__ cb, float* __restrict__ xc,
                       bf16* __restrict__ xcb){
    long idx = (long)blockIdx.x*blockDim.x + threadIdx.x;
    if (idx >= (long)NTOK*DI) return;
    int d = (int)(idx % DI);
    int row = (int)(idx / DI);
    int t = row % LSEQ, b = row / LSEQ;
    float s = cb[d];
    #pragma unroll
    for (int k = 0; k < 4; k++){
        int tt = t + k - 2;
        if (tt >= 0 && tt < LSEQ)
            s = fmaf(cw[d*4+k], xz[(long)(b*LSEQ+tt)*(2*DI) + d], s);
    }
    float v = siluf(s);
    xc[idx] = v;
    xcb[idx] = __float2bfloat16(v);
}

// ---------------- scan preprocessing ----------------
__global__ void scanprep_k(const float* __restrict__ dtBC, const float* __restrict__ bdt,
                           const float* __restrict__ A, float* __restrict__ sp){
    int idx = blockIdx.x*blockDim.x + threadIdx.x;
    if (idx >= NTOK*16) return;
    int n = idx & 15, row = idx >> 4;
    float dtp = dtBC[(long)row*64 + n] + bdt[n];
    float dt  = fmaxf(dtp, 0.f) + log1pf(expf(-fabsf(dtp)));
    sp[(long)row*48 + n]      = expf(dt * A[n]);
    sp[(long)row*48 + 16 + n] = dt * dtBC[(long)row*64 + 16 + n];
    sp[(long)row*48 + 32 + n] = dtBC[(long)row*64 + 32 + n];
}

// ---------------- chunked selective scan ----------------
__global__ void scanP_k(const float* __restrict__ sp, float* __restrict__ P){
    int b = blockIdx.x / NCH, ch = blockIdx.x % NCH;
    int n = threadIdx.x;
    if (n >= 16) return;
    float p = 1.f;
    long base = ((long)b*LSEQ + ch*CLEN)*48;
    for (int t = 0; t < CLEN; t++) p *= sp[base + t*48 + n];
    P[(b*NCH+ch)*16 + n] = p;
}

__global__ void scanA_k(const float* __restrict__ sp, const float* __restrict__ xc,
                        float* __restrict__ hend){
    int b = blockIdx.z, ch = blockIdx.y;
    int d = blockIdx.x*128 + threadIdx.x;
    __shared__ float s[CLEN*48];
    const float* src = sp + ((long)b*LSEQ + ch*CLEN)*48;
    for (int i = threadIdx.x; i < CLEN*48; i += 128) s[i] = src[i];
    __syncthreads();
    float h[16];
    #pragma unroll
    for (int n = 0; n < 16; n++) h[n] = 0.f;
    long rowbase = (long)b*LSEQ + ch*CLEN;
    float xv_next = xc[rowbase*DI + d];
    for (int tt = 0; tt < CLEN; tt++){
        float xv = xv_next;
        if (tt + 1 < CLEN) xv_next = xc[(rowbase + tt + 1)*DI + d];
        const float* e = s + tt*48;
        #pragma unroll
        for (int n = 0; n < 16; n++)
            h[n] = fmaf(e[n], h[n], e[16+n]*xv);
    }
    float* o = hend + (((long)(b*NCH + ch)*DI + d) << 4);
    #pragma unroll
    for (int n = 0; n < 16; n += 4)
        *reinterpret_cast<float4*>(o + n) = make_float4(h[n], h[n+1], h[n+2], h[n+3]);
}

__global__ void scanComb_k(const float* __restrict__ hend, const float* __restrict__ P,
                           float* __restrict__ h0){
    int g = blockIdx.x*128 + threadIdx.x;
    int b = g / DI, d = g % DI;
    __shared__ float sP[NCH*16];
    for (int i = threadIdx.x; i < NCH*16; i += 128) sP[i] = P[b*NCH*16 + i];
    __syncthreads();
    float h[16];
    #pragma unroll
    for (int n = 0; n < 16; n++) h[n] = 0.f;
    {
        float* o = h0 + (((long)(b*NCH)*DI + d) << 4);
        #pragma unroll
        for (int n = 0; n < 16; n += 4)
            *reinterpret_cast<float4*>(o + n) = make_float4(0.f, 0.f, 0.f, 0.f);
    }
    for (int c = 1; c < NCH; c++){
        const float* he = hend + (((long)(b*NCH + c - 1)*DI + d) << 4);
        #pragma unroll
        for (int n = 0; n < 16; n++)
            h[n] = fmaf(sP[(c-1)*16 + n], h[n], he[n]);
        float* o = h0 + (((long)(b*NCH + c)*DI + d) << 4);
        #pragma unroll
        for (int n = 0; n < 16; n += 4)
            *reinterpret_cast<float4*>(o + n) = make_float4(h[n], h[n+1], h[n+2], h[n+3]);
    }
}

__global__ void scanC_k(const float* __restrict__ sp, const float* __restrict__ xc,
                        const float* __restrict__ xz, const float* __restrict__ Dp,
                        const float* __restrict__ h0, bf16* __restrict__ ymulb){
    int b = blockIdx.z, ch = blockIdx.y;
    int d = blockIdx.x*128 + threadIdx.x;
    __shared__ float s[CLEN*48];
    const float* src = sp + ((long)b*LSEQ + ch*CLEN)*48;
    for (int i = threadIdx.x; i < CLEN*48; i += 128) s[i] = src[i];
    __syncthreads();
    float h[16];
    {   const float* hi = h0 + (((long)(b*NCH + ch)*DI + d) << 4);
        #pragma unroll
        for (int n = 0; n < 16; n += 4){
            float4 v = *reinterpret_cast<const float4*>(hi + n);
            h[n] = v.x; h[n+1] = v.y; h[n+2] = v.z; h[n+3] = v.w;
        }
    }
    const float dpv = Dp[d];
    long rowbase = (long)b*LSEQ + ch*CLEN;
    float xv_next = xc[rowbase*DI + d];
    float z_next  = xz[rowbase*(2*DI) + DI + d];
    for (int tt = 0; tt < CLEN; tt++){
        float xv = xv_next;
        float z  = z_next;
        if (tt + 1 < CLEN){
            xv_next = xc[(rowbase + tt + 1)*DI + d];
            z_next  = xz[(rowbase + tt + 1)*(2*DI) + DI + d];
        }
        const float* e = s + tt*48;
        float y = 0.f;
        #pragma unroll
        for (int n = 0; n < 16; n++){
            h[n] = fmaf(e[n], h[n], e[16+n]*xv);
            y = fmaf(h[n], e[32+n], y);
        }
        ymulb[(rowbase + tt)*DI + d] = __float2bfloat16((y + dpv*xv) * siluf(z));
    }
}

// ---------------- RoPE (bf16 qkv in) -> qb,kb,vb bf16 ----------------
__global__ void rope2_k(const bf16* __restrict__ qkv, bf16* __restrict__ qb,
                        bf16* __restrict__ kb, bf16* __restrict__ vb){
    int row = blockIdx.x;
    int t = row % LSEQ, b = row / LSEQ;
    __shared__ float q[DM], kk[DM];
    const bf16* base = qkv + (long)row*3*DM;
    for (int i = threadIdx.x; i < DM; i += 256){
        q[i]  = __bfloat162float(base[i]);
        kk[i] = __bfloat162float(base[DM+i]);
    }
    __syncthreads();
    const float sq = sqrtf((float)DH);
    const float lg = logf(10000.f) / 64.f;
    for (int idx = threadIdx.x; idx < DM; idx += 256){
        int h = idx / DH, i = idx % DH;
        int j = i & 63;
        float inv = expf(-(float)j * lg);
        float ang = (float)t * inv;
        float c = cosf(ang), s = sinf(ang);
        int off = h * DH;
        float rq, rk;
        if (i < 64){ rq = -q[off + 2*i + 1]; rk = -kk[off + 2*i + 1]; }
        else       { rq =  q[off + 2*(i-64)]; rk =  kk[off + 2*(i-64)]; }
        long o = ((long)(b*NH + h)*LSEQ + t)*DH + i;
        qb[o] = __float2bfloat16((q[idx]*c + rq*s) * sq);
        kb[o] = __float2bfloat16(kk[idx]*c + rk*s);
        vb[o] = base[2*DM + idx];
    }
}

// ---------------- gate stage 2 (bias+relu folded in; zeroes counters) ----------------
__global__ void gate2_k(const float* __restrict__ g1, const float* __restrict__ bg1,
                        const float* __restrict__ Wg2,
                        float* __restrict__ gs, int* __restrict__ topi, float* __restrict__ topw,
                        int* __restrict__ cnt){
    int row = blockIdx.x;
    int tid = threadIdx.x;
    if (row == 0 && tid < NEXP) cnt[tid] = 0;   // safe: assign_k launches after this kernel retires
    __shared__ float red[64*4];
    float a[4] = {0.f,0.f,0.f,0.f};
    for (int j = tid; j < 512; j += 64){
        float v = fmaxf(g1[(long)row*512 + j] + bg1[j], 0.f);
        #pragma unroll
        for (int e = 0; e < 4; e++) a[e] = fmaf(v, Wg2[j*4+e], a[e]);
    }
    #pragma unroll
    for (int e = 0; e < 4; e++) red[e*64 + tid] = a[e];
    __syncthreads();
    for (int st = 32; st > 0; st >>= 1){
        if (tid < st){
            #pragma unroll
            for (int e = 0; e < 4; e++) red[e*64+tid] += red[e*64+tid+st];
        }
        __syncthreads();
    }
    if (tid == 0){
        float l[4]; for (int e = 0; e < 4; e++) l[e] = red[e*64];
        float m = fmaxf(fmaxf(l[0],l[1]), fmaxf(l[2],l[3]));
        float ex[4]; float s = 0.f;
        for (int e = 0; e < 4; e++){ ex[e] = expf(l[e]-m); s += ex[e]; }
        float gsv[4];
        for (int e = 0; e < 4; e++){ gsv[e] = ex[e]/s; gs[(long)row*4+e] = gsv[e]; }
        int i0 = 0;
        for (int e = 1; e < 4; e++) if (gsv[e] > gsv[i0]) i0 = e;
        int i1 = -1;
        for (int e = 0; e < 4; e++) if (e != i0 && (i1 < 0 || gsv[e] > gsv[i1])) i1 = e;
        float v0 = gsv[i0], v1 = gsv[i1];
        float mm = fmaxf(v0, v1);
        float w0 = expf(v0-mm), w1 = expf(v1-mm);
        float ws = w0 + w1;
        topi[row*2] = i0; topi[row*2+1] = i1;
        topw[row*2] = w0/ws; topw[row*2+1] = w1/ws;
    }
}

// ---------------- balance loss ----------------
__global__ void bal_k(const float* __restrict__ gs, float* __restrict__ out){
    int tid = threadIdx.x;
    __shared__ float red[256*4];
    float a[4] = {0.f,0.f,0.f,0.f};
    for (int r = tid; r < NTOK; r += 256){
        #pragma unroll
        for (int e = 0; e < 4; e++) a[e] += gs[(long)r*4+e];
    }
    #pragma unroll
    for (int e = 0; e < 4; e++) red[e*256+tid] = a[e];
    __syncthreads();
    for (int st = 128; st > 0; st >>= 1){
        if (tid < st){
            #pragma unroll
            for (int e = 0; e < 4; e++) red[e*256+tid] += red[e*256+tid+st];
        }
        __syncthreads();
    }
    if (tid == 0){
        float bal = 0.f;
        for (int e = 0; e < 4; e++){
            float gm = red[e*256] / (float)NTOK;
            bal += gm * logf(gm + 1e-8f);
        }
        out[0] = (float)NEXP * bal;
    }
}

// ---------------- MoE routing ----------------
__global__ void assign_k(const int* __restrict__ topi, int* __restrict__ cnt,
                         int* __restrict__ slot){
    int idx = blockIdx.x*256 + threadIdx.x;
    if (idx >= NTOK*2) return;
    int e = topi[idx];
    int s = atomicAdd(&cnt[e], 1);
    slot[idx] = e*NTOK + s;
}

__global__ void gather_k(const bf16* __restrict__ xf, const int* __restrict__ slot,
                         bf16* __restrict__ xg){
    int idx = blockIdx.x;
    int tok = idx >> 1;
    int dst = slot[idx];
    const unsigned* src = reinterpret_cast<const unsigned*>(xf) + (long)tok*(DM/2);
    unsigned* d = reinterpret_cast<unsigned*>(xg) + (long)dst*(DM/2);
    for (int i = threadIdx.x; i < DM/2; i += 128) d[i] = src[i];
}

// ---------------- MoE combine + final residual ----------------
__global__ void combine2_k(const float* __restrict__ x2, const float* __restrict__ ls3,
                           const bf16* __restrict__ eo, const int* __restrict__ slot,
                           const float* __restrict__ topw, float* __restrict__ out){
    long idx = (long)blockIdx.x*blockDim.x + threadIdx.x;
    if (idx >= (long)NTOK*DM) return;
    int row = (int)(idx / DM), d = (int)(idx % DM);
    int s0 = slot[row*2], s1 = slot[row*2+1];
    float m = topw[row*2]   * __bfloat162float(eo[(long)s0*DM + d])
            + topw[row*2+1] * __bfloat162float(eo[(long)s1*DM + d]);
    out[idx] = fmaf(ls3[d], m, x2[idx]);
}

// ============================== host ==============================
#define SYMPF(p, s) do { void* _t; cudaGetSymbolAddress(&_t, s); p = (float*)_t; } while(0)
#define SYMPB(p, s) do { void* _t; cudaGetSymbolAddress(&_t, s); p = (bf16*)_t; } while(0)
#define SYMPI(p, s) do { void* _t; cudaGetSymbolAddress(&_t, s); p = (int*)_t; } while(0)

extern "C" void kernel_launch(void* const* d_in, const int* in_sizes, int n_in,
                              void* d_out, int out_size){
    const float* x      = (const float*)d_in[0];
    const float* rms1_w = (const float*)d_in[1];
    const float* rms2_w = (const float*)d_in[2];
    const float* rms3_w = (const float*)d_in[3];
    const float* ls1    = (const float*)d_in[4];
    const float* ls2    = (const float*)d_in[5];
    const float* ls3    = (const float*)d_in[6];
    const float* W_in   = (const float*)d_in[7];
    const float* conv_w = (const float*)d_in[8];
    const float* conv_b = (const float*)d_in[9];
    const float* W_B    = (const float*)d_in[10];
    const float* W_C    = (const float*)d_in[11];
    const float* W_dt   = (const float*)d_in[12];
    const float* b_dt   = (const float*)d_in[13];
    const float* W_out_m= (const float*)d_in[14];
    const float* Avec   = (const float*)d_in[15];
    const float* Dp     = (const float*)d_in[16];
    const float* W_qkv  = (const float*)d_in[17];
    const float* W_o    = (const float*)d_in[18];
    const float* ascale = (const float*)d_in[19];
    const float* Wg1    = (const float*)d_in[20];
    const float* bg1    = (const float*)d_in[21];
    const float* Wg2    = (const float*)d_in[22];
    const float* w1     = (const float*)d_in[23];
    const float* w2     = (const float*)d_in[24];
    const float* w3     = (const float*)d_in[25];
    float* out = (float*)d_out;

    float *p_xz, *p_xc, *p_dtBC, *p_scanp, *p_x1, *p_x2, *p_g1, *p_gs, *p_topw;
    float *p_hend, *p_h0, *p_P;
    int *p_topi, *p_cnt, *p_slot;
    bf16 *b_rms1, *b_xc, *b_ymul, *b_rms2, *b_qkv, *b_q, *b_k, *b_v, *b_att, *b_xf,
         *b_xg, *b_h, *b_eo;
    bf16 *b_Win, *b_Wout, *b_Wqkv, *b_Wo, *b_Wg1, *b_w12, *b_w3, *b_Wcat;

    SYMPF(p_xz, g_xz); SYMPF(p_xc, g_xc); SYMPF(p_dtBC, g_dtBC); SYMPF(p_scanp, g_scanp);
    SYMPF(p_x1, g_x1);
    SYMPF(p_x2, g_x2); SYMPF(p_g1, g_g1); SYMPF(p_gs, g_gs); SYMPF(p_topw, g_topw);
    SYMPF(p_hend, g_hend); SYMPF(p_h0, g_h0); SYMPF(p_P, g_P);
    SYMPI(p_topi, g_topi); SYMPI(p_cnt, g_cnt); SYMPI(p_slot, g_slot);
    SYMPB(b_rms1, g_rms1b); SYMPB(b_xc, g_xcb); SYMPB(b_ymul, g_ymulb); SYMPB(b_rms2, g_rms2b);
    SYMPB(b_qkv, g_qkvb); SYMPB(b_q, g_qb); SYMPB(b_k, g_kb); SYMPB(b_v, g_vb);
    SYMPB(b_att, g_attb); SYMPB(b_xf, g_xfb); SYMPB(b_xg, g_xgb);
    SYMPB(b_h, g_hb); SYMPB(b_eo, g_eob);
    SYMPB(b_Win, g_Winb); SYMPB(b_Wout, g_Woutb); SYMPB(b_Wqkv, g_Wqkvb); SYMPB(b_Wo, g_Wob);
    SYMPB(b_Wg1, g_Wg1b); SYMPB(b_w12, g_w12b); SYMPB(b_w3, g_w3b); SYMPB(b_Wcat, g_Wcatb);

    // ---- weight conversions ----
    #define CONV(src, dst, n) f2bf_k<<<(int)(((n)/4 + 255)/256), 256>>>(src, dst, (long)(n))
    CONV(W_in,   b_Win,  (long)DM*2*DI);
    CONV(W_out_m,b_Wout, (long)DI*DM);
    CONV(W_qkv,  b_Wqkv, (long)DM*3*DM);
    CONV(W_o,    b_Wo,   (long)DM*DM);
    CONV(Wg1,    b_Wg1,  (long)DM*512);
    CONV(w3,     b_w3,   (long)NEXP*DFF*DM);
    pack12_k<<<(int)(((long)NEXP*DM*DFF/4 + 255)/256), 256>>>(w1, w2, b_w12);
    packw_k<<<(DI*64+255)/256, 256>>>(W_dt, W_B, W_C, b_Wcat);

    // ---- 1. Mamba ----
    rmsnorm_bf_k<<<NTOK, 256>>>(x, rms1_w, b_rms1);
    {   dim3 g(2*DI/128, NTOK/256, 1);
        bgemm256_k<0,0><<<g, 256>>>(b_rms1, b_Win, p_xz, NTOK, 2*DI, DM, DM, 2*DI, 2*DI,
                                    0,0,0, nullptr, nullptr, nullptr); }
    conv_k<<<(int)(((long)NTOK*DI+255)/256), 256>>>(p_xz, conv_w, conv_b, p_xc, b_xc);
    {   dim3 g(1, NTOK/128, 1);
        bgemm_k<<<g, 256>>>(b_xc, b_Wcat, p_dtBC, NTOK, 64, DI, DI, 64, 64); }
    scanprep_k<<<(NTOK*16+255)/256, 256>>>(p_dtBC, b_dt, Avec, p_scanp);
    scanP_k<<<BB*NCH, 16>>>(p_scanp, p_P);
    {   dim3 g(16, NCH, BB);
        scanA_k<<<g, 128>>>(p_scanp, p_xc, p_hend); }
    scanComb_k<<<BB*DI/128, 128>>>(p_hend, p_P, p_h0);
    {   dim3 g(16, NCH, BB);
        scanC_k<<<g, 128>>>(p_scanp, p_xc, p_xz, Dp, p_h0, b_ymul); }
    {   dim3 g(DM/128, NTOK/256, 1);   // x1 = x + ls1 * (ymul @ Wout)
        bgemm256_k<2,0><<<g, 256>>>(b_ymul, b_Wout, p_x1, NTOK, DM, DI, DI, DM, DM,
                                    0,0,0, ls1, x, nullptr); }

    // ---- 2. Attention ----
    rmsnorm_bf_k<<<NTOK, 256>>>(p_x1, rms2_w, b_rms2);
    {   dim3 g(3*DM/128, NTOK/256, 1);   // qkv bf16 out
        bgemm256_k<0,1><<<g, 256>>>(b_rms2, b_Wqkv, b_qkv, NTOK, 3*DM, DM, DM, 3*DM, 3*DM,
                                    0,0,0, nullptr, nullptr, nullptr); }
    rope2_k<<<NTOK, 256>>>(b_qkv, b_q, b_k, b_v);
    {   cudaFuncSetAttribute(flash_k, cudaFuncAttributeMaxDynamicSharedMemorySize, FSMEM);
        dim3 g(LSEQ/128, BB*NH, 1);
        flash_k<<<g, 256, FSMEM>>>(b_q, b_k, b_v, ascale, b_att); }
    {   dim3 g(DM/128, NTOK/256, 1);   // x2 = x1 + ls2 * (att @ Wo)
        bgemm256_k<2,0><<<g, 256>>>(b_att, b_Wo, p_x2, NTOK, DM, DM, DM, DM, DM,
                                    0,0,0, ls2, p_x1, nullptr); }

    // ---- 3. MoE (top-2 sparse) ----
    rmsnorm_bf_k<<<NTOK, 256>>>(p_x2, rms3_w, b_xf);
    {   dim3 g(512/128, NTOK/128, 1);   // raw gate logits (bias+relu in gate2)
        bgemm_k<<<g, 256>>>(b_xf, b_Wg1, p_g1, NTOK, 512, DM, DM, 512, 512); }
    gate2_k<<<NTOK, 64>>>(p_g1, bg1, Wg2, p_gs, p_topi, p_topw, p_cnt);
    if (out_size > NTOK*DM)
        bal_k<<<1, 256>>>(p_gs, out + (long)NTOK*DM);
    assign_k<<<(NTOK*2+255)/256, 256>>>(p_topi, p_cnt, p_slot);
    gather_k<<<NTOK*2, 128>>>(b_xf, p_slot, b_xg);
    {   dim3 g12(2*DFF/128, NTOK/256, NEXP);
        bgemm256_k<3,1><<<g12, 256>>>(b_xg, b_w12, b_h,
                                      NTOK, 2*DFF, DM, DM, 2*DFF, 2*DFF,
                                      (long)NTOK*DM, (long)DM*2*DFF, (long)NTOK*DFF,
                                      nullptr, nullptr, p_cnt);
    }
    {   dim3 g3(DM/128, NTOK/256, NEXP);
        bgemm256_k<0,1><<<g3, 256>>>(b_h, b_w3, b_eo,
                                     NTOK, DM, DFF, DFF, DM, DM,
                                     (long)NTOK*DFF, (long)DFF*DM, (long)NTOK*DM,
                                     nullptr, nullptr, p_cnt);
    }
    combine2_k<<<(int)(((long)NTOK*DM+255)/256), 256>>>(p_x2, ls3, b_eo, p_slot, p_topw, out);
}

// round 13
// speedup vs baseline: 10.5964x; 1.0046x over previous
#include <cuda_runtime.h>
#include <cuda_bf16.h>
#include <math.h>

#define BB   2
#define LSEQ 2048
#define DM   1024
#define DI   2048
#define NH   8
#define DH   128
#define NEXP 4
#define DFF  4096
#define NTOK (BB*LSEQ)   // 4096
#define NCH  16
#define CLEN 128         // LSEQ/NCH

typedef __nv_bfloat16 bf16;

// ---------------- static scratch ----------------
__device__ float g_xz[NTOK*2*DI];
__device__ float g_xc[NTOK*DI];
__device__ float g_dtBC[NTOK*64];
__device__ float g_scanp[NTOK*48];
__device__ float g_x1[NTOK*DM];
__device__ float g_x2[NTOK*DM];
__device__ float g_g1[NTOK*512];
__device__ float g_gs[NTOK*NEXP];
__device__ int   g_topi[NTOK*2];
__device__ float g_topw[NTOK*2];
__device__ int   g_cnt[NEXP];
__device__ int   g_slot[NTOK*2];
__device__ float g_hend[BB*NCH*DI*16];
__device__ float g_h0[BB*NCH*DI*16];
__device__ float g_P[BB*NCH*16];

// bf16 activations
__device__ bf16 g_rms1b[NTOK*DM];
__device__ bf16 g_xcb[NTOK*DI];
__device__ bf16 g_ymulb[NTOK*DI];
__device__ bf16 g_rms2b[NTOK*DM];
__device__ bf16 g_qkvb[NTOK*3*DM];
__device__ bf16 g_qb[NTOK*DM];
__device__ bf16 g_kb[NTOK*DM];
__device__ bf16 g_vb[NTOK*DM];
__device__ bf16 g_attb[NTOK*DM];
__device__ bf16 g_xfb[NTOK*DM];
__device__ bf16 g_xgb[NEXP*NTOK*DM];
__device__ bf16 g_hb[(long)NEXP*NTOK*DFF];
__device__ bf16 g_eob[NEXP*NTOK*DM];

// bf16 weights
__device__ bf16 g_Winb[DM*2*DI];
__device__ bf16 g_Woutb[DI*DM];
__device__ bf16 g_Wqkvb[DM*3*DM];
__device__ bf16 g_Wob[DM*DM];
__device__ bf16 g_Wg1b[DM*512];
__device__ bf16 g_w12b[(long)NEXP*DM*2*DFF];   // interleaved (w1_j, w2_j) pairs
__device__ bf16 g_w3b[(long)NEXP*DFF*DM];
__device__ bf16 g_Wcatb[DI*64];

__device__ __forceinline__ float siluf(float x){ return x / (1.f + expf(-x)); }

// ---------------- merged fp32 -> bf16 conversions (6 segments) ----------------
__global__ void convall_k(const float* __restrict__ s0, bf16* __restrict__ d0, long n0,
                          const float* __restrict__ s1, bf16* __restrict__ d1, long n1,
                          const float* __restrict__ s2, bf16* __restrict__ d2, long n2,
                          const float* __restrict__ s3, bf16* __restrict__ d3, long n3,
                          const float* __restrict__ s4, bf16* __restrict__ d4, long n4,
                          const float* __restrict__ s5, bf16* __restrict__ d5, long n5){
    long i = ((long)blockIdx.x*blockDim.x + threadIdx.x)*4;
    const float* s; bf16* d;
    if (i < n0){ s = s0; d = d0; }
    else { i -= n0;
    if (i < n1){ s = s1; d = d1; }
    else { i -= n1;
    if (i < n2){ s = s2; d = d2; }
    else { i -= n2;
    if (i < n3){ s = s3; d = d3; }
    else { i -= n3;
    if (i < n4){ s = s4; d = d4; }
    else { i -= n4;
    if (i >= n5) return;
    s = s5; d = d5; }}}}}
    float4 v = *reinterpret_cast<const float4*>(s + i);
    *reinterpret_cast<__nv_bfloat162*>(d + i)     = __floats2bfloat162_rn(v.x, v.y);
    *reinterpret_cast<__nv_bfloat162*>(d + i + 2) = __floats2bfloat162_rn(v.z, v.w);
}

// pack w1|w2 INTERLEAVED
__global__ void pack12_k(const float* __restrict__ w1, const float* __restrict__ w2,
                         bf16* __restrict__ o){
    long i = ((long)blockIdx.x*blockDim.x + threadIdx.x)*4;
    if (i >= (long)NEXP*DM*DFF) return;
    long row = i >> 12;
    int  j   = (int)(i & 4095);
    float4 a = *reinterpret_cast<const float4*>(w1 + i);
    float4 b = *reinterpret_cast<const float4*>(w2 + i);
    bf16* d1 = o + row*(2*DFF) + 2*j;
    *reinterpret_cast<__nv_bfloat162*>(d1)   = __floats2bfloat162_rn(a.x, b.x);
    *reinterpret_cast<__nv_bfloat162*>(d1+2) = __floats2bfloat162_rn(a.y, b.y);
    *reinterpret_cast<__nv_bfloat162*>(d1+4) = __floats2bfloat162_rn(a.z, b.z);
    *reinterpret_cast<__nv_bfloat162*>(d1+6) = __floats2bfloat162_rn(a.w, b.w);
}

// pack [W_dt | W_B | W_C | 0] -> [2048][64] bf16
__global__ void packw_k(const float* __restrict__ Wdt, const float* __restrict__ WB,
                        const float* __restrict__ WC, bf16* __restrict__ o){
    int idx = blockIdx.x*256 + threadIdx.x;
    if (idx >= DI*64) return;
    int j = idx >> 6, n = idx & 63;
    float v = 0.f;
    if (n < 16) v = Wdt[j*16+n];
    else if (n < 32) v = WB[j*16+n-16];
    else if (n < 48) v = WC[j*16+n-32];
    o[idx] = __float2bfloat16(v);
}

// ---------------- RMSNorm -> bf16 ----------------
__global__ void rmsnorm_bf_k(const float* __restrict__ x, const float* __restrict__ w,
                             bf16* __restrict__ o){
    int row = blockIdx.x;
    const float* xr = x + (long)row*DM;
    __shared__ float red[256];
    float s = 0.f;
    for (int i = threadIdx.x; i < DM; i += 256){ float v = xr[i]; s += v*v; }
    red[threadIdx.x] = s; __syncthreads();
    for (int st = 128; st > 0; st >>= 1){
        if (threadIdx.x < st) red[threadIdx.x] += red[threadIdx.x+st];
        __syncthreads();
    }
    float r = rsqrtf(red[0]/(float)DM + 1e-6f);
    for (int i = threadIdx.x; i < DM; i += 256)
        o[(long)row*DM+i] = __float2bfloat16(w[i]*xr[i]*r);
}

// ---------------- MMA primitives ----------------
__device__ __forceinline__ void cpasync16(unsigned dst, const void* src, int ssz){
    asm volatile("cp.async.ca.shared.global [%0], [%1], 16, %2;"
        :: "r"(dst), "l"(src), "r"(ssz));
}
__device__ __forceinline__ void cp_commit(){ asm volatile("cp.async.commit_group;"); }
__device__ __forceinline__ void cp_wait0(){ asm volatile("cp.async.wait_group 0;"); }
__device__ __forceinline__ void cp_wait1(){ asm volatile("cp.async.wait_group 1;"); }
__device__ __forceinline__ void ldsm_x4(unsigned saddr, unsigned &o0, unsigned &o1,
                                        unsigned &o2, unsigned &o3){
    asm volatile("ldmatrix.sync.aligned.m8n8.x4.shared.b16 {%0,%1,%2,%3},[%4];"
        : "=r"(o0),"=r"(o1),"=r"(o2),"=r"(o3) : "r"(saddr));
}
__device__ __forceinline__ void ldsm_x4_t(unsigned saddr, unsigned &o0, unsigned &o1,
                                          unsigned &o2, unsigned &o3){
    asm volatile("ldmatrix.sync.aligned.m8n8.x4.trans.shared.b16 {%0,%1,%2,%3},[%4];"
        : "=r"(o0),"=r"(o1),"=r"(o2),"=r"(o3) : "r"(saddr));
}
__device__ __forceinline__ void mma16816(float* d, const unsigned* am, const unsigned* bm){
    asm volatile("mma.sync.aligned.m16n8k16.row.col.f32.bf16.bf16.f32 "
        "{%0,%1,%2,%3},{%4,%5,%6,%7},{%8,%9},{%0,%1,%2,%3};"
        : "+f"(d[0]),"+f"(d[1]),"+f"(d[2]),"+f"(d[3])
        : "r"(am[0]),"r"(am[1]),"r"(am[2]),"r"(am[3]), "r"(bm[0]),"r"(bm[1]));
}
__device__ __forceinline__ unsigned pkbf2(float x, float y){
    __nv_bfloat162 t = __floats2bfloat162_rn(x, y);
    return *reinterpret_cast<unsigned*>(&t);
}

// ---------------- 128x128 GEMM (fp32 out, no epilogue) ----------------
__device__ __forceinline__ void stage_tiles(const bf16* Ab, const bf16* Bb,
    int bm, int bn, int N, int lda, int ldb, int k0, int tid,
    unsigned Adst, unsigned Bdst)
{
    #pragma unroll
    for (int c = tid; c < 512; c += 256){
        int r  = c >> 2;
        int ko = (c & 3) << 3;
        cpasync16(Adst + 2u*(unsigned)(r*40 + ko),
                  Ab + (long)(bm + r)*lda + k0 + ko, 16);
    }
    #pragma unroll
    for (int c = tid; c < 512; c += 256){
        int r  = c >> 4;
        int no = (c & 15) << 3;
        const bf16* src = Bb + (long)(k0 + r)*ldb + bn + no;
        int ssz = 16;
        if (bn + no >= N){ src = Bb; ssz = 0; }
        cpasync16(Bdst + 2u*(unsigned)(r*136 + no), src, ssz);
    }
}

__global__ void __launch_bounds__(256) bgemm_k(
    const bf16* __restrict__ Aptr, const bf16* __restrict__ Bptr, float* __restrict__ Cv,
    int M, int N, int K, int lda, int ldb, int ldc)
{
    __shared__ bf16 As[3*5120];
    __shared__ bf16 Bs[3*5120];
    const int bm = blockIdx.y * 128;
    const int bn = blockIdx.x * 128;
    const int tid  = threadIdx.x;
    const int lane = tid & 31;
    const int warp = tid >> 5;
    const int wm = warp >> 1;
    const int wn = warp & 1;

    float acc[2][8][4];
    #pragma unroll
    for (int i = 0; i < 2; i++)
        #pragma unroll
        for (int j = 0; j < 8; j++)
            #pragma unroll
            for (int q = 0; q < 4; q++) acc[i][j][q] = 0.f;

    unsigned Afrag[2][4];
    unsigned Bfrag[8][2];

    const unsigned As_base = (unsigned)__cvta_generic_to_shared(As);
    const unsigned Bs_base = (unsigned)__cvta_generic_to_shared(Bs);

    const int rowA = wm*32 + (lane & 15);
    const int colA = (lane >> 4) * 8;
    unsigned aoff0 = As_base + 2u*(unsigned)( rowA       *40 + colA);
    unsigned aoff1 = As_base + 2u*(unsigned)((rowA + 16) *40 + colA);

    unsigned boff[4];
    #pragma unroll
    for (int p = 0; p < 4; p++){
        int brow = lane & 15;
        int bcol = (lane >> 4) * 8;
        boff[p] = Bs_base + 2u*(unsigned)(brow*136 + wn*64 + p*16 + bcol);
    }

    const int nk = K >> 5;
    stage_tiles(Aptr, Bptr, bm, bn, N, lda, ldb, 0, tid, As_base, Bs_base);
    cp_commit();
    if (nk > 1){
        stage_tiles(Aptr, Bptr, bm, bn, N, lda, ldb, 32, tid,
                    As_base + 10240u, Bs_base + 10240u);
        cp_commit();
    }

    unsigned sb = 0u;
    for (int it = 0; it < nk; it++){
        if (it + 1 < nk) cp_wait1(); else cp_wait0();
        __syncthreads();
        if (it + 2 < nk){
            unsigned off = (unsigned)((it + 2) % 3) * 10240u;
            stage_tiles(Aptr, Bptr, bm, bn, N, lda, ldb, (it+2) << 5, tid,
                        As_base + off, Bs_base + off);
            cp_commit();
        }
        #pragma unroll
        for (int ks = 0; ks < 32; ks += 16){
            ldsm_x4(aoff0 + sb + 2u*ks, Afrag[0][0], Afrag[0][1], Afrag[0][2], Afrag[0][3]);
            ldsm_x4(aoff1 + sb + 2u*ks, Afrag[1][0], Afrag[1][1], Afrag[1][2], Afrag[1][3]);
            #pragma unroll
            for (int p = 0; p < 4; p++){
                unsigned ba = boff[p] + sb + 2u*(unsigned)(ks*136);
                ldsm_x4_t(ba, Bfrag[2*p][0], Bfrag[2*p][1],
                              Bfrag[2*p+1][0], Bfrag[2*p+1][1]);
            }
            #pragma unroll
            for (int mt = 0; mt < 2; mt++)
                #pragma unroll
                for (int nt = 0; nt < 8; nt++)
                    mma16816(acc[mt][nt], Afrag[mt], Bfrag[nt]);
        }
        sb += 10240u;
        if (sb == 30720u) sb = 0u;
    }

    #pragma unroll
    for (int mt = 0; mt < 2; mt++){
        int r0 = bm + wm*32 + mt*16 + (lane >> 2);
        #pragma unroll
        for (int nt = 0; nt < 8; nt++){
            int col = bn + wn*64 + nt*8 + ((lane & 3) << 1);
            if (col < N){
                *reinterpret_cast<float2*>(&Cv[(long)r0*ldc + col]) =
                    make_float2(acc[mt][nt][0], acc[mt][nt][1]);
                *reinterpret_cast<float2*>(&Cv[(long)(r0+8)*ldc + col]) =
                    make_float2(acc[mt][nt][2], acc[mt][nt][3]);
            }
        }
    }
}

// ---------------- 256x128 GEMM, 3 slots x 64-K groups, dynamic smem ----------------
#define GSLOT_A 40960u   // bytes per A slot (2 chunks x 20480)
#define GSLOT_B 17408u   // bytes per B slot (2 chunks x 8704)
#define DSMEM256 (3*(GSLOT_A + GSLOT_B))   // 175104 bytes

__device__ __forceinline__ void stage256(const bf16* Ab, const bf16* Bb,
    int bm, int bn, int N, int lda, int ldb, int k0, int tid,
    unsigned Adst, unsigned Bdst)
{
    #pragma unroll
    for (int c = tid; c < 1024; c += 256){
        int r  = c >> 2;
        int ko = (c & 3) << 3;
        cpasync16(Adst + 2u*(unsigned)(r*40 + ko),
                  Ab + (long)(bm + r)*lda + k0 + ko, 16);
    }
    #pragma unroll
    for (int c = tid; c < 512; c += 256){
        int r  = c >> 4;
        int no = (c & 15) << 3;
        const bf16* src = Bb + (long)(k0 + r)*ldb + bn + no;
        int ssz = 16;
        if (bn + no >= N){ src = Bb; ssz = 0; }
        cpasync16(Bdst + 2u*(unsigned)(r*136 + no), src, ssz);
    }
}

// EPI: 0 none, 1 relu(acc+bias) fp32, 2 resid fp32, 3 siluGLU bf16
template<int EPI, int OUTBF>
__global__ void __launch_bounds__(256) bgemm256_k(
    const bf16* __restrict__ Aptr, const bf16* __restrict__ Bptr, void* __restrict__ Cv,
    int M, int N, int K, int lda, int ldb, int ldc,
    long sA, long sB, long sC, const float* __restrict__ bias,
    const float* __restrict__ resx, const int* __restrict__ mcnt)
{
    extern __shared__ bf16 dsm[];
    const int bm = blockIdx.y * 256;
    int Meff = M;
    if (mcnt) Meff = mcnt[blockIdx.z];
    if (bm >= Meff) return;
    const bf16* Ab = Aptr + (long)blockIdx.z * sA;
    const bf16* Bb = Bptr + (long)blockIdx.z * sB;
    const int bn = blockIdx.x * 128;
    const int tid  = threadIdx.x;
    const int lane = tid & 31;
    const int warp = tid >> 5;
    const int wm = warp >> 1;
    const int wn = warp & 1;

    float acc[4][8][4];
    #pragma unroll
    for (int i = 0; i < 4; i++)
        #pragma unroll
        for (int j = 0; j < 8; j++)
            #pragma unroll
            for (int q = 0; q < 4; q++) acc[i][j][q] = 0.f;

    unsigned Afrag[4][4];
    unsigned Bfrag[8][2];

    const unsigned As_base = (unsigned)__cvta_generic_to_shared(dsm);
    const unsigned Bs_base = As_base + 3u*GSLOT_A;

    const int rowA = wm*64 + (lane & 15);
    const int colA = (lane >> 4) * 8;
    unsigned aoff[4];
    #pragma unroll
    for (int mt = 0; mt < 4; mt++)
        aoff[mt] = As_base + 2u*(unsigned)((rowA + mt*16)*40 + colA);

    unsigned boff[4];
    {
        int brow = lane & 15;
        int bcol = (lane >> 4) * 8;
        #pragma unroll
        for (int p = 0; p < 4; p++)
            boff[p] = Bs_base + 2u*(unsigned)(brow*136 + wn*64 + p*16 + bcol);
    }

    const int ng = K >> 6;   // 64-wide K groups
    stage256(Ab, Bb, bm, bn, N, lda, ldb, 0,  tid, As_base,           Bs_base);
    stage256(Ab, Bb, bm, bn, N, lda, ldb, 32, tid, As_base + 20480u,  Bs_base + 8704u);
    cp_commit();
    if (ng > 1){
        stage256(Ab, Bb, bm, bn, N, lda, ldb, 64, tid, As_base + GSLOT_A,           Bs_base + GSLOT_B);
        stage256(Ab, Bb, bm, bn, N, lda, ldb, 96, tid, As_base + GSLOT_A + 20480u,  Bs_base + GSLOT_B + 8704u);
        cp_commit();
    }

    for (int g = 0; g < ng; g++){
        if (g + 1 < ng) cp_wait1(); else cp_wait0();
        __syncthreads();
        if (g + 2 < ng){
            unsigned sl = (unsigned)((g + 2) % 3);
            int k0 = (g + 2) << 6;
            stage256(Ab, Bb, bm, bn, N, lda, ldb, k0,      tid,
                     As_base + sl*GSLOT_A,           Bs_base + sl*GSLOT_B);
            stage256(Ab, Bb, bm, bn, N, lda, ldb, k0 + 32, tid,
                     As_base + sl*GSLOT_A + 20480u,  Bs_base + sl*GSLOT_B + 8704u);
            cp_commit();
        }
        unsigned slA = (unsigned)(g % 3) * GSLOT_A;
        unsigned slB = (unsigned)(g % 3) * GSLOT_B;
        #pragma unroll
        for (int sub = 0; sub < 2; sub++){
            unsigned sa  = slA + (unsigned)sub*20480u;
            unsigned sbb = slB + (unsigned)sub*8704u;
            #pragma unroll
            for (int ks = 0; ks < 32; ks += 16){
                #pragma unroll
                for (int mt = 0; mt < 4; mt++)
                    ldsm_x4(aoff[mt] + sa + 2u*ks,
                            Afrag[mt][0], Afrag[mt][1], Afrag[mt][2], Afrag[mt][3]);
                #pragma unroll
                for (int p = 0; p < 4; p++){
                    unsigned ba = boff[p] + sbb + 2u*(unsigned)(ks*136);
                    ldsm_x4_t(ba, Bfrag[2*p][0], Bfrag[2*p][1],
                                  Bfrag[2*p+1][0], Bfrag[2*p+1][1]);
                }
                #pragma unroll
                for (int mt = 0; mt < 4; mt++)
                    #pragma unroll
                    for (int nt = 0; nt < 8; nt++)
                        mma16816(acc[mt][nt], Afrag[mt], Bfrag[nt]);
            }
        }
        // no trailing barrier: next iteration's leading barrier orders buffer reuse
    }

    #pragma unroll
    for (int mt = 0; mt < 4; mt++){
        int r0 = bm + wm*64 + mt*16 + (lane >> 2);
        #pragma unroll
        for (int nt = 0; nt < 8; nt++){
            int col = bn + wn*64 + nt*8 + ((lane & 3) << 1);
            if (col < N){
                float v0 = acc[mt][nt][0];
                float v1 = acc[mt][nt][1];
                float v2 = acc[mt][nt][2];
                float v3 = acc[mt][nt][3];
                if (EPI == 3){
                    bf16* Cb = (bf16*)Cv + (long)blockIdx.z * sC;
                    int jc = col >> 1;
                    Cb[(long)r0*(N>>1) + jc]     = __float2bfloat16(siluf(v0)*v1);
                    Cb[(long)(r0+8)*(N>>1) + jc] = __float2bfloat16(siluf(v2)*v3);
                    continue;
                }
                if (EPI == 1){
                    float b0 = bias[col];
                    float b1 = bias[col+1];
                    v0 = fmaxf(v0+b0, 0.f); v1 = fmaxf(v1+b1, 0.f);
                    v2 = fmaxf(v2+b0, 0.f); v3 = fmaxf(v3+b1, 0.f);
                }
                if (EPI == 2){
                    float b0 = bias[col];
                    float b1 = bias[col+1];
                    v0 = fmaf(b0, v0, resx[(long)r0*ldc + col]);
                    v1 = fmaf(b1, v1, resx[(long)r0*ldc + col + 1]);
                    v2 = fmaf(b0, v2, resx[(long)(r0+8)*ldc + col]);
                    v3 = fmaf(b1, v3, resx[(long)(r0+8)*ldc + col + 1]);
                }
                if (OUTBF){
                    bf16* Cb = (bf16*)Cv + (long)blockIdx.z * sC;
                    *reinterpret_cast<__nv_bfloat162*>(&Cb[(long)r0*ldc + col]) =
                        __floats2bfloat162_rn(v0, v1);
                    *reinterpret_cast<__nv_bfloat162*>(&Cb[(long)(r0+8)*ldc + col]) =
                        __floats2bfloat162_rn(v2, v3);
                } else {
                    float* Cb = (float*)Cv + (long)blockIdx.z * sC;
                    *reinterpret_cast<float2*>(&Cb[(long)r0*ldc + col]) = make_float2(v0, v1);
                    *reinterpret_cast<float2*>(&Cb[(long)(r0+8)*ldc + col]) = make_float2(v2, v3);
                }
            }
        }
    }
}

// ---------------- fused flash attention ----------------
#define FTILE (128*136)
#define FSMEM (5*FTILE*2)

__device__ __forceinline__ void fstage(const bf16* src, unsigned dst, int tid){
    for (int i = tid; i < 2048; i += 256){
        int r = i >> 4, c = (i & 15) << 3;
        cpasync16(dst + 2u*(unsigned)(r*136 + c), src + r*DH + c, 16);
    }
}

__global__ void __launch_bounds__(256, 1) flash_k(
    const bf16* __restrict__ q, const bf16* __restrict__ k, const bf16* __restrict__ v,
    const float* __restrict__ ascale, bf16* __restrict__ att)
{
    extern __shared__ bf16 fs[];
    const int qt = blockIdx.x, bh = blockIdx.y;
    const int bb = bh >> 3, hh = bh & 7;
    const int tid = threadIdx.x, lane = tid & 31, w = tid >> 5;
    const float a = ascale[hh];

    const bf16* qg = q + ((long)bh*LSEQ + qt*128)*DH;
    const bf16* kg = k + (long)bh*LSEQ*DH;
    const bf16* vg = v + (long)bh*LSEQ*DH;

    const unsigned Qb = (unsigned)__cvta_generic_to_shared(fs);
    const unsigned Kb = Qb + 2u*FTILE;
    const unsigned Vb = Qb + 6u*FTILE;
    const unsigned TILEB = 2u*FTILE;

    fstage(qg, Qb, tid);
    fstage(kg, Kb, tid);
    fstage(vg, Vb, tid);
    cp_commit();
    cp_wait0();
    __syncthreads();

    unsigned qf[8][4];
    {
        int rq = w*16 + (lane & 15);
        int cq = (lane >> 4) << 3;
        #pragma unroll
        for (int ks = 0; ks < 8; ks++)
            ldsm_x4(Qb + 2u*(unsigned)(rq*136 + ks*16 + cq),
                    qf[ks][0], qf[ks][1], qf[ks][2], qf[ks][3]);
    }

    const int brow = (lane & 7) + (((lane >> 4) & 1) << 3);
    const int bcol = ((lane >> 3) & 1) << 3;
    unsigned kadr[8], vadr[8];
    #pragma unroll
    for (int p = 0; p < 8; p++){
        kadr[p] = Kb + 2u*(unsigned)((p*16 + brow)*136 + bcol);
        vadr[p] = Vb + 2u*(unsigned)((lane & 15)*136 + p*16 + ((lane >> 4) << 3));
    }

    float oacc[16][4];
    #pragma unroll
    for (int nt = 0; nt < 16; nt++)
        #pragma unroll
        for (int qq = 0; qq < 4; qq++) oacc[nt][qq] = 0.f;
    float m0 = -1e30f, m1 = -1e30f, l0 = 0.f, l1 = 0.f;

    for (int kt = 0; kt < 16; kt++){
        if (kt > 0){ cp_wait0(); __syncthreads(); }
        if (kt + 1 < 16){
            unsigned off = ((kt + 1) & 1) ? TILEB : 0u;
            fstage(kg + (long)(kt+1)*128*DH, Kb + off, tid);
            fstage(vg + (long)(kt+1)*128*DH, Vb + off, tid);
            cp_commit();
        }
        const unsigned sb = (kt & 1) ? TILEB : 0u;

        float sacc[16][4];
        #pragma unroll
        for (int nt = 0; nt < 16; nt++)
            #pragma unroll
            for (int qq = 0; qq < 4; qq++) sacc[nt][qq] = 0.f;

        #pragma unroll
        for (int ks = 0; ks < 8; ks++){
            #pragma unroll
            for (int p = 0; p < 8; p++){
                unsigned bf0[2], bf1[2];
                ldsm_x4(kadr[p] + sb + 2u*(unsigned)(ks*16),
                        bf0[0], bf0[1], bf1[0], bf1[1]);
                mma16816(sacc[2*p],   qf[ks], bf0);
                mma16816(sacc[2*p+1], qf[ks], bf1);
            }
        }

        float ax0 = -1e30f, ax1 = -1e30f;
        #pragma unroll
        for (int nt = 0; nt < 16; nt++){
            sacc[nt][0] *= a; sacc[nt][1] *= a; sacc[nt][2] *= a; sacc[nt][3] *= a;
            ax0 = fmaxf(ax0, fmaxf(sacc[nt][0], sacc[nt][1]));
            ax1 = fmaxf(ax1, fmaxf(sacc[nt][2], sacc[nt][3]));
        }
        ax0 = fmaxf(ax0, __shfl_xor_sync(0xffffffffu, ax0, 1));
        ax0 = fmaxf(ax0, __shfl_xor_sync(0xffffffffu, ax0, 2));
        ax1 = fmaxf(ax1, __shfl_xor_sync(0xffffffffu, ax1, 1));
        ax1 = fmaxf(ax1, __shfl_xor_sync(0xffffffffu, ax1, 2));
        float mn0 = fmaxf(m0, ax0), mn1 = fmaxf(m1, ax1);
        float f0 = expf(m0 - mn0), f1 = expf(m1 - mn1);

        float rs0 = 0.f, rs1 = 0.f;
        #pragma unroll
        for (int nt = 0; nt < 16; nt++){
            sacc[nt][0] = expf(sacc[nt][0] - mn0);
            sacc[nt][1] = expf(sacc[nt][1] - mn0);
            sacc[nt][2] = expf(sacc[nt][2] - mn1);
            sacc[nt][3] = expf(sacc[nt][3] - mn1);
            rs0 += sacc[nt][0] + sacc[nt][1];
            rs1 += sacc[nt][2] + sacc[nt][3];
        }
        rs0 += __shfl_xor_sync(0xffffffffu, rs0, 1);
        rs0 += __shfl_xor_sync(0xffffffffu, rs0, 2);
        rs1 += __shfl_xor_sync(0xffffffffu, rs1, 1);
        rs1 += __shfl_xor_sync(0xffffffffu, rs1, 2);
        l0 = l0*f0 + rs0; l1 = l1*f1 + rs1;
        m0 = mn0; m1 = mn1;

        #pragma unroll
        for (int nt = 0; nt < 16; nt++){
            oacc[nt][0] *= f0; oacc[nt][1] *= f0;
            oacc[nt][2] *= f1; oacc[nt][3] *= f1;
        }

        unsigned pa[8][4];
        #pragma unroll
        for (int ksp = 0; ksp < 8; ksp++){
            pa[ksp][0] = pkbf2(sacc[2*ksp][0],   sacc[2*ksp][1]);
            pa[ksp][1] = pkbf2(sacc[2*ksp][2],   sacc[2*ksp][3]);
            pa[ksp][2] = pkbf2(sacc[2*ksp+1][0], sacc[2*ksp+1][1]);
            pa[ksp][3] = pkbf2(sacc[2*ksp+1][2], sacc[2*ksp+1][3]);
        }

        #pragma unroll
        for (int ksp = 0; ksp < 8; ksp++){
            #pragma unroll
            for (int p = 0; p < 8; p++){
                unsigned bf0[2], bf1[2];
                ldsm_x4_t(vadr[p] + sb + 2u*(unsigned)(ksp*16*136),
                          bf0[0], bf0[1], bf1[0], bf1[1]);
                mma16816(oacc[2*p],   pa[ksp], bf0);
                mma16816(oacc[2*p+1], pa[ksp], bf1);
            }
        }
    }

    float inv0 = 1.f / l0, inv1 = 1.f / l1;
    long row0 = (long)bb*LSEQ + qt*128 + w*16 + (lane >> 2);
    long row1 = row0 + 8;
    int  cbase = hh*DH + ((lane & 3) << 1);
    #pragma unroll
    for (int nt = 0; nt < 16; nt++){
        int col = cbase + nt*8;
        *reinterpret_cast<__nv_bfloat162*>(&att[row0*DM + col]) =
            __floats2bfloat162_rn(oacc[nt][0]*inv0, oacc[nt][1]*inv0);
        *reinterpret_cast<__nv_bfloat162*>(&att[row1*DM + col]) =
            __floats2bfloat162_rn(oacc[nt][2]*inv1, oacc[nt][3]*inv1);
    }
}

// ---------------- depthwise conv + bias + SiLU ----------------
__global__ void conv_k(const float* __restrict__ xz, const float* __restrict__ cw,
                       const float* __restrict__ cb, float* __restrict__ xc,
                       bf16* __restrict__ xcb){
    long idx = (long)blockIdx.x*blockDim.x + threadIdx.x;
    if (idx >= (long)NTOK*DI) return;
    int d = (int)(idx % DI);
    int row = (int)(idx / DI);
    int t = row % LSEQ, b = row / LSEQ;
    float s = cb[d];
    #pragma unroll
    for (int k = 0; k < 4; k++){
        int tt = t + k - 2;
        if (tt >= 0 && tt < LSEQ)
            s = fmaf(cw[d*4+k], xz[(long)(b*LSEQ+tt)*(2*DI) + d], s);
    }
    float v = siluf(s);
    xc[idx] = v;
    xcb[idx] = __float2bfloat16(v);
}

// ---------------- scan preprocessing ----------------
__global__ void scanprep_k(const float* __restrict__ dtBC, const float* __restrict__ bdt,
                           const float* __restrict__ A, float* __restrict__ sp){
    int idx = blockIdx.x*blockDim.x + threadIdx.x;
    if (idx >= NTOK*16) return;
    int n = idx & 15, row = idx >> 4;
    float dtp = dtBC[(long)row*64 + n] + bdt[n];
    float dt  = fmaxf(dtp, 0.f) + log1pf(expf(-fabsf(dtp)));
    sp[(long)row*48 + n]      = expf(dt * A[n]);
    sp[(long)row*48 + 16 + n] = dt * dtBC[(long)row*64 + 16 + n];
    sp[(long)row*48 + 32 + n] = dtBC[(long)row*64 + 32 + n];
}

// ---------------- chunked selective scan ----------------
__global__ void scanP_k(const float* __restrict__ sp, float* __restrict__ P){
    int b = blockIdx.x / NCH, ch = blockIdx.x % NCH;
    int n = threadIdx.x;
    if (n >= 16) return;
    float p = 1.f;
    long base = ((long)b*LSEQ + ch*CLEN)*48;
    for (int t = 0; t < CLEN; t++) p *= sp[base + t*48 + n];
    P[(b*NCH+ch)*16 + n] = p;
}

__global__ void scanA_k(const float* __restrict__ sp, const float* __restrict__ xc,
                        float* __restrict__ hend){
    int b = blockIdx.z, ch = blockIdx.y;
    int d = blockIdx.x*128 + threadIdx.x;
    __shared__ float s[CLEN*48];
    const float* src = sp + ((long)b*LSEQ + ch*CLEN)*48;
    for (int i = threadIdx.x; i < CLEN*48; i += 128) s[i] = src[i];
    __syncthreads();
    float h[16];
    #pragma unroll
    for (int n = 0; n < 16; n++) h[n] = 0.f;
    long rowbase = (long)b*LSEQ + ch*CLEN;
    float xv_next = xc[rowbase*DI + d];
    for (int tt = 0; tt < CLEN; tt++){
        float xv = xv_next;
        if (tt + 1 < CLEN) xv_next = xc[(rowbase + tt + 1)*DI + d];
        const float* e = s + tt*48;
        #pragma unroll
        for (int n = 0; n < 16; n++)
            h[n] = fmaf(e[n], h[n], e[16+n]*xv);
    }
    float* o = hend + (((long)(b*NCH + ch)*DI + d) << 4);
    #pragma unroll
    for (int n = 0; n < 16; n += 4)
        *reinterpret_cast<float4*>(o + n) = make_float4(h[n], h[n+1], h[n+2], h[n+3]);
}

__global__ void scanComb_k(const float* __restrict__ hend, const float* __restrict__ P,
                           float* __restrict__ h0){
    int g = blockIdx.x*128 + threadIdx.x;
    int b = g / DI, d = g % DI;
    __shared__ float sP[NCH*16];
    for (int i = threadIdx.x; i < NCH*16; i += 128) sP[i] = P[b*NCH*16 + i];
    __syncthreads();
    float h[16];
    #pragma unroll
    for (int n = 0; n < 16; n++) h[n] = 0.f;
    {
        float* o = h0 + (((long)(b*NCH)*DI + d) << 4);
        #pragma unroll
        for (int n = 0; n < 16; n += 4)
            *reinterpret_cast<float4*>(o + n) = make_float4(0.f, 0.f, 0.f, 0.f);
    }
    for (int c = 1; c < NCH; c++){
        const float* he = hend + (((long)(b*NCH + c - 1)*DI + d) << 4);
        #pragma unroll
        for (int n = 0; n < 16; n++)
            h[n] = fmaf(sP[(c-1)*16 + n], h[n], he[n]);
        float* o = h0 + (((long)(b*NCH + c)*DI + d) << 4);
        #pragma unroll
        for (int n = 0; n < 16; n += 4)
            *reinterpret_cast<float4*>(o + n) = make_float4(h[n], h[n+1], h[n+2], h[n+3]);
    }
}

__global__ void scanC_k(const float* __restrict__ sp, const float* __restrict__ xc,
                        const float* __restrict__ xz, const float* __restrict__ Dp,
                        const float* __restrict__ h0, bf16* __restrict__ ymulb){
    int b = blockIdx.z, ch = blockIdx.y;
    int d = blockIdx.x*128 + threadIdx.x;
    __shared__ float s[CLEN*48];
    const float* src = sp + ((long)b*LSEQ + ch*CLEN)*48;
    for (int i = threadIdx.x; i < CLEN*48; i += 128) s[i] = src[i];
    __syncthreads();
    float h[16];
    {   const float* hi = h0 + (((long)(b*NCH + ch)*DI + d) << 4);
        #pragma unroll
        for (int n = 0; n < 16; n += 4){
            float4 v = *reinterpret_cast<const float4*>(hi + n);
            h[n] = v.x; h[n+1] = v.y; h[n+2] = v.z; h[n+3] = v.w;
        }
    }
    const float dpv = Dp[d];
    long rowbase = (long)b*LSEQ + ch*CLEN;
    float xv_next = xc[rowbase*DI + d];
    float z_next  = xz[rowbase*(2*DI) + DI + d];
    for (int tt = 0; tt < CLEN; tt++){
        float xv = xv_next;
        float z  = z_next;
        if (tt + 1 < CLEN){
            xv_next = xc[(rowbase + tt + 1)*DI + d];
            z_next  = xz[(rowbase + tt + 1)*(2*DI) + DI + d];
        }
        const float* e = s + tt*48;
        float y = 0.f;
        #pragma unroll
        for (int n = 0; n < 16; n++){
            h[n] = fmaf(e[n], h[n], e[16+n]*xv);
            y = fmaf(h[n], e[32+n], y);
        }
        ymulb[(rowbase + tt)*DI + d] = __float2bfloat16((y + dpv*xv) * siluf(z));
    }
}

// ---------------- RoPE (bf16 qkv in) -> qb,kb,vb bf16 ----------------
__global__ void rope2_k(const bf16* __restrict__ qkv, bf16* __restrict__ qb,
                        bf16* __restrict__ kb, bf16* __restrict__ vb){
    int row = blockIdx.x;
    int t = row % LSEQ, b = row / LSEQ;
    __shared__ float q[DM], kk[DM];
    const bf16* base = qkv + (long)row*3*DM;
    for (int i = threadIdx.x; i < DM; i += 256){
        q[i]  = __bfloat162float(base[i]);
        kk[i] = __bfloat162float(base[DM+i]);
    }
    __syncthreads();
    const float sq = sqrtf((float)DH);
    const float lg = logf(10000.f) / 64.f;
    for (int idx = threadIdx.x; idx < DM; idx += 256){
        int h = idx / DH, i = idx % DH;
        int j = i & 63;
        float inv = expf(-(float)j * lg);
        float ang = (float)t * inv;
        float c = cosf(ang), s = sinf(ang);
        int off = h * DH;
        float rq, rk;
        if (i < 64){ rq = -q[off + 2*i + 1]; rk = -kk[off + 2*i + 1]; }
        else       { rq =  q[off + 2*(i-64)]; rk =  kk[off + 2*(i-64)]; }
        long o = ((long)(b*NH + h)*LSEQ + t)*DH + i;
        qb[o] = __float2bfloat16((q[idx]*c + rq*s) * sq);
        kb[o] = __float2bfloat16(kk[idx]*c + rk*s);
        vb[o] = base[2*DM + idx];
    }
}

// ---------------- gate stage 2 (bias+relu folded in; zeroes counters) ----------------
__global__ void gate2_k(const float* __restrict__ g1, const float* __restrict__ bg1,
                        const float* __restrict__ Wg2,
                        float* __restrict__ gs, int* __restrict__ topi, float* __restrict__ topw,
                        int* __restrict__ cnt){
    int row = blockIdx.x;
    int tid = threadIdx.x;
    if (row == 0 && tid < NEXP) cnt[tid] = 0;   // safe: assign_k launches after this kernel retires
    __shared__ float red[64*4];
    float a[4] = {0.f,0.f,0.f,0.f};
    for (int j = tid; j < 512; j += 64){
        float v = fmaxf(g1[(long)row*512 + j] + bg1[j], 0.f);
        #pragma unroll
        for (int e = 0; e < 4; e++) a[e] = fmaf(v, Wg2[j*4+e], a[e]);
    }
    #pragma unroll
    for (int e = 0; e < 4; e++) red[e*64 + tid] = a[e];
    __syncthreads();
    for (int st = 32; st > 0; st >>= 1){
        if (tid < st){
            #pragma unroll
            for (int e = 0; e < 4; e++) red[e*64+tid] += red[e*64+tid+st];
        }
        __syncthreads();
    }
    if (tid == 0){
        float l[4]; for (int e = 0; e < 4; e++) l[e] = red[e*64];
        float m = fmaxf(fmaxf(l[0],l[1]), fmaxf(l[2],l[3]));
        float ex[4]; float s = 0.f;
        for (int e = 0; e < 4; e++){ ex[e] = expf(l[e]-m); s += ex[e]; }
        float gsv[4];
        for (int e = 0; e < 4; e++){ gsv[e] = ex[e]/s; gs[(long)row*4+e] = gsv[e]; }
        int i0 = 0;
        for (int e = 1; e < 4; e++) if (gsv[e] > gsv[i0]) i0 = e;
        int i1 = -1;
        for (int e = 0; e < 4; e++) if (e != i0 && (i1 < 0 || gsv[e] > gsv[i1])) i1 = e;
        float v0 = gsv[i0], v1 = gsv[i1];
        float mm = fmaxf(v0, v1);
        float w0 = expf(v0-mm), w1 = expf(v1-mm);
        float ws = w0 + w1;
        topi[row*2] = i0; topi[row*2+1] = i1;
        topw[row*2] = w0/ws; topw[row*2+1] = w1/ws;
    }
}

// ---------------- balance loss ----------------
__global__ void bal_k(const float* __restrict__ gs, float* __restrict__ out){
    int tid = threadIdx.x;
    __shared__ float red[256*4];
    float a[4] = {0.f,0.f,0.f,0.f};
    for (int r = tid; r < NTOK; r += 256){
        #pragma unroll
        for (int e = 0; e < 4; e++) a[e] += gs[(long)r*4+e];
    }
    #pragma unroll
    for (int e = 0; e < 4; e++) red[e*256+tid] = a[e];
    __syncthreads();
    for (int st = 128; st > 0; st >>= 1){
        if (tid < st){
            #pragma unroll
            for (int e = 0; e < 4; e++) red[e*256+tid] += red[e*256+tid+st];
        }
        __syncthreads();
    }
    if (tid == 0){
        float bal = 0.f;
        for (int e = 0; e < 4; e++){
            float gm = red[e*256] / (float)NTOK;
            bal += gm * logf(gm + 1e-8f);
        }
        out[0] = (float)NEXP * bal;
    }
}

// ---------------- MoE routing ----------------
__global__ void assign_k(const int* __restrict__ topi, int* __restrict__ cnt,
                         int* __restrict__ slot){
    int idx = blockIdx.x*256 + threadIdx.x;
    if (idx >= NTOK*2) return;
    int e = topi[idx];
    int s = atomicAdd(&cnt[e], 1);
    slot[idx] = e*NTOK + s;
}

__global__ void gather_k(const bf16* __restrict__ xf, const int* __restrict__ slot,
                         bf16* __restrict__ xg){
    int idx = blockIdx.x;
    int tok = idx >> 1;
    int dst = slot[idx];
    const unsigned* src = reinterpret_cast<const unsigned*>(xf) + (long)tok*(DM/2);
    unsigned* d = reinterpret_cast<unsigned*>(xg) + (long)dst*(DM/2);
    for (int i = threadIdx.x; i < DM/2; i += 128) d[i] = src[i];
}

// ---------------- MoE combine + final residual ----------------
__global__ void combine2_k(const float* __restrict__ x2, const float* __restrict__ ls3,
                           const bf16* __restrict__ eo, const int* __restrict__ slot,
                           const float* __restrict__ topw, float* __restrict__ out){
    long idx = (long)blockIdx.x*blockDim.x + threadIdx.x;
    if (idx >= (long)NTOK*DM) return;
    int row = (int)(idx / DM), d = (int)(idx % DM);
    int s0 = slot[row*2], s1 = slot[row*2+1];
    float m = topw[row*2]   * __bfloat162float(eo[(long)s0*DM + d])
            + topw[row*2+1] * __bfloat162float(eo[(long)s1*DM + d]);
    out[idx] = fmaf(ls3[d], m, x2[idx]);
}

// ============================== host ==============================
#define SYMPF(p, s) do { void* _t; cudaGetSymbolAddress(&_t, s); p = (float*)_t; } while(0)
#define SYMPB(p, s) do { void* _t; cudaGetSymbolAddress(&_t, s); p = (bf16*)_t; } while(0)
#define SYMPI(p, s) do { void* _t; cudaGetSymbolAddress(&_t, s); p = (int*)_t; } while(0)

extern "C" void kernel_launch(void* const* d_in, const int* in_sizes, int n_in,
                              void* d_out, int out_size){
    const float* x      = (const float*)d_in[0];
    const float* rms1_w = (const float*)d_in[1];
    const float* rms2_w = (const float*)d_in[2];
    const float* rms3_w = (const float*)d_in[3];
    const float* ls1    = (const float*)d_in[4];
    const float* ls2    = (const float*)d_in[5];
    const float* ls3    = (const float*)d_in[6];
    const float* W_in   = (const float*)d_in[7];
    const float* conv_w = (const float*)d_in[8];
    const float* conv_b = (const float*)d_in[9];
    const float* W_B    = (const float*)d_in[10];
    const float* W_C    = (const float*)d_in[11];
    const float* W_dt   = (const float*)d_in[12];
    const float* b_dt   = (const float*)d_in[13];
    const float* W_out_m= (const float*)d_in[14];
    const float* Avec   = (const float*)d_in[15];
    const float* Dp     = (const float*)d_in[16];
    const float* W_qkv  = (const float*)d_in[17];
    const float* W_o    = (const float*)d_in[18];
    const float* ascale = (const float*)d_in[19];
    const float* Wg1    = (const float*)d_in[20];
    const float* bg1    = (const float*)d_in[21];
    const float* Wg2    = (const float*)d_in[22];
    const float* w1     = (const float*)d_in[23];
    const float* w2     = (const float*)d_in[24];
    const float* w3     = (const float*)d_in[25];
    float* out = (float*)d_out;

    float *p_xz, *p_xc, *p_dtBC, *p_scanp, *p_x1, *p_x2, *p_g1, *p_gs, *p_topw;
    float *p_hend, *p_h0, *p_P;
    int *p_topi, *p_cnt, *p_slot;
    bf16 *b_rms1, *b_xc, *b_ymul, *b_rms2, *b_qkv, *b_q, *b_k, *b_v, *b_att, *b_xf,
         *b_xg, *b_h, *b_eo;
    bf16 *b_Win, *b_Wout, *b_Wqkv, *b_Wo, *b_Wg1, *b_w12, *b_w3, *b_Wcat;

    SYMPF(p_xz, g_xz); SYMPF(p_xc, g_xc); SYMPF(p_dtBC, g_dtBC); SYMPF(p_scanp, g_scanp);
    SYMPF(p_x1, g_x1);
    SYMPF(p_x2, g_x2); SYMPF(p_g1, g_g1); SYMPF(p_gs, g_gs); SYMPF(p_topw, g_topw);
    SYMPF(p_hend, g_hend); SYMPF(p_h0, g_h0); SYMPF(p_P, g_P);
    SYMPI(p_topi, g_topi); SYMPI(p_cnt, g_cnt); SYMPI(p_slot, g_slot);
    SYMPB(b_rms1, g_rms1b); SYMPB(b_xc, g_xcb); SYMPB(b_ymul, g_ymulb); SYMPB(b_rms2, g_rms2b);
    SYMPB(b_qkv, g_qkvb); SYMPB(b_q, g_qb); SYMPB(b_k, g_kb); SYMPB(b_v, g_vb);
    SYMPB(b_att, g_attb); SYMPB(b_xf, g_xfb); SYMPB(b_xg, g_xgb);
    SYMPB(b_h, g_hb); SYMPB(b_eo, g_eob);
    SYMPB(b_Win, g_Winb); SYMPB(b_Wout, g_Woutb); SYMPB(b_Wqkv, g_Wqkvb); SYMPB(b_Wo, g_Wob);
    SYMPB(b_Wg1, g_Wg1b); SYMPB(b_w12, g_w12b); SYMPB(b_w3, g_w3b); SYMPB(b_Wcat, g_Wcatb);

    // raise dynamic smem caps (host-side, not captured; same pattern as flash_k)
    cudaFuncSetAttribute(bgemm256_k<0,0>, cudaFuncAttributeMaxDynamicSharedMemorySize, DSMEM256);
    cudaFuncSetAttribute(bgemm256_k<2,0>, cudaFuncAttributeMaxDynamicSharedMemorySize, DSMEM256);
    cudaFuncSetAttribute(bgemm256_k<0,1>, cudaFuncAttributeMaxDynamicSharedMemorySize, DSMEM256);
    cudaFuncSetAttribute(bgemm256_k<3,1>, cudaFuncAttributeMaxDynamicSharedMemorySize, DSMEM256);
    cudaFuncSetAttribute(flash_k, cudaFuncAttributeMaxDynamicSharedMemorySize, FSMEM);

    // ---- weight conversions (merged) ----
    {
        long n0 = (long)DM*2*DI, n1 = (long)DI*DM, n2 = (long)DM*3*DM,
             n3 = (long)DM*DM, n4 = (long)DM*512, n5 = (long)NEXP*DFF*DM;
        long tot = n0+n1+n2+n3+n4+n5;
        convall_k<<<(int)((tot/4 + 255)/256), 256>>>(
            W_in, b_Win, n0,  W_out_m, b_Wout, n1,  W_qkv, b_Wqkv, n2,
            W_o,  b_Wo,  n3,  Wg1,     b_Wg1,  n4,  w3,    b_w3,   n5);
    }
    pack12_k<<<(int)(((long)NEXP*DM*DFF/4 + 255)/256), 256>>>(w1, w2, b_w12);
    packw_k<<<(DI*64+255)/256, 256>>>(W_dt, W_B, W_C, b_Wcat);

    // ---- 1. Mamba ----
    rmsnorm_bf_k<<<NTOK, 256>>>(x, rms1_w, b_rms1);
    {   dim3 g(2*DI/128, NTOK/256, 1);
        bgemm256_k<0,0><<<g, 256, DSMEM256>>>(b_rms1, b_Win, p_xz, NTOK, 2*DI, DM, DM, 2*DI, 2*DI,
                                              0,0,0, nullptr, nullptr, nullptr); }
    conv_k<<<(int)(((long)NTOK*DI+255)/256), 256>>>(p_xz, conv_w, conv_b, p_xc, b_xc);
    {   dim3 g(1, NTOK/128, 1);
        bgemm_k<<<g, 256>>>(b_xc, b_Wcat, p_dtBC, NTOK, 64, DI, DI, 64, 64); }
    scanprep_k<<<(NTOK*16+255)/256, 256>>>(p_dtBC, b_dt, Avec, p_scanp);
    scanP_k<<<BB*NCH, 16>>>(p_scanp, p_P);
    {   dim3 g(16, NCH, BB);
        scanA_k<<<g, 128>>>(p_scanp, p_xc, p_hend); }
    scanComb_k<<<BB*DI/128, 128>>>(p_hend, p_P, p_h0);
    {   dim3 g(16, NCH, BB);
        scanC_k<<<g, 128>>>(p_scanp, p_xc, p_xz, Dp, p_h0, b_ymul); }
    {   dim3 g(DM/128, NTOK/256, 1);   // x1 = x + ls1 * (ymul @ Wout)
        bgemm256_k<2,0><<<g, 256, DSMEM256>>>(b_ymul, b_Wout, p_x1, NTOK, DM, DI, DI, DM, DM,
                                              0,0,0, ls1, x, nullptr); }

    // ---- 2. Attention ----
    rmsnorm_bf_k<<<NTOK, 256>>>(p_x1, rms2_w, b_rms2);
    {   dim3 g(3*DM/128, NTOK/256, 1);   // qkv bf16 out
        bgemm256_k<0,1><<<g, 256, DSMEM256>>>(b_rms2, b_Wqkv, b_qkv, NTOK, 3*DM, DM, DM, 3*DM, 3*DM,
                                              0,0,0, nullptr, nullptr, nullptr); }
    rope2_k<<<NTOK, 256>>>(b_qkv, b_q, b_k, b_v);
    {   dim3 g(LSEQ/128, BB*NH, 1);
        flash_k<<<g, 256, FSMEM>>>(b_q, b_k, b_v, ascale, b_att); }
    {   dim3 g(DM/128, NTOK/256, 1);   // x2 = x1 + ls2 * (att @ Wo)
        bgemm256_k<2,0><<<g, 256, DSMEM256>>>(b_att, b_Wo, p_x2, NTOK, DM, DM, DM, DM, DM,
                                              0,0,0, ls2, p_x1, nullptr); }

    // ---- 3. MoE (top-2 sparse) ----
    rmsnorm_bf_k<<<NTOK, 256>>>(p_x2, rms3_w, b_xf);
    {   dim3 g(512/128, NTOK/128, 1);   // raw gate logits (bias+relu in gate2)
        bgemm_k<<<g, 256>>>(b_xf, b_Wg1, p_g1, NTOK, 512, DM, DM, 512, 512); }
    gate2_k<<<NTOK, 64>>>(p_g1, bg1, Wg2, p_gs, p_topi, p_topw, p_cnt);
    if (out_size > NTOK*DM)
        bal_k<<<1, 256>>>(p_gs, out + (long)NTOK*DM);
    assign_k<<<(NTOK*2+255)/256, 256>>>(p_topi, p_cnt, p_slot);
    gather_k<<<NTOK*2, 128>>>(b_xf, p_slot, b_xg);
    {   dim3 g12(2*DFF/128, NTOK/256, NEXP);
        bgemm256_k<3,1><<<g12, 256, DSMEM256>>>(b_xg, b_w12, b_h,
                                      NTOK, 2*DFF, DM, DM, 2*DFF, 2*DFF,
                                      (long)NTOK*DM, (long)DM*2*DFF, (long)NTOK*DFF,
                                      nullptr, nullptr, p_cnt);
    }
    {   dim3 g3(DM/128, NTOK/256, NEXP);
        bgemm256_k<0,1><<<g3, 256, DSMEM256>>>(b_h, b_w3, b_eo,
                                     NTOK, DM, DFF, DFF, DM, DM,
                                     (long)NTOK*DFF, (long)DFF*DM, (long)NTOK*DM,
                                     nullptr, nullptr, p_cnt);
    }
    combine2_k<<<(int)(((long)NTOK*DM+255)/256), 256>>>(p_x2, ls3, b_eo, p_slot, p_topw, out);
}

// round 14
// speedup vs baseline: 10.6791x; 1.0078x over previous
#include <cuda_runtime.h>
#include <cuda_bf16.h>
#include <math.h>

#define BB   2
#define LSEQ 2048
#define DM   1024
#define DI   2048
#define NH   8
#define DH   128
#define NEXP 4
#define DFF  4096
#define NTOK (BB*LSEQ)   // 4096
#define NCH  16
#define CLEN 128         // LSEQ/NCH

typedef __nv_bfloat16 bf16;

// ---------------- static scratch ----------------
__device__ float g_xz[NTOK*2*DI];
__device__ float g_xc[NTOK*DI];
__device__ float g_dtBC[NTOK*64];
__device__ float g_scanp[NTOK*48];
__device__ float g_x1[NTOK*DM];
__device__ float g_x2[NTOK*DM];
__device__ float g_g1[NTOK*512];
__device__ float g_gs[NTOK*NEXP];
__device__ int   g_topi[NTOK*2];
__device__ float g_topw[NTOK*2];
__device__ int   g_cnt[NEXP];
__device__ int   g_slot[NTOK*2];
__device__ float g_hend[BB*NCH*DI*16];
__device__ float g_h0[BB*NCH*DI*16];
__device__ float g_P[BB*NCH*16];

// bf16 activations
__device__ bf16 g_rms1b[NTOK*DM];
__device__ bf16 g_xcb[NTOK*DI];
__device__ bf16 g_ymulb[NTOK*DI];
__device__ bf16 g_rms2b[NTOK*DM];
__device__ bf16 g_qkvb[NTOK*3*DM];
__device__ bf16 g_qb[NTOK*DM];
__device__ bf16 g_kb[NTOK*DM];
__device__ bf16 g_vb[NTOK*DM];
__device__ bf16 g_attb[NTOK*DM];
__device__ bf16 g_xfb[NTOK*DM];
__device__ bf16 g_xgb[NEXP*NTOK*DM];
__device__ bf16 g_hb[(long)NEXP*NTOK*DFF];
__device__ bf16 g_eob[NEXP*NTOK*DM];

// bf16 weights
__device__ bf16 g_Winb[DM*2*DI];
__device__ bf16 g_Woutb[DI*DM];
__device__ bf16 g_Wqkvb[DM*3*DM];
__device__ bf16 g_Wob[DM*DM];
__device__ bf16 g_Wg1b[DM*512];
__device__ bf16 g_w12b[(long)NEXP*DM*2*DFF];   // interleaved (w1_j, w2_j) pairs
__device__ bf16 g_w3b[(long)NEXP*DFF*DM];
__device__ bf16 g_Wcatb[DI*64];

__device__ __forceinline__ float siluf(float x){ return x / (1.f + expf(-x)); }

// ---------------- merged fp32 -> bf16 conversions (6 segments) ----------------
__global__ void convall_k(const float* __restrict__ s0, bf16* __restrict__ d0, long n0,
                          const float* __restrict__ s1, bf16* __restrict__ d1, long n1,
                          const float* __restrict__ s2, bf16* __restrict__ d2, long n2,
                          const float* __restrict__ s3, bf16* __restrict__ d3, long n3,
                          const float* __restrict__ s4, bf16* __restrict__ d4, long n4,
                          const float* __restrict__ s5, bf16* __restrict__ d5, long n5){
    long i = ((long)blockIdx.x*blockDim.x + threadIdx.x)*4;
    const float* s; bf16* d;
    if (i < n0){ s = s0; d = d0; }
    else { i -= n0;
    if (i < n1){ s = s1; d = d1; }
    else { i -= n1;
    if (i < n2){ s = s2; d = d2; }
    else { i -= n2;
    if (i < n3){ s = s3; d = d3; }
    else { i -= n3;
    if (i < n4){ s = s4; d = d4; }
    else { i -= n4;
    if (i >= n5) return;
    s = s5; d = d5; }}}}}
    float4 v = *reinterpret_cast<const float4*>(s + i);
    *reinterpret_cast<__nv_bfloat162*>(d + i)     = __floats2bfloat162_rn(v.x, v.y);
    *reinterpret_cast<__nv_bfloat162*>(d + i + 2) = __floats2bfloat162_rn(v.z, v.w);
}

// pack w1|w2 INTERLEAVED
__global__ void pack12_k(const float* __restrict__ w1, const float* __restrict__ w2,
                         bf16* __restrict__ o){
    long i = ((long)blockIdx.x*blockDim.x + threadIdx.x)*4;
    if (i >= (long)NEXP*DM*DFF) return;
    long row = i >> 12;
    int  j   = (int)(i & 4095);
    float4 a = *reinterpret_cast<const float4*>(w1 + i);
    float4 b = *reinterpret_cast<const float4*>(w2 + i);
    bf16* d1 = o + row*(2*DFF) + 2*j;
    *reinterpret_cast<__nv_bfloat162*>(d1)   = __floats2bfloat162_rn(a.x, b.x);
    *reinterpret_cast<__nv_bfloat162*>(d1+2) = __floats2bfloat162_rn(a.y, b.y);
    *reinterpret_cast<__nv_bfloat162*>(d1+4) = __floats2bfloat162_rn(a.z, b.z);
    *reinterpret_cast<__nv_bfloat162*>(d1+6) = __floats2bfloat162_rn(a.w, b.w);
}

// pack [W_dt | W_B | W_C | 0] -> [2048][64] bf16
__global__ void packw_k(const float* __restrict__ Wdt, const float* __restrict__ WB,
                        const float* __restrict__ WC, bf16* __restrict__ o){
    int idx = blockIdx.x*256 + threadIdx.x;
    if (idx >= DI*64) return;
    int j = idx >> 6, n = idx & 63;
    float v = 0.f;
    if (n < 16) v = Wdt[j*16+n];
    else if (n < 32) v = WB[j*16+n-16];
    else if (n < 48) v = WC[j*16+n-32];
    o[idx] = __float2bfloat16(v);
}

// ---------------- RMSNorm -> bf16 (vectorized, warp reduce) ----------------
__global__ void rmsnorm_bf_k(const float* __restrict__ x, const float* __restrict__ w,
                             bf16* __restrict__ o){
    int row = blockIdx.x;
    int tid = threadIdx.x;
    const float* xr = x + (long)row*DM;
    float4 v = *reinterpret_cast<const float4*>(xr + tid*4);
    float s = v.x*v.x + v.y*v.y + v.z*v.z + v.w*v.w;
    #pragma unroll
    for (int off = 16; off > 0; off >>= 1)
        s += __shfl_xor_sync(0xffffffffu, s, off);
    __shared__ float red[8];
    if ((tid & 31) == 0) red[tid >> 5] = s;
    __syncthreads();
    float tot = red[0] + red[1] + red[2] + red[3]
              + red[4] + red[5] + red[6] + red[7];
    float r = rsqrtf(tot/(float)DM + 1e-6f);
    float4 wv = *reinterpret_cast<const float4*>(w + tid*4);
    bf16* ob = o + (long)row*DM + tid*4;
    *reinterpret_cast<__nv_bfloat162*>(ob)   = __floats2bfloat162_rn(wv.x*v.x*r, wv.y*v.y*r);
    *reinterpret_cast<__nv_bfloat162*>(ob+2) = __floats2bfloat162_rn(wv.z*v.z*r, wv.w*v.w*r);
}

// ---------------- MMA primitives ----------------
__device__ __forceinline__ void cpasync16(unsigned dst, const void* src, int ssz){
    asm volatile("cp.async.ca.shared.global [%0], [%1], 16, %2;"
        :: "r"(dst), "l"(src), "r"(ssz));
}
__device__ __forceinline__ void cp_commit(){ asm volatile("cp.async.commit_group;"); }
__device__ __forceinline__ void cp_wait0(){ asm volatile("cp.async.wait_group 0;"); }
__device__ __forceinline__ void cp_wait1(){ asm volatile("cp.async.wait_group 1;"); }
__device__ __forceinline__ void ldsm_x4(unsigned saddr, unsigned &o0, unsigned &o1,
                                        unsigned &o2, unsigned &o3){
    asm volatile("ldmatrix.sync.aligned.m8n8.x4.shared.b16 {%0,%1,%2,%3},[%4];"
        : "=r"(o0),"=r"(o1),"=r"(o2),"=r"(o3) : "r"(saddr));
}
__device__ __forceinline__ void ldsm_x4_t(unsigned saddr, unsigned &o0, unsigned &o1,
                                          unsigned &o2, unsigned &o3){
    asm volatile("ldmatrix.sync.aligned.m8n8.x4.trans.shared.b16 {%0,%1,%2,%3},[%4];"
        : "=r"(o0),"=r"(o1),"=r"(o2),"=r"(o3) : "r"(saddr));
}
__device__ __forceinline__ void mma16816(float* d, const unsigned* am, const unsigned* bm){
    asm volatile("mma.sync.aligned.m16n8k16.row.col.f32.bf16.bf16.f32 "
        "{%0,%1,%2,%3},{%4,%5,%6,%7},{%8,%9},{%0,%1,%2,%3};"
        : "+f"(d[0]),"+f"(d[1]),"+f"(d[2]),"+f"(d[3])
        : "r"(am[0]),"r"(am[1]),"r"(am[2]),"r"(am[3]), "r"(bm[0]),"r"(bm[1]));
}
__device__ __forceinline__ unsigned pkbf2(float x, float y){
    __nv_bfloat162 t = __floats2bfloat162_rn(x, y);
    return *reinterpret_cast<unsigned*>(&t);
}

// ---------------- 128x128 GEMM (fp32 out, no epilogue) ----------------
__device__ __forceinline__ void stage_tiles(const bf16* Ab, const bf16* Bb,
    int bm, int bn, int N, int lda, int ldb, int k0, int tid,
    unsigned Adst, unsigned Bdst)
{
    #pragma unroll
    for (int c = tid; c < 512; c += 256){
        int r  = c >> 2;
        int ko = (c & 3) << 3;
        cpasync16(Adst + 2u*(unsigned)(r*40 + ko),
                  Ab + (long)(bm + r)*lda + k0 + ko, 16);
    }
    #pragma unroll
    for (int c = tid; c < 512; c += 256){
        int r  = c >> 4;
        int no = (c & 15) << 3;
        const bf16* src = Bb + (long)(k0 + r)*ldb + bn + no;
        int ssz = 16;
        if (bn + no >= N){ src = Bb; ssz = 0; }
        cpasync16(Bdst + 2u*(unsigned)(r*136 + no), src, ssz);
    }
}

__global__ void __launch_bounds__(256) bgemm_k(
    const bf16* __restrict__ Aptr, const bf16* __restrict__ Bptr, float* __restrict__ Cv,
    int M, int N, int K, int lda, int ldb, int ldc)
{
    __shared__ bf16 As[3*5120];
    __shared__ bf16 Bs[3*5120];
    const int bm = blockIdx.y * 128;
    const int bn = blockIdx.x * 128;
    const int tid  = threadIdx.x;
    const int lane = tid & 31;
    const int warp = tid >> 5;
    const int wm = warp >> 1;
    const int wn = warp & 1;

    float acc[2][8][4];
    #pragma unroll
    for (int i = 0; i < 2; i++)
        #pragma unroll
        for (int j = 0; j < 8; j++)
            #pragma unroll
            for (int q = 0; q < 4; q++) acc[i][j][q] = 0.f;

    unsigned Afrag[2][4];
    unsigned Bfrag[8][2];

    const unsigned As_base = (unsigned)__cvta_generic_to_shared(As);
    const unsigned Bs_base = (unsigned)__cvta_generic_to_shared(Bs);

    const int rowA = wm*32 + (lane & 15);
    const int colA = (lane >> 4) * 8;
    unsigned aoff0 = As_base + 2u*(unsigned)( rowA       *40 + colA);
    unsigned aoff1 = As_base + 2u*(unsigned)((rowA + 16) *40 + colA);

    unsigned boff[4];
    #pragma unroll
    for (int p = 0; p < 4; p++){
        int brow = lane & 15;
        int bcol = (lane >> 4) * 8;
        boff[p] = Bs_base + 2u*(unsigned)(brow*136 + wn*64 + p*16 + bcol);
    }

    const int nk = K >> 5;
    stage_tiles(Aptr, Bptr, bm, bn, N, lda, ldb, 0, tid, As_base, Bs_base);
    cp_commit();
    if (nk > 1){
        stage_tiles(Aptr, Bptr, bm, bn, N, lda, ldb, 32, tid,
                    As_base + 10240u, Bs_base + 10240u);
        cp_commit();
    }

    unsigned sb = 0u;
    for (int it = 0; it < nk; it++){
        if (it + 1 < nk) cp_wait1(); else cp_wait0();
        __syncthreads();
        if (it + 2 < nk){
            unsigned off = (unsigned)((it + 2) % 3) * 10240u;
            stage_tiles(Aptr, Bptr, bm, bn, N, lda, ldb, (it+2) << 5, tid,
                        As_base + off, Bs_base + off);
            cp_commit();
        }
        #pragma unroll
        for (int ks = 0; ks < 32; ks += 16){
            ldsm_x4(aoff0 + sb + 2u*ks, Afrag[0][0], Afrag[0][1], Afrag[0][2], Afrag[0][3]);
            ldsm_x4(aoff1 + sb + 2u*ks, Afrag[1][0], Afrag[1][1], Afrag[1][2], Afrag[1][3]);
            #pragma unroll
            for (int p = 0; p < 4; p++){
                unsigned ba = boff[p] + sb + 2u*(unsigned)(ks*136);
                ldsm_x4_t(ba, Bfrag[2*p][0], Bfrag[2*p][1],
                              Bfrag[2*p+1][0], Bfrag[2*p+1][1]);
            }
            #pragma unroll
            for (int mt = 0; mt < 2; mt++)
                #pragma unroll
                for (int nt = 0; nt < 8; nt++)
                    mma16816(acc[mt][nt], Afrag[mt], Bfrag[nt]);
        }
        sb += 10240u;
        if (sb == 30720u) sb = 0u;
    }

    #pragma unroll
    for (int mt = 0; mt < 2; mt++){
        int r0 = bm + wm*32 + mt*16 + (lane >> 2);
        #pragma unroll
        for (int nt = 0; nt < 8; nt++){
            int col = bn + wn*64 + nt*8 + ((lane & 3) << 1);
            if (col < N){
                *reinterpret_cast<float2*>(&Cv[(long)r0*ldc + col]) =
                    make_float2(acc[mt][nt][0], acc[mt][nt][1]);
                *reinterpret_cast<float2*>(&Cv[(long)(r0+8)*ldc + col]) =
                    make_float2(acc[mt][nt][2], acc[mt][nt][3]);
            }
        }
    }
}

// ---------------- 256x128 GEMM, 3 slots x 64-K groups, dynamic smem ----------------
#define GSLOT_A 40960u
#define GSLOT_B 17408u
#define DSMEM256 (3*(GSLOT_A + GSLOT_B))   // 175104 bytes

__device__ __forceinline__ void stage256(const bf16* Ab, const bf16* Bb,
    int bm, int bn, int N, int lda, int ldb, int k0, int tid,
    unsigned Adst, unsigned Bdst)
{
    #pragma unroll
    for (int c = tid; c < 1024; c += 256){
        int r  = c >> 2;
        int ko = (c & 3) << 3;
        cpasync16(Adst + 2u*(unsigned)(r*40 + ko),
                  Ab + (long)(bm + r)*lda + k0 + ko, 16);
    }
    #pragma unroll
    for (int c = tid; c < 512; c += 256){
        int r  = c >> 4;
        int no = (c & 15) << 3;
        const bf16* src = Bb + (long)(k0 + r)*ldb + bn + no;
        int ssz = 16;
        if (bn + no >= N){ src = Bb; ssz = 0; }
        cpasync16(Bdst + 2u*(unsigned)(r*136 + no), src, ssz);
    }
}

// EPI: 0 none, 1 relu(acc+bias) fp32, 2 resid fp32, 3 siluGLU bf16
template<int EPI, int OUTBF>
__global__ void __launch_bounds__(256) bgemm256_k(
    const bf16* __restrict__ Aptr, const bf16* __restrict__ Bptr, void* __restrict__ Cv,
    int M, int N, int K, int lda, int ldb, int ldc,
    long sA, long sB, long sC, const float* __restrict__ bias,
    const float* __restrict__ resx, const int* __restrict__ mcnt)
{
    extern __shared__ bf16 dsm[];
    const int bm = blockIdx.y * 256;
    int Meff = M;
    if (mcnt) Meff = mcnt[blockIdx.z];
    if (bm >= Meff) return;
    const bf16* Ab = Aptr + (long)blockIdx.z * sA;
    const bf16* Bb = Bptr + (long)blockIdx.z * sB;
    const int bn = blockIdx.x * 128;
    const int tid  = threadIdx.x;
    const int lane = tid & 31;
    const int warp = tid >> 5;
    const int wm = warp >> 1;
    const int wn = warp & 1;

    float acc[4][8][4];
    #pragma unroll
    for (int i = 0; i < 4; i++)
        #pragma unroll
        for (int j = 0; j < 8; j++)
            #pragma unroll
            for (int q = 0; q < 4; q++) acc[i][j][q] = 0.f;

    unsigned Afrag[4][4];
    unsigned Bfrag[8][2];

    const unsigned As_base = (unsigned)__cvta_generic_to_shared(dsm);
    const unsigned Bs_base = As_base + 3u*GSLOT_A;

    const int rowA = wm*64 + (lane & 15);
    const int colA = (lane >> 4) * 8;
    unsigned aoff[4];
    #pragma unroll
    for (int mt = 0; mt < 4; mt++)
        aoff[mt] = As_base + 2u*(unsigned)((rowA + mt*16)*40 + colA);

    unsigned boff[4];
    {
        int brow = lane & 15;
        int bcol = (lane >> 4) * 8;
        #pragma unroll
        for (int p = 0; p < 4; p++)
            boff[p] = Bs_base + 2u*(unsigned)(brow*136 + wn*64 + p*16 + bcol);
    }

    const int ng = K >> 6;
    stage256(Ab, Bb, bm, bn, N, lda, ldb, 0,  tid, As_base,           Bs_base);
    stage256(Ab, Bb, bm, bn, N, lda, ldb, 32, tid, As_base + 20480u,  Bs_base + 8704u);
    cp_commit();
    if (ng > 1){
        stage256(Ab, Bb, bm, bn, N, lda, ldb, 64, tid, As_base + GSLOT_A,           Bs_base + GSLOT_B);
        stage256(Ab, Bb, bm, bn, N, lda, ldb, 96, tid, As_base + GSLOT_A + 20480u,  Bs_base + GSLOT_B + 8704u);
        cp_commit();
    }

    for (int g = 0; g < ng; g++){
        if (g + 1 < ng) cp_wait1(); else cp_wait0();
        __syncthreads();
        if (g + 2 < ng){
            unsigned sl = (unsigned)((g + 2) % 3);
            int k0 = (g + 2) << 6;
            stage256(Ab, Bb, bm, bn, N, lda, ldb, k0,      tid,
                     As_base + sl*GSLOT_A,           Bs_base + sl*GSLOT_B);
            stage256(Ab, Bb, bm, bn, N, lda, ldb, k0 + 32, tid,
                     As_base + sl*GSLOT_A + 20480u,  Bs_base + sl*GSLOT_B + 8704u);
            cp_commit();
        }
        unsigned slA = (unsigned)(g % 3) * GSLOT_A;
        unsigned slB = (unsigned)(g % 3) * GSLOT_B;
        #pragma unroll
        for (int sub = 0; sub < 2; sub++){
            unsigned sa  = slA + (unsigned)sub*20480u;
            unsigned sbb = slB + (unsigned)sub*8704u;
            #pragma unroll
            for (int ks = 0; ks < 32; ks += 16){
                #pragma unroll
                for (int mt = 0; mt < 4; mt++)
                    ldsm_x4(aoff[mt] + sa + 2u*ks,
                            Afrag[mt][0], Afrag[mt][1], Afrag[mt][2], Afrag[mt][3]);
                #pragma unroll
                for (int p = 0; p < 4; p++){
                    unsigned ba = boff[p] + sbb + 2u*(unsigned)(ks*136);
                    ldsm_x4_t(ba, Bfrag[2*p][0], Bfrag[2*p][1],
                                  Bfrag[2*p+1][0], Bfrag[2*p+1][1]);
                }
                #pragma unroll
                for (int mt = 0; mt < 4; mt++)
                    #pragma unroll
                    for (int nt = 0; nt < 8; nt++)
                        mma16816(acc[mt][nt], Afrag[mt], Bfrag[nt]);
            }
        }
    }

    #pragma unroll
    for (int mt = 0; mt < 4; mt++){
        int r0 = bm + wm*64 + mt*16 + (lane >> 2);
        #pragma unroll
        for (int nt = 0; nt < 8; nt++){
            int col = bn + wn*64 + nt*8 + ((lane & 3) << 1);
            if (col < N){
                float v0 = acc[mt][nt][0];
                float v1 = acc[mt][nt][1];
                float v2 = acc[mt][nt][2];
                float v3 = acc[mt][nt][3];
                if (EPI == 3){
                    bf16* Cb = (bf16*)Cv + (long)blockIdx.z * sC;
                    int jc = col >> 1;
                    Cb[(long)r0*(N>>1) + jc]     = __float2bfloat16(siluf(v0)*v1);
                    Cb[(long)(r0+8)*(N>>1) + jc] = __float2bfloat16(siluf(v2)*v3);
                    continue;
                }
                if (EPI == 1){
                    float b0 = bias[col];
                    float b1 = bias[col+1];
                    v0 = fmaxf(v0+b0, 0.f); v1 = fmaxf(v1+b1, 0.f);
                    v2 = fmaxf(v2+b0, 0.f); v3 = fmaxf(v3+b1, 0.f);
                }
                if (EPI == 2){
                    float b0 = bias[col];
                    float b1 = bias[col+1];
                    v0 = fmaf(b0, v0, resx[(long)r0*ldc + col]);
                    v1 = fmaf(b1, v1, resx[(long)r0*ldc + col + 1]);
                    v2 = fmaf(b0, v2, resx[(long)(r0+8)*ldc + col]);
                    v3 = fmaf(b1, v3, resx[(long)(r0+8)*ldc + col + 1]);
                }
                if (OUTBF){
                    bf16* Cb = (bf16*)Cv + (long)blockIdx.z * sC;
                    *reinterpret_cast<__nv_bfloat162*>(&Cb[(long)r0*ldc + col]) =
                        __floats2bfloat162_rn(v0, v1);
                    *reinterpret_cast<__nv_bfloat162*>(&Cb[(long)(r0+8)*ldc + col]) =
                        __floats2bfloat162_rn(v2, v3);
                } else {
                    float* Cb = (float*)Cv + (long)blockIdx.z * sC;
                    *reinterpret_cast<float2*>(&Cb[(long)r0*ldc + col]) = make_float2(v0, v1);
                    *reinterpret_cast<float2*>(&Cb[(long)(r0+8)*ldc + col]) = make_float2(v2, v3);
                }
            }
        }
    }
}

// ---------------- fused flash attention ----------------
#define FTILE (128*136)
#define FSMEM (5*FTILE*2)

__device__ __forceinline__ void fstage(const bf16* src, unsigned dst, int tid){
    for (int i = tid; i < 2048; i += 256){
        int r = i >> 4, c = (i & 15) << 3;
        cpasync16(dst + 2u*(unsigned)(r*136 + c), src + r*DH + c, 16);
    }
}

__global__ void __launch_bounds__(256, 1) flash_k(
    const bf16* __restrict__ q, const bf16* __restrict__ k, const bf16* __restrict__ v,
    const float* __restrict__ ascale, bf16* __restrict__ att)
{
    extern __shared__ bf16 fs[];
    const int qt = blockIdx.x, bh = blockIdx.y;
    const int bb = bh >> 3, hh = bh & 7;
    const int tid = threadIdx.x, lane = tid & 31, w = tid >> 5;
    const float a = ascale[hh];

    const bf16* qg = q + ((long)bh*LSEQ + qt*128)*DH;
    const bf16* kg = k + (long)bh*LSEQ*DH;
    const bf16* vg = v + (long)bh*LSEQ*DH;

    const unsigned Qb = (unsigned)__cvta_generic_to_shared(fs);
    const unsigned Kb = Qb + 2u*FTILE;
    const unsigned Vb = Qb + 6u*FTILE;
    const unsigned TILEB = 2u*FTILE;

    fstage(qg, Qb, tid);
    fstage(kg, Kb, tid);
    fstage(vg, Vb, tid);
    cp_commit();
    cp_wait0();
    __syncthreads();

    unsigned qf[8][4];
    {
        int rq = w*16 + (lane & 15);
        int cq = (lane >> 4) << 3;
        #pragma unroll
        for (int ks = 0; ks < 8; ks++)
            ldsm_x4(Qb + 2u*(unsigned)(rq*136 + ks*16 + cq),
                    qf[ks][0], qf[ks][1], qf[ks][2], qf[ks][3]);
    }

    const int brow = (lane & 7) + (((lane >> 4) & 1) << 3);
    const int bcol = ((lane >> 3) & 1) << 3;
    unsigned kadr[8], vadr[8];
    #pragma unroll
    for (int p = 0; p < 8; p++){
        kadr[p] = Kb + 2u*(unsigned)((p*16 + brow)*136 + bcol);
        vadr[p] = Vb + 2u*(unsigned)((lane & 15)*136 + p*16 + ((lane >> 4) << 3));
    }

    float oacc[16][4];
    #pragma unroll
    for (int nt = 0; nt < 16; nt++)
        #pragma unroll
        for (int qq = 0; qq < 4; qq++) oacc[nt][qq] = 0.f;
    float m0 = -1e30f, m1 = -1e30f, l0 = 0.f, l1 = 0.f;

    for (int kt = 0; kt < 16; kt++){
        if (kt > 0){ cp_wait0(); __syncthreads(); }
        if (kt + 1 < 16){
            unsigned off = ((kt + 1) & 1) ? TILEB : 0u;
            fstage(kg + (long)(kt+1)*128*DH, Kb + off, tid);
            fstage(vg + (long)(kt+1)*128*DH, Vb + off, tid);
            cp_commit();
        }
        const unsigned sb = (kt & 1) ? TILEB : 0u;

        float sacc[16][4];
        #pragma unroll
        for (int nt = 0; nt < 16; nt++)
            #pragma unroll
            for (int qq = 0; qq < 4; qq++) sacc[nt][qq] = 0.f;

        #pragma unroll
        for (int ks = 0; ks < 8; ks++){
            #pragma unroll
            for (int p = 0; p < 8; p++){
                unsigned bf0[2], bf1[2];
                ldsm_x4(kadr[p] + sb + 2u*(unsigned)(ks*16),
                        bf0[0], bf0[1], bf1[0], bf1[1]);
                mma16816(sacc[2*p],   qf[ks], bf0);
                mma16816(sacc[2*p+1], qf[ks], bf1);
            }
        }

        float ax0 = -1e30f, ax1 = -1e30f;
        #pragma unroll
        for (int nt = 0; nt < 16; nt++){
            sacc[nt][0] *= a; sacc[nt][1] *= a; sacc[nt][2] *= a; sacc[nt][3] *= a;
            ax0 = fmaxf(ax0, fmaxf(sacc[nt][0], sacc[nt][1]));
            ax1 = fmaxf(ax1, fmaxf(sacc[nt][2], sacc[nt][3]));
        }
        ax0 = fmaxf(ax0, __shfl_xor_sync(0xffffffffu, ax0, 1));
        ax0 = fmaxf(ax0, __shfl_xor_sync(0xffffffffu, ax0, 2));
        ax1 = fmaxf(ax1, __shfl_xor_sync(0xffffffffu, ax1, 1));
        ax1 = fmaxf(ax1, __shfl_xor_sync(0xffffffffu, ax1, 2));
        float mn0 = fmaxf(m0, ax0), mn1 = fmaxf(m1, ax1);
        float f0 = expf(m0 - mn0), f1 = expf(m1 - mn1);

        float rs0 = 0.f, rs1 = 0.f;
        #pragma unroll
        for (int nt = 0; nt < 16; nt++){
            sacc[nt][0] = expf(sacc[nt][0] - mn0);
            sacc[nt][1] = expf(sacc[nt][1] - mn0);
            sacc[nt][2] = expf(sacc[nt][2] - mn1);
            sacc[nt][3] = expf(sacc[nt][3] - mn1);
            rs0 += sacc[nt][0] + sacc[nt][1];
            rs1 += sacc[nt][2] + sacc[nt][3];
        }
        rs0 += __shfl_xor_sync(0xffffffffu, rs0, 1);
        rs0 += __shfl_xor_sync(0xffffffffu, rs0, 2);
        rs1 += __shfl_xor_sync(0xffffffffu, rs1, 1);
        rs1 += __shfl_xor_sync(0xffffffffu, rs1, 2);
        l0 = l0*f0 + rs0; l1 = l1*f1 + rs1;
        m0 = mn0; m1 = mn1;

        #pragma unroll
        for (int nt = 0; nt < 16; nt++){
            oacc[nt][0] *= f0; oacc[nt][1] *= f0;
            oacc[nt][2] *= f1; oacc[nt][3] *= f1;
        }

        unsigned pa[8][4];
        #pragma unroll
        for (int ksp = 0; ksp < 8; ksp++){
            pa[ksp][0] = pkbf2(sacc[2*ksp][0],   sacc[2*ksp][1]);
            pa[ksp][1] = pkbf2(sacc[2*ksp][2],   sacc[2*ksp][3]);
            pa[ksp][2] = pkbf2(sacc[2*ksp+1][0], sacc[2*ksp+1][1]);
            pa[ksp][3] = pkbf2(sacc[2*ksp+1][2], sacc[2*ksp+1][3]);
        }

        #pragma unroll
        for (int ksp = 0; ksp < 8; ksp++){
            #pragma unroll
            for (int p = 0; p < 8; p++){
                unsigned bf0[2], bf1[2];
                ldsm_x4_t(vadr[p] + sb + 2u*(unsigned)(ksp*16*136),
                          bf0[0], bf0[1], bf1[0], bf1[1]);
                mma16816(oacc[2*p],   pa[ksp], bf0);
                mma16816(oacc[2*p+1], pa[ksp], bf1);
            }
        }
    }

    float inv0 = 1.f / l0, inv1 = 1.f / l1;
    long row0 = (long)bb*LSEQ + qt*128 + w*16 + (lane >> 2);
    long row1 = row0 + 8;
    int  cbase = hh*DH + ((lane & 3) << 1);
    #pragma unroll
    for (int nt = 0; nt < 16; nt++){
        int col = cbase + nt*8;
        *reinterpret_cast<__nv_bfloat162*>(&att[row0*DM + col]) =
            __floats2bfloat162_rn(oacc[nt][0]*inv0, oacc[nt][1]*inv0);
        *reinterpret_cast<__nv_bfloat162*>(&att[row1*DM + col]) =
            __floats2bfloat162_rn(oacc[nt][2]*inv1, oacc[nt][3]*inv1);
    }
}

// ---------------- depthwise conv + bias + SiLU (4-wide vectorized) ----------------
__global__ void conv_k(const float* __restrict__ xz, const float* __restrict__ cw,
                       const float* __restrict__ cb, float* __restrict__ xc,
                       bf16* __restrict__ xcb){
    long idx4 = (long)blockIdx.x*blockDim.x + threadIdx.x;   // one per 4 elements
    if (idx4 >= (long)NTOK*DI/4) return;
    long idx = idx4 * 4;
    int d = (int)(idx % DI);
    int row = (int)(idx / DI);
    int t = row % LSEQ, b = row / LSEQ;
    float4 s = *reinterpret_cast<const float4*>(cb + d);
    float4 w0 = *reinterpret_cast<const float4*>(cw + d*4);
    float4 w1 = *reinterpret_cast<const float4*>(cw + (d+1)*4);
    float4 w2 = *reinterpret_cast<const float4*>(cw + (d+2)*4);
    float4 w3 = *reinterpret_cast<const float4*>(cw + (d+3)*4);
    const float* base = xz + (long)(b*LSEQ)*(2*DI) + d;
    #pragma unroll
    for (int k = 0; k < 4; k++){
        int tt = t + k - 2;
        if (tt >= 0 && tt < LSEQ){
            float4 xv = *reinterpret_cast<const float4*>(base + (long)tt*(2*DI));
            float wk0 = (k==0)?w0.x:(k==1)?w0.y:(k==2)?w0.z:w0.w;
            float wk1 = (k==0)?w1.x:(k==1)?w1.y:(k==2)?w1.z:w1.w;
            float wk2 = (k==0)?w2.x:(k==1)?w2.y:(k==2)?w2.z:w2.w;
            float wk3 = (k==0)?w3.x:(k==1)?w3.y:(k==2)?w3.z:w3.w;
            s.x = fmaf(wk0, xv.x, s.x);
            s.y = fmaf(wk1, xv.y, s.y);
            s.z = fmaf(wk2, xv.z, s.z);
            s.w = fmaf(wk3, xv.w, s.w);
        }
    }
    float4 v = make_float4(siluf(s.x), siluf(s.y), siluf(s.z), siluf(s.w));
    *reinterpret_cast<float4*>(xc + idx) = v;
    *reinterpret_cast<__nv_bfloat162*>(xcb + idx)     = __floats2bfloat162_rn(v.x, v.y);
    *reinterpret_cast<__nv_bfloat162*>(xcb + idx + 2) = __floats2bfloat162_rn(v.z, v.w);
}

// ---------------- scan preprocessing ----------------
__global__ void scanprep_k(const float* __restrict__ dtBC, const float* __restrict__ bdt,
                           const float* __restrict__ A, float* __restrict__ sp){
    int idx = blockIdx.x*blockDim.x + threadIdx.x;
    if (idx >= NTOK*16) return;
    int n = idx & 15, row = idx >> 4;
    float dtp = dtBC[(long)row*64 + n] + bdt[n];
    float dt  = fmaxf(dtp, 0.f) + log1pf(expf(-fabsf(dtp)));
    sp[(long)row*48 + n]      = expf(dt * A[n]);
    sp[(long)row*48 + 16 + n] = dt * dtBC[(long)row*64 + 16 + n];
    sp[(long)row*48 + 32 + n] = dtBC[(long)row*64 + 32 + n];
}

// ---------------- chunked selective scan ----------------
__global__ void scanP_k(const float* __restrict__ sp, float* __restrict__ P){
    int b = blockIdx.x / NCH, ch = blockIdx.x % NCH;
    int n = threadIdx.x;
    if (n >= 16) return;
    float p = 1.f;
    long base = ((long)b*LSEQ + ch*CLEN)*48;
    for (int t = 0; t < CLEN; t++) p *= sp[base + t*48 + n];
    P[(b*NCH+ch)*16 + n] = p;
}

__global__ void scanA_k(const float* __restrict__ sp, const float* __restrict__ xc,
                        float* __restrict__ hend){
    int b = blockIdx.z, ch = blockIdx.y;
    int d = blockIdx.x*128 + threadIdx.x;
    __shared__ float s[CLEN*48];
    const float* src = sp + ((long)b*LSEQ + ch*CLEN)*48;
    for (int i = threadIdx.x; i < CLEN*48; i += 128) s[i] = src[i];
    __syncthreads();
    float h[16];
    #pragma unroll
    for (int n = 0; n < 16; n++) h[n] = 0.f;
    long rowbase = (long)b*LSEQ + ch*CLEN;
    float xv_next = xc[rowbase*DI + d];
    for (int tt = 0; tt < CLEN; tt++){
        float xv = xv_next;
        if (tt + 1 < CLEN) xv_next = xc[(rowbase + tt + 1)*DI + d];
        const float* e = s + tt*48;
        #pragma unroll
        for (int n = 0; n < 16; n++)
            h[n] = fmaf(e[n], h[n], e[16+n]*xv);
    }
    float* o = hend + (((long)(b*NCH + ch)*DI + d) << 4);
    #pragma unroll
    for (int n = 0; n < 16; n += 4)
        *reinterpret_cast<float4*>(o + n) = make_float4(h[n], h[n+1], h[n+2], h[n+3]);
}

__global__ void scanComb_k(const float* __restrict__ hend, const float* __restrict__ P,
                           float* __restrict__ h0){
    int g = blockIdx.x*128 + threadIdx.x;
    int b = g / DI, d = g % DI;
    __shared__ float sP[NCH*16];
    for (int i = threadIdx.x; i < NCH*16; i += 128) sP[i] = P[b*NCH*16 + i];
    __syncthreads();
    float h[16];
    #pragma unroll
    for (int n = 0; n < 16; n++) h[n] = 0.f;
    {
        float* o = h0 + (((long)(b*NCH)*DI + d) << 4);
        #pragma unroll
        for (int n = 0; n < 16; n += 4)
            *reinterpret_cast<float4*>(o + n) = make_float4(0.f, 0.f, 0.f, 0.f);
    }
    for (int c = 1; c < NCH; c++){
        const float* he = hend + (((long)(b*NCH + c - 1)*DI + d) << 4);
        #pragma unroll
        for (int n = 0; n < 16; n++)
            h[n] = fmaf(sP[(c-1)*16 + n], h[n], he[n]);
        float* o = h0 + (((long)(b*NCH + c)*DI + d) << 4);
        #pragma unroll
        for (int n = 0; n < 16; n += 4)
            *reinterpret_cast<float4*>(o + n) = make_float4(h[n], h[n+1], h[n+2], h[n+3]);
    }
}

__global__ void scanC_k(const float* __restrict__ sp, const float* __restrict__ xc,
                        const float* __restrict__ xz, const float* __restrict__ Dp,
                        const float* __restrict__ h0, bf16* __restrict__ ymulb){
    int b = blockIdx.z, ch = blockIdx.y;
    int d = blockIdx.x*128 + threadIdx.x;
    __shared__ float s[CLEN*48];
    const float* src = sp + ((long)b*LSEQ + ch*CLEN)*48;
    for (int i = threadIdx.x; i < CLEN*48; i += 128) s[i] = src[i];
    __syncthreads();
    float h[16];
    {   const float* hi = h0 + (((long)(b*NCH + ch)*DI + d) << 4);
        #pragma unroll
        for (int n = 0; n < 16; n += 4){
            float4 v = *reinterpret_cast<const float4*>(hi + n);
            h[n] = v.x; h[n+1] = v.y; h[n+2] = v.z; h[n+3] = v.w;
        }
    }
    const float dpv = Dp[d];
    long rowbase = (long)b*LSEQ + ch*CLEN;
    float xv_next = xc[rowbase*DI + d];
    float z_next  = xz[rowbase*(2*DI) + DI + d];
    for (int tt = 0; tt < CLEN; tt++){
        float xv = xv_next;
        float z  = z_next;
        if (tt + 1 < CLEN){
            xv_next = xc[(rowbase + tt + 1)*DI + d];
            z_next  = xz[(rowbase + tt + 1)*(2*DI) + DI + d];
        }
        const float* e = s + tt*48;
        float y = 0.f;
        #pragma unroll
        for (int n = 0; n < 16; n++){
            h[n] = fmaf(e[n], h[n], e[16+n]*xv);
            y = fmaf(h[n], e[32+n], y);
        }
        ymulb[(rowbase + tt)*DI + d] = __float2bfloat16((y + dpv*xv) * siluf(z));
    }
}

// ---------------- RoPE (bf16 qkv in) -> qb,kb,vb bf16 ----------------
__global__ void rope2_k(const bf16* __restrict__ qkv, bf16* __restrict__ qb,
                        bf16* __restrict__ kb, bf16* __restrict__ vb){
    int row = blockIdx.x;
    int t = row % LSEQ, b = row / LSEQ;
    __shared__ float q[DM], kk[DM];
    const bf16* base = qkv + (long)row*3*DM;
    for (int i = threadIdx.x; i < DM; i += 256){
        q[i]  = __bfloat162float(base[i]);
        kk[i] = __bfloat162float(base[DM+i]);
    }
    __syncthreads();
    const float sq = sqrtf((float)DH);
    const float lg = logf(10000.f) / 64.f;
    for (int idx = threadIdx.x; idx < DM; idx += 256){
        int h = idx / DH, i = idx % DH;
        int j = i & 63;
        float inv = expf(-(float)j * lg);
        float ang = (float)t * inv;
        float c = cosf(ang), s = sinf(ang);
        int off = h * DH;
        float rq, rk;
        if (i < 64){ rq = -q[off + 2*i + 1]; rk = -kk[off + 2*i + 1]; }
        else       { rq =  q[off + 2*(i-64)]; rk =  kk[off + 2*(i-64)]; }
        long o = ((long)(b*NH + h)*LSEQ + t)*DH + i;
        qb[o] = __float2bfloat16((q[idx]*c + rq*s) * sq);
        kb[o] = __float2bfloat16(kk[idx]*c + rk*s);
        vb[o] = base[2*DM + idx];
    }
}

// ---------------- gate stage 2 (bias+relu folded in; zeroes counters) ----------------
__global__ void gate2_k(const float* __restrict__ g1, const float* __restrict__ bg1,
                        const float* __restrict__ Wg2,
                        float* __restrict__ gs, int* __restrict__ topi, float* __restrict__ topw,
                        int* __restrict__ cnt){
    int row = blockIdx.x;
    int tid = threadIdx.x;
    if (row == 0 && tid < NEXP) cnt[tid] = 0;
    __shared__ float red[64*4];
    float a[4] = {0.f,0.f,0.f,0.f};
    for (int j = tid; j < 512; j += 64){
        float v = fmaxf(g1[(long)row*512 + j] + bg1[j], 0.f);
        #pragma unroll
        for (int e = 0; e < 4; e++) a[e] = fmaf(v, Wg2[j*4+e], a[e]);
    }
    #pragma unroll
    for (int e = 0; e < 4; e++) red[e*64 + tid] = a[e];
    __syncthreads();
    for (int st = 32; st > 0; st >>= 1){
        if (tid < st){
            #pragma unroll
            for (int e = 0; e < 4; e++) red[e*64+tid] += red[e*64+tid+st];
        }
        __syncthreads();
    }
    if (tid == 0){
        float l[4]; for (int e = 0; e < 4; e++) l[e] = red[e*64];
        float m = fmaxf(fmaxf(l[0],l[1]), fmaxf(l[2],l[3]));
        float ex[4]; float s = 0.f;
        for (int e = 0; e < 4; e++){ ex[e] = expf(l[e]-m); s += ex[e]; }
        float gsv[4];
        for (int e = 0; e < 4; e++){ gsv[e] = ex[e]/s; gs[(long)row*4+e] = gsv[e]; }
        int i0 = 0;
        for (int e = 1; e < 4; e++) if (gsv[e] > gsv[i0]) i0 = e;
        int i1 = -1;
        for (int e = 0; e < 4; e++) if (e != i0 && (i1 < 0 || gsv[e] > gsv[i1])) i1 = e;
        float v0 = gsv[i0], v1 = gsv[i1];
        float mm = fmaxf(v0, v1);
        float w0 = expf(v0-mm), w1 = expf(v1-mm);
        float ws = w0 + w1;
        topi[row*2] = i0; topi[row*2+1] = i1;
        topw[row*2] = w0/ws; topw[row*2+1] = w1/ws;
    }
}

// ---------------- balance loss ----------------
__global__ void bal_k(const float* __restrict__ gs, float* __restrict__ out){
    int tid = threadIdx.x;
    __shared__ float red[256*4];
    float a[4] = {0.f,0.f,0.f,0.f};
    for (int r = tid; r < NTOK; r += 256){
        #pragma unroll
        for (int e = 0; e < 4; e++) a[e] += gs[(long)r*4+e];
    }
    #pragma unroll
    for (int e = 0; e < 4; e++) red[e*256+tid] = a[e];
    __syncthreads();
    for (int st = 128; st > 0; st >>= 1){
        if (tid < st){
            #pragma unroll
            for (int e = 0; e < 4; e++) red[e*256+tid] += red[e*256+tid+st];
        }
        __syncthreads();
    }
    if (tid == 0){
        float bal = 0.f;
        for (int e = 0; e < 4; e++){
            float gm = red[e*256] / (float)NTOK;
            bal += gm * logf(gm + 1e-8f);
        }
        out[0] = (float)NEXP * bal;
    }
}

// ---------------- MoE routing ----------------
__global__ void assign_k(const int* __restrict__ topi, int* __restrict__ cnt,
                         int* __restrict__ slot){
    int idx = blockIdx.x*256 + threadIdx.x;
    if (idx >= NTOK*2) return;
    int e = topi[idx];
    int s = atomicAdd(&cnt[e], 1);
    slot[idx] = e*NTOK + s;
}

__global__ void gather_k(const bf16* __restrict__ xf, const int* __restrict__ slot,
                         bf16* __restrict__ xg){
    int idx = blockIdx.x;
    int tok = idx >> 1;
    int dst = slot[idx];
    const unsigned* src = reinterpret_cast<const unsigned*>(xf) + (long)tok*(DM/2);
    unsigned* d = reinterpret_cast<unsigned*>(xg) + (long)dst*(DM/2);
    for (int i = threadIdx.x; i < DM/2; i += 128) d[i] = src[i];
}

// ---------------- MoE combine + final residual ----------------
__global__ void combine2_k(const float* __restrict__ x2, const float* __restrict__ ls3,
                           const bf16* __restrict__ eo, const int* __restrict__ slot,
                           const float* __restrict__ topw, float* __restrict__ out){
    long idx = (long)blockIdx.x*blockDim.x + threadIdx.x;
    if (idx >= (long)NTOK*DM) return;
    int row = (int)(idx / DM), d = (int)(idx % DM);
    int s0 = slot[row*2], s1 = slot[row*2+1];
    float m = topw[row*2]   * __bfloat162float(eo[(long)s0*DM + d])
            + topw[row*2+1] * __bfloat162float(eo[(long)s1*DM + d]);
    out[idx] = fmaf(ls3[d], m, x2[idx]);
}

// ============================== host ==============================
#define SYMPF(p, s) do { void* _t; cudaGetSymbolAddress(&_t, s); p = (float*)_t; } while(0)
#define SYMPB(p, s) do { void* _t; cudaGetSymbolAddress(&_t, s); p = (bf16*)_t; } while(0)
#define SYMPI(p, s) do { void* _t; cudaGetSymbolAddress(&_t, s); p = (int*)_t; } while(0)

extern "C" void kernel_launch(void* const* d_in, const int* in_sizes, int n_in,
                              void* d_out, int out_size){
    const float* x      = (const float*)d_in[0];
    const float* rms1_w = (const float*)d_in[1];
    const float* rms2_w = (const float*)d_in[2];
    const float* rms3_w = (const float*)d_in[3];
    const float* ls1    = (const float*)d_in[4];
    const float* ls2    = (const float*)d_in[5];
    const float* ls3    = (const float*)d_in[6];
    const float* W_in   = (const float*)d_in[7];
    const float* conv_w = (const float*)d_in[8];
    const float* conv_b = (const float*)d_in[9];
    const float* W_B    = (const float*)d_in[10];
    const float* W_C    = (const float*)d_in[11];
    const float* W_dt   = (const float*)d_in[12];
    const float* b_dt   = (const float*)d_in[13];
    const float* W_out_m= (const float*)d_in[14];
    const float* Avec   = (const float*)d_in[15];
    const float* Dp     = (const float*)d_in[16];
    const float* W_qkv  = (const float*)d_in[17];
    const float* W_o    = (const float*)d_in[18];
    const float* ascale = (const float*)d_in[19];
    const float* Wg1    = (const float*)d_in[20];
    const float* bg1    = (const float*)d_in[21];
    const float* Wg2    = (const float*)d_in[22];
    const float* w1     = (const float*)d_in[23];
    const float* w2     = (const float*)d_in[24];
    const float* w3     = (const float*)d_in[25];
    float* out = (float*)d_out;

    float *p_xz, *p_xc, *p_dtBC, *p_scanp, *p_x1, *p_x2, *p_g1, *p_gs, *p_topw;
    float *p_hend, *p_h0, *p_P;
    int *p_topi, *p_cnt, *p_slot;
    bf16 *b_rms1, *b_xc, *b_ymul, *b_rms2, *b_qkv, *b_q, *b_k, *b_v, *b_att, *b_xf,
         *b_xg, *b_h, *b_eo;
    bf16 *b_Win, *b_Wout, *b_Wqkv, *b_Wo, *b_Wg1, *b_w12, *b_w3, *b_Wcat;

    SYMPF(p_xz, g_xz); SYMPF(p_xc, g_xc); SYMPF(p_dtBC, g_dtBC); SYMPF(p_scanp, g_scanp);
    SYMPF(p_x1, g_x1);
    SYMPF(p_x2, g_x2); SYMPF(p_g1, g_g1); SYMPF(p_gs, g_gs); SYMPF(p_topw, g_topw);
    SYMPF(p_hend, g_hend); SYMPF(p_h0, g_h0); SYMPF(p_P, g_P);
    SYMPI(p_topi, g_topi); SYMPI(p_cnt, g_cnt); SYMPI(p_slot, g_slot);
    SYMPB(b_rms1, g_rms1b); SYMPB(b_xc, g_xcb); SYMPB(b_ymul, g_ymulb); SYMPB(b_rms2, g_rms2b);
    SYMPB(b_qkv, g_qkvb); SYMPB(b_q, g_qb); SYMPB(b_k, g_kb); SYMPB(b_v, g_vb);
    SYMPB(b_att, g_attb); SYMPB(b_xf, g_xfb); SYMPB(b_xg, g_xgb);
    SYMPB(b_h, g_hb); SYMPB(b_eo, g_eob);
    SYMPB(b_Win, g_Winb); SYMPB(b_Wout, g_Woutb); SYMPB(b_Wqkv, g_Wqkvb); SYMPB(b_Wo, g_Wob);
    SYMPB(b_Wg1, g_Wg1b); SYMPB(b_w12, g_w12b); SYMPB(b_w3, g_w3b); SYMPB(b_Wcat, g_Wcatb);

    cudaFuncSetAttribute(bgemm256_k<0,0>, cudaFuncAttributeMaxDynamicSharedMemorySize, DSMEM256);
    cudaFuncSetAttribute(bgemm256_k<2,0>, cudaFuncAttributeMaxDynamicSharedMemorySize, DSMEM256);
    cudaFuncSetAttribute(bgemm256_k<0,1>, cudaFuncAttributeMaxDynamicSharedMemorySize, DSMEM256);
    cudaFuncSetAttribute(bgemm256_k<3,1>, cudaFuncAttributeMaxDynamicSharedMemorySize, DSMEM256);
    cudaFuncSetAttribute(flash_k, cudaFuncAttributeMaxDynamicSharedMemorySize, FSMEM);

    // ---- weight conversions (merged) ----
    {
        long n0 = (long)DM*2*DI, n1 = (long)DI*DM, n2 = (long)DM*3*DM,
             n3 = (long)DM*DM, n4 = (long)DM*512, n5 = (long)NEXP*DFF*DM;
        long tot = n0+n1+n2+n3+n4+n5;
        convall_k<<<(int)((tot/4 + 255)/256), 256>>>(
            W_in, b_Win, n0,  W_out_m, b_Wout, n1,  W_qkv, b_Wqkv, n2,
            W_o,  b_Wo,  n3,  Wg1,     b_Wg1,  n4,  w3,    b_w3,   n5);
    }
    pack12_k<<<(int)(((long)NEXP*DM*DFF/4 + 255)/256), 256>>>(w1, w2, b_w12);
    packw_k<<<(DI*64+255)/256, 256>>>(W_dt, W_B, W_C, b_Wcat);

    // ---- 1. Mamba ----
    rmsnorm_bf_k<<<NTOK, 256>>>(x, rms1_w, b_rms1);
    {   dim3 g(2*DI/128, NTOK/256, 1);
        bgemm256_k<0,0><<<g, 256, DSMEM256>>>(b_rms1, b_Win, p_xz, NTOK, 2*DI, DM, DM, 2*DI, 2*DI,
                                              0,0,0, nullptr, nullptr, nullptr); }
    conv_k<<<(int)(((long)NTOK*DI/4+255)/256), 256>>>(p_xz, conv_w, conv_b, p_xc, b_xc);
    {   dim3 g(1, NTOK/128, 1);
        bgemm_k<<<g, 256>>>(b_xc, b_Wcat, p_dtBC, NTOK, 64, DI, DI, 64, 64); }
    scanprep_k<<<(NTOK*16+255)/256, 256>>>(p_dtBC, b_dt, Avec, p_scanp);
    scanP_k<<<BB*NCH, 16>>>(p_scanp, p_P);
    {   dim3 g(16, NCH, BB);
        scanA_k<<<g, 128>>>(p_scanp, p_xc, p_hend); }
    scanComb_k<<<BB*DI/128, 128>>>(p_hend, p_P, p_h0);
    {   dim3 g(16, NCH, BB);
        scanC_k<<<g, 128>>>(p_scanp, p_xc, p_xz, Dp, p_h0, b_ymul); }
    {   dim3 g(DM/128, NTOK/256, 1);
        bgemm256_k<2,0><<<g, 256, DSMEM256>>>(b_ymul, b_Wout, p_x1, NTOK, DM, DI, DI, DM, DM,
                                              0,0,0, ls1, x, nullptr); }

    // ---- 2. Attention ----
    rmsnorm_bf_k<<<NTOK, 256>>>(p_x1, rms2_w, b_rms2);
    {   dim3 g(3*DM/128, NTOK/256, 1);
        bgemm256_k<0,1><<<g, 256, DSMEM256>>>(b_rms2, b_Wqkv, b_qkv, NTOK, 3*DM, DM, DM, 3*DM, 3*DM,
                                              0,0,0, nullptr, nullptr, nullptr); }
    rope2_k<<<NTOK, 256>>>(b_qkv, b_q, b_k, b_v);
    {   dim3 g(LSEQ/128, BB*NH, 1);
        flash_k<<<g, 256, FSMEM>>>(b_q, b_k, b_v, ascale, b_att); }
    {   dim3 g(DM/128, NTOK/256, 1);
        bgemm256_k<2,0><<<g, 256, DSMEM256>>>(b_att, b_Wo, p_x2, NTOK, DM, DM, DM, DM, DM,
                                              0,0,0, ls2, p_x1, nullptr); }

    // ---- 3. MoE (top-2 sparse) ----
    rmsnorm_bf_k<<<NTOK, 256>>>(p_x2, rms3_w, b_xf);
    {   dim3 g(512/128, NTOK/128, 1);
        bgemm_k<<<g, 256>>>(b_xf, b_Wg1, p_g1, NTOK, 512, DM, DM, 512, 512); }
    gate2_k<<<NTOK, 64>>>(p_g1, bg1, Wg2, p_gs, p_topi, p_topw, p_cnt);
    if (out_size > NTOK*DM)
        bal_k<<<1, 256>>>(p_gs, out + (long)NTOK*DM);
    assign_k<<<(NTOK*2+255)/256, 256>>>(p_topi, p_cnt, p_slot);
    gather_k<<<NTOK*2, 128>>>(b_xf, p_slot, b_xg);
    {   dim3 g12(2*DFF/128, NTOK/256, NEXP);
        bgemm256_k<3,1><<<g12, 256, DSMEM256>>>(b_xg, b_w12, b_h,
                                      NTOK, 2*DFF, DM, DM, 2*DFF, 2*DFF,
                                      (long)NTOK*DM, (long)DM*2*DFF, (long)NTOK*DFF,
                                      nullptr, nullptr, p_cnt);
    }
    {   dim3 g3(DM/128, NTOK/256, NEXP);
        bgemm256_k<0,1><<<g3, 256, DSMEM256>>>(b_h, b_w3, b_eo,
                                     NTOK, DM, DFF, DFF, DM, DM,
                                     (long)NTOK*DFF, (long)DFF*DM, (long)NTOK*DM,
                                     nullptr, nullptr, p_cnt);
    }
    combine2_k<<<(int)(((long)NTOK*DM+255)/256), 256>>>(p_x2, ls3, b_eo, p_slot, p_topw, out);
}